// round 8
// baseline (speedup 1.0000x reference)
#include <cuda_runtime.h>
#include <cuda_bf16.h>
#include <cstdint>

#define NTg  100000
#define NCg  25000
#define ETTg 800000
#define ECTg 400000
#define HIDg 128

// ------------------------- scratch (device globals; allocation-free) -------------------------
__device__ float g_ht [NTg*HIDg];
__device__ float g_hc [NCg*HIDg];
__device__ float g_hs [NTg*HIDg];
__device__ float g_hd [NTg*HIDg];
__device__ float g_hcs[NCg*HIDg];
__device__ float g_asf[NTg*4];
__device__ float g_adf[NTg*4];
__device__ float g_asr[NTg*4];
__device__ float g_adr[NTg*4];
__device__ float g_adct[NTg*4];
__device__ float g_asct[NCg*4];
__device__ float g_wv [4*128];
__device__ int   g_deg[3*NTg];
__device__ int   g_cur[3*NTg];
__device__ int   g_aux[3*128];
__device__ int   g_csrf[ETTg];
__device__ int   g_csrr[ETTg];
__device__ int   g_csrct[ECTg];
// split weights: 6 slots of up to 128x128 bf16 ([N,K] layout, i.e., W^T)
__device__ __nv_bfloat16 g_whi[6*128*128];
__device__ __nv_bfloat16 g_wlo[6*128*128];

__device__ __forceinline__ float lrelu02(float x) { return x > 0.f ? x : 0.2f * x; }

__device__ __forceinline__ uint32_t smem_u32(const void* p) {
    uint32_t a;
    asm("{ .reg .u64 t; cvta.to.shared.u64 t, %1; cvt.u32.u64 %0, t; }" : "=r"(a) : "l"(p));
    return a;
}

__device__ __forceinline__ void ldm_x4(uint32_t* r, uint32_t addr) {
    asm volatile("ldmatrix.sync.aligned.m8n8.x4.shared.b16 {%0,%1,%2,%3}, [%4];"
                 : "=r"(r[0]), "=r"(r[1]), "=r"(r[2]), "=r"(r[3]) : "r"(addr));
}
__device__ __forceinline__ void mma_bf16(float* c, const uint32_t* a, const uint32_t* b) {
    asm volatile("mma.sync.aligned.m16n8k16.row.col.f32.bf16.bf16.f32 "
                 "{%0,%1,%2,%3}, {%4,%5,%6,%7}, {%8,%9}, {%0,%1,%2,%3};"
                 : "+f"(c[0]), "+f"(c[1]), "+f"(c[2]), "+f"(c[3])
                 : "r"(a[0]), "r"(a[1]), "r"(a[2]), "r"(a[3]), "r"(b[0]), "r"(b[1]));
}

// ------------------- batched W split/transpose: hi/lo[n*K+k] = split(W[k*128+n]) ------------
struct WJobs { const float* W[6]; int K[6]; };

__global__ void wsplit_all(WJobs jobs, __nv_bfloat16* __restrict__ hiB,
                           __nv_bfloat16* __restrict__ loB)
{
    int slot = blockIdx.y;
    const float* W = jobs.W[slot];
    int K = jobs.K[slot];
    __nv_bfloat16* hi = hiB + slot*16384;
    __nv_bfloat16* lo = loB + slot*16384;
    int tot = 128 * K;
    for (int i = blockIdx.x*blockDim.x + threadIdx.x; i < tot; i += gridDim.x*blockDim.x) {
        int n = i / K, k = i - n*K;
        float v = W[k*128 + n];
        __nv_bfloat16 h = __float2bfloat16(v);
        hi[i] = h;
        lo[i] = __float2bfloat16(v - __bfloat162float(h));
    }
}

// ----------------- wv[h*128+k] = sum_c W_ct_dst[k*128 + h*32 + c] * att[h*32+c] -------------
__global__ void wv_kernel(const float* __restrict__ W, const float* __restrict__ att,
                          float* __restrict__ wv)
{
    int i = threadIdx.x;           // 512 threads: k = i>>2, h = i&3
    int k = i >> 2, h = i & 3;
    float s = 0.f;
    #pragma unroll 8
    for (int c = 0; c < 32; c++) s += W[k*128 + h*32 + c] * att[h*32 + c];
    wv[h*128 + k] = s;
}

// --------- a_dct[n,h] = sum_{k=0..127} ht[n,k] * wv[h,k]  (warp per row, FULL reduction) ----
__global__ void attv_kernel(const float* __restrict__ ht, const float* __restrict__ wv,
                            float* __restrict__ out, int n)
{
    int gw   = (blockIdx.x*blockDim.x + threadIdx.x) >> 5;
    int lane = threadIdx.x & 31;
    if (gw >= n) return;
    float4 v = *reinterpret_cast<const float4*>(ht + (size_t)gw*128 + lane*4);
    float p0, p1, p2, p3;
    {
        float4 w0 = *reinterpret_cast<const float4*>(wv + 0*128 + lane*4);
        float4 w1 = *reinterpret_cast<const float4*>(wv + 1*128 + lane*4);
        float4 w2 = *reinterpret_cast<const float4*>(wv + 2*128 + lane*4);
        float4 w3 = *reinterpret_cast<const float4*>(wv + 3*128 + lane*4);
        p0 = v.x*w0.x + v.y*w0.y + v.z*w0.z + v.w*w0.w;
        p1 = v.x*w1.x + v.y*w1.y + v.z*w1.z + v.w*w1.w;
        p2 = v.x*w2.x + v.y*w2.y + v.z*w2.z + v.w*w2.w;
        p3 = v.x*w3.x + v.y*w3.y + v.z*w3.z + v.w*w3.w;
    }
    #pragma unroll
    for (int o = 16; o > 0; o >>= 1) {
        p0 += __shfl_xor_sync(0xffffffffu, p0, o);
        p1 += __shfl_xor_sync(0xffffffffu, p1, o);
        p2 += __shfl_xor_sync(0xffffffffu, p2, o);
        p3 += __shfl_xor_sync(0xffffffffu, p3, o);
    }
    if (lane == 0)
        *reinterpret_cast<float4*>(out + (size_t)gw*4) = make_float4(p0, p1, p2, p3);
}

// ---------------- HMMA GEMM: C[M,128] = A[M,K] @ W[K,128]  (3-split bf16) -------------------
// CTA tile 64x128 (2 CTAs/SM), 8 warps, warp tile 32x32. W^T ([N,K]) pre-split in gmem.
// NATT: 0 = none; 1 = fused logits outS = C.att(attS)
template<int K, bool RELU, bool BIAS, int NATT>
__global__ void __launch_bounds__(256, 2) tc_gemm(
    const float* __restrict__ A, const __nv_bfloat16* __restrict__ Whi,
    const __nv_bfloat16* __restrict__ Wlo, const float* __restrict__ bias,
    float* __restrict__ C, int M,
    const float* __restrict__ attS, float* __restrict__ outS)
{
    constexpr int LDA = K + 8;
    extern __shared__ __nv_bfloat16 smb[];
    __nv_bfloat16* sAhi = smb;                 // 64*LDA
    __nv_bfloat16* sAlo = sAhi + 64*LDA;
    __nv_bfloat16* sWhi = sAlo + 64*LDA;       // 128*LDA
    __nv_bfloat16* sWlo = sWhi + 128*LDA;

    const int tid  = threadIdx.x;
    const int lane = tid & 31;
    const int wid  = tid >> 5;
    const int bm   = blockIdx.x * 64;

    for (int idx = tid; idx < 64*(K/4); idx += 256) {
        int r  = idx / (K/4);
        int k0 = (idx % (K/4)) * 4;
        int row = bm + r;
        float4 v = make_float4(0.f, 0.f, 0.f, 0.f);
        if (row < M) v = *reinterpret_cast<const float4*>(A + (size_t)row*K + k0);
        __nv_bfloat16 h0 = __float2bfloat16(v.x), h1 = __float2bfloat16(v.y);
        __nv_bfloat16 h2 = __float2bfloat16(v.z), h3 = __float2bfloat16(v.w);
        __nv_bfloat16 l0 = __float2bfloat16(v.x - __bfloat162float(h0));
        __nv_bfloat16 l1 = __float2bfloat16(v.y - __bfloat162float(h1));
        __nv_bfloat16 l2 = __float2bfloat16(v.z - __bfloat162float(h2));
        __nv_bfloat16 l3 = __float2bfloat16(v.w - __bfloat162float(h3));
        __nv_bfloat16* pH = sAhi + r*LDA + k0;
        __nv_bfloat16* pL = sAlo + r*LDA + k0;
        *reinterpret_cast<__nv_bfloat162*>(pH)     = __halves2bfloat162(h0, h1);
        *reinterpret_cast<__nv_bfloat162*>(pH + 2) = __halves2bfloat162(h2, h3);
        *reinterpret_cast<__nv_bfloat162*>(pL)     = __halves2bfloat162(l0, l1);
        *reinterpret_cast<__nv_bfloat162*>(pL + 2) = __halves2bfloat162(l2, l3);
    }
    for (int idx = tid; idx < 128*(K/8); idx += 256) {
        int n  = idx / (K/8);
        int k0 = (idx % (K/8)) * 8;
        *reinterpret_cast<uint4*>(sWhi + n*LDA + k0) = *reinterpret_cast<const uint4*>(Whi + (size_t)n*K + k0);
        *reinterpret_cast<uint4*>(sWlo + n*LDA + k0) = *reinterpret_cast<const uint4*>(Wlo + (size_t)n*K + k0);
    }
    __syncthreads();

    const int row0 = (wid & 1) * 32;
    const int col0 = (wid >> 1) * 32;

    uint32_t aB[2][2], bB[2][2];
    {
        int ar = (lane & 15), ac = (lane >> 4) * 8;
        #pragma unroll
        for (int mi = 0; mi < 2; mi++) {
            aB[0][mi] = smem_u32(sAhi + (row0 + mi*16 + ar)*LDA + ac);
            aB[1][mi] = smem_u32(sAlo + (row0 + mi*16 + ar)*LDA + ac);
        }
        int q  = lane >> 3;
        int nr = (q >> 1)*8 + (lane & 7);
        int nc = (q & 1)*8;
        #pragma unroll
        for (int nt = 0; nt < 2; nt++) {
            bB[0][nt] = smem_u32(sWhi + (col0 + nt*16 + nr)*LDA + nc);
            bB[1][nt] = smem_u32(sWlo + (col0 + nt*16 + nr)*LDA + nc);
        }
    }

    float acc[2][4][4];
    #pragma unroll
    for (int mi = 0; mi < 2; mi++)
        #pragma unroll
        for (int ni = 0; ni < 4; ni++)
            { acc[mi][ni][0]=0.f; acc[mi][ni][1]=0.f; acc[mi][ni][2]=0.f; acc[mi][ni][3]=0.f; }

    #pragma unroll 2
    for (int ks = 0; ks < K/16; ks++) {
        uint32_t koff = (uint32_t)ks * 32u;
        uint32_t ah[2][4], al[2][4], bh[2][4], bl[2][4];
        #pragma unroll
        for (int mi = 0; mi < 2; mi++) { ldm_x4(ah[mi], aB[0][mi] + koff); ldm_x4(al[mi], aB[1][mi] + koff); }
        #pragma unroll
        for (int nt = 0; nt < 2; nt++) { ldm_x4(bh[nt], bB[0][nt] + koff); ldm_x4(bl[nt], bB[1][nt] + koff); }
        #pragma unroll
        for (int mi = 0; mi < 2; mi++)
            #pragma unroll
            for (int nt = 0; nt < 2; nt++) {
                mma_bf16(acc[mi][nt*2],   ah[mi], &bh[nt][0]);
                mma_bf16(acc[mi][nt*2+1], ah[mi], &bh[nt][2]);
                mma_bf16(acc[mi][nt*2],   ah[mi], &bl[nt][0]);
                mma_bf16(acc[mi][nt*2+1], ah[mi], &bl[nt][2]);
                mma_bf16(acc[mi][nt*2],   al[mi], &bh[nt][0]);
                mma_bf16(acc[mi][nt*2+1], al[mi], &bh[nt][2]);
            }
    }

    const int g = lane >> 2, t = lane & 3;
    float lsS[2][2];
    if (NATT >= 1) { lsS[0][0]=0.f; lsS[0][1]=0.f; lsS[1][0]=0.f; lsS[1][1]=0.f; }
    #pragma unroll
    for (int mi = 0; mi < 2; mi++) {
        #pragma unroll
        for (int ni = 0; ni < 4; ni++) {
            int cc = col0 + ni*8 + t*2;
            float bx = 0.f, by = 0.f;
            if (BIAS) { bx = bias[cc]; by = bias[cc+1]; }
            int r1 = bm + row0 + mi*16 + g;
            float2 v0 = make_float2(acc[mi][ni][0] + bx, acc[mi][ni][1] + by);
            float2 v1 = make_float2(acc[mi][ni][2] + bx, acc[mi][ni][3] + by);
            if (RELU) {
                v0.x = fmaxf(v0.x, 0.f); v0.y = fmaxf(v0.y, 0.f);
                v1.x = fmaxf(v1.x, 0.f); v1.y = fmaxf(v1.y, 0.f);
            }
            if (NATT >= 1) {
                float a0 = __ldg(attS + cc), a1 = __ldg(attS + cc + 1);
                lsS[mi][0] += v0.x*a0 + v0.y*a1;
                lsS[mi][1] += v1.x*a0 + v1.y*a1;
            }
            if (r1 < M)     *reinterpret_cast<float2*>(C + (size_t)r1*128 + cc)     = v0;
            if (r1 + 8 < M) *reinterpret_cast<float2*>(C + (size_t)(r1+8)*128 + cc) = v1;
        }
    }
    if (NATT >= 1) {
        #pragma unroll
        for (int mi = 0; mi < 2; mi++)
            #pragma unroll
            for (int rr = 0; rr < 2; rr++) {
                float v = lsS[mi][rr];
                v += __shfl_xor_sync(0xffffffffu, v, 1);
                v += __shfl_xor_sync(0xffffffffu, v, 2);
                lsS[mi][rr] = v;
            }
        if (t == 0) {
            int head = col0 >> 5;
            #pragma unroll
            for (int mi = 0; mi < 2; mi++)
                #pragma unroll
                for (int rr = 0; rr < 2; rr++) {
                    int r = bm + row0 + mi*16 + g + rr*8;
                    if (r < M) outS[(size_t)r*4 + head] = lsS[mi][rr];
                }
        }
    }
}

// ------------- dual-slot HMMA GEMM: A resident; computes hs AND hd + both logit pairs -------
__global__ void __launch_bounds__(256, 2) tc_gemm_dual(
    const float* __restrict__ A,
    const __nv_bfloat16* __restrict__ Whi0, const __nv_bfloat16* __restrict__ Wlo0,
    const __nv_bfloat16* __restrict__ Whi1, const __nv_bfloat16* __restrict__ Wlo1,
    float* __restrict__ C0, float* __restrict__ C1, int M,
    const float* __restrict__ attS0, const float* __restrict__ attD0,
    const float* __restrict__ attS1, const float* __restrict__ attD1,
    float* __restrict__ outS0, float* __restrict__ outD0,
    float* __restrict__ outS1, float* __restrict__ outD1)
{
    constexpr int K = 128, LDA = K + 8;
    extern __shared__ __nv_bfloat16 smb[];
    __nv_bfloat16* sAhi = smb;
    __nv_bfloat16* sAlo = sAhi + 64*LDA;
    __nv_bfloat16* sWhi = sAlo + 64*LDA;
    __nv_bfloat16* sWlo = sWhi + 128*LDA;

    const int tid  = threadIdx.x;
    const int lane = tid & 31;
    const int wid  = tid >> 5;
    const int bm   = blockIdx.x * 64;

    for (int idx = tid; idx < 64*(K/4); idx += 256) {
        int r  = idx / (K/4);
        int k0 = (idx % (K/4)) * 4;
        int row = bm + r;
        float4 v = make_float4(0.f, 0.f, 0.f, 0.f);
        if (row < M) v = *reinterpret_cast<const float4*>(A + (size_t)row*K + k0);
        __nv_bfloat16 h0 = __float2bfloat16(v.x), h1 = __float2bfloat16(v.y);
        __nv_bfloat16 h2 = __float2bfloat16(v.z), h3 = __float2bfloat16(v.w);
        __nv_bfloat16 l0 = __float2bfloat16(v.x - __bfloat162float(h0));
        __nv_bfloat16 l1 = __float2bfloat16(v.y - __bfloat162float(h1));
        __nv_bfloat16 l2 = __float2bfloat16(v.z - __bfloat162float(h2));
        __nv_bfloat16 l3 = __float2bfloat16(v.w - __bfloat162float(h3));
        __nv_bfloat16* pH = sAhi + r*LDA + k0;
        __nv_bfloat16* pL = sAlo + r*LDA + k0;
        *reinterpret_cast<__nv_bfloat162*>(pH)     = __halves2bfloat162(h0, h1);
        *reinterpret_cast<__nv_bfloat162*>(pH + 2) = __halves2bfloat162(h2, h3);
        *reinterpret_cast<__nv_bfloat162*>(pL)     = __halves2bfloat162(l0, l1);
        *reinterpret_cast<__nv_bfloat162*>(pL + 2) = __halves2bfloat162(l2, l3);
    }

    const int row0 = (wid & 1) * 32;
    const int col0 = (wid >> 1) * 32;
    uint32_t aB[2][2], bB[2][2];
    {
        int ar = (lane & 15), ac = (lane >> 4) * 8;
        #pragma unroll
        for (int mi = 0; mi < 2; mi++) {
            aB[0][mi] = smem_u32(sAhi + (row0 + mi*16 + ar)*LDA + ac);
            aB[1][mi] = smem_u32(sAlo + (row0 + mi*16 + ar)*LDA + ac);
        }
        int q  = lane >> 3;
        int nr = (q >> 1)*8 + (lane & 7);
        int nc = (q & 1)*8;
        #pragma unroll
        for (int nt = 0; nt < 2; nt++) {
            bB[0][nt] = smem_u32(sWhi + (col0 + nt*16 + nr)*LDA + nc);
            bB[1][nt] = smem_u32(sWlo + (col0 + nt*16 + nr)*LDA + nc);
        }
    }
    const int g = lane >> 2, t = lane & 3;

    #pragma unroll
    for (int slot = 0; slot < 2; slot++) {
        const __nv_bfloat16* Whi = slot ? Whi1 : Whi0;
        const __nv_bfloat16* Wlo = slot ? Wlo1 : Wlo0;
        float* C = slot ? C1 : C0;
        const float* attS = slot ? attS1 : attS0;
        const float* attD = slot ? attD1 : attD0;
        float* outS = slot ? outS1 : outS0;
        float* outD = slot ? outD1 : outD0;

        for (int idx = tid; idx < 128*(K/8); idx += 256) {
            int n  = idx / (K/8);
            int k0 = (idx % (K/8)) * 8;
            *reinterpret_cast<uint4*>(sWhi + n*LDA + k0) = *reinterpret_cast<const uint4*>(Whi + (size_t)n*K + k0);
            *reinterpret_cast<uint4*>(sWlo + n*LDA + k0) = *reinterpret_cast<const uint4*>(Wlo + (size_t)n*K + k0);
        }
        __syncthreads();

        float acc[2][4][4];
        #pragma unroll
        for (int mi = 0; mi < 2; mi++)
            #pragma unroll
            for (int ni = 0; ni < 4; ni++)
                { acc[mi][ni][0]=0.f; acc[mi][ni][1]=0.f; acc[mi][ni][2]=0.f; acc[mi][ni][3]=0.f; }

        #pragma unroll 2
        for (int ks = 0; ks < K/16; ks++) {
            uint32_t koff = (uint32_t)ks * 32u;
            uint32_t ah[2][4], al[2][4], bh[2][4], bl[2][4];
            #pragma unroll
            for (int mi = 0; mi < 2; mi++) { ldm_x4(ah[mi], aB[0][mi] + koff); ldm_x4(al[mi], aB[1][mi] + koff); }
            #pragma unroll
            for (int nt = 0; nt < 2; nt++) { ldm_x4(bh[nt], bB[0][nt] + koff); ldm_x4(bl[nt], bB[1][nt] + koff); }
            #pragma unroll
            for (int mi = 0; mi < 2; mi++)
                #pragma unroll
                for (int nt = 0; nt < 2; nt++) {
                    mma_bf16(acc[mi][nt*2],   ah[mi], &bh[nt][0]);
                    mma_bf16(acc[mi][nt*2+1], ah[mi], &bh[nt][2]);
                    mma_bf16(acc[mi][nt*2],   ah[mi], &bl[nt][0]);
                    mma_bf16(acc[mi][nt*2+1], ah[mi], &bl[nt][2]);
                    mma_bf16(acc[mi][nt*2],   al[mi], &bh[nt][0]);
                    mma_bf16(acc[mi][nt*2+1], al[mi], &bh[nt][2]);
                }
        }

        float lsS[2][2], lsD[2][2];
        lsS[0][0]=0.f; lsS[0][1]=0.f; lsS[1][0]=0.f; lsS[1][1]=0.f;
        lsD[0][0]=0.f; lsD[0][1]=0.f; lsD[1][0]=0.f; lsD[1][1]=0.f;

        #pragma unroll
        for (int mi = 0; mi < 2; mi++) {
            #pragma unroll
            for (int ni = 0; ni < 4; ni++) {
                int cc = col0 + ni*8 + t*2;
                int r1 = bm + row0 + mi*16 + g;
                float2 v0 = make_float2(acc[mi][ni][0], acc[mi][ni][1]);
                float2 v1 = make_float2(acc[mi][ni][2], acc[mi][ni][3]);
                float a0 = __ldg(attS + cc), a1 = __ldg(attS + cc + 1);
                float d0 = __ldg(attD + cc), d1 = __ldg(attD + cc + 1);
                lsS[mi][0] += v0.x*a0 + v0.y*a1;
                lsS[mi][1] += v1.x*a0 + v1.y*a1;
                lsD[mi][0] += v0.x*d0 + v0.y*d1;
                lsD[mi][1] += v1.x*d0 + v1.y*d1;
                if (r1 < M)     *reinterpret_cast<float2*>(C + (size_t)r1*128 + cc)     = v0;
                if (r1 + 8 < M) *reinterpret_cast<float2*>(C + (size_t)(r1+8)*128 + cc) = v1;
            }
        }
        #pragma unroll
        for (int mi = 0; mi < 2; mi++)
            #pragma unroll
            for (int rr = 0; rr < 2; rr++) {
                float v = lsS[mi][rr];
                v += __shfl_xor_sync(0xffffffffu, v, 1);
                v += __shfl_xor_sync(0xffffffffu, v, 2);
                lsS[mi][rr] = v;
                float w = lsD[mi][rr];
                w += __shfl_xor_sync(0xffffffffu, w, 1);
                w += __shfl_xor_sync(0xffffffffu, w, 2);
                lsD[mi][rr] = w;
            }
        if (t == 0) {
            int head = col0 >> 5;
            #pragma unroll
            for (int mi = 0; mi < 2; mi++)
                #pragma unroll
                for (int rr = 0; rr < 2; rr++) {
                    int r = bm + row0 + mi*16 + g + rr*8;
                    if (r < M) {
                        outS[(size_t)r*4 + head] = lsS[mi][rr];
                        outD[(size_t)r*4 + head] = lsD[mi][rr];
                    }
                }
        }
        __syncthreads();   // all warps done with W smem before next slot reload
    }
}

// --------------------------------- CSR build ------------------------------------------------
__global__ void hist_tt_kernel(const int* __restrict__ e0, const int* __restrict__ e1)
{
    for (int i = blockIdx.x*blockDim.x + threadIdx.x; i < ETTg; i += gridDim.x*blockDim.x) {
        atomicAdd(&g_deg[0*NTg + e1[i]], 1);
        atomicAdd(&g_deg[1*NTg + e0[i]], 1);
    }
}
__global__ void hist_ct_kernel(const int* __restrict__ ed)
{
    for (int i = blockIdx.x*blockDim.x + threadIdx.x; i < ECTg; i += gridDim.x*blockDim.x)
        atomicAdd(&g_deg[2*NTg + ed[i]], 1);
}

__global__ void scan1_kernel()
{
    int arr  = blockIdx.y;
    int base = blockIdx.x * 1024 + threadIdx.x;
    int lane = threadIdx.x & 31, wid = threadIdx.x >> 5;
    int v = (base < NTg) ? g_deg[arr*NTg + base] : 0;
    int x = v;
    #pragma unroll
    for (int o = 1; o < 32; o <<= 1) { int y = __shfl_up_sync(0xffffffffu, x, o); if (lane >= o) x += y; }
    __shared__ int ws[32];
    if (lane == 31) ws[wid] = x;
    __syncthreads();
    if (wid == 0) {
        int wv = ws[lane]; int wx = wv;
        #pragma unroll
        for (int o = 1; o < 32; o <<= 1) { int y = __shfl_up_sync(0xffffffffu, wx, o); if (lane >= o) wx += y; }
        if (lane == 31) g_aux[arr*128 + blockIdx.x] = wx;
        ws[lane] = wx - wv;
    }
    __syncthreads();
    int excl = x - v + ws[wid];
    if (base < NTg) g_cur[arr*NTg + base] = excl;
}

__global__ void scan2_kernel()
{
    int arr  = threadIdx.x >> 5;
    int lane = threadIdx.x & 31;
    if (arr >= 3) return;
    const int NB = (NTg + 1023) / 1024;
    int carry = 0;
    for (int c = 0; c*32 < NB; c++) {
        int idx = c*32 + lane;
        int v = (idx < NB) ? g_aux[arr*128 + idx] : 0;
        int x = v;
        #pragma unroll
        for (int o = 1; o < 32; o <<= 1) { int y = __shfl_up_sync(0xffffffffu, x, o); if (lane >= o) x += y; }
        if (idx < NB) g_aux[arr*128 + idx] = x - v + carry;
        carry += __shfl_sync(0xffffffffu, x, 31);
    }
}

__global__ void scan3_kernel()
{
    for (int i = blockIdx.x*blockDim.x + threadIdx.x; i < 3*NTg; i += gridDim.x*blockDim.x) {
        int arr = i / NTg; int idx = i - arr*NTg;
        g_cur[i] += g_aux[arr*128 + (idx >> 10)];
    }
}

__global__ void fill_tt_kernel(const int* __restrict__ e0, const int* __restrict__ e1)
{
    for (int i = blockIdx.x*blockDim.x + threadIdx.x; i < ETTg; i += gridDim.x*blockDim.x) {
        int s = e0[i], d = e1[i];
        int p = atomicAdd(&g_cur[0*NTg + d], 1); g_csrf[p] = s;
        int q = atomicAdd(&g_cur[1*NTg + s], 1); g_csrr[q] = d;
    }
}
__global__ void fill_ct_kernel(const int* __restrict__ es, const int* __restrict__ ed)
{
    for (int i = blockIdx.x*blockDim.x + threadIdx.x; i < ECTg; i += gridDim.x*blockDim.x) {
        int p = atomicAdd(&g_cur[2*NTg + ed[i]], 1); g_csrct[p] = es[i];
    }
}

// --------- per-relation GAT, single pass, batch-4 edge processing for MLP -------------------
template<bool SELF>
__device__ __forceinline__ void gat_rel(
    const float* __restrict__ hsrc, const float* __restrict__ a_s,
    const int* __restrict__ csr, int start, int cnt, int d, int lane,
    float4 ad, float wgt, float r[4])
{
    if (!SELF && cnt == 0) { r[0]=0.f; r[1]=0.f; r[2]=0.f; r[3]=0.f; return; }

    float den0 = 0.f, den1 = 0.f, den2 = 0.f, den3 = 0.f;
    float ac0 = 0.f, ac1 = 0.f, ac2 = 0.f, ac3 = 0.f;

    if (SELF) {
        float4 as = *reinterpret_cast<const float4*>(a_s + (size_t)d*4);
        float p0 = __expf(lrelu02(as.x + ad.x));
        float p1 = __expf(lrelu02(as.y + ad.y));
        float p2 = __expf(lrelu02(as.z + ad.z));
        float p3 = __expf(lrelu02(as.w + ad.w));
        den0 = p0; den1 = p1; den2 = p2; den3 = p3;
        const float* row = hsrc + (size_t)d*128;
        ac0 = p0 * row[lane];      ac1 = p1 * row[32 + lane];
        ac2 = p2 * row[64 + lane]; ac3 = p3 * row[96 + lane];
    }

    int i = 0;
    for (; i + 4 <= cnt; i += 4) {
        int s0 = csr[start + i],     s1 = csr[start + i + 1];
        int s2 = csr[start + i + 2], s3 = csr[start + i + 3];
        float4 e0 = *reinterpret_cast<const float4*>(a_s + (size_t)s0*4);
        float4 e1 = *reinterpret_cast<const float4*>(a_s + (size_t)s1*4);
        float4 e2 = *reinterpret_cast<const float4*>(a_s + (size_t)s2*4);
        float4 e3 = *reinterpret_cast<const float4*>(a_s + (size_t)s3*4);
        float q00 = __expf(lrelu02(e0.x + ad.x)), q01 = __expf(lrelu02(e0.y + ad.y));
        float q02 = __expf(lrelu02(e0.z + ad.z)), q03 = __expf(lrelu02(e0.w + ad.w));
        float q10 = __expf(lrelu02(e1.x + ad.x)), q11 = __expf(lrelu02(e1.y + ad.y));
        float q12 = __expf(lrelu02(e1.z + ad.z)), q13 = __expf(lrelu02(e1.w + ad.w));
        float q20 = __expf(lrelu02(e2.x + ad.x)), q21 = __expf(lrelu02(e2.y + ad.y));
        float q22 = __expf(lrelu02(e2.z + ad.z)), q23 = __expf(lrelu02(e2.w + ad.w));
        float q30 = __expf(lrelu02(e3.x + ad.x)), q31 = __expf(lrelu02(e3.y + ad.y));
        float q32 = __expf(lrelu02(e3.z + ad.z)), q33 = __expf(lrelu02(e3.w + ad.w));
        den0 += (q00 + q10) + (q20 + q30);
        den1 += (q01 + q11) + (q21 + q31);
        den2 += (q02 + q12) + (q22 + q32);
        den3 += (q03 + q13) + (q23 + q33);
        const float* r0 = hsrc + (size_t)s0*128;
        const float* r1 = hsrc + (size_t)s1*128;
        const float* r2 = hsrc + (size_t)s2*128;
        const float* r3 = hsrc + (size_t)s3*128;
        ac0 = fmaf(q00, r0[lane],      fmaf(q10, r1[lane],      fmaf(q20, r2[lane],      fmaf(q30, r3[lane],      ac0))));
        ac1 = fmaf(q01, r0[32 + lane], fmaf(q11, r1[32 + lane], fmaf(q21, r2[32 + lane], fmaf(q31, r3[32 + lane], ac1))));
        ac2 = fmaf(q02, r0[64 + lane], fmaf(q12, r1[64 + lane], fmaf(q22, r2[64 + lane], fmaf(q32, r3[64 + lane], ac2))));
        ac3 = fmaf(q03, r0[96 + lane], fmaf(q13, r1[96 + lane], fmaf(q23, r2[96 + lane], fmaf(q33, r3[96 + lane], ac3))));
    }
    for (; i < cnt; i++) {
        int s = csr[start + i];
        float4 as = *reinterpret_cast<const float4*>(a_s + (size_t)s*4);
        float p0 = __expf(lrelu02(as.x + ad.x));
        float p1 = __expf(lrelu02(as.y + ad.y));
        float p2 = __expf(lrelu02(as.z + ad.z));
        float p3 = __expf(lrelu02(as.w + ad.w));
        den0 += p0; den1 += p1; den2 += p2; den3 += p3;
        const float* row = hsrc + (size_t)s*128;
        ac0 = fmaf(p0, row[lane],       ac0);
        ac1 = fmaf(p1, row[32 + lane],  ac1);
        ac2 = fmaf(p2, row[64 + lane],  ac2);
        ac3 = fmaf(p3, row[96 + lane],  ac3);
    }

    r[0] = ac0 * (wgt / den0); r[1] = ac1 * (wgt / den1);
    r[2] = ac2 * (wgt / den2); r[3] = ac3 * (wgt / den3);
}

// ---- FUSED: GAT(all 3 relations) -> z split into smem bf16 tiles -> out = z @ W_out + b ----
__global__ void __launch_bounds__(256, 2) gat_gemm_out(
    const float* __restrict__ hs, const float* __restrict__ hd, const float* __restrict__ hcs,
    const float* __restrict__ ht,
    const float* __restrict__ asf, const float* __restrict__ adf,
    const float* __restrict__ asr, const float* __restrict__ adr,
    const float* __restrict__ asct, const float* __restrict__ adct,
    const int* __restrict__ cur, const int* __restrict__ deg,
    const int* __restrict__ csrf, const int* __restrict__ csrr, const int* __restrict__ csrct,
    const float* __restrict__ bsd, const float* __restrict__ bds, const float* __restrict__ bct,
    const __nv_bfloat16* __restrict__ Whi, const __nv_bfloat16* __restrict__ Wlo,
    const float* __restrict__ bout, float* __restrict__ C, int M)
{
    constexpr int K = 128, LDA = K + 8;
    extern __shared__ __nv_bfloat16 smb[];
    __nv_bfloat16* sAhi = smb;
    __nv_bfloat16* sAlo = sAhi + 64*LDA;
    __nv_bfloat16* sWhi = sAlo + 64*LDA;
    __nv_bfloat16* sWlo = sWhi + 128*LDA;

    const int tid  = threadIdx.x;
    const int lane = tid & 31;
    const int wid  = tid >> 5;
    const int bm   = blockIdx.x * 64;

    // W tiles first (loads in flight while GAT computes)
    for (int idx = tid; idx < 128*(K/8); idx += 256) {
        int n  = idx / (K/8);
        int k0 = (idx % (K/8)) * 8;
        *reinterpret_cast<uint4*>(sWhi + n*LDA + k0) = *reinterpret_cast<const uint4*>(Whi + (size_t)n*K + k0);
        *reinterpret_cast<uint4*>(sWlo + n*LDA + k0) = *reinterpret_cast<const uint4*>(Wlo + (size_t)n*K + k0);
    }

    // GAT phase: warp per dst row, 8 rows per warp; z row split directly into smem tiles
    for (int rr8 = 0; rr8 < 8; rr8++) {
        int r   = wid*8 + rr8;
        int row = bm + r;
        float z0 = 0.f, z1 = 0.f, z2 = 0.f, z3 = 0.f;
        if (row < M) {
            float rf[4], rv[4], rc[4];
            {
                int c = deg[0*NTg + row];
                gat_rel<true >(hs, asf, csrf, cur[0*NTg + row] - c, c, row, lane,
                               *reinterpret_cast<const float4*>(adf + (size_t)row*4), 0.25f, rf);
            }
            {
                int c = deg[1*NTg + row];
                gat_rel<true >(hd, asr, csrr, cur[1*NTg + row] - c, c, row, lane,
                               *reinterpret_cast<const float4*>(adr + (size_t)row*4), 0.25f, rv);
            }
            {
                int c = deg[2*NTg + row];
                gat_rel<false>(hcs, asct, csrct, cur[2*NTg + row] - c, c, row, lane,
                               *reinterpret_cast<const float4*>(adct + (size_t)row*4), 0.5f, rc);
            }
            const float* hrow = ht + (size_t)row*128;
            z0 = fmaxf(rf[0] + rv[0] + rc[0] + hrow[lane]      + 0.25f*bsd[lane]      + 0.25f*bds[lane]      + 0.5f*bct[lane],      0.f);
            z1 = fmaxf(rf[1] + rv[1] + rc[1] + hrow[32 + lane] + 0.25f*bsd[32 + lane] + 0.25f*bds[32 + lane] + 0.5f*bct[32 + lane], 0.f);
            z2 = fmaxf(rf[2] + rv[2] + rc[2] + hrow[64 + lane] + 0.25f*bsd[64 + lane] + 0.25f*bds[64 + lane] + 0.5f*bct[64 + lane], 0.f);
            z3 = fmaxf(rf[3] + rv[3] + rc[3] + hrow[96 + lane] + 0.25f*bsd[96 + lane] + 0.25f*bds[96 + lane] + 0.5f*bct[96 + lane], 0.f);
        }
        __nv_bfloat16 h0 = __float2bfloat16(z0), h1 = __float2bfloat16(z1);
        __nv_bfloat16 h2 = __float2bfloat16(z2), h3 = __float2bfloat16(z3);
        __nv_bfloat16* pH = sAhi + r*LDA;
        __nv_bfloat16* pL = sAlo + r*LDA;
        pH[lane]      = h0;  pL[lane]      = __float2bfloat16(z0 - __bfloat162float(h0));
        pH[32 + lane] = h1;  pL[32 + lane] = __float2bfloat16(z1 - __bfloat162float(h1));
        pH[64 + lane] = h2;  pL[64 + lane] = __float2bfloat16(z2 - __bfloat162float(h2));
        pH[96 + lane] = h3;  pL[96 + lane] = __float2bfloat16(z3 - __bfloat162float(h3));
    }
    __syncthreads();

    // ---- GEMM mainloop (identical structure to tc_gemm K=128) ----
    const int row0 = (wid & 1) * 32;
    const int col0 = (wid >> 1) * 32;
    uint32_t aB[2][2], bB[2][2];
    {
        int ar = (lane & 15), ac = (lane >> 4) * 8;
        #pragma unroll
        for (int mi = 0; mi < 2; mi++) {
            aB[0][mi] = smem_u32(sAhi + (row0 + mi*16 + ar)*LDA + ac);
            aB[1][mi] = smem_u32(sAlo + (row0 + mi*16 + ar)*LDA + ac);
        }
        int q  = lane >> 3;
        int nr = (q >> 1)*8 + (lane & 7);
        int nc = (q & 1)*8;
        #pragma unroll
        for (int nt = 0; nt < 2; nt++) {
            bB[0][nt] = smem_u32(sWhi + (col0 + nt*16 + nr)*LDA + nc);
            bB[1][nt] = smem_u32(sWlo + (col0 + nt*16 + nr)*LDA + nc);
        }
    }

    float acc[2][4][4];
    #pragma unroll
    for (int mi = 0; mi < 2; mi++)
        #pragma unroll
        for (int ni = 0; ni < 4; ni++)
            { acc[mi][ni][0]=0.f; acc[mi][ni][1]=0.f; acc[mi][ni][2]=0.f; acc[mi][ni][3]=0.f; }

    #pragma unroll 2
    for (int ks = 0; ks < K/16; ks++) {
        uint32_t koff = (uint32_t)ks * 32u;
        uint32_t ah[2][4], al[2][4], bh[2][4], bl[2][4];
        #pragma unroll
        for (int mi = 0; mi < 2; mi++) { ldm_x4(ah[mi], aB[0][mi] + koff); ldm_x4(al[mi], aB[1][mi] + koff); }
        #pragma unroll
        for (int nt = 0; nt < 2; nt++) { ldm_x4(bh[nt], bB[0][nt] + koff); ldm_x4(bl[nt], bB[1][nt] + koff); }
        #pragma unroll
        for (int mi = 0; mi < 2; mi++)
            #pragma unroll
            for (int nt = 0; nt < 2; nt++) {
                mma_bf16(acc[mi][nt*2],   ah[mi], &bh[nt][0]);
                mma_bf16(acc[mi][nt*2+1], ah[mi], &bh[nt][2]);
                mma_bf16(acc[mi][nt*2],   ah[mi], &bl[nt][0]);
                mma_bf16(acc[mi][nt*2+1], ah[mi], &bl[nt][2]);
                mma_bf16(acc[mi][nt*2],   al[mi], &bh[nt][0]);
                mma_bf16(acc[mi][nt*2+1], al[mi], &bh[nt][2]);
            }
    }

    const int g = lane >> 2, t = lane & 3;
    #pragma unroll
    for (int mi = 0; mi < 2; mi++) {
        #pragma unroll
        for (int ni = 0; ni < 4; ni++) {
            int cc = col0 + ni*8 + t*2;
            float bx = bout[cc], by = bout[cc+1];
            int r1 = bm + row0 + mi*16 + g;
            float2 v0 = make_float2(acc[mi][ni][0] + bx, acc[mi][ni][1] + by);
            float2 v1 = make_float2(acc[mi][ni][2] + bx, acc[mi][ni][3] + by);
            if (r1 < M)     *reinterpret_cast<float2*>(C + (size_t)r1*128 + cc)     = v0;
            if (r1 + 8 < M) *reinterpret_cast<float2*>(C + (size_t)(r1+8)*128 + cc) = v1;
        }
    }
}

// ----------------------------------- launch -------------------------------------------------
extern "C" void kernel_launch(void* const* d_in, const int* in_sizes, int n_in,
                              void* d_out, int out_size)
{
    const float* x_t     = (const float*)d_in[0];
    const float* x_c     = (const float*)d_in[1];
    const int*   ett     = (const int*)d_in[2];
    const int*   e0      = ett;
    const int*   e1      = ett + ETTg;
    const int*   ect_s   = (const int*)d_in[3];
    const int*   ect_d   = (const int*)d_in[4];
    const float* W_pre_t = (const float*)d_in[5];
    const float* b_pre_t = (const float*)d_in[6];
    const float* W_pre_c = (const float*)d_in[7];
    const float* b_pre_c = (const float*)d_in[8];
    const float* W_sd    = (const float*)d_in[9];
    const float* att_s_sd= (const float*)d_in[10];
    const float* att_d_sd= (const float*)d_in[11];
    const float* b_sd    = (const float*)d_in[12];
    const float* W_ds    = (const float*)d_in[13];
    const float* att_s_ds= (const float*)d_in[14];
    const float* att_d_ds= (const float*)d_in[15];
    const float* b_ds    = (const float*)d_in[16];
    const float* W_ct_s  = (const float*)d_in[17];
    const float* W_ct_d  = (const float*)d_in[18];
    const float* att_s_ct= (const float*)d_in[19];
    const float* att_d_ct= (const float*)d_in[20];
    const float* b_ct    = (const float*)d_in[21];
    const float* W_out   = (const float*)d_in[22];
    const float* b_out   = (const float*)d_in[23];
    float* out = (float*)d_out;

    float *p_ht, *p_hc, *p_hs, *p_hd, *p_hcs, *p_wv;
    float *p_asf, *p_adf, *p_asr, *p_adr, *p_adct, *p_asct;
    int *p_deg, *p_cur, *p_csrf, *p_csrr, *p_csrct;
    __nv_bfloat16 *p_whi, *p_wlo;
    cudaGetSymbolAddress((void**)&p_ht,  g_ht);
    cudaGetSymbolAddress((void**)&p_hc,  g_hc);
    cudaGetSymbolAddress((void**)&p_hs,  g_hs);
    cudaGetSymbolAddress((void**)&p_hd,  g_hd);
    cudaGetSymbolAddress((void**)&p_hcs, g_hcs);
    cudaGetSymbolAddress((void**)&p_wv,  g_wv);
    cudaGetSymbolAddress((void**)&p_asf, g_asf);
    cudaGetSymbolAddress((void**)&p_adf, g_adf);
    cudaGetSymbolAddress((void**)&p_asr, g_asr);
    cudaGetSymbolAddress((void**)&p_adr, g_adr);
    cudaGetSymbolAddress((void**)&p_adct,g_adct);
    cudaGetSymbolAddress((void**)&p_asct,g_asct);
    cudaGetSymbolAddress((void**)&p_deg, g_deg);
    cudaGetSymbolAddress((void**)&p_cur, g_cur);
    cudaGetSymbolAddress((void**)&p_csrf, g_csrf);
    cudaGetSymbolAddress((void**)&p_csrr, g_csrr);
    cudaGetSymbolAddress((void**)&p_csrct,g_csrct);
    cudaGetSymbolAddress((void**)&p_whi, g_whi);
    cudaGetSymbolAddress((void**)&p_wlo, g_wlo);

    // smem: (2*64 + 2*128) rows * (K+8) cols * 2B
    const int SM128 = (2*64 + 2*128) * (128 + 8) * 2;   // 104448
    const int SM64  = (2*64 + 2*128) * (64  + 8) * 2;   // 55296
    const int SM32  = (2*64 + 2*128) * (32  + 8) * 2;   // 30720
    cudaFuncSetAttribute(tc_gemm_dual,               cudaFuncAttributeMaxDynamicSharedMemorySize, SM128);
    cudaFuncSetAttribute(tc_gemm<128,false,false,1>, cudaFuncAttributeMaxDynamicSharedMemorySize, SM128);
    cudaFuncSetAttribute(gat_gemm_out,               cudaFuncAttributeMaxDynamicSharedMemorySize, SM128);
    cudaFuncSetAttribute(tc_gemm<64, true, true, 0>, cudaFuncAttributeMaxDynamicSharedMemorySize, SM64);
    cudaFuncSetAttribute(tc_gemm<32, true, true, 0>, cudaFuncAttributeMaxDynamicSharedMemorySize, SM32);

    const int GT = (NTg + 63) / 64;   // 1563
    const int GC = (NCg + 63) / 64;   // 391

    // slots: 0 pre_t K=64, 1 pre_c K=32, 2 sd, 3 ds, 4 ct_s, 5 out  (W_ct_d folded into wv)
    WJobs jobs;
    jobs.W[0] = W_pre_t; jobs.K[0] = 64;
    jobs.W[1] = W_pre_c; jobs.K[1] = 32;
    jobs.W[2] = W_sd;    jobs.K[2] = 128;
    jobs.W[3] = W_ds;    jobs.K[3] = 128;
    jobs.W[4] = W_ct_s;  jobs.K[4] = 128;
    jobs.W[5] = W_out;   jobs.K[5] = 128;

    wv_kernel<<<1, 512>>>(W_ct_d, att_d_ct, p_wv);                                  // k1
    wsplit_all<<<dim3(64, 6), 256>>>(jobs, p_whi, p_wlo);                           // k2
    tc_gemm<64,true,true,0><<<GT, 256, SM64>>>(x_t, p_whi + 0*16384, p_wlo + 0*16384,
        b_pre_t, p_ht, NTg, nullptr, nullptr);                                      // k3
    tc_gemm_dual<<<GT, 256, SM128>>>(p_ht,
        p_whi + 2*16384, p_wlo + 2*16384, p_whi + 3*16384, p_wlo + 3*16384,
        p_hs, p_hd, NTg,
        att_s_sd, att_d_sd, att_s_ds, att_d_ds,
        p_asf, p_adf, p_asr, p_adr);                                                // k4 <- ncu
    tc_gemm<32,true,true,0><<<GC, 256, SM32>>>(x_c, p_whi + 1*16384, p_wlo + 1*16384,
        b_pre_c, p_hc, NCg, nullptr, nullptr);                                      // k5
    tc_gemm<128,false,false,1><<<GC, 256, SM128>>>(p_hc, p_whi + 4*16384, p_wlo + 4*16384,
        nullptr, p_hcs, NCg, att_s_ct, p_asct);                                     // k6
    attv_kernel<<<(NTg + 7) / 8, 256>>>(p_ht, p_wv, p_adct, NTg);                   // k7

    // CSR build
    cudaMemsetAsync(p_deg, 0, 3*NTg*sizeof(int));
    hist_tt_kernel<<<512, 256>>>(e0, e1);
    hist_ct_kernel<<<256, 256>>>(ect_d);
    dim3 g1((NTg + 1023) / 1024, 3);
    scan1_kernel<<<g1, 1024>>>();
    scan2_kernel<<<1, 96>>>();
    scan3_kernel<<<256, 256>>>();
    fill_tt_kernel<<<512, 256>>>(e0, e1);
    fill_ct_kernel<<<256, 256>>>(ect_s, ect_d);

    // fused: GAT(3 relations) -> z (in smem) -> out = z @ W_out + b_out
    gat_gemm_out<<<GT, 256, SM128>>>(
        p_hs, p_hd, p_hcs, p_ht,
        p_asf, p_adf, p_asr, p_adr, p_asct, p_adct,
        p_cur, p_deg, p_csrf, p_csrr, p_csrct,
        b_sd, b_ds, b_ct,
        p_whi + 5*16384, p_wlo + 5*16384, b_out, out, NTg);
}

// round 9
// speedup vs baseline: 1.2560x; 1.2560x over previous
#include <cuda_runtime.h>
#include <cuda_bf16.h>
#include <cstdint>

#define NTg  100000
#define NCg  25000
#define ETTg 800000
#define ECTg 400000
#define HIDg 128

// ------------------------- scratch (device globals; allocation-free) -------------------------
__device__ float g_ht [NTg*HIDg];
__device__ float g_hc [NCg*HIDg];
__device__ float g_hs [NTg*HIDg];
__device__ float g_hd [NTg*HIDg];
__device__ float g_hcs[NCg*HIDg];
__device__ float g_z  [NTg*HIDg];
__device__ float g_asf[NTg*4];
__device__ float g_adf[NTg*4];
__device__ float g_asr[NTg*4];
__device__ float g_adr[NTg*4];
__device__ float g_adct[NTg*4];
__device__ float g_asct[NCg*4];
__device__ float g_wv [4*128];
__device__ int   g_deg[3*NTg];
__device__ int   g_cur[3*NTg];
__device__ int   g_aux[3*128];
__device__ int   g_csrf[ETTg];
__device__ int   g_csrr[ETTg];
__device__ int   g_csrct[ECTg];
// split weights: 6 slots of up to 128x128 bf16 ([N,K] layout, i.e., W^T)
__device__ __nv_bfloat16 g_whi[6*128*128];
__device__ __nv_bfloat16 g_wlo[6*128*128];

__device__ __forceinline__ float lrelu02(float x) { return x > 0.f ? x : 0.2f * x; }

__device__ __forceinline__ uint32_t smem_u32(const void* p) {
    uint32_t a;
    asm("{ .reg .u64 t; cvta.to.shared.u64 t, %1; cvt.u32.u64 %0, t; }" : "=r"(a) : "l"(p));
    return a;
}

__device__ __forceinline__ void ldm_x4(uint32_t* r, uint32_t addr) {
    asm volatile("ldmatrix.sync.aligned.m8n8.x4.shared.b16 {%0,%1,%2,%3}, [%4];"
                 : "=r"(r[0]), "=r"(r[1]), "=r"(r[2]), "=r"(r[3]) : "r"(addr));
}
__device__ __forceinline__ void mma_bf16(float* c, const uint32_t* a, const uint32_t* b) {
    asm volatile("mma.sync.aligned.m16n8k16.row.col.f32.bf16.bf16.f32 "
                 "{%0,%1,%2,%3}, {%4,%5,%6,%7}, {%8,%9}, {%0,%1,%2,%3};"
                 : "+f"(c[0]), "+f"(c[1]), "+f"(c[2]), "+f"(c[3])
                 : "r"(a[0]), "r"(a[1]), "r"(a[2]), "r"(a[3]), "r"(b[0]), "r"(b[1]));
}

// ------------------- batched W split/transpose: hi/lo[n*K+k] = split(W[k*128+n]) ------------
struct WJobs { const float* W[6]; int K[6]; };

__global__ void wsplit_all(WJobs jobs, __nv_bfloat16* __restrict__ hiB,
                           __nv_bfloat16* __restrict__ loB)
{
    int slot = blockIdx.y;
    const float* W = jobs.W[slot];
    int K = jobs.K[slot];
    __nv_bfloat16* hi = hiB + slot*16384;
    __nv_bfloat16* lo = loB + slot*16384;
    int tot = 128 * K;
    for (int i = blockIdx.x*blockDim.x + threadIdx.x; i < tot; i += gridDim.x*blockDim.x) {
        int n = i / K, k = i - n*K;
        float v = W[k*128 + n];
        __nv_bfloat16 h = __float2bfloat16(v);
        hi[i] = h;
        lo[i] = __float2bfloat16(v - __bfloat162float(h));
    }
}

// ----------------- wv[h*128+k] = sum_c W_ct_dst[k*128 + h*32 + c] * att[h*32+c] -------------
__global__ void wv_kernel(const float* __restrict__ W, const float* __restrict__ att,
                          float* __restrict__ wv)
{
    int i = threadIdx.x;           // 512 threads: k = i>>2, h = i&3
    int k = i >> 2, h = i & 3;
    float s = 0.f;
    #pragma unroll 8
    for (int c = 0; c < 32; c++) s += W[k*128 + h*32 + c] * att[h*32 + c];
    wv[h*128 + k] = s;
}

// --------- a_dct[n,h] = sum_{k=0..127} ht[n,k] * wv[h,k]  (warp per row, FULL reduction) ----
__global__ void attv_kernel(const float* __restrict__ ht, const float* __restrict__ wv,
                            float* __restrict__ out, int n)
{
    int gw   = (blockIdx.x*blockDim.x + threadIdx.x) >> 5;
    int lane = threadIdx.x & 31;
    if (gw >= n) return;
    float4 v = *reinterpret_cast<const float4*>(ht + (size_t)gw*128 + lane*4);
    float p0, p1, p2, p3;
    {
        float4 w0 = *reinterpret_cast<const float4*>(wv + 0*128 + lane*4);
        float4 w1 = *reinterpret_cast<const float4*>(wv + 1*128 + lane*4);
        float4 w2 = *reinterpret_cast<const float4*>(wv + 2*128 + lane*4);
        float4 w3 = *reinterpret_cast<const float4*>(wv + 3*128 + lane*4);
        p0 = v.x*w0.x + v.y*w0.y + v.z*w0.z + v.w*w0.w;
        p1 = v.x*w1.x + v.y*w1.y + v.z*w1.z + v.w*w1.w;
        p2 = v.x*w2.x + v.y*w2.y + v.z*w2.z + v.w*w2.w;
        p3 = v.x*w3.x + v.y*w3.y + v.z*w3.z + v.w*w3.w;
    }
    #pragma unroll
    for (int o = 16; o > 0; o >>= 1) {
        p0 += __shfl_xor_sync(0xffffffffu, p0, o);
        p1 += __shfl_xor_sync(0xffffffffu, p1, o);
        p2 += __shfl_xor_sync(0xffffffffu, p2, o);
        p3 += __shfl_xor_sync(0xffffffffu, p3, o);
    }
    if (lane == 0)
        *reinterpret_cast<float4*>(out + (size_t)gw*4) = make_float4(p0, p1, p2, p3);
}

// ---------------- HMMA GEMM: C[M,128] = A[M,K] @ W[K,128]  (3-split bf16) -------------------
// CTA tile 64x128 (2 CTAs/SM), 8 warps, warp tile 32x32. W^T ([N,K]) pre-split in gmem.
// NATT: 0 = none; 1 = fused logits outS = C.att(attS)
template<int K, bool RELU, bool BIAS, int NATT>
__global__ void __launch_bounds__(256, 2) tc_gemm(
    const float* __restrict__ A, const __nv_bfloat16* __restrict__ Whi,
    const __nv_bfloat16* __restrict__ Wlo, const float* __restrict__ bias,
    float* __restrict__ C, int M,
    const float* __restrict__ attS, float* __restrict__ outS)
{
    constexpr int LDA = K + 8;
    extern __shared__ __nv_bfloat16 smb[];
    __nv_bfloat16* sAhi = smb;                 // 64*LDA
    __nv_bfloat16* sAlo = sAhi + 64*LDA;
    __nv_bfloat16* sWhi = sAlo + 64*LDA;       // 128*LDA
    __nv_bfloat16* sWlo = sWhi + 128*LDA;

    const int tid  = threadIdx.x;
    const int lane = tid & 31;
    const int wid  = tid >> 5;
    const int bm   = blockIdx.x * 64;

    for (int idx = tid; idx < 64*(K/4); idx += 256) {
        int r  = idx / (K/4);
        int k0 = (idx % (K/4)) * 4;
        int row = bm + r;
        float4 v = make_float4(0.f, 0.f, 0.f, 0.f);
        if (row < M) v = *reinterpret_cast<const float4*>(A + (size_t)row*K + k0);
        __nv_bfloat16 h0 = __float2bfloat16(v.x), h1 = __float2bfloat16(v.y);
        __nv_bfloat16 h2 = __float2bfloat16(v.z), h3 = __float2bfloat16(v.w);
        __nv_bfloat16 l0 = __float2bfloat16(v.x - __bfloat162float(h0));
        __nv_bfloat16 l1 = __float2bfloat16(v.y - __bfloat162float(h1));
        __nv_bfloat16 l2 = __float2bfloat16(v.z - __bfloat162float(h2));
        __nv_bfloat16 l3 = __float2bfloat16(v.w - __bfloat162float(h3));
        __nv_bfloat16* pH = sAhi + r*LDA + k0;
        __nv_bfloat16* pL = sAlo + r*LDA + k0;
        *reinterpret_cast<__nv_bfloat162*>(pH)     = __halves2bfloat162(h0, h1);
        *reinterpret_cast<__nv_bfloat162*>(pH + 2) = __halves2bfloat162(h2, h3);
        *reinterpret_cast<__nv_bfloat162*>(pL)     = __halves2bfloat162(l0, l1);
        *reinterpret_cast<__nv_bfloat162*>(pL + 2) = __halves2bfloat162(l2, l3);
    }
    for (int idx = tid; idx < 128*(K/8); idx += 256) {
        int n  = idx / (K/8);
        int k0 = (idx % (K/8)) * 8;
        *reinterpret_cast<uint4*>(sWhi + n*LDA + k0) = *reinterpret_cast<const uint4*>(Whi + (size_t)n*K + k0);
        *reinterpret_cast<uint4*>(sWlo + n*LDA + k0) = *reinterpret_cast<const uint4*>(Wlo + (size_t)n*K + k0);
    }
    __syncthreads();

    const int row0 = (wid & 1) * 32;
    const int col0 = (wid >> 1) * 32;

    uint32_t aB[2][2], bB[2][2];
    {
        int ar = (lane & 15), ac = (lane >> 4) * 8;
        #pragma unroll
        for (int mi = 0; mi < 2; mi++) {
            aB[0][mi] = smem_u32(sAhi + (row0 + mi*16 + ar)*LDA + ac);
            aB[1][mi] = smem_u32(sAlo + (row0 + mi*16 + ar)*LDA + ac);
        }
        int q  = lane >> 3;
        int nr = (q >> 1)*8 + (lane & 7);
        int nc = (q & 1)*8;
        #pragma unroll
        for (int nt = 0; nt < 2; nt++) {
            bB[0][nt] = smem_u32(sWhi + (col0 + nt*16 + nr)*LDA + nc);
            bB[1][nt] = smem_u32(sWlo + (col0 + nt*16 + nr)*LDA + nc);
        }
    }

    float acc[2][4][4];
    #pragma unroll
    for (int mi = 0; mi < 2; mi++)
        #pragma unroll
        for (int ni = 0; ni < 4; ni++)
            { acc[mi][ni][0]=0.f; acc[mi][ni][1]=0.f; acc[mi][ni][2]=0.f; acc[mi][ni][3]=0.f; }

    #pragma unroll 2
    for (int ks = 0; ks < K/16; ks++) {
        uint32_t koff = (uint32_t)ks * 32u;
        uint32_t ah[2][4], al[2][4], bh[2][4], bl[2][4];
        #pragma unroll
        for (int mi = 0; mi < 2; mi++) { ldm_x4(ah[mi], aB[0][mi] + koff); ldm_x4(al[mi], aB[1][mi] + koff); }
        #pragma unroll
        for (int nt = 0; nt < 2; nt++) { ldm_x4(bh[nt], bB[0][nt] + koff); ldm_x4(bl[nt], bB[1][nt] + koff); }
        #pragma unroll
        for (int mi = 0; mi < 2; mi++)
            #pragma unroll
            for (int nt = 0; nt < 2; nt++) {
                mma_bf16(acc[mi][nt*2],   ah[mi], &bh[nt][0]);
                mma_bf16(acc[mi][nt*2+1], ah[mi], &bh[nt][2]);
                mma_bf16(acc[mi][nt*2],   ah[mi], &bl[nt][0]);
                mma_bf16(acc[mi][nt*2+1], ah[mi], &bl[nt][2]);
                mma_bf16(acc[mi][nt*2],   al[mi], &bh[nt][0]);
                mma_bf16(acc[mi][nt*2+1], al[mi], &bh[nt][2]);
            }
    }

    const int g = lane >> 2, t = lane & 3;
    float lsS[2][2];
    if (NATT >= 1) { lsS[0][0]=0.f; lsS[0][1]=0.f; lsS[1][0]=0.f; lsS[1][1]=0.f; }
    #pragma unroll
    for (int mi = 0; mi < 2; mi++) {
        #pragma unroll
        for (int ni = 0; ni < 4; ni++) {
            int cc = col0 + ni*8 + t*2;
            float bx = 0.f, by = 0.f;
            if (BIAS) { bx = bias[cc]; by = bias[cc+1]; }
            int r1 = bm + row0 + mi*16 + g;
            float2 v0 = make_float2(acc[mi][ni][0] + bx, acc[mi][ni][1] + by);
            float2 v1 = make_float2(acc[mi][ni][2] + bx, acc[mi][ni][3] + by);
            if (RELU) {
                v0.x = fmaxf(v0.x, 0.f); v0.y = fmaxf(v0.y, 0.f);
                v1.x = fmaxf(v1.x, 0.f); v1.y = fmaxf(v1.y, 0.f);
            }
            if (NATT >= 1) {
                float a0 = __ldg(attS + cc), a1 = __ldg(attS + cc + 1);
                lsS[mi][0] += v0.x*a0 + v0.y*a1;
                lsS[mi][1] += v1.x*a0 + v1.y*a1;
            }
            if (r1 < M)     *reinterpret_cast<float2*>(C + (size_t)r1*128 + cc)     = v0;
            if (r1 + 8 < M) *reinterpret_cast<float2*>(C + (size_t)(r1+8)*128 + cc) = v1;
        }
    }
    if (NATT >= 1) {
        #pragma unroll
        for (int mi = 0; mi < 2; mi++)
            #pragma unroll
            for (int rr = 0; rr < 2; rr++) {
                float v = lsS[mi][rr];
                v += __shfl_xor_sync(0xffffffffu, v, 1);
                v += __shfl_xor_sync(0xffffffffu, v, 2);
                lsS[mi][rr] = v;
            }
        if (t == 0) {
            int head = col0 >> 5;
            #pragma unroll
            for (int mi = 0; mi < 2; mi++)
                #pragma unroll
                for (int rr = 0; rr < 2; rr++) {
                    int r = bm + row0 + mi*16 + g + rr*8;
                    if (r < M) outS[(size_t)r*4 + head] = lsS[mi][rr];
                }
        }
    }
}

// ------------- dual-slot HMMA GEMM: A resident; computes hs AND hd + both logit pairs -------
__global__ void __launch_bounds__(256, 2) tc_gemm_dual(
    const float* __restrict__ A,
    const __nv_bfloat16* __restrict__ Whi0, const __nv_bfloat16* __restrict__ Wlo0,
    const __nv_bfloat16* __restrict__ Whi1, const __nv_bfloat16* __restrict__ Wlo1,
    float* __restrict__ C0, float* __restrict__ C1, int M,
    const float* __restrict__ attS0, const float* __restrict__ attD0,
    const float* __restrict__ attS1, const float* __restrict__ attD1,
    float* __restrict__ outS0, float* __restrict__ outD0,
    float* __restrict__ outS1, float* __restrict__ outD1)
{
    constexpr int K = 128, LDA = K + 8;
    extern __shared__ __nv_bfloat16 smb[];
    __nv_bfloat16* sAhi = smb;
    __nv_bfloat16* sAlo = sAhi + 64*LDA;
    __nv_bfloat16* sWhi = sAlo + 64*LDA;
    __nv_bfloat16* sWlo = sWhi + 128*LDA;

    const int tid  = threadIdx.x;
    const int lane = tid & 31;
    const int wid  = tid >> 5;
    const int bm   = blockIdx.x * 64;

    for (int idx = tid; idx < 64*(K/4); idx += 256) {
        int r  = idx / (K/4);
        int k0 = (idx % (K/4)) * 4;
        int row = bm + r;
        float4 v = make_float4(0.f, 0.f, 0.f, 0.f);
        if (row < M) v = *reinterpret_cast<const float4*>(A + (size_t)row*K + k0);
        __nv_bfloat16 h0 = __float2bfloat16(v.x), h1 = __float2bfloat16(v.y);
        __nv_bfloat16 h2 = __float2bfloat16(v.z), h3 = __float2bfloat16(v.w);
        __nv_bfloat16 l0 = __float2bfloat16(v.x - __bfloat162float(h0));
        __nv_bfloat16 l1 = __float2bfloat16(v.y - __bfloat162float(h1));
        __nv_bfloat16 l2 = __float2bfloat16(v.z - __bfloat162float(h2));
        __nv_bfloat16 l3 = __float2bfloat16(v.w - __bfloat162float(h3));
        __nv_bfloat16* pH = sAhi + r*LDA + k0;
        __nv_bfloat16* pL = sAlo + r*LDA + k0;
        *reinterpret_cast<__nv_bfloat162*>(pH)     = __halves2bfloat162(h0, h1);
        *reinterpret_cast<__nv_bfloat162*>(pH + 2) = __halves2bfloat162(h2, h3);
        *reinterpret_cast<__nv_bfloat162*>(pL)     = __halves2bfloat162(l0, l1);
        *reinterpret_cast<__nv_bfloat162*>(pL + 2) = __halves2bfloat162(l2, l3);
    }

    const int row0 = (wid & 1) * 32;
    const int col0 = (wid >> 1) * 32;
    uint32_t aB[2][2], bB[2][2];
    {
        int ar = (lane & 15), ac = (lane >> 4) * 8;
        #pragma unroll
        for (int mi = 0; mi < 2; mi++) {
            aB[0][mi] = smem_u32(sAhi + (row0 + mi*16 + ar)*LDA + ac);
            aB[1][mi] = smem_u32(sAlo + (row0 + mi*16 + ar)*LDA + ac);
        }
        int q  = lane >> 3;
        int nr = (q >> 1)*8 + (lane & 7);
        int nc = (q & 1)*8;
        #pragma unroll
        for (int nt = 0; nt < 2; nt++) {
            bB[0][nt] = smem_u32(sWhi + (col0 + nt*16 + nr)*LDA + nc);
            bB[1][nt] = smem_u32(sWlo + (col0 + nt*16 + nr)*LDA + nc);
        }
    }
    const int g = lane >> 2, t = lane & 3;

    #pragma unroll
    for (int slot = 0; slot < 2; slot++) {
        const __nv_bfloat16* Whi = slot ? Whi1 : Whi0;
        const __nv_bfloat16* Wlo = slot ? Wlo1 : Wlo0;
        float* C = slot ? C1 : C0;
        const float* attS = slot ? attS1 : attS0;
        const float* attD = slot ? attD1 : attD0;
        float* outS = slot ? outS1 : outS0;
        float* outD = slot ? outD1 : outD0;

        for (int idx = tid; idx < 128*(K/8); idx += 256) {
            int n  = idx / (K/8);
            int k0 = (idx % (K/8)) * 8;
            *reinterpret_cast<uint4*>(sWhi + n*LDA + k0) = *reinterpret_cast<const uint4*>(Whi + (size_t)n*K + k0);
            *reinterpret_cast<uint4*>(sWlo + n*LDA + k0) = *reinterpret_cast<const uint4*>(Wlo + (size_t)n*K + k0);
        }
        __syncthreads();

        float acc[2][4][4];
        #pragma unroll
        for (int mi = 0; mi < 2; mi++)
            #pragma unroll
            for (int ni = 0; ni < 4; ni++)
                { acc[mi][ni][0]=0.f; acc[mi][ni][1]=0.f; acc[mi][ni][2]=0.f; acc[mi][ni][3]=0.f; }

        #pragma unroll 2
        for (int ks = 0; ks < K/16; ks++) {
            uint32_t koff = (uint32_t)ks * 32u;
            uint32_t ah[2][4], al[2][4], bh[2][4], bl[2][4];
            #pragma unroll
            for (int mi = 0; mi < 2; mi++) { ldm_x4(ah[mi], aB[0][mi] + koff); ldm_x4(al[mi], aB[1][mi] + koff); }
            #pragma unroll
            for (int nt = 0; nt < 2; nt++) { ldm_x4(bh[nt], bB[0][nt] + koff); ldm_x4(bl[nt], bB[1][nt] + koff); }
            #pragma unroll
            for (int mi = 0; mi < 2; mi++)
                #pragma unroll
                for (int nt = 0; nt < 2; nt++) {
                    mma_bf16(acc[mi][nt*2],   ah[mi], &bh[nt][0]);
                    mma_bf16(acc[mi][nt*2+1], ah[mi], &bh[nt][2]);
                    mma_bf16(acc[mi][nt*2],   ah[mi], &bl[nt][0]);
                    mma_bf16(acc[mi][nt*2+1], ah[mi], &bl[nt][2]);
                    mma_bf16(acc[mi][nt*2],   al[mi], &bh[nt][0]);
                    mma_bf16(acc[mi][nt*2+1], al[mi], &bh[nt][2]);
                }
        }

        float lsS[2][2], lsD[2][2];
        lsS[0][0]=0.f; lsS[0][1]=0.f; lsS[1][0]=0.f; lsS[1][1]=0.f;
        lsD[0][0]=0.f; lsD[0][1]=0.f; lsD[1][0]=0.f; lsD[1][1]=0.f;

        #pragma unroll
        for (int mi = 0; mi < 2; mi++) {
            #pragma unroll
            for (int ni = 0; ni < 4; ni++) {
                int cc = col0 + ni*8 + t*2;
                int r1 = bm + row0 + mi*16 + g;
                float2 v0 = make_float2(acc[mi][ni][0], acc[mi][ni][1]);
                float2 v1 = make_float2(acc[mi][ni][2], acc[mi][ni][3]);
                float a0 = __ldg(attS + cc), a1 = __ldg(attS + cc + 1);
                float d0 = __ldg(attD + cc), d1 = __ldg(attD + cc + 1);
                lsS[mi][0] += v0.x*a0 + v0.y*a1;
                lsS[mi][1] += v1.x*a0 + v1.y*a1;
                lsD[mi][0] += v0.x*d0 + v0.y*d1;
                lsD[mi][1] += v1.x*d0 + v1.y*d1;
                if (r1 < M)     *reinterpret_cast<float2*>(C + (size_t)r1*128 + cc)     = v0;
                if (r1 + 8 < M) *reinterpret_cast<float2*>(C + (size_t)(r1+8)*128 + cc) = v1;
            }
        }
        #pragma unroll
        for (int mi = 0; mi < 2; mi++)
            #pragma unroll
            for (int rr = 0; rr < 2; rr++) {
                float v = lsS[mi][rr];
                v += __shfl_xor_sync(0xffffffffu, v, 1);
                v += __shfl_xor_sync(0xffffffffu, v, 2);
                lsS[mi][rr] = v;
                float w = lsD[mi][rr];
                w += __shfl_xor_sync(0xffffffffu, w, 1);
                w += __shfl_xor_sync(0xffffffffu, w, 2);
                lsD[mi][rr] = w;
            }
        if (t == 0) {
            int head = col0 >> 5;
            #pragma unroll
            for (int mi = 0; mi < 2; mi++)
                #pragma unroll
                for (int rr = 0; rr < 2; rr++) {
                    int r = bm + row0 + mi*16 + g + rr*8;
                    if (r < M) {
                        outS[(size_t)r*4 + head] = lsS[mi][rr];
                        outD[(size_t)r*4 + head] = lsD[mi][rr];
                    }
                }
        }
        __syncthreads();   // all warps done with W smem before next slot reload
    }
}

// --------------------------------- CSR build ------------------------------------------------
__global__ void hist_tt_kernel(const int* __restrict__ e0, const int* __restrict__ e1)
{
    for (int i = blockIdx.x*blockDim.x + threadIdx.x; i < ETTg; i += gridDim.x*blockDim.x) {
        atomicAdd(&g_deg[0*NTg + e1[i]], 1);
        atomicAdd(&g_deg[1*NTg + e0[i]], 1);
    }
}
__global__ void hist_ct_kernel(const int* __restrict__ ed)
{
    for (int i = blockIdx.x*blockDim.x + threadIdx.x; i < ECTg; i += gridDim.x*blockDim.x)
        atomicAdd(&g_deg[2*NTg + ed[i]], 1);
}

__global__ void scan1_kernel()
{
    int arr  = blockIdx.y;
    int base = blockIdx.x * 1024 + threadIdx.x;
    int lane = threadIdx.x & 31, wid = threadIdx.x >> 5;
    int v = (base < NTg) ? g_deg[arr*NTg + base] : 0;
    int x = v;
    #pragma unroll
    for (int o = 1; o < 32; o <<= 1) { int y = __shfl_up_sync(0xffffffffu, x, o); if (lane >= o) x += y; }
    __shared__ int ws[32];
    if (lane == 31) ws[wid] = x;
    __syncthreads();
    if (wid == 0) {
        int wv = ws[lane]; int wx = wv;
        #pragma unroll
        for (int o = 1; o < 32; o <<= 1) { int y = __shfl_up_sync(0xffffffffu, wx, o); if (lane >= o) wx += y; }
        if (lane == 31) g_aux[arr*128 + blockIdx.x] = wx;
        ws[lane] = wx - wv;
    }
    __syncthreads();
    int excl = x - v + ws[wid];
    if (base < NTg) g_cur[arr*NTg + base] = excl;
}

__global__ void scan2_kernel()
{
    int arr  = threadIdx.x >> 5;
    int lane = threadIdx.x & 31;
    if (arr >= 3) return;
    const int NB = (NTg + 1023) / 1024;
    int carry = 0;
    for (int c = 0; c*32 < NB; c++) {
        int idx = c*32 + lane;
        int v = (idx < NB) ? g_aux[arr*128 + idx] : 0;
        int x = v;
        #pragma unroll
        for (int o = 1; o < 32; o <<= 1) { int y = __shfl_up_sync(0xffffffffu, x, o); if (lane >= o) x += y; }
        if (idx < NB) g_aux[arr*128 + idx] = x - v + carry;
        carry += __shfl_sync(0xffffffffu, x, 31);
    }
}

__global__ void scan3_kernel()
{
    for (int i = blockIdx.x*blockDim.x + threadIdx.x; i < 3*NTg; i += gridDim.x*blockDim.x) {
        int arr = i / NTg; int idx = i - arr*NTg;
        g_cur[i] += g_aux[arr*128 + (idx >> 10)];
    }
}

__global__ void fill_tt_kernel(const int* __restrict__ e0, const int* __restrict__ e1)
{
    for (int i = blockIdx.x*blockDim.x + threadIdx.x; i < ETTg; i += gridDim.x*blockDim.x) {
        int s = e0[i], d = e1[i];
        int p = atomicAdd(&g_cur[0*NTg + d], 1); g_csrf[p] = s;
        int q = atomicAdd(&g_cur[1*NTg + s], 1); g_csrr[q] = d;
    }
}
__global__ void fill_ct_kernel(const int* __restrict__ es, const int* __restrict__ ed)
{
    for (int i = blockIdx.x*blockDim.x + threadIdx.x; i < ECTg; i += gridDim.x*blockDim.x) {
        int p = atomicAdd(&g_cur[2*NTg + ed[i]], 1); g_csrct[p] = es[i];
    }
}

// --------- per-relation GAT, single pass, batch-4 edge processing for MLP -------------------
template<bool SELF>
__device__ __forceinline__ void gat_rel(
    const float* __restrict__ hsrc, const float* __restrict__ a_s,
    const int* __restrict__ csr, int start, int cnt, int d, int lane,
    float4 ad, float wgt, float r[4])
{
    if (!SELF && cnt == 0) { r[0]=0.f; r[1]=0.f; r[2]=0.f; r[3]=0.f; return; }

    float den0 = 0.f, den1 = 0.f, den2 = 0.f, den3 = 0.f;
    float ac0 = 0.f, ac1 = 0.f, ac2 = 0.f, ac3 = 0.f;

    if (SELF) {
        float4 as = *reinterpret_cast<const float4*>(a_s + (size_t)d*4);
        float p0 = __expf(lrelu02(as.x + ad.x));
        float p1 = __expf(lrelu02(as.y + ad.y));
        float p2 = __expf(lrelu02(as.z + ad.z));
        float p3 = __expf(lrelu02(as.w + ad.w));
        den0 = p0; den1 = p1; den2 = p2; den3 = p3;
        const float* row = hsrc + (size_t)d*128;
        ac0 = p0 * row[lane];      ac1 = p1 * row[32 + lane];
        ac2 = p2 * row[64 + lane]; ac3 = p3 * row[96 + lane];
    }

    int i = 0;
    for (; i + 4 <= cnt; i += 4) {
        int s0 = csr[start + i],     s1 = csr[start + i + 1];
        int s2 = csr[start + i + 2], s3 = csr[start + i + 3];
        float4 e0 = *reinterpret_cast<const float4*>(a_s + (size_t)s0*4);
        float4 e1 = *reinterpret_cast<const float4*>(a_s + (size_t)s1*4);
        float4 e2 = *reinterpret_cast<const float4*>(a_s + (size_t)s2*4);
        float4 e3 = *reinterpret_cast<const float4*>(a_s + (size_t)s3*4);
        float q00 = __expf(lrelu02(e0.x + ad.x)), q01 = __expf(lrelu02(e0.y + ad.y));
        float q02 = __expf(lrelu02(e0.z + ad.z)), q03 = __expf(lrelu02(e0.w + ad.w));
        float q10 = __expf(lrelu02(e1.x + ad.x)), q11 = __expf(lrelu02(e1.y + ad.y));
        float q12 = __expf(lrelu02(e1.z + ad.z)), q13 = __expf(lrelu02(e1.w + ad.w));
        float q20 = __expf(lrelu02(e2.x + ad.x)), q21 = __expf(lrelu02(e2.y + ad.y));
        float q22 = __expf(lrelu02(e2.z + ad.z)), q23 = __expf(lrelu02(e2.w + ad.w));
        float q30 = __expf(lrelu02(e3.x + ad.x)), q31 = __expf(lrelu02(e3.y + ad.y));
        float q32 = __expf(lrelu02(e3.z + ad.z)), q33 = __expf(lrelu02(e3.w + ad.w));
        den0 += (q00 + q10) + (q20 + q30);
        den1 += (q01 + q11) + (q21 + q31);
        den2 += (q02 + q12) + (q22 + q32);
        den3 += (q03 + q13) + (q23 + q33);
        const float* r0 = hsrc + (size_t)s0*128;
        const float* r1 = hsrc + (size_t)s1*128;
        const float* r2 = hsrc + (size_t)s2*128;
        const float* r3 = hsrc + (size_t)s3*128;
        ac0 = fmaf(q00, r0[lane],      fmaf(q10, r1[lane],      fmaf(q20, r2[lane],      fmaf(q30, r3[lane],      ac0))));
        ac1 = fmaf(q01, r0[32 + lane], fmaf(q11, r1[32 + lane], fmaf(q21, r2[32 + lane], fmaf(q31, r3[32 + lane], ac1))));
        ac2 = fmaf(q02, r0[64 + lane], fmaf(q12, r1[64 + lane], fmaf(q22, r2[64 + lane], fmaf(q32, r3[64 + lane], ac2))));
        ac3 = fmaf(q03, r0[96 + lane], fmaf(q13, r1[96 + lane], fmaf(q23, r2[96 + lane], fmaf(q33, r3[96 + lane], ac3))));
    }
    for (; i < cnt; i++) {
        int s = csr[start + i];
        float4 as = *reinterpret_cast<const float4*>(a_s + (size_t)s*4);
        float p0 = __expf(lrelu02(as.x + ad.x));
        float p1 = __expf(lrelu02(as.y + ad.y));
        float p2 = __expf(lrelu02(as.z + ad.z));
        float p3 = __expf(lrelu02(as.w + ad.w));
        den0 += p0; den1 += p1; den2 += p2; den3 += p3;
        const float* row = hsrc + (size_t)s*128;
        ac0 = fmaf(p0, row[lane],       ac0);
        ac1 = fmaf(p1, row[32 + lane],  ac1);
        ac2 = fmaf(p2, row[64 + lane],  ac2);
        ac3 = fmaf(p3, row[96 + lane],  ac3);
    }

    r[0] = ac0 * (wgt / den0); r[1] = ac1 * (wgt / den1);
    r[2] = ac2 * (wgt / den2); r[3] = ac3 * (wgt / den3);
}

// --- merged GAT over all 3 relations; writes z = relu(acc + cbias + ht) directly ------------
__global__ void gat_all_kernel(
    const float* __restrict__ hs, const float* __restrict__ hd, const float* __restrict__ hcs,
    const float* __restrict__ ht,
    const float* __restrict__ asf, const float* __restrict__ adf,
    const float* __restrict__ asr, const float* __restrict__ adr,
    const float* __restrict__ asct, const float* __restrict__ adct,
    const int* __restrict__ cur, const int* __restrict__ deg,
    const int* __restrict__ csrf, const int* __restrict__ csrr, const int* __restrict__ csrct,
    const float* __restrict__ bsd, const float* __restrict__ bds, const float* __restrict__ bct,
    float* __restrict__ z)
{
    int d    = (blockIdx.x * blockDim.x + threadIdx.x) >> 5;
    int lane = threadIdx.x & 31;
    if (d >= NTg) return;

    float rf[4], rr_[4], rc[4];
    {
        int c = deg[0*NTg + d];
        gat_rel<true >(hs, asf, csrf, cur[0*NTg + d] - c, c, d, lane,
                       *reinterpret_cast<const float4*>(adf + (size_t)d*4), 0.25f, rf);
    }
    {
        int c = deg[1*NTg + d];
        gat_rel<true >(hd, asr, csrr, cur[1*NTg + d] - c, c, d, lane,
                       *reinterpret_cast<const float4*>(adr + (size_t)d*4), 0.25f, rr_);
    }
    {
        int c = deg[2*NTg + d];
        gat_rel<false>(hcs, asct, csrct, cur[2*NTg + d] - c, c, d, lane,
                       *reinterpret_cast<const float4*>(adct + (size_t)d*4), 0.5f, rc);
    }

    const float* hrow = ht + (size_t)d*128;
    float* zrow = z + (size_t)d*128;
    #pragma unroll
    for (int h = 0; h < 4; h++) {
        int c = h*32 + lane;
        float cb = 0.25f*bsd[c] + 0.25f*bds[c] + 0.5f*bct[c];
        float v  = rf[h] + rr_[h] + rc[h] + hrow[c] + cb;
        zrow[c] = fmaxf(v, 0.f);
    }
}

// ----------------------------------- launch -------------------------------------------------
extern "C" void kernel_launch(void* const* d_in, const int* in_sizes, int n_in,
                              void* d_out, int out_size)
{
    const float* x_t     = (const float*)d_in[0];
    const float* x_c     = (const float*)d_in[1];
    const int*   ett     = (const int*)d_in[2];
    const int*   e0      = ett;
    const int*   e1      = ett + ETTg;
    const int*   ect_s   = (const int*)d_in[3];
    const int*   ect_d   = (const int*)d_in[4];
    const float* W_pre_t = (const float*)d_in[5];
    const float* b_pre_t = (const float*)d_in[6];
    const float* W_pre_c = (const float*)d_in[7];
    const float* b_pre_c = (const float*)d_in[8];
    const float* W_sd    = (const float*)d_in[9];
    const float* att_s_sd= (const float*)d_in[10];
    const float* att_d_sd= (const float*)d_in[11];
    const float* b_sd    = (const float*)d_in[12];
    const float* W_ds    = (const float*)d_in[13];
    const float* att_s_ds= (const float*)d_in[14];
    const float* att_d_ds= (const float*)d_in[15];
    const float* b_ds    = (const float*)d_in[16];
    const float* W_ct_s  = (const float*)d_in[17];
    const float* W_ct_d  = (const float*)d_in[18];
    const float* att_s_ct= (const float*)d_in[19];
    const float* att_d_ct= (const float*)d_in[20];
    const float* b_ct    = (const float*)d_in[21];
    const float* W_out   = (const float*)d_in[22];
    const float* b_out   = (const float*)d_in[23];
    float* out = (float*)d_out;

    float *p_ht, *p_hc, *p_hs, *p_hd, *p_hcs, *p_z, *p_wv;
    float *p_asf, *p_adf, *p_asr, *p_adr, *p_adct, *p_asct;
    int *p_deg, *p_cur, *p_csrf, *p_csrr, *p_csrct;
    __nv_bfloat16 *p_whi, *p_wlo;
    cudaGetSymbolAddress((void**)&p_ht,  g_ht);
    cudaGetSymbolAddress((void**)&p_hc,  g_hc);
    cudaGetSymbolAddress((void**)&p_hs,  g_hs);
    cudaGetSymbolAddress((void**)&p_hd,  g_hd);
    cudaGetSymbolAddress((void**)&p_hcs, g_hcs);
    cudaGetSymbolAddress((void**)&p_z,   g_z);
    cudaGetSymbolAddress((void**)&p_wv,  g_wv);
    cudaGetSymbolAddress((void**)&p_asf, g_asf);
    cudaGetSymbolAddress((void**)&p_adf, g_adf);
    cudaGetSymbolAddress((void**)&p_asr, g_asr);
    cudaGetSymbolAddress((void**)&p_adr, g_adr);
    cudaGetSymbolAddress((void**)&p_adct,g_adct);
    cudaGetSymbolAddress((void**)&p_asct,g_asct);
    cudaGetSymbolAddress((void**)&p_deg, g_deg);
    cudaGetSymbolAddress((void**)&p_cur, g_cur);
    cudaGetSymbolAddress((void**)&p_csrf, g_csrf);
    cudaGetSymbolAddress((void**)&p_csrr, g_csrr);
    cudaGetSymbolAddress((void**)&p_csrct,g_csrct);
    cudaGetSymbolAddress((void**)&p_whi, g_whi);
    cudaGetSymbolAddress((void**)&p_wlo, g_wlo);

    // smem: (2*64 + 2*128) rows * (K+8) cols * 2B
    const int SM128 = (2*64 + 2*128) * (128 + 8) * 2;   // 104448
    const int SM64  = (2*64 + 2*128) * (64  + 8) * 2;   // 55296
    const int SM32  = (2*64 + 2*128) * (32  + 8) * 2;   // 30720
    cudaFuncSetAttribute(tc_gemm_dual,               cudaFuncAttributeMaxDynamicSharedMemorySize, SM128);
    cudaFuncSetAttribute(tc_gemm<128,false,false,1>, cudaFuncAttributeMaxDynamicSharedMemorySize, SM128);
    cudaFuncSetAttribute(tc_gemm<128,false,true, 0>, cudaFuncAttributeMaxDynamicSharedMemorySize, SM128);
    cudaFuncSetAttribute(tc_gemm<64, true, true, 0>, cudaFuncAttributeMaxDynamicSharedMemorySize, SM64);
    cudaFuncSetAttribute(tc_gemm<32, true, true, 0>, cudaFuncAttributeMaxDynamicSharedMemorySize, SM32);

    const int GT = (NTg + 63) / 64;   // 1563
    const int GC = (NCg + 63) / 64;   // 391

    // slots: 0 pre_t K=64, 1 pre_c K=32, 2 sd, 3 ds, 4 ct_s, 5 out  (W_ct_d folded into wv)
    WJobs jobs;
    jobs.W[0] = W_pre_t; jobs.K[0] = 64;
    jobs.W[1] = W_pre_c; jobs.K[1] = 32;
    jobs.W[2] = W_sd;    jobs.K[2] = 128;
    jobs.W[3] = W_ds;    jobs.K[3] = 128;
    jobs.W[4] = W_ct_s;  jobs.K[4] = 128;
    jobs.W[5] = W_out;   jobs.K[5] = 128;

    wv_kernel<<<1, 512>>>(W_ct_d, att_d_ct, p_wv);                                  // k1
    wsplit_all<<<dim3(64, 6), 256>>>(jobs, p_whi, p_wlo);                           // k2
    tc_gemm<64,true,true,0><<<GT, 256, SM64>>>(x_t, p_whi + 0*16384, p_wlo + 0*16384,
        b_pre_t, p_ht, NTg, nullptr, nullptr);                                      // k3
    tc_gemm_dual<<<GT, 256, SM128>>>(p_ht,
        p_whi + 2*16384, p_wlo + 2*16384, p_whi + 3*16384, p_wlo + 3*16384,
        p_hs, p_hd, NTg,
        att_s_sd, att_d_sd, att_s_ds, att_d_ds,
        p_asf, p_adf, p_asr, p_adr);                                                // k4 <- ncu
    tc_gemm<32,true,true,0><<<GC, 256, SM32>>>(x_c, p_whi + 1*16384, p_wlo + 1*16384,
        b_pre_c, p_hc, NCg, nullptr, nullptr);                                      // k5
    tc_gemm<128,false,false,1><<<GC, 256, SM128>>>(p_hc, p_whi + 4*16384, p_wlo + 4*16384,
        nullptr, p_hcs, NCg, att_s_ct, p_asct);                                     // k6
    attv_kernel<<<(NTg + 7) / 8, 256>>>(p_ht, p_wv, p_adct, NTg);                   // k7

    // CSR build
    cudaMemsetAsync(p_deg, 0, 3*NTg*sizeof(int));
    hist_tt_kernel<<<512, 256>>>(e0, e1);
    hist_ct_kernel<<<256, 256>>>(ect_d);
    dim3 g1((NTg + 1023) / 1024, 3);
    scan1_kernel<<<g1, 1024>>>();
    scan2_kernel<<<1, 96>>>();
    scan3_kernel<<<256, 256>>>();
    fill_tt_kernel<<<512, 256>>>(e0, e1);
    fill_ct_kernel<<<256, 256>>>(ect_s, ect_d);

    // merged GAT (high occupancy, batch-4 MLP): z = relu(0.25*sd + 0.25*ds + 0.5*ct + cbias + ht)
    gat_all_kernel<<<(NTg + 7) / 8, 256>>>(
        p_hs, p_hd, p_hcs, p_ht,
        p_asf, p_adf, p_asr, p_adr, p_asct, p_adct,
        p_cur, p_deg, p_csrf, p_csrr, p_csrct,
        b_sd, b_ds, b_ct, p_z);

    // final: out = z @ W_out + b_out
    tc_gemm<128,false,true,0><<<GT, 256, SM128>>>(p_z, p_whi + 5*16384, p_wlo + 5*16384,
        b_out, out, NTg, nullptr, nullptr);
}

// round 10
// speedup vs baseline: 1.3487x; 1.0738x over previous
#include <cuda_runtime.h>
#include <cuda_bf16.h>
#include <cstdint>

#define NTg  100000
#define NCg  25000
#define ETTg 800000
#define ECTg 400000
#define HIDg 128

// ------------------------- scratch (device globals; allocation-free) -------------------------
__device__ float g_ht [NTg*HIDg];
__device__ float g_hs [NTg*HIDg];
__device__ float g_hd [NTg*HIDg];
__device__ float g_hcs[NCg*HIDg];
__device__ float g_z  [NTg*HIDg];
__device__ float g_asf[NTg*4];
__device__ float g_adf[NTg*4];
__device__ float g_asr[NTg*4];
__device__ float g_adr[NTg*4];
__device__ float g_adct[NTg*4];
__device__ float g_asct[NCg*4];
__device__ float g_wv [4*128];
__device__ int   g_deg[3*NTg];
__device__ int   g_cur[3*NTg];
__device__ int   g_aux[3*128];
__device__ int   g_csrf[ETTg];
__device__ int   g_csrr[ETTg];
__device__ int   g_csrct[ECTg];
// split weights: 6 slots of up to 128x128 bf16 ([N,K] layout, i.e., W^T)
__device__ __nv_bfloat16 g_whi[6*128*128];
__device__ __nv_bfloat16 g_wlo[6*128*128];

__device__ __forceinline__ float lrelu02(float x) { return x > 0.f ? x : 0.2f * x; }

__device__ __forceinline__ uint32_t smem_u32(const void* p) {
    uint32_t a;
    asm("{ .reg .u64 t; cvta.to.shared.u64 t, %1; cvt.u32.u64 %0, t; }" : "=r"(a) : "l"(p));
    return a;
}

__device__ __forceinline__ void ldm_x4(uint32_t* r, uint32_t addr) {
    asm volatile("ldmatrix.sync.aligned.m8n8.x4.shared.b16 {%0,%1,%2,%3}, [%4];"
                 : "=r"(r[0]), "=r"(r[1]), "=r"(r[2]), "=r"(r[3]) : "r"(addr));
}
__device__ __forceinline__ void mma_bf16(float* c, const uint32_t* a, const uint32_t* b) {
    asm volatile("mma.sync.aligned.m16n8k16.row.col.f32.bf16.bf16.f32 "
                 "{%0,%1,%2,%3}, {%4,%5,%6,%7}, {%8,%9}, {%0,%1,%2,%3};"
                 : "+f"(c[0]), "+f"(c[1]), "+f"(c[2]), "+f"(c[3])
                 : "r"(a[0]), "r"(a[1]), "r"(a[2]), "r"(a[3]), "r"(b[0]), "r"(b[1]));
}

// ------------------- batched W split/transpose: hi/lo[n*K+k] = split(W[k*128+n]) ------------
struct WJobs { const float* W[6]; int K[6]; };

__global__ void wsplit_all(WJobs jobs, __nv_bfloat16* __restrict__ hiB,
                           __nv_bfloat16* __restrict__ loB)
{
    int slot = blockIdx.y;
    const float* W = jobs.W[slot];
    int K = jobs.K[slot];
    __nv_bfloat16* hi = hiB + slot*16384;
    __nv_bfloat16* lo = loB + slot*16384;
    int tot = 128 * K;
    for (int i = blockIdx.x*blockDim.x + threadIdx.x; i < tot; i += gridDim.x*blockDim.x) {
        int n = i / K, k = i - n*K;
        float v = W[k*128 + n];
        __nv_bfloat16 h = __float2bfloat16(v);
        hi[i] = h;
        lo[i] = __float2bfloat16(v - __bfloat162float(h));
    }
}

// ----------------- wv[h*128+k] = sum_c W_ct_dst[k*128 + h*32 + c] * att[h*32+c] -------------
__global__ void wv_kernel(const float* __restrict__ W, const float* __restrict__ att,
                          float* __restrict__ wv)
{
    int i = threadIdx.x;           // 512 threads: k = i>>2, h = i&3
    int k = i >> 2, h = i & 3;
    float s = 0.f;
    #pragma unroll 8
    for (int c = 0; c < 32; c++) s += W[k*128 + h*32 + c] * att[h*32 + c];
    wv[h*128 + k] = s;
}

// ---------------- HMMA GEMM: C[M,128] = A[M,K] @ W[K,128]  (3-split bf16) -------------------
// CTA tile 64x128 (2 CTAs/SM), 8 warps, warp tile 32x32. W^T ([N,K]) pre-split in gmem.
// NATT: 0 = none; 1 = fused logits outS[r,head] = sum_c C[r,c]*attS[c] (head = c>>5)
//       3 = fused full-row dots outS[r,h] = sum_{c=0..127} C[r,c]*attS[h*128+c]  (attS = wv)
template<int K, bool RELU, bool BIAS, int NATT>
__global__ void __launch_bounds__(256, 2) tc_gemm(
    const float* __restrict__ A, const __nv_bfloat16* __restrict__ Whi,
    const __nv_bfloat16* __restrict__ Wlo, const float* __restrict__ bias,
    float* __restrict__ C, int M,
    const float* __restrict__ attS, float* __restrict__ outS)
{
    constexpr int LDA = K + 8;
    extern __shared__ __nv_bfloat16 smb[];
    __nv_bfloat16* sAhi = smb;                 // 64*LDA
    __nv_bfloat16* sAlo = sAhi + 64*LDA;
    __nv_bfloat16* sWhi = sAlo + 64*LDA;       // 128*LDA
    __nv_bfloat16* sWlo = sWhi + 128*LDA;

    const int tid  = threadIdx.x;
    const int lane = tid & 31;
    const int wid  = tid >> 5;
    const int bm   = blockIdx.x * 64;

    for (int idx = tid; idx < 64*(K/4); idx += 256) {
        int r  = idx / (K/4);
        int k0 = (idx % (K/4)) * 4;
        int row = bm + r;
        float4 v = make_float4(0.f, 0.f, 0.f, 0.f);
        if (row < M) v = *reinterpret_cast<const float4*>(A + (size_t)row*K + k0);
        __nv_bfloat16 h0 = __float2bfloat16(v.x), h1 = __float2bfloat16(v.y);
        __nv_bfloat16 h2 = __float2bfloat16(v.z), h3 = __float2bfloat16(v.w);
        __nv_bfloat16 l0 = __float2bfloat16(v.x - __bfloat162float(h0));
        __nv_bfloat16 l1 = __float2bfloat16(v.y - __bfloat162float(h1));
        __nv_bfloat16 l2 = __float2bfloat16(v.z - __bfloat162float(h2));
        __nv_bfloat16 l3 = __float2bfloat16(v.w - __bfloat162float(h3));
        __nv_bfloat16* pH = sAhi + r*LDA + k0;
        __nv_bfloat16* pL = sAlo + r*LDA + k0;
        *reinterpret_cast<__nv_bfloat162*>(pH)     = __halves2bfloat162(h0, h1);
        *reinterpret_cast<__nv_bfloat162*>(pH + 2) = __halves2bfloat162(h2, h3);
        *reinterpret_cast<__nv_bfloat162*>(pL)     = __halves2bfloat162(l0, l1);
        *reinterpret_cast<__nv_bfloat162*>(pL + 2) = __halves2bfloat162(l2, l3);
    }
    for (int idx = tid; idx < 128*(K/8); idx += 256) {
        int n  = idx / (K/8);
        int k0 = (idx % (K/8)) * 8;
        *reinterpret_cast<uint4*>(sWhi + n*LDA + k0) = *reinterpret_cast<const uint4*>(Whi + (size_t)n*K + k0);
        *reinterpret_cast<uint4*>(sWlo + n*LDA + k0) = *reinterpret_cast<const uint4*>(Wlo + (size_t)n*K + k0);
    }
    __syncthreads();

    const int row0 = (wid & 1) * 32;
    const int col0 = (wid >> 1) * 32;

    uint32_t aB[2][2], bB[2][2];
    {
        int ar = (lane & 15), ac = (lane >> 4) * 8;
        #pragma unroll
        for (int mi = 0; mi < 2; mi++) {
            aB[0][mi] = smem_u32(sAhi + (row0 + mi*16 + ar)*LDA + ac);
            aB[1][mi] = smem_u32(sAlo + (row0 + mi*16 + ar)*LDA + ac);
        }
        int q  = lane >> 3;
        int nr = (q >> 1)*8 + (lane & 7);
        int nc = (q & 1)*8;
        #pragma unroll
        for (int nt = 0; nt < 2; nt++) {
            bB[0][nt] = smem_u32(sWhi + (col0 + nt*16 + nr)*LDA + nc);
            bB[1][nt] = smem_u32(sWlo + (col0 + nt*16 + nr)*LDA + nc);
        }
    }

    float acc[2][4][4];
    #pragma unroll
    for (int mi = 0; mi < 2; mi++)
        #pragma unroll
        for (int ni = 0; ni < 4; ni++)
            { acc[mi][ni][0]=0.f; acc[mi][ni][1]=0.f; acc[mi][ni][2]=0.f; acc[mi][ni][3]=0.f; }

    #pragma unroll 2
    for (int ks = 0; ks < K/16; ks++) {
        uint32_t koff = (uint32_t)ks * 32u;
        uint32_t ah[2][4], al[2][4], bh[2][4], bl[2][4];
        #pragma unroll
        for (int mi = 0; mi < 2; mi++) { ldm_x4(ah[mi], aB[0][mi] + koff); ldm_x4(al[mi], aB[1][mi] + koff); }
        #pragma unroll
        for (int nt = 0; nt < 2; nt++) { ldm_x4(bh[nt], bB[0][nt] + koff); ldm_x4(bl[nt], bB[1][nt] + koff); }
        #pragma unroll
        for (int mi = 0; mi < 2; mi++)
            #pragma unroll
            for (int nt = 0; nt < 2; nt++) {
                mma_bf16(acc[mi][nt*2],   ah[mi], &bh[nt][0]);
                mma_bf16(acc[mi][nt*2+1], ah[mi], &bh[nt][2]);
                mma_bf16(acc[mi][nt*2],   ah[mi], &bl[nt][0]);
                mma_bf16(acc[mi][nt*2+1], ah[mi], &bl[nt][2]);
                mma_bf16(acc[mi][nt*2],   al[mi], &bh[nt][0]);
                mma_bf16(acc[mi][nt*2+1], al[mi], &bh[nt][2]);
            }
    }

    const int g = lane >> 2, t = lane & 3;
    float lsS[2][2];
    float lsA[2][2][4];
    if (NATT == 1) { lsS[0][0]=0.f; lsS[0][1]=0.f; lsS[1][0]=0.f; lsS[1][1]=0.f; }
    if (NATT == 3) {
        #pragma unroll
        for (int a = 0; a < 2; a++)
            #pragma unroll
            for (int b = 0; b < 2; b++)
                #pragma unroll
                for (int h = 0; h < 4; h++) lsA[a][b][h] = 0.f;
    }
    #pragma unroll
    for (int mi = 0; mi < 2; mi++) {
        #pragma unroll
        for (int ni = 0; ni < 4; ni++) {
            int cc = col0 + ni*8 + t*2;
            float bx = 0.f, by = 0.f;
            if (BIAS) { bx = bias[cc]; by = bias[cc+1]; }
            int r1 = bm + row0 + mi*16 + g;
            float2 v0 = make_float2(acc[mi][ni][0] + bx, acc[mi][ni][1] + by);
            float2 v1 = make_float2(acc[mi][ni][2] + bx, acc[mi][ni][3] + by);
            if (RELU) {
                v0.x = fmaxf(v0.x, 0.f); v0.y = fmaxf(v0.y, 0.f);
                v1.x = fmaxf(v1.x, 0.f); v1.y = fmaxf(v1.y, 0.f);
            }
            if (NATT == 1) {
                float a0 = __ldg(attS + cc), a1 = __ldg(attS + cc + 1);
                lsS[mi][0] += v0.x*a0 + v0.y*a1;
                lsS[mi][1] += v1.x*a0 + v1.y*a1;
            }
            if (NATT == 3) {
                #pragma unroll
                for (int h = 0; h < 4; h++) {
                    float w0 = __ldg(attS + h*128 + cc), w1 = __ldg(attS + h*128 + cc + 1);
                    lsA[mi][0][h] += v0.x*w0 + v0.y*w1;
                    lsA[mi][1][h] += v1.x*w0 + v1.y*w1;
                }
            }
            if (r1 < M)     *reinterpret_cast<float2*>(C + (size_t)r1*128 + cc)     = v0;
            if (r1 + 8 < M) *reinterpret_cast<float2*>(C + (size_t)(r1+8)*128 + cc) = v1;
        }
    }
    if (NATT == 1) {
        #pragma unroll
        for (int mi = 0; mi < 2; mi++)
            #pragma unroll
            for (int rr = 0; rr < 2; rr++) {
                float v = lsS[mi][rr];
                v += __shfl_xor_sync(0xffffffffu, v, 1);
                v += __shfl_xor_sync(0xffffffffu, v, 2);
                lsS[mi][rr] = v;
            }
        if (t == 0) {
            int head = col0 >> 5;
            #pragma unroll
            for (int mi = 0; mi < 2; mi++)
                #pragma unroll
                for (int rr = 0; rr < 2; rr++) {
                    int r = bm + row0 + mi*16 + g + rr*8;
                    if (r < M) outS[(size_t)r*4 + head] = lsS[mi][rr];
                }
        }
    }
    if (NATT == 3) {
        float* sRed = reinterpret_cast<float*>(smb + (size_t)(2*64 + 2*128)*LDA);  // [64][16]
        #pragma unroll
        for (int mi = 0; mi < 2; mi++)
            #pragma unroll
            for (int rr = 0; rr < 2; rr++)
                #pragma unroll
                for (int h = 0; h < 4; h++) {
                    float v = lsA[mi][rr][h];
                    v += __shfl_xor_sync(0xffffffffu, v, 1);
                    v += __shfl_xor_sync(0xffffffffu, v, 2);
                    lsA[mi][rr][h] = v;
                }
        int cg = wid >> 1;
        if (t == 0) {
            #pragma unroll
            for (int mi = 0; mi < 2; mi++)
                #pragma unroll
                for (int rr = 0; rr < 2; rr++) {
                    int lr = row0 + mi*16 + g + rr*8;
                    #pragma unroll
                    for (int h = 0; h < 4; h++)
                        sRed[lr*16 + cg*4 + h] = lsA[mi][rr][h];
                }
        }
        __syncthreads();
        {
            int lr = tid >> 2, h = tid & 3;
            float s = sRed[lr*16 + h] + sRed[lr*16 + 4 + h]
                    + sRed[lr*16 + 8 + h] + sRed[lr*16 + 12 + h];
            int r = bm + lr;
            if (r < M) outS[(size_t)r*4 + h] = s;
        }
    }
}

// ------------- dual-slot HMMA GEMM: A resident; computes hs AND hd + both logit pairs -------
__global__ void __launch_bounds__(256, 2) tc_gemm_dual(
    const float* __restrict__ A,
    const __nv_bfloat16* __restrict__ Whi0, const __nv_bfloat16* __restrict__ Wlo0,
    const __nv_bfloat16* __restrict__ Whi1, const __nv_bfloat16* __restrict__ Wlo1,
    float* __restrict__ C0, float* __restrict__ C1, int M,
    const float* __restrict__ attS0, const float* __restrict__ attD0,
    const float* __restrict__ attS1, const float* __restrict__ attD1,
    float* __restrict__ outS0, float* __restrict__ outD0,
    float* __restrict__ outS1, float* __restrict__ outD1)
{
    constexpr int K = 128, LDA = K + 8;
    extern __shared__ __nv_bfloat16 smb[];
    __nv_bfloat16* sAhi = smb;
    __nv_bfloat16* sAlo = sAhi + 64*LDA;
    __nv_bfloat16* sWhi = sAlo + 64*LDA;
    __nv_bfloat16* sWlo = sWhi + 128*LDA;

    const int tid  = threadIdx.x;
    const int lane = tid & 31;
    const int wid  = tid >> 5;
    const int bm   = blockIdx.x * 64;

    for (int idx = tid; idx < 64*(K/4); idx += 256) {
        int r  = idx / (K/4);
        int k0 = (idx % (K/4)) * 4;
        int row = bm + r;
        float4 v = make_float4(0.f, 0.f, 0.f, 0.f);
        if (row < M) v = *reinterpret_cast<const float4*>(A + (size_t)row*K + k0);
        __nv_bfloat16 h0 = __float2bfloat16(v.x), h1 = __float2bfloat16(v.y);
        __nv_bfloat16 h2 = __float2bfloat16(v.z), h3 = __float2bfloat16(v.w);
        __nv_bfloat16 l0 = __float2bfloat16(v.x - __bfloat162float(h0));
        __nv_bfloat16 l1 = __float2bfloat16(v.y - __bfloat162float(h1));
        __nv_bfloat16 l2 = __float2bfloat16(v.z - __bfloat162float(h2));
        __nv_bfloat16 l3 = __float2bfloat16(v.w - __bfloat162float(h3));
        __nv_bfloat16* pH = sAhi + r*LDA + k0;
        __nv_bfloat16* pL = sAlo + r*LDA + k0;
        *reinterpret_cast<__nv_bfloat162*>(pH)     = __halves2bfloat162(h0, h1);
        *reinterpret_cast<__nv_bfloat162*>(pH + 2) = __halves2bfloat162(h2, h3);
        *reinterpret_cast<__nv_bfloat162*>(pL)     = __halves2bfloat162(l0, l1);
        *reinterpret_cast<__nv_bfloat162*>(pL + 2) = __halves2bfloat162(l2, l3);
    }

    const int row0 = (wid & 1) * 32;
    const int col0 = (wid >> 1) * 32;
    uint32_t aB[2][2], bB[2][2];
    {
        int ar = (lane & 15), ac = (lane >> 4) * 8;
        #pragma unroll
        for (int mi = 0; mi < 2; mi++) {
            aB[0][mi] = smem_u32(sAhi + (row0 + mi*16 + ar)*LDA + ac);
            aB[1][mi] = smem_u32(sAlo + (row0 + mi*16 + ar)*LDA + ac);
        }
        int q  = lane >> 3;
        int nr = (q >> 1)*8 + (lane & 7);
        int nc = (q & 1)*8;
        #pragma unroll
        for (int nt = 0; nt < 2; nt++) {
            bB[0][nt] = smem_u32(sWhi + (col0 + nt*16 + nr)*LDA + nc);
            bB[1][nt] = smem_u32(sWlo + (col0 + nt*16 + nr)*LDA + nc);
        }
    }
    const int g = lane >> 2, t = lane & 3;

    #pragma unroll
    for (int slot = 0; slot < 2; slot++) {
        const __nv_bfloat16* Whi = slot ? Whi1 : Whi0;
        const __nv_bfloat16* Wlo = slot ? Wlo1 : Wlo0;
        float* C = slot ? C1 : C0;
        const float* attS = slot ? attS1 : attS0;
        const float* attD = slot ? attD1 : attD0;
        float* outS = slot ? outS1 : outS0;
        float* outD = slot ? outD1 : outD0;

        for (int idx = tid; idx < 128*(K/8); idx += 256) {
            int n  = idx / (K/8);
            int k0 = (idx % (K/8)) * 8;
            *reinterpret_cast<uint4*>(sWhi + n*LDA + k0) = *reinterpret_cast<const uint4*>(Whi + (size_t)n*K + k0);
            *reinterpret_cast<uint4*>(sWlo + n*LDA + k0) = *reinterpret_cast<const uint4*>(Wlo + (size_t)n*K + k0);
        }
        __syncthreads();

        float acc[2][4][4];
        #pragma unroll
        for (int mi = 0; mi < 2; mi++)
            #pragma unroll
            for (int ni = 0; ni < 4; ni++)
                { acc[mi][ni][0]=0.f; acc[mi][ni][1]=0.f; acc[mi][ni][2]=0.f; acc[mi][ni][3]=0.f; }

        #pragma unroll 2
        for (int ks = 0; ks < K/16; ks++) {
            uint32_t koff = (uint32_t)ks * 32u;
            uint32_t ah[2][4], al[2][4], bh[2][4], bl[2][4];
            #pragma unroll
            for (int mi = 0; mi < 2; mi++) { ldm_x4(ah[mi], aB[0][mi] + koff); ldm_x4(al[mi], aB[1][mi] + koff); }
            #pragma unroll
            for (int nt = 0; nt < 2; nt++) { ldm_x4(bh[nt], bB[0][nt] + koff); ldm_x4(bl[nt], bB[1][nt] + koff); }
            #pragma unroll
            for (int mi = 0; mi < 2; mi++)
                #pragma unroll
                for (int nt = 0; nt < 2; nt++) {
                    mma_bf16(acc[mi][nt*2],   ah[mi], &bh[nt][0]);
                    mma_bf16(acc[mi][nt*2+1], ah[mi], &bh[nt][2]);
                    mma_bf16(acc[mi][nt*2],   ah[mi], &bl[nt][0]);
                    mma_bf16(acc[mi][nt*2+1], ah[mi], &bl[nt][2]);
                    mma_bf16(acc[mi][nt*2],   al[mi], &bh[nt][0]);
                    mma_bf16(acc[mi][nt*2+1], al[mi], &bh[nt][2]);
                }
        }

        float lsS[2][2], lsD[2][2];
        lsS[0][0]=0.f; lsS[0][1]=0.f; lsS[1][0]=0.f; lsS[1][1]=0.f;
        lsD[0][0]=0.f; lsD[0][1]=0.f; lsD[1][0]=0.f; lsD[1][1]=0.f;

        #pragma unroll
        for (int mi = 0; mi < 2; mi++) {
            #pragma unroll
            for (int ni = 0; ni < 4; ni++) {
                int cc = col0 + ni*8 + t*2;
                int r1 = bm + row0 + mi*16 + g;
                float2 v0 = make_float2(acc[mi][ni][0], acc[mi][ni][1]);
                float2 v1 = make_float2(acc[mi][ni][2], acc[mi][ni][3]);
                float a0 = __ldg(attS + cc), a1 = __ldg(attS + cc + 1);
                float d0 = __ldg(attD + cc), d1 = __ldg(attD + cc + 1);
                lsS[mi][0] += v0.x*a0 + v0.y*a1;
                lsS[mi][1] += v1.x*a0 + v1.y*a1;
                lsD[mi][0] += v0.x*d0 + v0.y*d1;
                lsD[mi][1] += v1.x*d0 + v1.y*d1;
                if (r1 < M)     *reinterpret_cast<float2*>(C + (size_t)r1*128 + cc)     = v0;
                if (r1 + 8 < M) *reinterpret_cast<float2*>(C + (size_t)(r1+8)*128 + cc) = v1;
            }
        }
        #pragma unroll
        for (int mi = 0; mi < 2; mi++)
            #pragma unroll
            for (int rr = 0; rr < 2; rr++) {
                float v = lsS[mi][rr];
                v += __shfl_xor_sync(0xffffffffu, v, 1);
                v += __shfl_xor_sync(0xffffffffu, v, 2);
                lsS[mi][rr] = v;
                float w = lsD[mi][rr];
                w += __shfl_xor_sync(0xffffffffu, w, 1);
                w += __shfl_xor_sync(0xffffffffu, w, 2);
                lsD[mi][rr] = w;
            }
        if (t == 0) {
            int head = col0 >> 5;
            #pragma unroll
            for (int mi = 0; mi < 2; mi++)
                #pragma unroll
                for (int rr = 0; rr < 2; rr++) {
                    int r = bm + row0 + mi*16 + g + rr*8;
                    if (r < M) {
                        outS[(size_t)r*4 + head] = lsS[mi][rr];
                        outD[(size_t)r*4 + head] = lsD[mi][rr];
                    }
                }
        }
        __syncthreads();   // all warps done with W smem before next slot reload
    }
}

// ----- chained GEMM: hc = relu(x_c@W_pre_c + b) (K=32, smem-resident) -> hcs = hc@W_ct_s ----
__global__ void __launch_bounds__(256, 2) tc_gemm_chain(
    const float* __restrict__ xc,
    const __nv_bfloat16* __restrict__ W1hi, const __nv_bfloat16* __restrict__ W1lo,
    const float* __restrict__ b1,
    const __nv_bfloat16* __restrict__ W2hi, const __nv_bfloat16* __restrict__ W2lo,
    float* __restrict__ C, int M,
    const float* __restrict__ attS, float* __restrict__ outS)
{
    constexpr int LDA = 136;   // 128+8, used for both phases
    extern __shared__ __nv_bfloat16 smb[];
    __nv_bfloat16* sAhi = smb;
    __nv_bfloat16* sAlo = sAhi + 64*LDA;
    __nv_bfloat16* sWhi = sAlo + 64*LDA;
    __nv_bfloat16* sWlo = sWhi + 128*LDA;

    const int tid  = threadIdx.x;
    const int lane = tid & 31;
    const int wid  = tid >> 5;
    const int bm   = blockIdx.x * 64;

    // ---- phase 1 loads: x_c tile [64,32] split; W1 (K=32) [128,32] ----
    for (int idx = tid; idx < 64*8; idx += 256) {
        int r  = idx >> 3;
        int k0 = (idx & 7) * 4;
        int row = bm + r;
        float4 v = make_float4(0.f, 0.f, 0.f, 0.f);
        if (row < M) v = *reinterpret_cast<const float4*>(xc + (size_t)row*32 + k0);
        __nv_bfloat16 h0 = __float2bfloat16(v.x), h1 = __float2bfloat16(v.y);
        __nv_bfloat16 h2 = __float2bfloat16(v.z), h3 = __float2bfloat16(v.w);
        __nv_bfloat16 l0 = __float2bfloat16(v.x - __bfloat162float(h0));
        __nv_bfloat16 l1 = __float2bfloat16(v.y - __bfloat162float(h1));
        __nv_bfloat16 l2 = __float2bfloat16(v.z - __bfloat162float(h2));
        __nv_bfloat16 l3 = __float2bfloat16(v.w - __bfloat162float(h3));
        __nv_bfloat16* pH = sAhi + r*LDA + k0;
        __nv_bfloat16* pL = sAlo + r*LDA + k0;
        *reinterpret_cast<__nv_bfloat162*>(pH)     = __halves2bfloat162(h0, h1);
        *reinterpret_cast<__nv_bfloat162*>(pH + 2) = __halves2bfloat162(h2, h3);
        *reinterpret_cast<__nv_bfloat162*>(pL)     = __halves2bfloat162(l0, l1);
        *reinterpret_cast<__nv_bfloat162*>(pL + 2) = __halves2bfloat162(l2, l3);
    }
    for (int idx = tid; idx < 128*4; idx += 256) {
        int n  = idx >> 2;
        int k0 = (idx & 3) * 8;
        *reinterpret_cast<uint4*>(sWhi + n*LDA + k0) = *reinterpret_cast<const uint4*>(W1hi + (size_t)n*32 + k0);
        *reinterpret_cast<uint4*>(sWlo + n*LDA + k0) = *reinterpret_cast<const uint4*>(W1lo + (size_t)n*32 + k0);
    }
    __syncthreads();

    const int row0 = (wid & 1) * 32;
    const int col0 = (wid >> 1) * 32;
    uint32_t aB[2][2], bB[2][2];
    {
        int ar = (lane & 15), ac = (lane >> 4) * 8;
        #pragma unroll
        for (int mi = 0; mi < 2; mi++) {
            aB[0][mi] = smem_u32(sAhi + (row0 + mi*16 + ar)*LDA + ac);
            aB[1][mi] = smem_u32(sAlo + (row0 + mi*16 + ar)*LDA + ac);
        }
        int q  = lane >> 3;
        int nr = (q >> 1)*8 + (lane & 7);
        int nc = (q & 1)*8;
        #pragma unroll
        for (int nt = 0; nt < 2; nt++) {
            bB[0][nt] = smem_u32(sWhi + (col0 + nt*16 + nr)*LDA + nc);
            bB[1][nt] = smem_u32(sWlo + (col0 + nt*16 + nr)*LDA + nc);
        }
    }
    const int g = lane >> 2, t = lane & 3;

    float acc[2][4][4];
    #pragma unroll
    for (int mi = 0; mi < 2; mi++)
        #pragma unroll
        for (int ni = 0; ni < 4; ni++)
            { acc[mi][ni][0]=0.f; acc[mi][ni][1]=0.f; acc[mi][ni][2]=0.f; acc[mi][ni][3]=0.f; }

    #pragma unroll
    for (int ks = 0; ks < 2; ks++) {     // K=32
        uint32_t koff = (uint32_t)ks * 32u;
        uint32_t ah[2][4], al[2][4], bh[2][4], bl[2][4];
        #pragma unroll
        for (int mi = 0; mi < 2; mi++) { ldm_x4(ah[mi], aB[0][mi] + koff); ldm_x4(al[mi], aB[1][mi] + koff); }
        #pragma unroll
        for (int nt = 0; nt < 2; nt++) { ldm_x4(bh[nt], bB[0][nt] + koff); ldm_x4(bl[nt], bB[1][nt] + koff); }
        #pragma unroll
        for (int mi = 0; mi < 2; mi++)
            #pragma unroll
            for (int nt = 0; nt < 2; nt++) {
                mma_bf16(acc[mi][nt*2],   ah[mi], &bh[nt][0]);
                mma_bf16(acc[mi][nt*2+1], ah[mi], &bh[nt][2]);
                mma_bf16(acc[mi][nt*2],   ah[mi], &bl[nt][0]);
                mma_bf16(acc[mi][nt*2+1], ah[mi], &bl[nt][2]);
                mma_bf16(acc[mi][nt*2],   al[mi], &bh[nt][0]);
                mma_bf16(acc[mi][nt*2+1], al[mi], &bh[nt][2]);
            }
    }
    __syncthreads();   // all ldmatrix reads done before overwriting A/W tiles

    // ---- epilogue 1: hc = relu(acc + b1) -> split directly into smem A tiles ----
    #pragma unroll
    for (int mi = 0; mi < 2; mi++) {
        #pragma unroll
        for (int ni = 0; ni < 4; ni++) {
            int cc = col0 + ni*8 + t*2;
            float bx = b1[cc], by = b1[cc+1];
            float2 v0 = make_float2(fmaxf(acc[mi][ni][0] + bx, 0.f), fmaxf(acc[mi][ni][1] + by, 0.f));
            float2 v1 = make_float2(fmaxf(acc[mi][ni][2] + bx, 0.f), fmaxf(acc[mi][ni][3] + by, 0.f));
            int rl0 = row0 + mi*16 + g;
            __nv_bfloat16 a0 = __float2bfloat16(v0.x), a1 = __float2bfloat16(v0.y);
            __nv_bfloat16 c0 = __float2bfloat16(v1.x), c1 = __float2bfloat16(v1.y);
            *reinterpret_cast<__nv_bfloat162*>(sAhi + rl0*LDA + cc)     = __halves2bfloat162(a0, a1);
            *reinterpret_cast<__nv_bfloat162*>(sAlo + rl0*LDA + cc)     =
                __halves2bfloat162(__float2bfloat16(v0.x - __bfloat162float(a0)),
                                   __float2bfloat16(v0.y - __bfloat162float(a1)));
            *reinterpret_cast<__nv_bfloat162*>(sAhi + (rl0+8)*LDA + cc) = __halves2bfloat162(c0, c1);
            *reinterpret_cast<__nv_bfloat162*>(sAlo + (rl0+8)*LDA + cc) =
                __halves2bfloat162(__float2bfloat16(v1.x - __bfloat162float(c0)),
                                   __float2bfloat16(v1.y - __bfloat162float(c1)));
        }
    }
    // ---- W2 (K=128) load ----
    for (int idx = tid; idx < 128*16; idx += 256) {
        int n  = idx >> 4;
        int k0 = (idx & 15) * 8;
        *reinterpret_cast<uint4*>(sWhi + n*LDA + k0) = *reinterpret_cast<const uint4*>(W2hi + (size_t)n*128 + k0);
        *reinterpret_cast<uint4*>(sWlo + n*LDA + k0) = *reinterpret_cast<const uint4*>(W2lo + (size_t)n*128 + k0);
    }
    __syncthreads();

    // ---- phase 2 mainloop (K=128) ----
    #pragma unroll
    for (int mi = 0; mi < 2; mi++)
        #pragma unroll
        for (int ni = 0; ni < 4; ni++)
            { acc[mi][ni][0]=0.f; acc[mi][ni][1]=0.f; acc[mi][ni][2]=0.f; acc[mi][ni][3]=0.f; }

    #pragma unroll 2
    for (int ks = 0; ks < 8; ks++) {
        uint32_t koff = (uint32_t)ks * 32u;
        uint32_t ah[2][4], al[2][4], bh[2][4], bl[2][4];
        #pragma unroll
        for (int mi = 0; mi < 2; mi++) { ldm_x4(ah[mi], aB[0][mi] + koff); ldm_x4(al[mi], aB[1][mi] + koff); }
        #pragma unroll
        for (int nt = 0; nt < 2; nt++) { ldm_x4(bh[nt], bB[0][nt] + koff); ldm_x4(bl[nt], bB[1][nt] + koff); }
        #pragma unroll
        for (int mi = 0; mi < 2; mi++)
            #pragma unroll
            for (int nt = 0; nt < 2; nt++) {
                mma_bf16(acc[mi][nt*2],   ah[mi], &bh[nt][0]);
                mma_bf16(acc[mi][nt*2+1], ah[mi], &bh[nt][2]);
                mma_bf16(acc[mi][nt*2],   ah[mi], &bl[nt][0]);
                mma_bf16(acc[mi][nt*2+1], ah[mi], &bl[nt][2]);
                mma_bf16(acc[mi][nt*2],   al[mi], &bh[nt][0]);
                mma_bf16(acc[mi][nt*2+1], al[mi], &bh[nt][2]);
            }
    }

    // ---- epilogue 2: hcs to gmem + fused logits (att_s_ct) ----
    float lsS[2][2];
    lsS[0][0]=0.f; lsS[0][1]=0.f; lsS[1][0]=0.f; lsS[1][1]=0.f;
    #pragma unroll
    for (int mi = 0; mi < 2; mi++) {
        #pragma unroll
        for (int ni = 0; ni < 4; ni++) {
            int cc = col0 + ni*8 + t*2;
            int r1 = bm + row0 + mi*16 + g;
            float2 v0 = make_float2(acc[mi][ni][0], acc[mi][ni][1]);
            float2 v1 = make_float2(acc[mi][ni][2], acc[mi][ni][3]);
            float a0 = __ldg(attS + cc), a1 = __ldg(attS + cc + 1);
            lsS[mi][0] += v0.x*a0 + v0.y*a1;
            lsS[mi][1] += v1.x*a0 + v1.y*a1;
            if (r1 < M)     *reinterpret_cast<float2*>(C + (size_t)r1*128 + cc)     = v0;
            if (r1 + 8 < M) *reinterpret_cast<float2*>(C + (size_t)(r1+8)*128 + cc) = v1;
        }
    }
    #pragma unroll
    for (int mi = 0; mi < 2; mi++)
        #pragma unroll
        for (int rr = 0; rr < 2; rr++) {
            float v = lsS[mi][rr];
            v += __shfl_xor_sync(0xffffffffu, v, 1);
            v += __shfl_xor_sync(0xffffffffu, v, 2);
            lsS[mi][rr] = v;
        }
    if (t == 0) {
        int head = col0 >> 5;
        #pragma unroll
        for (int mi = 0; mi < 2; mi++)
            #pragma unroll
            for (int rr = 0; rr < 2; rr++) {
                int r = bm + row0 + mi*16 + g + rr*8;
                if (r < M) outS[(size_t)r*4 + head] = lsS[mi][rr];
            }
    }
}

// --------------------------------- CSR build ------------------------------------------------
__global__ void hist_tt_kernel(const int* __restrict__ e0, const int* __restrict__ e1)
{
    for (int i = blockIdx.x*blockDim.x + threadIdx.x; i < ETTg; i += gridDim.x*blockDim.x) {
        atomicAdd(&g_deg[0*NTg + e1[i]], 1);
        atomicAdd(&g_deg[1*NTg + e0[i]], 1);
    }
}
__global__ void hist_ct_kernel(const int* __restrict__ ed)
{
    for (int i = blockIdx.x*blockDim.x + threadIdx.x; i < ECTg; i += gridDim.x*blockDim.x)
        atomicAdd(&g_deg[2*NTg + ed[i]], 1);
}

__global__ void scan1_kernel()
{
    int arr  = blockIdx.y;
    int base = blockIdx.x * 1024 + threadIdx.x;
    int lane = threadIdx.x & 31, wid = threadIdx.x >> 5;
    int v = (base < NTg) ? g_deg[arr*NTg + base] : 0;
    int x = v;
    #pragma unroll
    for (int o = 1; o < 32; o <<= 1) { int y = __shfl_up_sync(0xffffffffu, x, o); if (lane >= o) x += y; }
    __shared__ int ws[32];
    if (lane == 31) ws[wid] = x;
    __syncthreads();
    if (wid == 0) {
        int wv = ws[lane]; int wx = wv;
        #pragma unroll
        for (int o = 1; o < 32; o <<= 1) { int y = __shfl_up_sync(0xffffffffu, wx, o); if (lane >= o) wx += y; }
        if (lane == 31) g_aux[arr*128 + blockIdx.x] = wx;
        ws[lane] = wx - wv;
    }
    __syncthreads();
    int excl = x - v + ws[wid];
    if (base < NTg) g_cur[arr*NTg + base] = excl;
}

__global__ void scan2_kernel()
{
    int arr  = threadIdx.x >> 5;
    int lane = threadIdx.x & 31;
    if (arr >= 3) return;
    const int NB = (NTg + 1023) / 1024;
    int carry = 0;
    for (int c = 0; c*32 < NB; c++) {
        int idx = c*32 + lane;
        int v = (idx < NB) ? g_aux[arr*128 + idx] : 0;
        int x = v;
        #pragma unroll
        for (int o = 1; o < 32; o <<= 1) { int y = __shfl_up_sync(0xffffffffu, x, o); if (lane >= o) x += y; }
        if (idx < NB) g_aux[arr*128 + idx] = x - v + carry;
        carry += __shfl_sync(0xffffffffu, x, 31);
    }
}

__global__ void scan3_kernel()
{
    for (int i = blockIdx.x*blockDim.x + threadIdx.x; i < 3*NTg; i += gridDim.x*blockDim.x) {
        int arr = i / NTg; int idx = i - arr*NTg;
        g_cur[i] += g_aux[arr*128 + (idx >> 10)];
    }
}

__global__ void fill_tt_kernel(const int* __restrict__ e0, const int* __restrict__ e1)
{
    for (int i = blockIdx.x*blockDim.x + threadIdx.x; i < ETTg; i += gridDim.x*blockDim.x) {
        int s = e0[i], d = e1[i];
        int p = atomicAdd(&g_cur[0*NTg + d], 1); g_csrf[p] = s;
        int q = atomicAdd(&g_cur[1*NTg + s], 1); g_csrr[q] = d;
    }
}
__global__ void fill_ct_kernel(const int* __restrict__ es, const int* __restrict__ ed)
{
    for (int i = blockIdx.x*blockDim.x + threadIdx.x; i < ECTg; i += gridDim.x*blockDim.x) {
        int p = atomicAdd(&g_cur[2*NTg + ed[i]], 1); g_csrct[p] = es[i];
    }
}

// --------- per-relation GAT, single pass (no max-shift; logits are O(0.1), safe) ------------
template<bool SELF>
__device__ __forceinline__ void gat_rel(
    const float* __restrict__ hsrc, const float* __restrict__ a_s,
    const int* __restrict__ csr, int start, int cnt, int d, int lane,
    float4 ad, float wgt, float r[4])
{
    if (!SELF && cnt == 0) { r[0]=0.f; r[1]=0.f; r[2]=0.f; r[3]=0.f; return; }

    float den0 = 0.f, den1 = 0.f, den2 = 0.f, den3 = 0.f;
    float ac0 = 0.f, ac1 = 0.f, ac2 = 0.f, ac3 = 0.f;

    if (SELF) {
        float4 as = *reinterpret_cast<const float4*>(a_s + (size_t)d*4);
        float p0 = __expf(lrelu02(as.x + ad.x));
        float p1 = __expf(lrelu02(as.y + ad.y));
        float p2 = __expf(lrelu02(as.z + ad.z));
        float p3 = __expf(lrelu02(as.w + ad.w));
        den0 = p0; den1 = p1; den2 = p2; den3 = p3;
        const float* row = hsrc + (size_t)d*128;
        ac0 = p0 * row[lane];      ac1 = p1 * row[32 + lane];
        ac2 = p2 * row[64 + lane]; ac3 = p3 * row[96 + lane];
    }
    #pragma unroll 2
    for (int i = 0; i < cnt; i++) {
        int s = csr[start + i];
        float4 as = *reinterpret_cast<const float4*>(a_s + (size_t)s*4);
        float p0 = __expf(lrelu02(as.x + ad.x));
        float p1 = __expf(lrelu02(as.y + ad.y));
        float p2 = __expf(lrelu02(as.z + ad.z));
        float p3 = __expf(lrelu02(as.w + ad.w));
        den0 += p0; den1 += p1; den2 += p2; den3 += p3;
        const float* row = hsrc + (size_t)s*128;
        ac0 = fmaf(p0, row[lane],       ac0);
        ac1 = fmaf(p1, row[32 + lane],  ac1);
        ac2 = fmaf(p2, row[64 + lane],  ac2);
        ac3 = fmaf(p3, row[96 + lane],  ac3);
    }

    r[0] = ac0 * (wgt / den0); r[1] = ac1 * (wgt / den1);
    r[2] = ac2 * (wgt / den2); r[3] = ac3 * (wgt / den3);
}

// --- merged GAT over all 3 relations; writes z = relu(acc + cbias + ht) directly ------------
__global__ void gat_all_kernel(
    const float* __restrict__ hs, const float* __restrict__ hd, const float* __restrict__ hcs,
    const float* __restrict__ ht,
    const float* __restrict__ asf, const float* __restrict__ adf,
    const float* __restrict__ asr, const float* __restrict__ adr,
    const float* __restrict__ asct, const float* __restrict__ adct,
    const int* __restrict__ cur, const int* __restrict__ deg,
    const int* __restrict__ csrf, const int* __restrict__ csrr, const int* __restrict__ csrct,
    const float* __restrict__ bsd, const float* __restrict__ bds, const float* __restrict__ bct,
    float* __restrict__ z)
{
    int d    = (blockIdx.x * blockDim.x + threadIdx.x) >> 5;
    int lane = threadIdx.x & 31;
    if (d >= NTg) return;

    float rf[4], rr_[4], rc[4];
    {
        int c = deg[0*NTg + d];
        gat_rel<true >(hs, asf, csrf, cur[0*NTg + d] - c, c, d, lane,
                       *reinterpret_cast<const float4*>(adf + (size_t)d*4), 0.25f, rf);
    }
    {
        int c = deg[1*NTg + d];
        gat_rel<true >(hd, asr, csrr, cur[1*NTg + d] - c, c, d, lane,
                       *reinterpret_cast<const float4*>(adr + (size_t)d*4), 0.25f, rr_);
    }
    {
        int c = deg[2*NTg + d];
        gat_rel<false>(hcs, asct, csrct, cur[2*NTg + d] - c, c, d, lane,
                       *reinterpret_cast<const float4*>(adct + (size_t)d*4), 0.5f, rc);
    }

    const float* hrow = ht + (size_t)d*128;
    float* zrow = z + (size_t)d*128;
    #pragma unroll
    for (int h = 0; h < 4; h++) {
        int c = h*32 + lane;
        float cb = 0.25f*bsd[c] + 0.25f*bds[c] + 0.5f*bct[c];
        float v  = rf[h] + rr_[h] + rc[h] + hrow[c] + cb;
        zrow[c] = fmaxf(v, 0.f);
    }
}

// ----------------------------------- launch -------------------------------------------------
extern "C" void kernel_launch(void* const* d_in, const int* in_sizes, int n_in,
                              void* d_out, int out_size)
{
    const float* x_t     = (const float*)d_in[0];
    const float* x_c     = (const float*)d_in[1];
    const int*   ett     = (const int*)d_in[2];
    const int*   e0      = ett;
    const int*   e1      = ett + ETTg;
    const int*   ect_s   = (const int*)d_in[3];
    const int*   ect_d   = (const int*)d_in[4];
    const float* W_pre_t = (const float*)d_in[5];
    const float* b_pre_t = (const float*)d_in[6];
    const float* W_pre_c = (const float*)d_in[7];
    const float* b_pre_c = (const float*)d_in[8];
    const float* W_sd    = (const float*)d_in[9];
    const float* att_s_sd= (const float*)d_in[10];
    const float* att_d_sd= (const float*)d_in[11];
    const float* b_sd    = (const float*)d_in[12];
    const float* W_ds    = (const float*)d_in[13];
    const float* att_s_ds= (const float*)d_in[14];
    const float* att_d_ds= (const float*)d_in[15];
    const float* b_ds    = (const float*)d_in[16];
    const float* W_ct_s  = (const float*)d_in[17];
    const float* W_ct_d  = (const float*)d_in[18];
    const float* att_s_ct= (const float*)d_in[19];
    const float* att_d_ct= (const float*)d_in[20];
    const float* b_ct    = (const float*)d_in[21];
    const float* W_out   = (const float*)d_in[22];
    const float* b_out   = (const float*)d_in[23];
    float* out = (float*)d_out;

    float *p_ht, *p_hs, *p_hd, *p_hcs, *p_z, *p_wv;
    float *p_asf, *p_adf, *p_asr, *p_adr, *p_adct, *p_asct;
    int *p_deg, *p_cur, *p_csrf, *p_csrr, *p_csrct;
    __nv_bfloat16 *p_whi, *p_wlo;
    cudaGetSymbolAddress((void**)&p_ht,  g_ht);
    cudaGetSymbolAddress((void**)&p_hs,  g_hs);
    cudaGetSymbolAddress((void**)&p_hd,  g_hd);
    cudaGetSymbolAddress((void**)&p_hcs, g_hcs);
    cudaGetSymbolAddress((void**)&p_z,   g_z);
    cudaGetSymbolAddress((void**)&p_wv,  g_wv);
    cudaGetSymbolAddress((void**)&p_asf, g_asf);
    cudaGetSymbolAddress((void**)&p_adf, g_adf);
    cudaGetSymbolAddress((void**)&p_asr, g_asr);
    cudaGetSymbolAddress((void**)&p_adr, g_adr);
    cudaGetSymbolAddress((void**)&p_adct,g_adct);
    cudaGetSymbolAddress((void**)&p_asct,g_asct);
    cudaGetSymbolAddress((void**)&p_deg, g_deg);
    cudaGetSymbolAddress((void**)&p_cur, g_cur);
    cudaGetSymbolAddress((void**)&p_csrf, g_csrf);
    cudaGetSymbolAddress((void**)&p_csrr, g_csrr);
    cudaGetSymbolAddress((void**)&p_csrct,g_csrct);
    cudaGetSymbolAddress((void**)&p_whi, g_whi);
    cudaGetSymbolAddress((void**)&p_wlo, g_wlo);

    // smem: (2*64 + 2*128) rows * (K+8) cols * 2B   (+4KB reduce scratch for NATT==3)
    const int SM128 = (2*64 + 2*128) * (128 + 8) * 2;   // 104448
    const int SM64  = (2*64 + 2*128) * (64  + 8) * 2;   // 55296
    cudaFuncSetAttribute(tc_gemm_dual,               cudaFuncAttributeMaxDynamicSharedMemorySize, SM128);
    cudaFuncSetAttribute(tc_gemm_chain,              cudaFuncAttributeMaxDynamicSharedMemorySize, SM128);
    cudaFuncSetAttribute(tc_gemm<128,false,true, 0>, cudaFuncAttributeMaxDynamicSharedMemorySize, SM128);
    cudaFuncSetAttribute(tc_gemm<64, true, true, 3>, cudaFuncAttributeMaxDynamicSharedMemorySize, SM64 + 4096);

    const int GT = (NTg + 63) / 64;   // 1563
    const int GC = (NCg + 63) / 64;   // 391

    // slots: 0 pre_t K=64, 1 pre_c K=32, 2 sd, 3 ds, 4 ct_s, 5 out  (W_ct_d folded into wv)
    WJobs jobs;
    jobs.W[0] = W_pre_t; jobs.K[0] = 64;
    jobs.W[1] = W_pre_c; jobs.K[1] = 32;
    jobs.W[2] = W_sd;    jobs.K[2] = 128;
    jobs.W[3] = W_ds;    jobs.K[3] = 128;
    jobs.W[4] = W_ct_s;  jobs.K[4] = 128;
    jobs.W[5] = W_out;   jobs.K[5] = 128;

    wv_kernel<<<1, 512>>>(W_ct_d, att_d_ct, p_wv);                                  // k1
    wsplit_all<<<dim3(64, 6), 256>>>(jobs, p_whi, p_wlo);                           // k2
    // pre_t GEMM with fused a_dct = ht . wv^T  (NATT=3)
    tc_gemm<64,true,true,3><<<GT, 256, SM64 + 4096>>>(x_t, p_whi + 0*16384, p_wlo + 0*16384,
        b_pre_t, p_ht, NTg, p_wv, p_adct);                                          // k3
    tc_gemm_dual<<<GT, 256, SM128>>>(p_ht,
        p_whi + 2*16384, p_wlo + 2*16384, p_whi + 3*16384, p_wlo + 3*16384,
        p_hs, p_hd, NTg,
        att_s_sd, att_d_sd, att_s_ds, att_d_ds,
        p_asf, p_adf, p_asr, p_adr);                                                // k4 <- ncu
    // chained: hc (K=32, smem-resident) -> hcs = hc @ W_ct_s, fused asct logits
    tc_gemm_chain<<<GC, 256, SM128>>>(x_c,
        p_whi + 1*16384, p_wlo + 1*16384, b_pre_c,
        p_whi + 4*16384, p_wlo + 4*16384,
        p_hcs, NCg, att_s_ct, p_asct);                                              // k5

    // CSR build
    cudaMemsetAsync(p_deg, 0, 3*NTg*sizeof(int));
    hist_tt_kernel<<<512, 256>>>(e0, e1);
    hist_ct_kernel<<<256, 256>>>(ect_d);
    dim3 g1((NTg + 1023) / 1024, 3);
    scan1_kernel<<<g1, 1024>>>();
    scan2_kernel<<<1, 96>>>();
    scan3_kernel<<<256, 256>>>();
    fill_tt_kernel<<<512, 256>>>(e0, e1);
    fill_ct_kernel<<<256, 256>>>(ect_s, ect_d);

    // merged GAT (high occupancy, serial loop): z = relu(0.25*sd + 0.25*ds + 0.5*ct + cbias + ht)
    gat_all_kernel<<<(NTg + 7) / 8, 256>>>(
        p_hs, p_hd, p_hcs, p_ht,
        p_asf, p_adf, p_asr, p_adr, p_asct, p_adct,
        p_cur, p_deg, p_csrf, p_csrr, p_csrct,
        b_sd, b_ds, b_ct, p_z);

    // final: out = z @ W_out + b_out
    tc_gemm<128,false,true,0><<<GT, 256, SM128>>>(p_z, p_whi + 5*16384, p_wlo + 5*16384,
        b_out, out, NTg, nullptr, nullptr);
}

// round 11
// speedup vs baseline: 1.4261x; 1.0574x over previous
#include <cuda_runtime.h>
#include <cuda_bf16.h>
#include <cuda_fp16.h>
#include <cstdint>

#define NTg  100000
#define NCg  25000
#define ETTg 800000
#define ECTg 400000
#define HIDg 128

// ------------------------- scratch (device globals; allocation-free) -------------------------
__device__ float  g_ht [NTg*HIDg];
__device__ __half g_hs [NTg*HIDg];
__device__ __half g_hd [NTg*HIDg];
__device__ __half g_hcs[NCg*HIDg];
__device__ float  g_z  [NTg*HIDg];
__device__ float g_asf[NTg*4];
__device__ float g_adf[NTg*4];
__device__ float g_asr[NTg*4];
__device__ float g_adr[NTg*4];
__device__ float g_adct[NTg*4];
__device__ float g_asct[NCg*4];
__device__ float g_wv [4*128];
__device__ int   g_deg[3*NTg];
__device__ int   g_cur[3*NTg];
__device__ int   g_aux[3*128];
__device__ int   g_csrf[ETTg];
__device__ int   g_csrr[ETTg];
__device__ int   g_csrct[ECTg];
// split weights: 6 slots of up to 128x128 bf16 ([N,K] layout, i.e., W^T)
__device__ __nv_bfloat16 g_whi[6*128*128];
__device__ __nv_bfloat16 g_wlo[6*128*128];

__device__ __forceinline__ float lrelu02(float x) { return x > 0.f ? x : 0.2f * x; }

__device__ __forceinline__ uint32_t smem_u32(const void* p) {
    uint32_t a;
    asm("{ .reg .u64 t; cvta.to.shared.u64 t, %1; cvt.u32.u64 %0, t; }" : "=r"(a) : "l"(p));
    return a;
}

__device__ __forceinline__ void ldm_x4(uint32_t* r, uint32_t addr) {
    asm volatile("ldmatrix.sync.aligned.m8n8.x4.shared.b16 {%0,%1,%2,%3}, [%4];"
                 : "=r"(r[0]), "=r"(r[1]), "=r"(r[2]), "=r"(r[3]) : "r"(addr));
}
__device__ __forceinline__ void mma_bf16(float* c, const uint32_t* a, const uint32_t* b) {
    asm volatile("mma.sync.aligned.m16n8k16.row.col.f32.bf16.bf16.f32 "
                 "{%0,%1,%2,%3}, {%4,%5,%6,%7}, {%8,%9}, {%0,%1,%2,%3};"
                 : "+f"(c[0]), "+f"(c[1]), "+f"(c[2]), "+f"(c[3])
                 : "r"(a[0]), "r"(a[1]), "r"(a[2]), "r"(a[3]), "r"(b[0]), "r"(b[1]));
}

// ------------------- batched W split/transpose: hi/lo[n*K+k] = split(W[k*128+n]) ------------
struct WJobs { const float* W[6]; int K[6]; };

__global__ void wsplit_all(WJobs jobs, __nv_bfloat16* __restrict__ hiB,
                           __nv_bfloat16* __restrict__ loB)
{
    int slot = blockIdx.y;
    const float* W = jobs.W[slot];
    int K = jobs.K[slot];
    __nv_bfloat16* hi = hiB + slot*16384;
    __nv_bfloat16* lo = loB + slot*16384;
    int tot = 128 * K;
    for (int i = blockIdx.x*blockDim.x + threadIdx.x; i < tot; i += gridDim.x*blockDim.x) {
        int n = i / K, k = i - n*K;
        float v = W[k*128 + n];
        __nv_bfloat16 h = __float2bfloat16(v);
        hi[i] = h;
        lo[i] = __float2bfloat16(v - __bfloat162float(h));
    }
}

// ----------------- wv[h*128+k] = sum_c W_ct_dst[k*128 + h*32 + c] * att[h*32+c] -------------
__global__ void wv_kernel(const float* __restrict__ W, const float* __restrict__ att,
                          float* __restrict__ wv)
{
    int i = threadIdx.x;           // 512 threads: k = i>>2, h = i&3
    int k = i >> 2, h = i & 3;
    float s = 0.f;
    #pragma unroll 8
    for (int c = 0; c < 32; c++) s += W[k*128 + h*32 + c] * att[h*32 + c];
    wv[h*128 + k] = s;
}

// ---------------- HMMA GEMM: C[M,128] = A[M,K] @ W[K,128]  (3-split bf16) -------------------
// CTA tile 64x128 (2 CTAs/SM), 8 warps, warp tile 32x32. W^T ([N,K]) pre-split in gmem.
// NATT: 0 = none; 1 = fused logits outS[r,head] = sum_c C[r,c]*attS[c] (head = c>>5)
//       3 = fused full-row dots outS[r,h] = sum_{c=0..127} C[r,c]*attS[h*128+c]  (attS = wv)
template<int K, bool RELU, bool BIAS, int NATT>
__global__ void __launch_bounds__(256, 2) tc_gemm(
    const float* __restrict__ A, const __nv_bfloat16* __restrict__ Whi,
    const __nv_bfloat16* __restrict__ Wlo, const float* __restrict__ bias,
    float* __restrict__ C, int M,
    const float* __restrict__ attS, float* __restrict__ outS)
{
    constexpr int LDA = K + 8;
    extern __shared__ __nv_bfloat16 smb[];
    __nv_bfloat16* sAhi = smb;                 // 64*LDA
    __nv_bfloat16* sAlo = sAhi + 64*LDA;
    __nv_bfloat16* sWhi = sAlo + 64*LDA;       // 128*LDA
    __nv_bfloat16* sWlo = sWhi + 128*LDA;

    const int tid  = threadIdx.x;
    const int lane = tid & 31;
    const int wid  = tid >> 5;
    const int bm   = blockIdx.x * 64;

    for (int idx = tid; idx < 64*(K/4); idx += 256) {
        int r  = idx / (K/4);
        int k0 = (idx % (K/4)) * 4;
        int row = bm + r;
        float4 v = make_float4(0.f, 0.f, 0.f, 0.f);
        if (row < M) v = *reinterpret_cast<const float4*>(A + (size_t)row*K + k0);
        __nv_bfloat16 h0 = __float2bfloat16(v.x), h1 = __float2bfloat16(v.y);
        __nv_bfloat16 h2 = __float2bfloat16(v.z), h3 = __float2bfloat16(v.w);
        __nv_bfloat16 l0 = __float2bfloat16(v.x - __bfloat162float(h0));
        __nv_bfloat16 l1 = __float2bfloat16(v.y - __bfloat162float(h1));
        __nv_bfloat16 l2 = __float2bfloat16(v.z - __bfloat162float(h2));
        __nv_bfloat16 l3 = __float2bfloat16(v.w - __bfloat162float(h3));
        __nv_bfloat16* pH = sAhi + r*LDA + k0;
        __nv_bfloat16* pL = sAlo + r*LDA + k0;
        *reinterpret_cast<__nv_bfloat162*>(pH)     = __halves2bfloat162(h0, h1);
        *reinterpret_cast<__nv_bfloat162*>(pH + 2) = __halves2bfloat162(h2, h3);
        *reinterpret_cast<__nv_bfloat162*>(pL)     = __halves2bfloat162(l0, l1);
        *reinterpret_cast<__nv_bfloat162*>(pL + 2) = __halves2bfloat162(l2, l3);
    }
    for (int idx = tid; idx < 128*(K/8); idx += 256) {
        int n  = idx / (K/8);
        int k0 = (idx % (K/8)) * 8;
        *reinterpret_cast<uint4*>(sWhi + n*LDA + k0) = *reinterpret_cast<const uint4*>(Whi + (size_t)n*K + k0);
        *reinterpret_cast<uint4*>(sWlo + n*LDA + k0) = *reinterpret_cast<const uint4*>(Wlo + (size_t)n*K + k0);
    }
    __syncthreads();

    const int row0 = (wid & 1) * 32;
    const int col0 = (wid >> 1) * 32;

    uint32_t aB[2][2], bB[2][2];
    {
        int ar = (lane & 15), ac = (lane >> 4) * 8;
        #pragma unroll
        for (int mi = 0; mi < 2; mi++) {
            aB[0][mi] = smem_u32(sAhi + (row0 + mi*16 + ar)*LDA + ac);
            aB[1][mi] = smem_u32(sAlo + (row0 + mi*16 + ar)*LDA + ac);
        }
        int q  = lane >> 3;
        int nr = (q >> 1)*8 + (lane & 7);
        int nc = (q & 1)*8;
        #pragma unroll
        for (int nt = 0; nt < 2; nt++) {
            bB[0][nt] = smem_u32(sWhi + (col0 + nt*16 + nr)*LDA + nc);
            bB[1][nt] = smem_u32(sWlo + (col0 + nt*16 + nr)*LDA + nc);
        }
    }

    float acc[2][4][4];
    #pragma unroll
    for (int mi = 0; mi < 2; mi++)
        #pragma unroll
        for (int ni = 0; ni < 4; ni++)
            { acc[mi][ni][0]=0.f; acc[mi][ni][1]=0.f; acc[mi][ni][2]=0.f; acc[mi][ni][3]=0.f; }

    #pragma unroll 2
    for (int ks = 0; ks < K/16; ks++) {
        uint32_t koff = (uint32_t)ks * 32u;
        uint32_t ah[2][4], al[2][4], bh[2][4], bl[2][4];
        #pragma unroll
        for (int mi = 0; mi < 2; mi++) { ldm_x4(ah[mi], aB[0][mi] + koff); ldm_x4(al[mi], aB[1][mi] + koff); }
        #pragma unroll
        for (int nt = 0; nt < 2; nt++) { ldm_x4(bh[nt], bB[0][nt] + koff); ldm_x4(bl[nt], bB[1][nt] + koff); }
        #pragma unroll
        for (int mi = 0; mi < 2; mi++)
            #pragma unroll
            for (int nt = 0; nt < 2; nt++) {
                mma_bf16(acc[mi][nt*2],   ah[mi], &bh[nt][0]);
                mma_bf16(acc[mi][nt*2+1], ah[mi], &bh[nt][2]);
                mma_bf16(acc[mi][nt*2],   ah[mi], &bl[nt][0]);
                mma_bf16(acc[mi][nt*2+1], ah[mi], &bl[nt][2]);
                mma_bf16(acc[mi][nt*2],   al[mi], &bh[nt][0]);
                mma_bf16(acc[mi][nt*2+1], al[mi], &bh[nt][2]);
            }
    }

    const int g = lane >> 2, t = lane & 3;
    float lsS[2][2];
    float lsA[2][2][4];
    if (NATT == 1) { lsS[0][0]=0.f; lsS[0][1]=0.f; lsS[1][0]=0.f; lsS[1][1]=0.f; }
    if (NATT == 3) {
        #pragma unroll
        for (int a = 0; a < 2; a++)
            #pragma unroll
            for (int b = 0; b < 2; b++)
                #pragma unroll
                for (int h = 0; h < 4; h++) lsA[a][b][h] = 0.f;
    }
    #pragma unroll
    for (int mi = 0; mi < 2; mi++) {
        #pragma unroll
        for (int ni = 0; ni < 4; ni++) {
            int cc = col0 + ni*8 + t*2;
            float bx = 0.f, by = 0.f;
            if (BIAS) { bx = bias[cc]; by = bias[cc+1]; }
            int r1 = bm + row0 + mi*16 + g;
            float2 v0 = make_float2(acc[mi][ni][0] + bx, acc[mi][ni][1] + by);
            float2 v1 = make_float2(acc[mi][ni][2] + bx, acc[mi][ni][3] + by);
            if (RELU) {
                v0.x = fmaxf(v0.x, 0.f); v0.y = fmaxf(v0.y, 0.f);
                v1.x = fmaxf(v1.x, 0.f); v1.y = fmaxf(v1.y, 0.f);
            }
            if (NATT == 1) {
                float a0 = __ldg(attS + cc), a1 = __ldg(attS + cc + 1);
                lsS[mi][0] += v0.x*a0 + v0.y*a1;
                lsS[mi][1] += v1.x*a0 + v1.y*a1;
            }
            if (NATT == 3) {
                #pragma unroll
                for (int h = 0; h < 4; h++) {
                    float w0 = __ldg(attS + h*128 + cc), w1 = __ldg(attS + h*128 + cc + 1);
                    lsA[mi][0][h] += v0.x*w0 + v0.y*w1;
                    lsA[mi][1][h] += v1.x*w0 + v1.y*w1;
                }
            }
            if (r1 < M)     *reinterpret_cast<float2*>(C + (size_t)r1*128 + cc)     = v0;
            if (r1 + 8 < M) *reinterpret_cast<float2*>(C + (size_t)(r1+8)*128 + cc) = v1;
        }
    }
    if (NATT == 1) {
        #pragma unroll
        for (int mi = 0; mi < 2; mi++)
            #pragma unroll
            for (int rr = 0; rr < 2; rr++) {
                float v = lsS[mi][rr];
                v += __shfl_xor_sync(0xffffffffu, v, 1);
                v += __shfl_xor_sync(0xffffffffu, v, 2);
                lsS[mi][rr] = v;
            }
        if (t == 0) {
            int head = col0 >> 5;
            #pragma unroll
            for (int mi = 0; mi < 2; mi++)
                #pragma unroll
                for (int rr = 0; rr < 2; rr++) {
                    int r = bm + row0 + mi*16 + g + rr*8;
                    if (r < M) outS[(size_t)r*4 + head] = lsS[mi][rr];
                }
        }
    }
    if (NATT == 3) {
        float* sRed = reinterpret_cast<float*>(smb + (size_t)(2*64 + 2*128)*LDA);  // [64][16]
        #pragma unroll
        for (int mi = 0; mi < 2; mi++)
            #pragma unroll
            for (int rr = 0; rr < 2; rr++)
                #pragma unroll
                for (int h = 0; h < 4; h++) {
                    float v = lsA[mi][rr][h];
                    v += __shfl_xor_sync(0xffffffffu, v, 1);
                    v += __shfl_xor_sync(0xffffffffu, v, 2);
                    lsA[mi][rr][h] = v;
                }
        int cg = wid >> 1;
        if (t == 0) {
            #pragma unroll
            for (int mi = 0; mi < 2; mi++)
                #pragma unroll
                for (int rr = 0; rr < 2; rr++) {
                    int lr = row0 + mi*16 + g + rr*8;
                    #pragma unroll
                    for (int h = 0; h < 4; h++)
                        sRed[lr*16 + cg*4 + h] = lsA[mi][rr][h];
                }
        }
        __syncthreads();
        {
            int lr = tid >> 2, h = tid & 3;
            float s = sRed[lr*16 + h] + sRed[lr*16 + 4 + h]
                    + sRed[lr*16 + 8 + h] + sRed[lr*16 + 12 + h];
            int r = bm + lr;
            if (r < M) outS[(size_t)r*4 + h] = s;
        }
    }
}

// ------------- dual-slot HMMA GEMM: A resident; computes hs AND hd (fp16 out) ---------------
__global__ void __launch_bounds__(256, 2) tc_gemm_dual(
    const float* __restrict__ A,
    const __nv_bfloat16* __restrict__ Whi0, const __nv_bfloat16* __restrict__ Wlo0,
    const __nv_bfloat16* __restrict__ Whi1, const __nv_bfloat16* __restrict__ Wlo1,
    __half* __restrict__ C0, __half* __restrict__ C1, int M,
    const float* __restrict__ attS0, const float* __restrict__ attD0,
    const float* __restrict__ attS1, const float* __restrict__ attD1,
    float* __restrict__ outS0, float* __restrict__ outD0,
    float* __restrict__ outS1, float* __restrict__ outD1)
{
    constexpr int K = 128, LDA = K + 8;
    extern __shared__ __nv_bfloat16 smb[];
    __nv_bfloat16* sAhi = smb;
    __nv_bfloat16* sAlo = sAhi + 64*LDA;
    __nv_bfloat16* sWhi = sAlo + 64*LDA;
    __nv_bfloat16* sWlo = sWhi + 128*LDA;

    const int tid  = threadIdx.x;
    const int lane = tid & 31;
    const int wid  = tid >> 5;
    const int bm   = blockIdx.x * 64;

    for (int idx = tid; idx < 64*(K/4); idx += 256) {
        int r  = idx / (K/4);
        int k0 = (idx % (K/4)) * 4;
        int row = bm + r;
        float4 v = make_float4(0.f, 0.f, 0.f, 0.f);
        if (row < M) v = *reinterpret_cast<const float4*>(A + (size_t)row*K + k0);
        __nv_bfloat16 h0 = __float2bfloat16(v.x), h1 = __float2bfloat16(v.y);
        __nv_bfloat16 h2 = __float2bfloat16(v.z), h3 = __float2bfloat16(v.w);
        __nv_bfloat16 l0 = __float2bfloat16(v.x - __bfloat162float(h0));
        __nv_bfloat16 l1 = __float2bfloat16(v.y - __bfloat162float(h1));
        __nv_bfloat16 l2 = __float2bfloat16(v.z - __bfloat162float(h2));
        __nv_bfloat16 l3 = __float2bfloat16(v.w - __bfloat162float(h3));
        __nv_bfloat16* pH = sAhi + r*LDA + k0;
        __nv_bfloat16* pL = sAlo + r*LDA + k0;
        *reinterpret_cast<__nv_bfloat162*>(pH)     = __halves2bfloat162(h0, h1);
        *reinterpret_cast<__nv_bfloat162*>(pH + 2) = __halves2bfloat162(h2, h3);
        *reinterpret_cast<__nv_bfloat162*>(pL)     = __halves2bfloat162(l0, l1);
        *reinterpret_cast<__nv_bfloat162*>(pL + 2) = __halves2bfloat162(l2, l3);
    }

    const int row0 = (wid & 1) * 32;
    const int col0 = (wid >> 1) * 32;
    uint32_t aB[2][2], bB[2][2];
    {
        int ar = (lane & 15), ac = (lane >> 4) * 8;
        #pragma unroll
        for (int mi = 0; mi < 2; mi++) {
            aB[0][mi] = smem_u32(sAhi + (row0 + mi*16 + ar)*LDA + ac);
            aB[1][mi] = smem_u32(sAlo + (row0 + mi*16 + ar)*LDA + ac);
        }
        int q  = lane >> 3;
        int nr = (q >> 1)*8 + (lane & 7);
        int nc = (q & 1)*8;
        #pragma unroll
        for (int nt = 0; nt < 2; nt++) {
            bB[0][nt] = smem_u32(sWhi + (col0 + nt*16 + nr)*LDA + nc);
            bB[1][nt] = smem_u32(sWlo + (col0 + nt*16 + nr)*LDA + nc);
        }
    }
    const int g = lane >> 2, t = lane & 3;

    #pragma unroll
    for (int slot = 0; slot < 2; slot++) {
        const __nv_bfloat16* Whi = slot ? Whi1 : Whi0;
        const __nv_bfloat16* Wlo = slot ? Wlo1 : Wlo0;
        __half* C = slot ? C1 : C0;
        const float* attS = slot ? attS1 : attS0;
        const float* attD = slot ? attD1 : attD0;
        float* outS = slot ? outS1 : outS0;
        float* outD = slot ? outD1 : outD0;

        for (int idx = tid; idx < 128*(K/8); idx += 256) {
            int n  = idx / (K/8);
            int k0 = (idx % (K/8)) * 8;
            *reinterpret_cast<uint4*>(sWhi + n*LDA + k0) = *reinterpret_cast<const uint4*>(Whi + (size_t)n*K + k0);
            *reinterpret_cast<uint4*>(sWlo + n*LDA + k0) = *reinterpret_cast<const uint4*>(Wlo + (size_t)n*K + k0);
        }
        __syncthreads();

        float acc[2][4][4];
        #pragma unroll
        for (int mi = 0; mi < 2; mi++)
            #pragma unroll
            for (int ni = 0; ni < 4; ni++)
                { acc[mi][ni][0]=0.f; acc[mi][ni][1]=0.f; acc[mi][ni][2]=0.f; acc[mi][ni][3]=0.f; }

        #pragma unroll 2
        for (int ks = 0; ks < K/16; ks++) {
            uint32_t koff = (uint32_t)ks * 32u;
            uint32_t ah[2][4], al[2][4], bh[2][4], bl[2][4];
            #pragma unroll
            for (int mi = 0; mi < 2; mi++) { ldm_x4(ah[mi], aB[0][mi] + koff); ldm_x4(al[mi], aB[1][mi] + koff); }
            #pragma unroll
            for (int nt = 0; nt < 2; nt++) { ldm_x4(bh[nt], bB[0][nt] + koff); ldm_x4(bl[nt], bB[1][nt] + koff); }
            #pragma unroll
            for (int mi = 0; mi < 2; mi++)
                #pragma unroll
                for (int nt = 0; nt < 2; nt++) {
                    mma_bf16(acc[mi][nt*2],   ah[mi], &bh[nt][0]);
                    mma_bf16(acc[mi][nt*2+1], ah[mi], &bh[nt][2]);
                    mma_bf16(acc[mi][nt*2],   ah[mi], &bl[nt][0]);
                    mma_bf16(acc[mi][nt*2+1], ah[mi], &bl[nt][2]);
                    mma_bf16(acc[mi][nt*2],   al[mi], &bh[nt][0]);
                    mma_bf16(acc[mi][nt*2+1], al[mi], &bh[nt][2]);
                }
        }

        float lsS[2][2], lsD[2][2];
        lsS[0][0]=0.f; lsS[0][1]=0.f; lsS[1][0]=0.f; lsS[1][1]=0.f;
        lsD[0][0]=0.f; lsD[0][1]=0.f; lsD[1][0]=0.f; lsD[1][1]=0.f;

        #pragma unroll
        for (int mi = 0; mi < 2; mi++) {
            #pragma unroll
            for (int ni = 0; ni < 4; ni++) {
                int cc = col0 + ni*8 + t*2;
                int r1 = bm + row0 + mi*16 + g;
                float2 v0 = make_float2(acc[mi][ni][0], acc[mi][ni][1]);
                float2 v1 = make_float2(acc[mi][ni][2], acc[mi][ni][3]);
                float a0 = __ldg(attS + cc), a1 = __ldg(attS + cc + 1);
                float d0 = __ldg(attD + cc), d1 = __ldg(attD + cc + 1);
                lsS[mi][0] += v0.x*a0 + v0.y*a1;
                lsS[mi][1] += v1.x*a0 + v1.y*a1;
                lsD[mi][0] += v0.x*d0 + v0.y*d1;
                lsD[mi][1] += v1.x*d0 + v1.y*d1;
                if (r1 < M)     *reinterpret_cast<__half2*>(C + (size_t)r1*128 + cc)     = __floats2half2_rn(v0.x, v0.y);
                if (r1 + 8 < M) *reinterpret_cast<__half2*>(C + (size_t)(r1+8)*128 + cc) = __floats2half2_rn(v1.x, v1.y);
            }
        }
        #pragma unroll
        for (int mi = 0; mi < 2; mi++)
            #pragma unroll
            for (int rr = 0; rr < 2; rr++) {
                float v = lsS[mi][rr];
                v += __shfl_xor_sync(0xffffffffu, v, 1);
                v += __shfl_xor_sync(0xffffffffu, v, 2);
                lsS[mi][rr] = v;
                float w = lsD[mi][rr];
                w += __shfl_xor_sync(0xffffffffu, w, 1);
                w += __shfl_xor_sync(0xffffffffu, w, 2);
                lsD[mi][rr] = w;
            }
        if (t == 0) {
            int head = col0 >> 5;
            #pragma unroll
            for (int mi = 0; mi < 2; mi++)
                #pragma unroll
                for (int rr = 0; rr < 2; rr++) {
                    int r = bm + row0 + mi*16 + g + rr*8;
                    if (r < M) {
                        outS[(size_t)r*4 + head] = lsS[mi][rr];
                        outD[(size_t)r*4 + head] = lsD[mi][rr];
                    }
                }
        }
        __syncthreads();   // all warps done with W smem before next slot reload
    }
}

// ----- chained GEMM: hc = relu(x_c@W_pre_c + b) (K=32, smem-resident) -> hcs = hc@W_ct_s ----
__global__ void __launch_bounds__(256, 2) tc_gemm_chain(
    const float* __restrict__ xc,
    const __nv_bfloat16* __restrict__ W1hi, const __nv_bfloat16* __restrict__ W1lo,
    const float* __restrict__ b1,
    const __nv_bfloat16* __restrict__ W2hi, const __nv_bfloat16* __restrict__ W2lo,
    __half* __restrict__ C, int M,
    const float* __restrict__ attS, float* __restrict__ outS)
{
    constexpr int LDA = 136;
    extern __shared__ __nv_bfloat16 smb[];
    __nv_bfloat16* sAhi = smb;
    __nv_bfloat16* sAlo = sAhi + 64*LDA;
    __nv_bfloat16* sWhi = sAlo + 64*LDA;
    __nv_bfloat16* sWlo = sWhi + 128*LDA;

    const int tid  = threadIdx.x;
    const int lane = tid & 31;
    const int wid  = tid >> 5;
    const int bm   = blockIdx.x * 64;

    for (int idx = tid; idx < 64*8; idx += 256) {
        int r  = idx >> 3;
        int k0 = (idx & 7) * 4;
        int row = bm + r;
        float4 v = make_float4(0.f, 0.f, 0.f, 0.f);
        if (row < M) v = *reinterpret_cast<const float4*>(xc + (size_t)row*32 + k0);
        __nv_bfloat16 h0 = __float2bfloat16(v.x), h1 = __float2bfloat16(v.y);
        __nv_bfloat16 h2 = __float2bfloat16(v.z), h3 = __float2bfloat16(v.w);
        __nv_bfloat16 l0 = __float2bfloat16(v.x - __bfloat162float(h0));
        __nv_bfloat16 l1 = __float2bfloat16(v.y - __bfloat162float(h1));
        __nv_bfloat16 l2 = __float2bfloat16(v.z - __bfloat162float(h2));
        __nv_bfloat16 l3 = __float2bfloat16(v.w - __bfloat162float(h3));
        __nv_bfloat16* pH = sAhi + r*LDA + k0;
        __nv_bfloat16* pL = sAlo + r*LDA + k0;
        *reinterpret_cast<__nv_bfloat162*>(pH)     = __halves2bfloat162(h0, h1);
        *reinterpret_cast<__nv_bfloat162*>(pH + 2) = __halves2bfloat162(h2, h3);
        *reinterpret_cast<__nv_bfloat162*>(pL)     = __halves2bfloat162(l0, l1);
        *reinterpret_cast<__nv_bfloat162*>(pL + 2) = __halves2bfloat162(l2, l3);
    }
    for (int idx = tid; idx < 128*4; idx += 256) {
        int n  = idx >> 2;
        int k0 = (idx & 3) * 8;
        *reinterpret_cast<uint4*>(sWhi + n*LDA + k0) = *reinterpret_cast<const uint4*>(W1hi + (size_t)n*32 + k0);
        *reinterpret_cast<uint4*>(sWlo + n*LDA + k0) = *reinterpret_cast<const uint4*>(W1lo + (size_t)n*32 + k0);
    }
    __syncthreads();

    const int row0 = (wid & 1) * 32;
    const int col0 = (wid >> 1) * 32;
    uint32_t aB[2][2], bB[2][2];
    {
        int ar = (lane & 15), ac = (lane >> 4) * 8;
        #pragma unroll
        for (int mi = 0; mi < 2; mi++) {
            aB[0][mi] = smem_u32(sAhi + (row0 + mi*16 + ar)*LDA + ac);
            aB[1][mi] = smem_u32(sAlo + (row0 + mi*16 + ar)*LDA + ac);
        }
        int q  = lane >> 3;
        int nr = (q >> 1)*8 + (lane & 7);
        int nc = (q & 1)*8;
        #pragma unroll
        for (int nt = 0; nt < 2; nt++) {
            bB[0][nt] = smem_u32(sWhi + (col0 + nt*16 + nr)*LDA + nc);
            bB[1][nt] = smem_u32(sWlo + (col0 + nt*16 + nr)*LDA + nc);
        }
    }
    const int g = lane >> 2, t = lane & 3;

    float acc[2][4][4];
    #pragma unroll
    for (int mi = 0; mi < 2; mi++)
        #pragma unroll
        for (int ni = 0; ni < 4; ni++)
            { acc[mi][ni][0]=0.f; acc[mi][ni][1]=0.f; acc[mi][ni][2]=0.f; acc[mi][ni][3]=0.f; }

    #pragma unroll
    for (int ks = 0; ks < 2; ks++) {     // K=32
        uint32_t koff = (uint32_t)ks * 32u;
        uint32_t ah[2][4], al[2][4], bh[2][4], bl[2][4];
        #pragma unroll
        for (int mi = 0; mi < 2; mi++) { ldm_x4(ah[mi], aB[0][mi] + koff); ldm_x4(al[mi], aB[1][mi] + koff); }
        #pragma unroll
        for (int nt = 0; nt < 2; nt++) { ldm_x4(bh[nt], bB[0][nt] + koff); ldm_x4(bl[nt], bB[1][nt] + koff); }
        #pragma unroll
        for (int mi = 0; mi < 2; mi++)
            #pragma unroll
            for (int nt = 0; nt < 2; nt++) {
                mma_bf16(acc[mi][nt*2],   ah[mi], &bh[nt][0]);
                mma_bf16(acc[mi][nt*2+1], ah[mi], &bh[nt][2]);
                mma_bf16(acc[mi][nt*2],   ah[mi], &bl[nt][0]);
                mma_bf16(acc[mi][nt*2+1], ah[mi], &bl[nt][2]);
                mma_bf16(acc[mi][nt*2],   al[mi], &bh[nt][0]);
                mma_bf16(acc[mi][nt*2+1], al[mi], &bh[nt][2]);
            }
    }
    __syncthreads();

    // ---- epilogue 1: hc = relu(acc + b1) -> split directly into smem A tiles ----
    #pragma unroll
    for (int mi = 0; mi < 2; mi++) {
        #pragma unroll
        for (int ni = 0; ni < 4; ni++) {
            int cc = col0 + ni*8 + t*2;
            float bx = b1[cc], by = b1[cc+1];
            float2 v0 = make_float2(fmaxf(acc[mi][ni][0] + bx, 0.f), fmaxf(acc[mi][ni][1] + by, 0.f));
            float2 v1 = make_float2(fmaxf(acc[mi][ni][2] + bx, 0.f), fmaxf(acc[mi][ni][3] + by, 0.f));
            int rl0 = row0 + mi*16 + g;
            __nv_bfloat16 a0 = __float2bfloat16(v0.x), a1 = __float2bfloat16(v0.y);
            __nv_bfloat16 c0 = __float2bfloat16(v1.x), c1 = __float2bfloat16(v1.y);
            *reinterpret_cast<__nv_bfloat162*>(sAhi + rl0*LDA + cc)     = __halves2bfloat162(a0, a1);
            *reinterpret_cast<__nv_bfloat162*>(sAlo + rl0*LDA + cc)     =
                __halves2bfloat162(__float2bfloat16(v0.x - __bfloat162float(a0)),
                                   __float2bfloat16(v0.y - __bfloat162float(a1)));
            *reinterpret_cast<__nv_bfloat162*>(sAhi + (rl0+8)*LDA + cc) = __halves2bfloat162(c0, c1);
            *reinterpret_cast<__nv_bfloat162*>(sAlo + (rl0+8)*LDA + cc) =
                __halves2bfloat162(__float2bfloat16(v1.x - __bfloat162float(c0)),
                                   __float2bfloat16(v1.y - __bfloat162float(c1)));
        }
    }
    for (int idx = tid; idx < 128*16; idx += 256) {
        int n  = idx >> 4;
        int k0 = (idx & 15) * 8;
        *reinterpret_cast<uint4*>(sWhi + n*LDA + k0) = *reinterpret_cast<const uint4*>(W2hi + (size_t)n*128 + k0);
        *reinterpret_cast<uint4*>(sWlo + n*LDA + k0) = *reinterpret_cast<const uint4*>(W2lo + (size_t)n*128 + k0);
    }
    __syncthreads();

    #pragma unroll
    for (int mi = 0; mi < 2; mi++)
        #pragma unroll
        for (int ni = 0; ni < 4; ni++)
            { acc[mi][ni][0]=0.f; acc[mi][ni][1]=0.f; acc[mi][ni][2]=0.f; acc[mi][ni][3]=0.f; }

    #pragma unroll 2
    for (int ks = 0; ks < 8; ks++) {
        uint32_t koff = (uint32_t)ks * 32u;
        uint32_t ah[2][4], al[2][4], bh[2][4], bl[2][4];
        #pragma unroll
        for (int mi = 0; mi < 2; mi++) { ldm_x4(ah[mi], aB[0][mi] + koff); ldm_x4(al[mi], aB[1][mi] + koff); }
        #pragma unroll
        for (int nt = 0; nt < 2; nt++) { ldm_x4(bh[nt], bB[0][nt] + koff); ldm_x4(bl[nt], bB[1][nt] + koff); }
        #pragma unroll
        for (int mi = 0; mi < 2; mi++)
            #pragma unroll
            for (int nt = 0; nt < 2; nt++) {
                mma_bf16(acc[mi][nt*2],   ah[mi], &bh[nt][0]);
                mma_bf16(acc[mi][nt*2+1], ah[mi], &bh[nt][2]);
                mma_bf16(acc[mi][nt*2],   ah[mi], &bl[nt][0]);
                mma_bf16(acc[mi][nt*2+1], ah[mi], &bl[nt][2]);
                mma_bf16(acc[mi][nt*2],   al[mi], &bh[nt][0]);
                mma_bf16(acc[mi][nt*2+1], al[mi], &bh[nt][2]);
            }
    }

    // ---- epilogue 2: hcs (fp16) to gmem + fused logits (att_s_ct) ----
    float lsS[2][2];
    lsS[0][0]=0.f; lsS[0][1]=0.f; lsS[1][0]=0.f; lsS[1][1]=0.f;
    #pragma unroll
    for (int mi = 0; mi < 2; mi++) {
        #pragma unroll
        for (int ni = 0; ni < 4; ni++) {
            int cc = col0 + ni*8 + t*2;
            int r1 = bm + row0 + mi*16 + g;
            float2 v0 = make_float2(acc[mi][ni][0], acc[mi][ni][1]);
            float2 v1 = make_float2(acc[mi][ni][2], acc[mi][ni][3]);
            float a0 = __ldg(attS + cc), a1 = __ldg(attS + cc + 1);
            lsS[mi][0] += v0.x*a0 + v0.y*a1;
            lsS[mi][1] += v1.x*a0 + v1.y*a1;
            if (r1 < M)     *reinterpret_cast<__half2*>(C + (size_t)r1*128 + cc)     = __floats2half2_rn(v0.x, v0.y);
            if (r1 + 8 < M) *reinterpret_cast<__half2*>(C + (size_t)(r1+8)*128 + cc) = __floats2half2_rn(v1.x, v1.y);
        }
    }
    #pragma unroll
    for (int mi = 0; mi < 2; mi++)
        #pragma unroll
        for (int rr = 0; rr < 2; rr++) {
            float v = lsS[mi][rr];
            v += __shfl_xor_sync(0xffffffffu, v, 1);
            v += __shfl_xor_sync(0xffffffffu, v, 2);
            lsS[mi][rr] = v;
        }
    if (t == 0) {
        int head = col0 >> 5;
        #pragma unroll
        for (int mi = 0; mi < 2; mi++)
            #pragma unroll
            for (int rr = 0; rr < 2; rr++) {
                int r = bm + row0 + mi*16 + g + rr*8;
                if (r < M) outS[(size_t)r*4 + head] = lsS[mi][rr];
            }
    }
}

// --------------------------------- CSR build ------------------------------------------------
__global__ void hist_tt_kernel(const int* __restrict__ e0, const int* __restrict__ e1)
{
    for (int i = blockIdx.x*blockDim.x + threadIdx.x; i < ETTg; i += gridDim.x*blockDim.x) {
        atomicAdd(&g_deg[0*NTg + e1[i]], 1);
        atomicAdd(&g_deg[1*NTg + e0[i]], 1);
    }
}
__global__ void hist_ct_kernel(const int* __restrict__ ed)
{
    for (int i = blockIdx.x*blockDim.x + threadIdx.x; i < ECTg; i += gridDim.x*blockDim.x)
        atomicAdd(&g_deg[2*NTg + ed[i]], 1);
}

__global__ void scan1_kernel()
{
    int arr  = blockIdx.y;
    int base = blockIdx.x * 1024 + threadIdx.x;
    int lane = threadIdx.x & 31, wid = threadIdx.x >> 5;
    int v = (base < NTg) ? g_deg[arr*NTg + base] : 0;
    int x = v;
    #pragma unroll
    for (int o = 1; o < 32; o <<= 1) { int y = __shfl_up_sync(0xffffffffu, x, o); if (lane >= o) x += y; }
    __shared__ int ws[32];
    if (lane == 31) ws[wid] = x;
    __syncthreads();
    if (wid == 0) {
        int wv = ws[lane]; int wx = wv;
        #pragma unroll
        for (int o = 1; o < 32; o <<= 1) { int y = __shfl_up_sync(0xffffffffu, wx, o); if (lane >= o) wx += y; }
        if (lane == 31) g_aux[arr*128 + blockIdx.x] = wx;
        ws[lane] = wx - wv;
    }
    __syncthreads();
    int excl = x - v + ws[wid];
    if (base < NTg) g_cur[arr*NTg + base] = excl;
}

__global__ void scan2_kernel()
{
    int arr  = threadIdx.x >> 5;
    int lane = threadIdx.x & 31;
    if (arr >= 3) return;
    const int NB = (NTg + 1023) / 1024;
    int carry = 0;
    for (int c = 0; c*32 < NB; c++) {
        int idx = c*32 + lane;
        int v = (idx < NB) ? g_aux[arr*128 + idx] : 0;
        int x = v;
        #pragma unroll
        for (int o = 1; o < 32; o <<= 1) { int y = __shfl_up_sync(0xffffffffu, x, o); if (lane >= o) x += y; }
        if (idx < NB) g_aux[arr*128 + idx] = x - v + carry;
        carry += __shfl_sync(0xffffffffu, x, 31);
    }
}

__global__ void scan3_kernel()
{
    for (int i = blockIdx.x*blockDim.x + threadIdx.x; i < 3*NTg; i += gridDim.x*blockDim.x) {
        int arr = i / NTg; int idx = i - arr*NTg;
        g_cur[i] += g_aux[arr*128 + (idx >> 10)];
    }
}

__global__ void fill_tt_kernel(const int* __restrict__ e0, const int* __restrict__ e1)
{
    for (int i = blockIdx.x*blockDim.x + threadIdx.x; i < ETTg; i += gridDim.x*blockDim.x) {
        int s = e0[i], d = e1[i];
        int p = atomicAdd(&g_cur[0*NTg + d], 1); g_csrf[p] = s;
        int q = atomicAdd(&g_cur[1*NTg + s], 1); g_csrr[q] = d;
    }
}
__global__ void fill_ct_kernel(const int* __restrict__ es, const int* __restrict__ ed)
{
    for (int i = blockIdx.x*blockDim.x + threadIdx.x; i < ECTg; i += gridDim.x*blockDim.x) {
        int p = atomicAdd(&g_cur[2*NTg + ed[i]], 1); g_csrct[p] = es[i];
    }
}

// --------- per-relation GAT, single pass (no max-shift; logits are O(0.1), safe) ------------
template<bool SELF>
__device__ __forceinline__ void gat_rel(
    const __half* __restrict__ hsrc, const float* __restrict__ a_s,
    const int* __restrict__ csr, int start, int cnt, int d, int lane,
    float4 ad, float wgt, float r[4])
{
    if (!SELF && cnt == 0) { r[0]=0.f; r[1]=0.f; r[2]=0.f; r[3]=0.f; return; }

    float den0 = 0.f, den1 = 0.f, den2 = 0.f, den3 = 0.f;
    float ac0 = 0.f, ac1 = 0.f, ac2 = 0.f, ac3 = 0.f;

    if (SELF) {
        float4 as = *reinterpret_cast<const float4*>(a_s + (size_t)d*4);
        float p0 = __expf(lrelu02(as.x + ad.x));
        float p1 = __expf(lrelu02(as.y + ad.y));
        float p2 = __expf(lrelu02(as.z + ad.z));
        float p3 = __expf(lrelu02(as.w + ad.w));
        den0 = p0; den1 = p1; den2 = p2; den3 = p3;
        const __half* row = hsrc + (size_t)d*128;
        ac0 = p0 * __half2float(row[lane]);
        ac1 = p1 * __half2float(row[32 + lane]);
        ac2 = p2 * __half2float(row[64 + lane]);
        ac3 = p3 * __half2float(row[96 + lane]);
    }
    #pragma unroll 2
    for (int i = 0; i < cnt; i++) {
        int s = csr[start + i];
        float4 as = *reinterpret_cast<const float4*>(a_s + (size_t)s*4);
        float p0 = __expf(lrelu02(as.x + ad.x));
        float p1 = __expf(lrelu02(as.y + ad.y));
        float p2 = __expf(lrelu02(as.z + ad.z));
        float p3 = __expf(lrelu02(as.w + ad.w));
        den0 += p0; den1 += p1; den2 += p2; den3 += p3;
        const __half* row = hsrc + (size_t)s*128;
        ac0 = fmaf(p0, __half2float(row[lane]),       ac0);
        ac1 = fmaf(p1, __half2float(row[32 + lane]),  ac1);
        ac2 = fmaf(p2, __half2float(row[64 + lane]),  ac2);
        ac3 = fmaf(p3, __half2float(row[96 + lane]),  ac3);
    }

    r[0] = ac0 * (wgt / den0); r[1] = ac1 * (wgt / den1);
    r[2] = ac2 * (wgt / den2); r[3] = ac3 * (wgt / den3);
}

// --- merged GAT over all 3 relations; writes z = relu(acc + cbias + ht) directly ------------
__global__ void gat_all_kernel(
    const __half* __restrict__ hs, const __half* __restrict__ hd, const __half* __restrict__ hcs,
    const float* __restrict__ ht,
    const float* __restrict__ asf, const float* __restrict__ adf,
    const float* __restrict__ asr, const float* __restrict__ adr,
    const float* __restrict__ asct, const float* __restrict__ adct,
    const int* __restrict__ cur, const int* __restrict__ deg,
    const int* __restrict__ csrf, const int* __restrict__ csrr, const int* __restrict__ csrct,
    const float* __restrict__ bsd, const float* __restrict__ bds, const float* __restrict__ bct,
    float* __restrict__ z)
{
    int d    = (blockIdx.x * blockDim.x + threadIdx.x) >> 5;
    int lane = threadIdx.x & 31;
    if (d >= NTg) return;

    float rf[4], rr_[4], rc[4];
    {
        int c = deg[0*NTg + d];
        gat_rel<true >(hs, asf, csrf, cur[0*NTg + d] - c, c, d, lane,
                       *reinterpret_cast<const float4*>(adf + (size_t)d*4), 0.25f, rf);
    }
    {
        int c = deg[1*NTg + d];
        gat_rel<true >(hd, asr, csrr, cur[1*NTg + d] - c, c, d, lane,
                       *reinterpret_cast<const float4*>(adr + (size_t)d*4), 0.25f, rr_);
    }
    {
        int c = deg[2*NTg + d];
        gat_rel<false>(hcs, asct, csrct, cur[2*NTg + d] - c, c, d, lane,
                       *reinterpret_cast<const float4*>(adct + (size_t)d*4), 0.5f, rc);
    }

    const float* hrow = ht + (size_t)d*128;
    float* zrow = z + (size_t)d*128;
    #pragma unroll
    for (int h = 0; h < 4; h++) {
        int c = h*32 + lane;
        float cb = 0.25f*bsd[c] + 0.25f*bds[c] + 0.5f*bct[c];
        float v  = rf[h] + rr_[h] + rc[h] + hrow[c] + cb;
        zrow[c] = fmaxf(v, 0.f);
    }
}

// ----------------------------------- launch -------------------------------------------------
extern "C" void kernel_launch(void* const* d_in, const int* in_sizes, int n_in,
                              void* d_out, int out_size)
{
    const float* x_t     = (const float*)d_in[0];
    const float* x_c     = (const float*)d_in[1];
    const int*   ett     = (const int*)d_in[2];
    const int*   e0      = ett;
    const int*   e1      = ett + ETTg;
    const int*   ect_s   = (const int*)d_in[3];
    const int*   ect_d   = (const int*)d_in[4];
    const float* W_pre_t = (const float*)d_in[5];
    const float* b_pre_t = (const float*)d_in[6];
    const float* W_pre_c = (const float*)d_in[7];
    const float* b_pre_c = (const float*)d_in[8];
    const float* W_sd    = (const float*)d_in[9];
    const float* att_s_sd= (const float*)d_in[10];
    const float* att_d_sd= (const float*)d_in[11];
    const float* b_sd    = (const float*)d_in[12];
    const float* W_ds    = (const float*)d_in[13];
    const float* att_s_ds= (const float*)d_in[14];
    const float* att_d_ds= (const float*)d_in[15];
    const float* b_ds    = (const float*)d_in[16];
    const float* W_ct_s  = (const float*)d_in[17];
    const float* W_ct_d  = (const float*)d_in[18];
    const float* att_s_ct= (const float*)d_in[19];
    const float* att_d_ct= (const float*)d_in[20];
    const float* b_ct    = (const float*)d_in[21];
    const float* W_out   = (const float*)d_in[22];
    const float* b_out   = (const float*)d_in[23];
    float* out = (float*)d_out;

    float *p_ht, *p_z, *p_wv;
    __half *p_hs, *p_hd, *p_hcs;
    float *p_asf, *p_adf, *p_asr, *p_adr, *p_adct, *p_asct;
    int *p_deg, *p_cur, *p_csrf, *p_csrr, *p_csrct;
    __nv_bfloat16 *p_whi, *p_wlo;
    cudaGetSymbolAddress((void**)&p_ht,  g_ht);
    cudaGetSymbolAddress((void**)&p_hs,  g_hs);
    cudaGetSymbolAddress((void**)&p_hd,  g_hd);
    cudaGetSymbolAddress((void**)&p_hcs, g_hcs);
    cudaGetSymbolAddress((void**)&p_z,   g_z);
    cudaGetSymbolAddress((void**)&p_wv,  g_wv);
    cudaGetSymbolAddress((void**)&p_asf, g_asf);
    cudaGetSymbolAddress((void**)&p_adf, g_adf);
    cudaGetSymbolAddress((void**)&p_asr, g_asr);
    cudaGetSymbolAddress((void**)&p_adr, g_adr);
    cudaGetSymbolAddress((void**)&p_adct,g_adct);
    cudaGetSymbolAddress((void**)&p_asct,g_asct);
    cudaGetSymbolAddress((void**)&p_deg, g_deg);
    cudaGetSymbolAddress((void**)&p_cur, g_cur);
    cudaGetSymbolAddress((void**)&p_csrf, g_csrf);
    cudaGetSymbolAddress((void**)&p_csrr, g_csrr);
    cudaGetSymbolAddress((void**)&p_csrct,g_csrct);
    cudaGetSymbolAddress((void**)&p_whi, g_whi);
    cudaGetSymbolAddress((void**)&p_wlo, g_wlo);

    // smem: (2*64 + 2*128) rows * (K+8) cols * 2B   (+4KB reduce scratch for NATT==3)
    const int SM128 = (2*64 + 2*128) * (128 + 8) * 2;   // 104448
    const int SM64  = (2*64 + 2*128) * (64  + 8) * 2;   // 55296
    cudaFuncSetAttribute(tc_gemm_dual,               cudaFuncAttributeMaxDynamicSharedMemorySize, SM128);
    cudaFuncSetAttribute(tc_gemm_chain,              cudaFuncAttributeMaxDynamicSharedMemorySize, SM128);
    cudaFuncSetAttribute(tc_gemm<128,false,true, 0>, cudaFuncAttributeMaxDynamicSharedMemorySize, SM128);
    cudaFuncSetAttribute(tc_gemm<64, true, true, 3>, cudaFuncAttributeMaxDynamicSharedMemorySize, SM64 + 4096);

    const int GT = (NTg + 63) / 64;   // 1563
    const int GC = (NCg + 63) / 64;   // 391

    // slots: 0 pre_t K=64, 1 pre_c K=32, 2 sd, 3 ds, 4 ct_s, 5 out  (W_ct_d folded into wv)
    WJobs jobs;
    jobs.W[0] = W_pre_t; jobs.K[0] = 64;
    jobs.W[1] = W_pre_c; jobs.K[1] = 32;
    jobs.W[2] = W_sd;    jobs.K[2] = 128;
    jobs.W[3] = W_ds;    jobs.K[3] = 128;
    jobs.W[4] = W_ct_s;  jobs.K[4] = 128;
    jobs.W[5] = W_out;   jobs.K[5] = 128;

    wv_kernel<<<1, 512>>>(W_ct_d, att_d_ct, p_wv);                                  // k1
    wsplit_all<<<dim3(64, 6), 256>>>(jobs, p_whi, p_wlo);                           // k2
    // pre_t GEMM with fused a_dct = ht . wv^T  (NATT=3)
    tc_gemm<64,true,true,3><<<GT, 256, SM64 + 4096>>>(x_t, p_whi + 0*16384, p_wlo + 0*16384,
        b_pre_t, p_ht, NTg, p_wv, p_adct);                                          // k3
    tc_gemm_dual<<<GT, 256, SM128>>>(p_ht,
        p_whi + 2*16384, p_wlo + 2*16384, p_whi + 3*16384, p_wlo + 3*16384,
        p_hs, p_hd, NTg,
        att_s_sd, att_d_sd, att_s_ds, att_d_ds,
        p_asf, p_adf, p_asr, p_adr);                                                // k4 <- ncu
    // chained: hc (K=32, smem-resident) -> hcs = hc @ W_ct_s, fused asct logits
    tc_gemm_chain<<<GC, 256, SM128>>>(x_c,
        p_whi + 1*16384, p_wlo + 1*16384, b_pre_c,
        p_whi + 4*16384, p_wlo + 4*16384,
        p_hcs, NCg, att_s_ct, p_asct);                                              // k5

    // CSR build
    cudaMemsetAsync(p_deg, 0, 3*NTg*sizeof(int));
    hist_tt_kernel<<<512, 256>>>(e0, e1);
    hist_ct_kernel<<<256, 256>>>(ect_d);
    dim3 g1((NTg + 1023) / 1024, 3);
    scan1_kernel<<<g1, 1024>>>();
    scan2_kernel<<<1, 96>>>();
    scan3_kernel<<<256, 256>>>();
    fill_tt_kernel<<<512, 256>>>(e0, e1);
    fill_ct_kernel<<<256, 256>>>(ect_s, ect_d);

    // merged GAT (high occupancy, fp16 gathers): z = relu(0.25*sd + 0.25*ds + 0.5*ct + cbias + ht)
    gat_all_kernel<<<(NTg + 7) / 8, 256>>>(
        p_hs, p_hd, p_hcs, p_ht,
        p_asf, p_adf, p_asr, p_adr, p_asct, p_adct,
        p_cur, p_deg, p_csrf, p_csrr, p_csrct,
        b_sd, b_ds, b_ct, p_z);

    // final: out = z @ W_out + b_out
    tc_gemm<128,false,true,0><<<GT, 256, SM128>>>(p_z, p_whi + 5*16384, p_wlo + 5*16384,
        b_out, out, NTg, nullptr, nullptr);
}

// round 12
// speedup vs baseline: 1.4632x; 1.0260x over previous
#include <cuda_runtime.h>
#include <cuda_bf16.h>
#include <cuda_fp16.h>
#include <cstdint>

#define NTg  100000
#define NCg  25000
#define ETTg 800000
#define ECTg 400000
#define HIDg 128

// ------------------------- scratch (device globals; allocation-free) -------------------------
__device__ float  g_ht [NTg*HIDg];
__device__ __half g_hs [NTg*HIDg];
__device__ __half g_hd [NTg*HIDg];
__device__ __half g_hcs[NCg*HIDg];
__device__ float  g_z  [NTg*HIDg];
__device__ float g_asf[NTg*4];
__device__ float g_adf[NTg*4];
__device__ float g_asr[NTg*4];
__device__ float g_adr[NTg*4];
__device__ float g_adct[NTg*4];
__device__ float g_asct[NCg*4];
__device__ float g_wv [4*128];
__device__ int   g_deg[3*NTg];
__device__ int   g_cur[3*NTg];
__device__ int   g_aux[3*128];
__device__ int   g_csrf[ETTg];
__device__ int   g_csrr[ETTg];
__device__ int   g_csrct[ECTg];
// split weights: 6 slots of up to 128x128 bf16 ([N,K] layout, i.e., W^T)
__device__ __nv_bfloat16 g_whi[6*128*128];
__device__ __nv_bfloat16 g_wlo[6*128*128];

__device__ __forceinline__ float lrelu02(float x) { return x > 0.f ? x : 0.2f * x; }

__device__ __forceinline__ uint32_t smem_u32(const void* p) {
    uint32_t a;
    asm("{ .reg .u64 t; cvta.to.shared.u64 t, %1; cvt.u32.u64 %0, t; }" : "=r"(a) : "l"(p));
    return a;
}

__device__ __forceinline__ void ldm_x4(uint32_t* r, uint32_t addr) {
    asm volatile("ldmatrix.sync.aligned.m8n8.x4.shared.b16 {%0,%1,%2,%3}, [%4];"
                 : "=r"(r[0]), "=r"(r[1]), "=r"(r[2]), "=r"(r[3]) : "r"(addr));
}
__device__ __forceinline__ void mma_bf16(float* c, const uint32_t* a, const uint32_t* b) {
    asm volatile("mma.sync.aligned.m16n8k16.row.col.f32.bf16.bf16.f32 "
                 "{%0,%1,%2,%3}, {%4,%5,%6,%7}, {%8,%9}, {%0,%1,%2,%3};"
                 : "+f"(c[0]), "+f"(c[1]), "+f"(c[2]), "+f"(c[3])
                 : "r"(a[0]), "r"(a[1]), "r"(a[2]), "r"(a[3]), "r"(b[0]), "r"(b[1]));
}

// ------------------- batched W split/transpose: hi/lo[n*K+k] = split(W[k*128+n]) ------------
struct WJobs { const float* W[6]; int K[6]; };

__global__ void wsplit_all(WJobs jobs, __nv_bfloat16* __restrict__ hiB,
                           __nv_bfloat16* __restrict__ loB)
{
    int slot = blockIdx.y;
    const float* W = jobs.W[slot];
    int K = jobs.K[slot];
    __nv_bfloat16* hi = hiB + slot*16384;
    __nv_bfloat16* lo = loB + slot*16384;
    int tot = 128 * K;
    for (int i = blockIdx.x*blockDim.x + threadIdx.x; i < tot; i += gridDim.x*blockDim.x) {
        int n = i / K, k = i - n*K;
        float v = W[k*128 + n];
        __nv_bfloat16 h = __float2bfloat16(v);
        hi[i] = h;
        lo[i] = __float2bfloat16(v - __bfloat162float(h));
    }
}

// ----------------- wv[h*128+k] = sum_c W_ct_dst[k*128 + h*32 + c] * att[h*32+c] -------------
__global__ void wv_kernel(const float* __restrict__ W, const float* __restrict__ att,
                          float* __restrict__ wv)
{
    int i = threadIdx.x;           // 512 threads: k = i>>2, h = i&3
    int k = i >> 2, h = i & 3;
    float s = 0.f;
    #pragma unroll 8
    for (int c = 0; c < 32; c++) s += W[k*128 + h*32 + c] * att[h*32 + c];
    wv[h*128 + k] = s;
}

// ---------------- HMMA GEMM: C[M,128] = A[M,K] @ W[K,128]  (3-split bf16) -------------------
// CTA tile 64x128 (2 CTAs/SM), 8 warps, warp tile 32x32. W^T ([N,K]) pre-split in gmem.
// NATT: 0 = none; 1 = fused logits outS[r,head] = sum_c C[r,c]*attS[c] (head = c>>5)
//       3 = fused full-row dots outS[r,h] = sum_{c=0..127} C[r,c]*attS[h*128+c]  (attS = wv)
template<int K, bool RELU, bool BIAS, int NATT>
__global__ void __launch_bounds__(256, 2) tc_gemm(
    const float* __restrict__ A, const __nv_bfloat16* __restrict__ Whi,
    const __nv_bfloat16* __restrict__ Wlo, const float* __restrict__ bias,
    float* __restrict__ C, int M,
    const float* __restrict__ attS, float* __restrict__ outS)
{
    constexpr int LDA = K + 8;
    extern __shared__ __nv_bfloat16 smb[];
    __nv_bfloat16* sAhi = smb;                 // 64*LDA
    __nv_bfloat16* sAlo = sAhi + 64*LDA;
    __nv_bfloat16* sWhi = sAlo + 64*LDA;       // 128*LDA
    __nv_bfloat16* sWlo = sWhi + 128*LDA;

    const int tid  = threadIdx.x;
    const int lane = tid & 31;
    const int wid  = tid >> 5;
    const int bm   = blockIdx.x * 64;

    for (int idx = tid; idx < 64*(K/4); idx += 256) {
        int r  = idx / (K/4);
        int k0 = (idx % (K/4)) * 4;
        int row = bm + r;
        float4 v = make_float4(0.f, 0.f, 0.f, 0.f);
        if (row < M) v = *reinterpret_cast<const float4*>(A + (size_t)row*K + k0);
        __nv_bfloat16 h0 = __float2bfloat16(v.x), h1 = __float2bfloat16(v.y);
        __nv_bfloat16 h2 = __float2bfloat16(v.z), h3 = __float2bfloat16(v.w);
        __nv_bfloat16 l0 = __float2bfloat16(v.x - __bfloat162float(h0));
        __nv_bfloat16 l1 = __float2bfloat16(v.y - __bfloat162float(h1));
        __nv_bfloat16 l2 = __float2bfloat16(v.z - __bfloat162float(h2));
        __nv_bfloat16 l3 = __float2bfloat16(v.w - __bfloat162float(h3));
        __nv_bfloat16* pH = sAhi + r*LDA + k0;
        __nv_bfloat16* pL = sAlo + r*LDA + k0;
        *reinterpret_cast<__nv_bfloat162*>(pH)     = __halves2bfloat162(h0, h1);
        *reinterpret_cast<__nv_bfloat162*>(pH + 2) = __halves2bfloat162(h2, h3);
        *reinterpret_cast<__nv_bfloat162*>(pL)     = __halves2bfloat162(l0, l1);
        *reinterpret_cast<__nv_bfloat162*>(pL + 2) = __halves2bfloat162(l2, l3);
    }
    for (int idx = tid; idx < 128*(K/8); idx += 256) {
        int n  = idx / (K/8);
        int k0 = (idx % (K/8)) * 8;
        *reinterpret_cast<uint4*>(sWhi + n*LDA + k0) = *reinterpret_cast<const uint4*>(Whi + (size_t)n*K + k0);
        *reinterpret_cast<uint4*>(sWlo + n*LDA + k0) = *reinterpret_cast<const uint4*>(Wlo + (size_t)n*K + k0);
    }
    __syncthreads();

    const int row0 = (wid & 1) * 32;
    const int col0 = (wid >> 1) * 32;

    uint32_t aB[2][2], bB[2][2];
    {
        int ar = (lane & 15), ac = (lane >> 4) * 8;
        #pragma unroll
        for (int mi = 0; mi < 2; mi++) {
            aB[0][mi] = smem_u32(sAhi + (row0 + mi*16 + ar)*LDA + ac);
            aB[1][mi] = smem_u32(sAlo + (row0 + mi*16 + ar)*LDA + ac);
        }
        int q  = lane >> 3;
        int nr = (q >> 1)*8 + (lane & 7);
        int nc = (q & 1)*8;
        #pragma unroll
        for (int nt = 0; nt < 2; nt++) {
            bB[0][nt] = smem_u32(sWhi + (col0 + nt*16 + nr)*LDA + nc);
            bB[1][nt] = smem_u32(sWlo + (col0 + nt*16 + nr)*LDA + nc);
        }
    }

    float acc[2][4][4];
    #pragma unroll
    for (int mi = 0; mi < 2; mi++)
        #pragma unroll
        for (int ni = 0; ni < 4; ni++)
            { acc[mi][ni][0]=0.f; acc[mi][ni][1]=0.f; acc[mi][ni][2]=0.f; acc[mi][ni][3]=0.f; }

    #pragma unroll 2
    for (int ks = 0; ks < K/16; ks++) {
        uint32_t koff = (uint32_t)ks * 32u;
        uint32_t ah[2][4], al[2][4], bh[2][4], bl[2][4];
        #pragma unroll
        for (int mi = 0; mi < 2; mi++) { ldm_x4(ah[mi], aB[0][mi] + koff); ldm_x4(al[mi], aB[1][mi] + koff); }
        #pragma unroll
        for (int nt = 0; nt < 2; nt++) { ldm_x4(bh[nt], bB[0][nt] + koff); ldm_x4(bl[nt], bB[1][nt] + koff); }
        #pragma unroll
        for (int mi = 0; mi < 2; mi++)
            #pragma unroll
            for (int nt = 0; nt < 2; nt++) {
                mma_bf16(acc[mi][nt*2],   ah[mi], &bh[nt][0]);
                mma_bf16(acc[mi][nt*2+1], ah[mi], &bh[nt][2]);
                mma_bf16(acc[mi][nt*2],   ah[mi], &bl[nt][0]);
                mma_bf16(acc[mi][nt*2+1], ah[mi], &bl[nt][2]);
                mma_bf16(acc[mi][nt*2],   al[mi], &bh[nt][0]);
                mma_bf16(acc[mi][nt*2+1], al[mi], &bh[nt][2]);
            }
    }

    const int g = lane >> 2, t = lane & 3;
    float lsS[2][2];
    float lsA[2][2][4];
    if (NATT == 1) { lsS[0][0]=0.f; lsS[0][1]=0.f; lsS[1][0]=0.f; lsS[1][1]=0.f; }
    if (NATT == 3) {
        #pragma unroll
        for (int a = 0; a < 2; a++)
            #pragma unroll
            for (int b = 0; b < 2; b++)
                #pragma unroll
                for (int h = 0; h < 4; h++) lsA[a][b][h] = 0.f;
    }
    #pragma unroll
    for (int mi = 0; mi < 2; mi++) {
        #pragma unroll
        for (int ni = 0; ni < 4; ni++) {
            int cc = col0 + ni*8 + t*2;
            float bx = 0.f, by = 0.f;
            if (BIAS) { bx = bias[cc]; by = bias[cc+1]; }
            int r1 = bm + row0 + mi*16 + g;
            float2 v0 = make_float2(acc[mi][ni][0] + bx, acc[mi][ni][1] + by);
            float2 v1 = make_float2(acc[mi][ni][2] + bx, acc[mi][ni][3] + by);
            if (RELU) {
                v0.x = fmaxf(v0.x, 0.f); v0.y = fmaxf(v0.y, 0.f);
                v1.x = fmaxf(v1.x, 0.f); v1.y = fmaxf(v1.y, 0.f);
            }
            if (NATT == 1) {
                float a0 = __ldg(attS + cc), a1 = __ldg(attS + cc + 1);
                lsS[mi][0] += v0.x*a0 + v0.y*a1;
                lsS[mi][1] += v1.x*a0 + v1.y*a1;
            }
            if (NATT == 3) {
                #pragma unroll
                for (int h = 0; h < 4; h++) {
                    float w0 = __ldg(attS + h*128 + cc), w1 = __ldg(attS + h*128 + cc + 1);
                    lsA[mi][0][h] += v0.x*w0 + v0.y*w1;
                    lsA[mi][1][h] += v1.x*w0 + v1.y*w1;
                }
            }
            if (r1 < M)     *reinterpret_cast<float2*>(C + (size_t)r1*128 + cc)     = v0;
            if (r1 + 8 < M) *reinterpret_cast<float2*>(C + (size_t)(r1+8)*128 + cc) = v1;
        }
    }
    if (NATT == 1) {
        #pragma unroll
        for (int mi = 0; mi < 2; mi++)
            #pragma unroll
            for (int rr = 0; rr < 2; rr++) {
                float v = lsS[mi][rr];
                v += __shfl_xor_sync(0xffffffffu, v, 1);
                v += __shfl_xor_sync(0xffffffffu, v, 2);
                lsS[mi][rr] = v;
            }
        if (t == 0) {
            int head = col0 >> 5;
            #pragma unroll
            for (int mi = 0; mi < 2; mi++)
                #pragma unroll
                for (int rr = 0; rr < 2; rr++) {
                    int r = bm + row0 + mi*16 + g + rr*8;
                    if (r < M) outS[(size_t)r*4 + head] = lsS[mi][rr];
                }
        }
    }
    if (NATT == 3) {
        float* sRed = reinterpret_cast<float*>(smb + (size_t)(2*64 + 2*128)*LDA);  // [64][16]
        #pragma unroll
        for (int mi = 0; mi < 2; mi++)
            #pragma unroll
            for (int rr = 0; rr < 2; rr++)
                #pragma unroll
                for (int h = 0; h < 4; h++) {
                    float v = lsA[mi][rr][h];
                    v += __shfl_xor_sync(0xffffffffu, v, 1);
                    v += __shfl_xor_sync(0xffffffffu, v, 2);
                    lsA[mi][rr][h] = v;
                }
        int cg = wid >> 1;
        if (t == 0) {
            #pragma unroll
            for (int mi = 0; mi < 2; mi++)
                #pragma unroll
                for (int rr = 0; rr < 2; rr++) {
                    int lr = row0 + mi*16 + g + rr*8;
                    #pragma unroll
                    for (int h = 0; h < 4; h++)
                        sRed[lr*16 + cg*4 + h] = lsA[mi][rr][h];
                }
        }
        __syncthreads();
        {
            int lr = tid >> 2, h = tid & 3;
            float s = sRed[lr*16 + h] + sRed[lr*16 + 4 + h]
                    + sRed[lr*16 + 8 + h] + sRed[lr*16 + 12 + h];
            int r = bm + lr;
            if (r < M) outS[(size_t)r*4 + h] = s;
        }
    }
}

// ------------- dual-slot HMMA GEMM: A resident; computes hs AND hd (fp16 out) ---------------
__global__ void __launch_bounds__(256, 2) tc_gemm_dual(
    const float* __restrict__ A,
    const __nv_bfloat16* __restrict__ Whi0, const __nv_bfloat16* __restrict__ Wlo0,
    const __nv_bfloat16* __restrict__ Whi1, const __nv_bfloat16* __restrict__ Wlo1,
    __half* __restrict__ C0, __half* __restrict__ C1, int M,
    const float* __restrict__ attS0, const float* __restrict__ attD0,
    const float* __restrict__ attS1, const float* __restrict__ attD1,
    float* __restrict__ outS0, float* __restrict__ outD0,
    float* __restrict__ outS1, float* __restrict__ outD1)
{
    constexpr int K = 128, LDA = K + 8;
    extern __shared__ __nv_bfloat16 smb[];
    __nv_bfloat16* sAhi = smb;
    __nv_bfloat16* sAlo = sAhi + 64*LDA;
    __nv_bfloat16* sWhi = sAlo + 64*LDA;
    __nv_bfloat16* sWlo = sWhi + 128*LDA;

    const int tid  = threadIdx.x;
    const int lane = tid & 31;
    const int wid  = tid >> 5;
    const int bm   = blockIdx.x * 64;

    for (int idx = tid; idx < 64*(K/4); idx += 256) {
        int r  = idx / (K/4);
        int k0 = (idx % (K/4)) * 4;
        int row = bm + r;
        float4 v = make_float4(0.f, 0.f, 0.f, 0.f);
        if (row < M) v = *reinterpret_cast<const float4*>(A + (size_t)row*K + k0);
        __nv_bfloat16 h0 = __float2bfloat16(v.x), h1 = __float2bfloat16(v.y);
        __nv_bfloat16 h2 = __float2bfloat16(v.z), h3 = __float2bfloat16(v.w);
        __nv_bfloat16 l0 = __float2bfloat16(v.x - __bfloat162float(h0));
        __nv_bfloat16 l1 = __float2bfloat16(v.y - __bfloat162float(h1));
        __nv_bfloat16 l2 = __float2bfloat16(v.z - __bfloat162float(h2));
        __nv_bfloat16 l3 = __float2bfloat16(v.w - __bfloat162float(h3));
        __nv_bfloat16* pH = sAhi + r*LDA + k0;
        __nv_bfloat16* pL = sAlo + r*LDA + k0;
        *reinterpret_cast<__nv_bfloat162*>(pH)     = __halves2bfloat162(h0, h1);
        *reinterpret_cast<__nv_bfloat162*>(pH + 2) = __halves2bfloat162(h2, h3);
        *reinterpret_cast<__nv_bfloat162*>(pL)     = __halves2bfloat162(l0, l1);
        *reinterpret_cast<__nv_bfloat162*>(pL + 2) = __halves2bfloat162(l2, l3);
    }

    const int row0 = (wid & 1) * 32;
    const int col0 = (wid >> 1) * 32;
    uint32_t aB[2][2], bB[2][2];
    {
        int ar = (lane & 15), ac = (lane >> 4) * 8;
        #pragma unroll
        for (int mi = 0; mi < 2; mi++) {
            aB[0][mi] = smem_u32(sAhi + (row0 + mi*16 + ar)*LDA + ac);
            aB[1][mi] = smem_u32(sAlo + (row0 + mi*16 + ar)*LDA + ac);
        }
        int q  = lane >> 3;
        int nr = (q >> 1)*8 + (lane & 7);
        int nc = (q & 1)*8;
        #pragma unroll
        for (int nt = 0; nt < 2; nt++) {
            bB[0][nt] = smem_u32(sWhi + (col0 + nt*16 + nr)*LDA + nc);
            bB[1][nt] = smem_u32(sWlo + (col0 + nt*16 + nr)*LDA + nc);
        }
    }
    const int g = lane >> 2, t = lane & 3;

    #pragma unroll
    for (int slot = 0; slot < 2; slot++) {
        const __nv_bfloat16* Whi = slot ? Whi1 : Whi0;
        const __nv_bfloat16* Wlo = slot ? Wlo1 : Wlo0;
        __half* C = slot ? C1 : C0;
        const float* attS = slot ? attS1 : attS0;
        const float* attD = slot ? attD1 : attD0;
        float* outS = slot ? outS1 : outS0;
        float* outD = slot ? outD1 : outD0;

        for (int idx = tid; idx < 128*(K/8); idx += 256) {
            int n  = idx / (K/8);
            int k0 = (idx % (K/8)) * 8;
            *reinterpret_cast<uint4*>(sWhi + n*LDA + k0) = *reinterpret_cast<const uint4*>(Whi + (size_t)n*K + k0);
            *reinterpret_cast<uint4*>(sWlo + n*LDA + k0) = *reinterpret_cast<const uint4*>(Wlo + (size_t)n*K + k0);
        }
        __syncthreads();

        float acc[2][4][4];
        #pragma unroll
        for (int mi = 0; mi < 2; mi++)
            #pragma unroll
            for (int ni = 0; ni < 4; ni++)
                { acc[mi][ni][0]=0.f; acc[mi][ni][1]=0.f; acc[mi][ni][2]=0.f; acc[mi][ni][3]=0.f; }

        #pragma unroll 2
        for (int ks = 0; ks < K/16; ks++) {
            uint32_t koff = (uint32_t)ks * 32u;
            uint32_t ah[2][4], al[2][4], bh[2][4], bl[2][4];
            #pragma unroll
            for (int mi = 0; mi < 2; mi++) { ldm_x4(ah[mi], aB[0][mi] + koff); ldm_x4(al[mi], aB[1][mi] + koff); }
            #pragma unroll
            for (int nt = 0; nt < 2; nt++) { ldm_x4(bh[nt], bB[0][nt] + koff); ldm_x4(bl[nt], bB[1][nt] + koff); }
            #pragma unroll
            for (int mi = 0; mi < 2; mi++)
                #pragma unroll
                for (int nt = 0; nt < 2; nt++) {
                    mma_bf16(acc[mi][nt*2],   ah[mi], &bh[nt][0]);
                    mma_bf16(acc[mi][nt*2+1], ah[mi], &bh[nt][2]);
                    mma_bf16(acc[mi][nt*2],   ah[mi], &bl[nt][0]);
                    mma_bf16(acc[mi][nt*2+1], ah[mi], &bl[nt][2]);
                    mma_bf16(acc[mi][nt*2],   al[mi], &bh[nt][0]);
                    mma_bf16(acc[mi][nt*2+1], al[mi], &bh[nt][2]);
                }
        }

        float lsS[2][2], lsD[2][2];
        lsS[0][0]=0.f; lsS[0][1]=0.f; lsS[1][0]=0.f; lsS[1][1]=0.f;
        lsD[0][0]=0.f; lsD[0][1]=0.f; lsD[1][0]=0.f; lsD[1][1]=0.f;

        #pragma unroll
        for (int mi = 0; mi < 2; mi++) {
            #pragma unroll
            for (int ni = 0; ni < 4; ni++) {
                int cc = col0 + ni*8 + t*2;
                int r1 = bm + row0 + mi*16 + g;
                float2 v0 = make_float2(acc[mi][ni][0], acc[mi][ni][1]);
                float2 v1 = make_float2(acc[mi][ni][2], acc[mi][ni][3]);
                float a0 = __ldg(attS + cc), a1 = __ldg(attS + cc + 1);
                float d0 = __ldg(attD + cc), d1 = __ldg(attD + cc + 1);
                lsS[mi][0] += v0.x*a0 + v0.y*a1;
                lsS[mi][1] += v1.x*a0 + v1.y*a1;
                lsD[mi][0] += v0.x*d0 + v0.y*d1;
                lsD[mi][1] += v1.x*d0 + v1.y*d1;
                if (r1 < M)     *reinterpret_cast<__half2*>(C + (size_t)r1*128 + cc)     = __floats2half2_rn(v0.x, v0.y);
                if (r1 + 8 < M) *reinterpret_cast<__half2*>(C + (size_t)(r1+8)*128 + cc) = __floats2half2_rn(v1.x, v1.y);
            }
        }
        #pragma unroll
        for (int mi = 0; mi < 2; mi++)
            #pragma unroll
            for (int rr = 0; rr < 2; rr++) {
                float v = lsS[mi][rr];
                v += __shfl_xor_sync(0xffffffffu, v, 1);
                v += __shfl_xor_sync(0xffffffffu, v, 2);
                lsS[mi][rr] = v;
                float w = lsD[mi][rr];
                w += __shfl_xor_sync(0xffffffffu, w, 1);
                w += __shfl_xor_sync(0xffffffffu, w, 2);
                lsD[mi][rr] = w;
            }
        if (t == 0) {
            int head = col0 >> 5;
            #pragma unroll
            for (int mi = 0; mi < 2; mi++)
                #pragma unroll
                for (int rr = 0; rr < 2; rr++) {
                    int r = bm + row0 + mi*16 + g + rr*8;
                    if (r < M) {
                        outS[(size_t)r*4 + head] = lsS[mi][rr];
                        outD[(size_t)r*4 + head] = lsD[mi][rr];
                    }
                }
        }
        __syncthreads();   // all warps done with W smem before next slot reload
    }
}

// ----- chained GEMM: hc = relu(x_c@W_pre_c + b) (K=32, smem-resident) -> hcs = hc@W_ct_s ----
__global__ void __launch_bounds__(256, 2) tc_gemm_chain(
    const float* __restrict__ xc,
    const __nv_bfloat16* __restrict__ W1hi, const __nv_bfloat16* __restrict__ W1lo,
    const float* __restrict__ b1,
    const __nv_bfloat16* __restrict__ W2hi, const __nv_bfloat16* __restrict__ W2lo,
    __half* __restrict__ C, int M,
    const float* __restrict__ attS, float* __restrict__ outS)
{
    constexpr int LDA = 136;
    extern __shared__ __nv_bfloat16 smb[];
    __nv_bfloat16* sAhi = smb;
    __nv_bfloat16* sAlo = sAhi + 64*LDA;
    __nv_bfloat16* sWhi = sAlo + 64*LDA;
    __nv_bfloat16* sWlo = sWhi + 128*LDA;

    const int tid  = threadIdx.x;
    const int lane = tid & 31;
    const int wid  = tid >> 5;
    const int bm   = blockIdx.x * 64;

    for (int idx = tid; idx < 64*8; idx += 256) {
        int r  = idx >> 3;
        int k0 = (idx & 7) * 4;
        int row = bm + r;
        float4 v = make_float4(0.f, 0.f, 0.f, 0.f);
        if (row < M) v = *reinterpret_cast<const float4*>(xc + (size_t)row*32 + k0);
        __nv_bfloat16 h0 = __float2bfloat16(v.x), h1 = __float2bfloat16(v.y);
        __nv_bfloat16 h2 = __float2bfloat16(v.z), h3 = __float2bfloat16(v.w);
        __nv_bfloat16 l0 = __float2bfloat16(v.x - __bfloat162float(h0));
        __nv_bfloat16 l1 = __float2bfloat16(v.y - __bfloat162float(h1));
        __nv_bfloat16 l2 = __float2bfloat16(v.z - __bfloat162float(h2));
        __nv_bfloat16 l3 = __float2bfloat16(v.w - __bfloat162float(h3));
        __nv_bfloat16* pH = sAhi + r*LDA + k0;
        __nv_bfloat16* pL = sAlo + r*LDA + k0;
        *reinterpret_cast<__nv_bfloat162*>(pH)     = __halves2bfloat162(h0, h1);
        *reinterpret_cast<__nv_bfloat162*>(pH + 2) = __halves2bfloat162(h2, h3);
        *reinterpret_cast<__nv_bfloat162*>(pL)     = __halves2bfloat162(l0, l1);
        *reinterpret_cast<__nv_bfloat162*>(pL + 2) = __halves2bfloat162(l2, l3);
    }
    for (int idx = tid; idx < 128*4; idx += 256) {
        int n  = idx >> 2;
        int k0 = (idx & 3) * 8;
        *reinterpret_cast<uint4*>(sWhi + n*LDA + k0) = *reinterpret_cast<const uint4*>(W1hi + (size_t)n*32 + k0);
        *reinterpret_cast<uint4*>(sWlo + n*LDA + k0) = *reinterpret_cast<const uint4*>(W1lo + (size_t)n*32 + k0);
    }
    __syncthreads();

    const int row0 = (wid & 1) * 32;
    const int col0 = (wid >> 1) * 32;
    uint32_t aB[2][2], bB[2][2];
    {
        int ar = (lane & 15), ac = (lane >> 4) * 8;
        #pragma unroll
        for (int mi = 0; mi < 2; mi++) {
            aB[0][mi] = smem_u32(sAhi + (row0 + mi*16 + ar)*LDA + ac);
            aB[1][mi] = smem_u32(sAlo + (row0 + mi*16 + ar)*LDA + ac);
        }
        int q  = lane >> 3;
        int nr = (q >> 1)*8 + (lane & 7);
        int nc = (q & 1)*8;
        #pragma unroll
        for (int nt = 0; nt < 2; nt++) {
            bB[0][nt] = smem_u32(sWhi + (col0 + nt*16 + nr)*LDA + nc);
            bB[1][nt] = smem_u32(sWlo + (col0 + nt*16 + nr)*LDA + nc);
        }
    }
    const int g = lane >> 2, t = lane & 3;

    float acc[2][4][4];
    #pragma unroll
    for (int mi = 0; mi < 2; mi++)
        #pragma unroll
        for (int ni = 0; ni < 4; ni++)
            { acc[mi][ni][0]=0.f; acc[mi][ni][1]=0.f; acc[mi][ni][2]=0.f; acc[mi][ni][3]=0.f; }

    #pragma unroll
    for (int ks = 0; ks < 2; ks++) {     // K=32
        uint32_t koff = (uint32_t)ks * 32u;
        uint32_t ah[2][4], al[2][4], bh[2][4], bl[2][4];
        #pragma unroll
        for (int mi = 0; mi < 2; mi++) { ldm_x4(ah[mi], aB[0][mi] + koff); ldm_x4(al[mi], aB[1][mi] + koff); }
        #pragma unroll
        for (int nt = 0; nt < 2; nt++) { ldm_x4(bh[nt], bB[0][nt] + koff); ldm_x4(bl[nt], bB[1][nt] + koff); }
        #pragma unroll
        for (int mi = 0; mi < 2; mi++)
            #pragma unroll
            for (int nt = 0; nt < 2; nt++) {
                mma_bf16(acc[mi][nt*2],   ah[mi], &bh[nt][0]);
                mma_bf16(acc[mi][nt*2+1], ah[mi], &bh[nt][2]);
                mma_bf16(acc[mi][nt*2],   ah[mi], &bl[nt][0]);
                mma_bf16(acc[mi][nt*2+1], ah[mi], &bl[nt][2]);
                mma_bf16(acc[mi][nt*2],   al[mi], &bh[nt][0]);
                mma_bf16(acc[mi][nt*2+1], al[mi], &bh[nt][2]);
            }
    }
    __syncthreads();

    // ---- epilogue 1: hc = relu(acc + b1) -> split directly into smem A tiles ----
    #pragma unroll
    for (int mi = 0; mi < 2; mi++) {
        #pragma unroll
        for (int ni = 0; ni < 4; ni++) {
            int cc = col0 + ni*8 + t*2;
            float bx = b1[cc], by = b1[cc+1];
            float2 v0 = make_float2(fmaxf(acc[mi][ni][0] + bx, 0.f), fmaxf(acc[mi][ni][1] + by, 0.f));
            float2 v1 = make_float2(fmaxf(acc[mi][ni][2] + bx, 0.f), fmaxf(acc[mi][ni][3] + by, 0.f));
            int rl0 = row0 + mi*16 + g;
            __nv_bfloat16 a0 = __float2bfloat16(v0.x), a1 = __float2bfloat16(v0.y);
            __nv_bfloat16 c0 = __float2bfloat16(v1.x), c1 = __float2bfloat16(v1.y);
            *reinterpret_cast<__nv_bfloat162*>(sAhi + rl0*LDA + cc)     = __halves2bfloat162(a0, a1);
            *reinterpret_cast<__nv_bfloat162*>(sAlo + rl0*LDA + cc)     =
                __halves2bfloat162(__float2bfloat16(v0.x - __bfloat162float(a0)),
                                   __float2bfloat16(v0.y - __bfloat162float(a1)));
            *reinterpret_cast<__nv_bfloat162*>(sAhi + (rl0+8)*LDA + cc) = __halves2bfloat162(c0, c1);
            *reinterpret_cast<__nv_bfloat162*>(sAlo + (rl0+8)*LDA + cc) =
                __halves2bfloat162(__float2bfloat16(v1.x - __bfloat162float(c0)),
                                   __float2bfloat16(v1.y - __bfloat162float(c1)));
        }
    }
    for (int idx = tid; idx < 128*16; idx += 256) {
        int n  = idx >> 4;
        int k0 = (idx & 15) * 8;
        *reinterpret_cast<uint4*>(sWhi + n*LDA + k0) = *reinterpret_cast<const uint4*>(W2hi + (size_t)n*128 + k0);
        *reinterpret_cast<uint4*>(sWlo + n*LDA + k0) = *reinterpret_cast<const uint4*>(W2lo + (size_t)n*128 + k0);
    }
    __syncthreads();

    #pragma unroll
    for (int mi = 0; mi < 2; mi++)
        #pragma unroll
        for (int ni = 0; ni < 4; ni++)
            { acc[mi][ni][0]=0.f; acc[mi][ni][1]=0.f; acc[mi][ni][2]=0.f; acc[mi][ni][3]=0.f; }

    #pragma unroll 2
    for (int ks = 0; ks < 8; ks++) {
        uint32_t koff = (uint32_t)ks * 32u;
        uint32_t ah[2][4], al[2][4], bh[2][4], bl[2][4];
        #pragma unroll
        for (int mi = 0; mi < 2; mi++) { ldm_x4(ah[mi], aB[0][mi] + koff); ldm_x4(al[mi], aB[1][mi] + koff); }
        #pragma unroll
        for (int nt = 0; nt < 2; nt++) { ldm_x4(bh[nt], bB[0][nt] + koff); ldm_x4(bl[nt], bB[1][nt] + koff); }
        #pragma unroll
        for (int mi = 0; mi < 2; mi++)
            #pragma unroll
            for (int nt = 0; nt < 2; nt++) {
                mma_bf16(acc[mi][nt*2],   ah[mi], &bh[nt][0]);
                mma_bf16(acc[mi][nt*2+1], ah[mi], &bh[nt][2]);
                mma_bf16(acc[mi][nt*2],   ah[mi], &bl[nt][0]);
                mma_bf16(acc[mi][nt*2+1], ah[mi], &bl[nt][2]);
                mma_bf16(acc[mi][nt*2],   al[mi], &bh[nt][0]);
                mma_bf16(acc[mi][nt*2+1], al[mi], &bh[nt][2]);
            }
    }

    // ---- epilogue 2: hcs (fp16) to gmem + fused logits (att_s_ct) ----
    float lsS[2][2];
    lsS[0][0]=0.f; lsS[0][1]=0.f; lsS[1][0]=0.f; lsS[1][1]=0.f;
    #pragma unroll
    for (int mi = 0; mi < 2; mi++) {
        #pragma unroll
        for (int ni = 0; ni < 4; ni++) {
            int cc = col0 + ni*8 + t*2;
            int r1 = bm + row0 + mi*16 + g;
            float2 v0 = make_float2(acc[mi][ni][0], acc[mi][ni][1]);
            float2 v1 = make_float2(acc[mi][ni][2], acc[mi][ni][3]);
            float a0 = __ldg(attS + cc), a1 = __ldg(attS + cc + 1);
            lsS[mi][0] += v0.x*a0 + v0.y*a1;
            lsS[mi][1] += v1.x*a0 + v1.y*a1;
            if (r1 < M)     *reinterpret_cast<__half2*>(C + (size_t)r1*128 + cc)     = __floats2half2_rn(v0.x, v0.y);
            if (r1 + 8 < M) *reinterpret_cast<__half2*>(C + (size_t)(r1+8)*128 + cc) = __floats2half2_rn(v1.x, v1.y);
        }
    }
    #pragma unroll
    for (int mi = 0; mi < 2; mi++)
        #pragma unroll
        for (int rr = 0; rr < 2; rr++) {
            float v = lsS[mi][rr];
            v += __shfl_xor_sync(0xffffffffu, v, 1);
            v += __shfl_xor_sync(0xffffffffu, v, 2);
            lsS[mi][rr] = v;
        }
    if (t == 0) {
        int head = col0 >> 5;
        #pragma unroll
        for (int mi = 0; mi < 2; mi++)
            #pragma unroll
            for (int rr = 0; rr < 2; rr++) {
                int r = bm + row0 + mi*16 + g + rr*8;
                if (r < M) outS[(size_t)r*4 + head] = lsS[mi][rr];
            }
    }
}

// --------------------------------- CSR build ------------------------------------------------
__global__ void hist_tt_kernel(const int* __restrict__ e0, const int* __restrict__ e1)
{
    for (int i = blockIdx.x*blockDim.x + threadIdx.x; i < ETTg; i += gridDim.x*blockDim.x) {
        atomicAdd(&g_deg[0*NTg + e1[i]], 1);
        atomicAdd(&g_deg[1*NTg + e0[i]], 1);
    }
}
__global__ void hist_ct_kernel(const int* __restrict__ ed)
{
    for (int i = blockIdx.x*blockDim.x + threadIdx.x; i < ECTg; i += gridDim.x*blockDim.x)
        atomicAdd(&g_deg[2*NTg + ed[i]], 1);
}

__global__ void scan1_kernel()
{
    int arr  = blockIdx.y;
    int base = blockIdx.x * 1024 + threadIdx.x;
    int lane = threadIdx.x & 31, wid = threadIdx.x >> 5;
    int v = (base < NTg) ? g_deg[arr*NTg + base] : 0;
    int x = v;
    #pragma unroll
    for (int o = 1; o < 32; o <<= 1) { int y = __shfl_up_sync(0xffffffffu, x, o); if (lane >= o) x += y; }
    __shared__ int ws[32];
    if (lane == 31) ws[wid] = x;
    __syncthreads();
    if (wid == 0) {
        int wv = ws[lane]; int wx = wv;
        #pragma unroll
        for (int o = 1; o < 32; o <<= 1) { int y = __shfl_up_sync(0xffffffffu, wx, o); if (lane >= o) wx += y; }
        if (lane == 31) g_aux[arr*128 + blockIdx.x] = wx;
        ws[lane] = wx - wv;
    }
    __syncthreads();
    int excl = x - v + ws[wid];
    if (base < NTg) g_cur[arr*NTg + base] = excl;
}

__global__ void scan2_kernel()
{
    int arr  = threadIdx.x >> 5;
    int lane = threadIdx.x & 31;
    if (arr >= 3) return;
    const int NB = (NTg + 1023) / 1024;
    int carry = 0;
    for (int c = 0; c*32 < NB; c++) {
        int idx = c*32 + lane;
        int v = (idx < NB) ? g_aux[arr*128 + idx] : 0;
        int x = v;
        #pragma unroll
        for (int o = 1; o < 32; o <<= 1) { int y = __shfl_up_sync(0xffffffffu, x, o); if (lane >= o) x += y; }
        if (idx < NB) g_aux[arr*128 + idx] = x - v + carry;
        carry += __shfl_sync(0xffffffffu, x, 31);
    }
}

__global__ void scan3_kernel()
{
    for (int i = blockIdx.x*blockDim.x + threadIdx.x; i < 3*NTg; i += gridDim.x*blockDim.x) {
        int arr = i / NTg; int idx = i - arr*NTg;
        g_cur[i] += g_aux[arr*128 + (idx >> 10)];
    }
}

__global__ void fill_tt_kernel(const int* __restrict__ e0, const int* __restrict__ e1)
{
    for (int i = blockIdx.x*blockDim.x + threadIdx.x; i < ETTg; i += gridDim.x*blockDim.x) {
        int s = e0[i], d = e1[i];
        int p = atomicAdd(&g_cur[0*NTg + d], 1); g_csrf[p] = s;
        int q = atomicAdd(&g_cur[1*NTg + s], 1); g_csrr[q] = d;
    }
}
__global__ void fill_ct_kernel(const int* __restrict__ es, const int* __restrict__ ed)
{
    for (int i = blockIdx.x*blockDim.x + threadIdx.x; i < ECTg; i += gridDim.x*blockDim.x) {
        int p = atomicAdd(&g_cur[2*NTg + ed[i]], 1); g_csrct[p] = es[i];
    }
}

// ----- per-relation GAT, half2 layout: lane owns cols {2l,2l+1} (head l>=16) and {64+2l,..} --
// r packs {ra.x, ra.y, rb.x, rb.y} in the half2 lane layout.
template<bool SELF>
__device__ __forceinline__ void gat_rel(
    const __half* __restrict__ hsrc, const float* __restrict__ a_s,
    const int* __restrict__ csr, int start, int cnt, int d, int lane,
    float4 ad, float wgt, float r[4])
{
    if (!SELF && cnt == 0) { r[0]=0.f; r[1]=0.f; r[2]=0.f; r[3]=0.f; return; }

    const bool hi16 = (lane >= 16);
    const float adA = hi16 ? ad.y : ad.x;
    const float adB = hi16 ? ad.w : ad.z;

    float denA = 0.f, denB = 0.f;
    float2 acA = make_float2(0.f, 0.f), acB = make_float2(0.f, 0.f);

    if (SELF) {
        float4 as = *reinterpret_cast<const float4*>(a_s + (size_t)d*4);
        float pa = __expf(lrelu02((hi16 ? as.y : as.x) + adA));
        float pb = __expf(lrelu02((hi16 ? as.w : as.z) + adB));
        denA = pa; denB = pb;
        const __half2* row2 = reinterpret_cast<const __half2*>(hsrc + (size_t)d*128);
        float2 fa = __half22float2(row2[lane]);
        float2 fb = __half22float2(row2[32 + lane]);
        acA.x = pa * fa.x; acA.y = pa * fa.y;
        acB.x = pb * fb.x; acB.y = pb * fb.y;
    }
    #pragma unroll 2
    for (int i = 0; i < cnt; i++) {
        int s = csr[start + i];
        float4 as = *reinterpret_cast<const float4*>(a_s + (size_t)s*4);
        float pa = __expf(lrelu02((hi16 ? as.y : as.x) + adA));
        float pb = __expf(lrelu02((hi16 ? as.w : as.z) + adB));
        denA += pa; denB += pb;
        const __half2* row2 = reinterpret_cast<const __half2*>(hsrc + (size_t)s*128);
        float2 fa = __half22float2(row2[lane]);
        float2 fb = __half22float2(row2[32 + lane]);
        acA.x = fmaf(pa, fa.x, acA.x); acA.y = fmaf(pa, fa.y, acA.y);
        acB.x = fmaf(pb, fb.x, acB.x); acB.y = fmaf(pb, fb.y, acB.y);
    }

    float ia = wgt / denA, ib = wgt / denB;
    r[0] = acA.x * ia; r[1] = acA.y * ia;
    r[2] = acB.x * ib; r[3] = acB.y * ib;
}

// --- merged GAT over all 3 relations; writes z = relu(acc + cbias + ht) (half2 lane map) ----
__global__ void gat_all_kernel(
    const __half* __restrict__ hs, const __half* __restrict__ hd, const __half* __restrict__ hcs,
    const float* __restrict__ ht,
    const float* __restrict__ asf, const float* __restrict__ adf,
    const float* __restrict__ asr, const float* __restrict__ adr,
    const float* __restrict__ asct, const float* __restrict__ adct,
    const int* __restrict__ cur, const int* __restrict__ deg,
    const int* __restrict__ csrf, const int* __restrict__ csrr, const int* __restrict__ csrct,
    const float* __restrict__ bsd, const float* __restrict__ bds, const float* __restrict__ bct,
    float* __restrict__ z)
{
    int d    = (blockIdx.x * blockDim.x + threadIdx.x) >> 5;
    int lane = threadIdx.x & 31;
    if (d >= NTg) return;

    float rf[4], rr_[4], rc[4];
    {
        int c = deg[0*NTg + d];
        gat_rel<true >(hs, asf, csrf, cur[0*NTg + d] - c, c, d, lane,
                       *reinterpret_cast<const float4*>(adf + (size_t)d*4), 0.25f, rf);
    }
    {
        int c = deg[1*NTg + d];
        gat_rel<true >(hd, asr, csrr, cur[1*NTg + d] - c, c, d, lane,
                       *reinterpret_cast<const float4*>(adr + (size_t)d*4), 0.25f, rr_);
    }
    {
        int c = deg[2*NTg + d];
        gat_rel<false>(hcs, asct, csrct, cur[2*NTg + d] - c, c, d, lane,
                       *reinterpret_cast<const float4*>(adct + (size_t)d*4), 0.5f, rc);
    }

    // lane owns columns cA = 2*lane, cA+1 and cB = 64 + 2*lane, cB+1
    int cA = 2*lane, cB = 64 + 2*lane;
    const float2* hrow2 = reinterpret_cast<const float2*>(ht + (size_t)d*128);
    float2 ha = hrow2[lane], hb = hrow2[32 + lane];
    float cbA0 = 0.25f*bsd[cA]   + 0.25f*bds[cA]   + 0.5f*bct[cA];
    float cbA1 = 0.25f*bsd[cA+1] + 0.25f*bds[cA+1] + 0.5f*bct[cA+1];
    float cbB0 = 0.25f*bsd[cB]   + 0.25f*bds[cB]   + 0.5f*bct[cB];
    float cbB1 = 0.25f*bsd[cB+1] + 0.25f*bds[cB+1] + 0.5f*bct[cB+1];

    float2* zrow2 = reinterpret_cast<float2*>(z + (size_t)d*128);
    float2 za, zb;
    za.x = fmaxf(rf[0] + rr_[0] + rc[0] + ha.x + cbA0, 0.f);
    za.y = fmaxf(rf[1] + rr_[1] + rc[1] + ha.y + cbA1, 0.f);
    zb.x = fmaxf(rf[2] + rr_[2] + rc[2] + hb.x + cbB0, 0.f);
    zb.y = fmaxf(rf[3] + rr_[3] + rc[3] + hb.y + cbB1, 0.f);
    zrow2[lane]      = za;
    zrow2[32 + lane] = zb;
}

// ----------------------------------- launch -------------------------------------------------
extern "C" void kernel_launch(void* const* d_in, const int* in_sizes, int n_in,
                              void* d_out, int out_size)
{
    const float* x_t     = (const float*)d_in[0];
    const float* x_c     = (const float*)d_in[1];
    const int*   ett     = (const int*)d_in[2];
    const int*   e0      = ett;
    const int*   e1      = ett + ETTg;
    const int*   ect_s   = (const int*)d_in[3];
    const int*   ect_d   = (const int*)d_in[4];
    const float* W_pre_t = (const float*)d_in[5];
    const float* b_pre_t = (const float*)d_in[6];
    const float* W_pre_c = (const float*)d_in[7];
    const float* b_pre_c = (const float*)d_in[8];
    const float* W_sd    = (const float*)d_in[9];
    const float* att_s_sd= (const float*)d_in[10];
    const float* att_d_sd= (const float*)d_in[11];
    const float* b_sd    = (const float*)d_in[12];
    const float* W_ds    = (const float*)d_in[13];
    const float* att_s_ds= (const float*)d_in[14];
    const float* att_d_ds= (const float*)d_in[15];
    const float* b_ds    = (const float*)d_in[16];
    const float* W_ct_s  = (const float*)d_in[17];
    const float* W_ct_d  = (const float*)d_in[18];
    const float* att_s_ct= (const float*)d_in[19];
    const float* att_d_ct= (const float*)d_in[20];
    const float* b_ct    = (const float*)d_in[21];
    const float* W_out   = (const float*)d_in[22];
    const float* b_out   = (const float*)d_in[23];
    float* out = (float*)d_out;

    float *p_ht, *p_z, *p_wv;
    __half *p_hs, *p_hd, *p_hcs;
    float *p_asf, *p_adf, *p_asr, *p_adr, *p_adct, *p_asct;
    int *p_deg, *p_cur, *p_csrf, *p_csrr, *p_csrct;
    __nv_bfloat16 *p_whi, *p_wlo;
    cudaGetSymbolAddress((void**)&p_ht,  g_ht);
    cudaGetSymbolAddress((void**)&p_hs,  g_hs);
    cudaGetSymbolAddress((void**)&p_hd,  g_hd);
    cudaGetSymbolAddress((void**)&p_hcs, g_hcs);
    cudaGetSymbolAddress((void**)&p_z,   g_z);
    cudaGetSymbolAddress((void**)&p_wv,  g_wv);
    cudaGetSymbolAddress((void**)&p_asf, g_asf);
    cudaGetSymbolAddress((void**)&p_adf, g_adf);
    cudaGetSymbolAddress((void**)&p_asr, g_asr);
    cudaGetSymbolAddress((void**)&p_adr, g_adr);
    cudaGetSymbolAddress((void**)&p_adct,g_adct);
    cudaGetSymbolAddress((void**)&p_asct,g_asct);
    cudaGetSymbolAddress((void**)&p_deg, g_deg);
    cudaGetSymbolAddress((void**)&p_cur, g_cur);
    cudaGetSymbolAddress((void**)&p_csrf, g_csrf);
    cudaGetSymbolAddress((void**)&p_csrr, g_csrr);
    cudaGetSymbolAddress((void**)&p_csrct,g_csrct);
    cudaGetSymbolAddress((void**)&p_whi, g_whi);
    cudaGetSymbolAddress((void**)&p_wlo, g_wlo);

    // smem: (2*64 + 2*128) rows * (K+8) cols * 2B   (+4KB reduce scratch for NATT==3)
    const int SM128 = (2*64 + 2*128) * (128 + 8) * 2;   // 104448
    const int SM64  = (2*64 + 2*128) * (64  + 8) * 2;   // 55296
    cudaFuncSetAttribute(tc_gemm_dual,               cudaFuncAttributeMaxDynamicSharedMemorySize, SM128);
    cudaFuncSetAttribute(tc_gemm_chain,              cudaFuncAttributeMaxDynamicSharedMemorySize, SM128);
    cudaFuncSetAttribute(tc_gemm<128,false,true, 0>, cudaFuncAttributeMaxDynamicSharedMemorySize, SM128);
    cudaFuncSetAttribute(tc_gemm<64, true, true, 3>, cudaFuncAttributeMaxDynamicSharedMemorySize, SM64 + 4096);

    const int GT = (NTg + 63) / 64;   // 1563
    const int GC = (NCg + 63) / 64;   // 391

    // slots: 0 pre_t K=64, 1 pre_c K=32, 2 sd, 3 ds, 4 ct_s, 5 out  (W_ct_d folded into wv)
    WJobs jobs;
    jobs.W[0] = W_pre_t; jobs.K[0] = 64;
    jobs.W[1] = W_pre_c; jobs.K[1] = 32;
    jobs.W[2] = W_sd;    jobs.K[2] = 128;
    jobs.W[3] = W_ds;    jobs.K[3] = 128;
    jobs.W[4] = W_ct_s;  jobs.K[4] = 128;
    jobs.W[5] = W_out;   jobs.K[5] = 128;

    wv_kernel<<<1, 512>>>(W_ct_d, att_d_ct, p_wv);                                  // k1
    wsplit_all<<<dim3(64, 6), 256>>>(jobs, p_whi, p_wlo);                           // k2
    // pre_t GEMM with fused a_dct = ht . wv^T  (NATT=3)
    tc_gemm<64,true,true,3><<<GT, 256, SM64 + 4096>>>(x_t, p_whi + 0*16384, p_wlo + 0*16384,
        b_pre_t, p_ht, NTg, p_wv, p_adct);                                          // k3
    tc_gemm_dual<<<GT, 256, SM128>>>(p_ht,
        p_whi + 2*16384, p_wlo + 2*16384, p_whi + 3*16384, p_wlo + 3*16384,
        p_hs, p_hd, NTg,
        att_s_sd, att_d_sd, att_s_ds, att_d_ds,
        p_asf, p_adf, p_asr, p_adr);                                                // k4 <- ncu
    // chained: hc (K=32, smem-resident) -> hcs = hc @ W_ct_s, fused asct logits
    tc_gemm_chain<<<GC, 256, SM128>>>(x_c,
        p_whi + 1*16384, p_wlo + 1*16384, b_pre_c,
        p_whi + 4*16384, p_wlo + 4*16384,
        p_hcs, NCg, att_s_ct, p_asct);                                              // k5

    // CSR build
    cudaMemsetAsync(p_deg, 0, 3*NTg*sizeof(int));
    hist_tt_kernel<<<512, 256>>>(e0, e1);
    hist_ct_kernel<<<256, 256>>>(ect_d);
    dim3 g1((NTg + 1023) / 1024, 3);
    scan1_kernel<<<g1, 1024>>>();
    scan2_kernel<<<1, 96>>>();
    scan3_kernel<<<256, 256>>>();
    fill_tt_kernel<<<512, 256>>>(e0, e1);
    fill_ct_kernel<<<256, 256>>>(ect_s, ect_d);

    // merged GAT (half2 layout, 2 wavefronts + 2 exps per edge)
    gat_all_kernel<<<(NTg + 7) / 8, 256>>>(
        p_hs, p_hd, p_hcs, p_ht,
        p_asf, p_adf, p_asr, p_adr, p_asct, p_adct,
        p_cur, p_deg, p_csrf, p_csrr, p_csrct,
        b_sd, b_ds, b_ct, p_z);

    // final: out = z @ W_out + b_out
    tc_gemm<128,false,true,0><<<GT, 256, SM128>>>(p_z, p_whi + 5*16384, p_wlo + 5*16384,
        b_out, out, NTg, nullptr, nullptr);
}

// round 13
// speedup vs baseline: 1.5006x; 1.0256x over previous
#include <cuda_runtime.h>
#include <cuda_bf16.h>
#include <cuda_fp16.h>
#include <cstdint>

#define NTg  100000
#define NCg  25000
#define ETTg 800000
#define ECTg 400000
#define HIDg 128

// ------------------------- scratch (device globals; allocation-free) -------------------------
__device__ float  g_ht [NTg*HIDg];
__device__ __half g_hs [NTg*HIDg];
__device__ __half g_hd [NTg*HIDg];
__device__ __half g_hcs[NCg*HIDg];
__device__ float  g_z  [NTg*HIDg];
__device__ float g_asf[NTg*4];
__device__ float g_adf[NTg*4];
__device__ float g_asr[NTg*4];
__device__ float g_adr[NTg*4];
__device__ float g_adct[NTg*4];
__device__ float g_asct[NCg*4];
__device__ float g_wv [4*128];
__device__ int   g_deg[3*NTg];
__device__ int   g_cur[3*NTg];
__device__ int   g_aux[3*128];
__device__ int   g_csrf[ETTg];
__device__ int   g_csrr[ETTg];
__device__ int   g_csrct[ECTg];
// split weights: 6 slots of up to 128x128 bf16 ([N,K] layout, i.e., W^T)
__device__ __nv_bfloat16 g_whi[6*128*128];
__device__ __nv_bfloat16 g_wlo[6*128*128];

__device__ __forceinline__ float lrelu02(float x) { return x > 0.f ? x : 0.2f * x; }

__device__ __forceinline__ uint32_t smem_u32(const void* p) {
    uint32_t a;
    asm("{ .reg .u64 t; cvta.to.shared.u64 t, %1; cvt.u32.u64 %0, t; }" : "=r"(a) : "l"(p));
    return a;
}

__device__ __forceinline__ void ldm_x4(uint32_t* r, uint32_t addr) {
    asm volatile("ldmatrix.sync.aligned.m8n8.x4.shared.b16 {%0,%1,%2,%3}, [%4];"
                 : "=r"(r[0]), "=r"(r[1]), "=r"(r[2]), "=r"(r[3]) : "r"(addr));
}
__device__ __forceinline__ void mma_bf16(float* c, const uint32_t* a, const uint32_t* b) {
    asm volatile("mma.sync.aligned.m16n8k16.row.col.f32.bf16.bf16.f32 "
                 "{%0,%1,%2,%3}, {%4,%5,%6,%7}, {%8,%9}, {%0,%1,%2,%3};"
                 : "+f"(c[0]), "+f"(c[1]), "+f"(c[2]), "+f"(c[3])
                 : "r"(a[0]), "r"(a[1]), "r"(a[2]), "r"(a[3]), "r"(b[0]), "r"(b[1]));
}

// ------------------- batched W split/transpose: hi/lo[n*K+k] = split(W[k*128+n]) ------------
struct WJobs { const float* W[6]; int K[6]; };

__global__ void wsplit_all(WJobs jobs, __nv_bfloat16* __restrict__ hiB,
                           __nv_bfloat16* __restrict__ loB)
{
    int slot = blockIdx.y;
    const float* W = jobs.W[slot];
    int K = jobs.K[slot];
    __nv_bfloat16* hi = hiB + slot*16384;
    __nv_bfloat16* lo = loB + slot*16384;
    int tot = 128 * K;
    for (int i = blockIdx.x*blockDim.x + threadIdx.x; i < tot; i += gridDim.x*blockDim.x) {
        int n = i / K, k = i - n*K;
        float v = W[k*128 + n];
        __nv_bfloat16 h = __float2bfloat16(v);
        hi[i] = h;
        lo[i] = __float2bfloat16(v - __bfloat162float(h));
    }
}

// ----------------- wv[h*128+k] = sum_c W_ct_dst[k*128 + h*32 + c] * att[h*32+c] -------------
__global__ void wv_kernel(const float* __restrict__ W, const float* __restrict__ att,
                          float* __restrict__ wv)
{
    int i = threadIdx.x;           // 512 threads: k = i>>2, h = i&3
    int k = i >> 2, h = i & 3;
    float s = 0.f;
    #pragma unroll 8
    for (int c = 0; c < 32; c++) s += W[k*128 + h*32 + c] * att[h*32 + c];
    wv[h*128 + k] = s;
}

// ---------------- HMMA GEMM: C[M,128] = A[M,K] @ W[K,128]  (3-split bf16) -------------------
// CTA tile 64x128 (2 CTAs/SM), 8 warps, warp tile 32x32. W^T ([N,K]) pre-split in gmem.
template<int K, bool RELU, bool BIAS>
__global__ void __launch_bounds__(256, 2) tc_gemm(
    const float* __restrict__ A, const __nv_bfloat16* __restrict__ Whi,
    const __nv_bfloat16* __restrict__ Wlo, const float* __restrict__ bias,
    float* __restrict__ C, int M)
{
    constexpr int LDA = K + 8;
    extern __shared__ __nv_bfloat16 smb[];
    __nv_bfloat16* sAhi = smb;
    __nv_bfloat16* sAlo = sAhi + 64*LDA;
    __nv_bfloat16* sWhi = sAlo + 64*LDA;
    __nv_bfloat16* sWlo = sWhi + 128*LDA;

    const int tid  = threadIdx.x;
    const int lane = tid & 31;
    const int wid  = tid >> 5;
    const int bm   = blockIdx.x * 64;

    for (int idx = tid; idx < 64*(K/4); idx += 256) {
        int r  = idx / (K/4);
        int k0 = (idx % (K/4)) * 4;
        int row = bm + r;
        float4 v = make_float4(0.f, 0.f, 0.f, 0.f);
        if (row < M) v = *reinterpret_cast<const float4*>(A + (size_t)row*K + k0);
        __nv_bfloat16 h0 = __float2bfloat16(v.x), h1 = __float2bfloat16(v.y);
        __nv_bfloat16 h2 = __float2bfloat16(v.z), h3 = __float2bfloat16(v.w);
        __nv_bfloat16 l0 = __float2bfloat16(v.x - __bfloat162float(h0));
        __nv_bfloat16 l1 = __float2bfloat16(v.y - __bfloat162float(h1));
        __nv_bfloat16 l2 = __float2bfloat16(v.z - __bfloat162float(h2));
        __nv_bfloat16 l3 = __float2bfloat16(v.w - __bfloat162float(h3));
        __nv_bfloat16* pH = sAhi + r*LDA + k0;
        __nv_bfloat16* pL = sAlo + r*LDA + k0;
        *reinterpret_cast<__nv_bfloat162*>(pH)     = __halves2bfloat162(h0, h1);
        *reinterpret_cast<__nv_bfloat162*>(pH + 2) = __halves2bfloat162(h2, h3);
        *reinterpret_cast<__nv_bfloat162*>(pL)     = __halves2bfloat162(l0, l1);
        *reinterpret_cast<__nv_bfloat162*>(pL + 2) = __halves2bfloat162(l2, l3);
    }
    for (int idx = tid; idx < 128*(K/8); idx += 256) {
        int n  = idx / (K/8);
        int k0 = (idx % (K/8)) * 8;
        *reinterpret_cast<uint4*>(sWhi + n*LDA + k0) = *reinterpret_cast<const uint4*>(Whi + (size_t)n*K + k0);
        *reinterpret_cast<uint4*>(sWlo + n*LDA + k0) = *reinterpret_cast<const uint4*>(Wlo + (size_t)n*K + k0);
    }
    __syncthreads();

    const int row0 = (wid & 1) * 32;
    const int col0 = (wid >> 1) * 32;

    uint32_t aB[2][2], bB[2][2];
    {
        int ar = (lane & 15), ac = (lane >> 4) * 8;
        #pragma unroll
        for (int mi = 0; mi < 2; mi++) {
            aB[0][mi] = smem_u32(sAhi + (row0 + mi*16 + ar)*LDA + ac);
            aB[1][mi] = smem_u32(sAlo + (row0 + mi*16 + ar)*LDA + ac);
        }
        int q  = lane >> 3;
        int nr = (q >> 1)*8 + (lane & 7);
        int nc = (q & 1)*8;
        #pragma unroll
        for (int nt = 0; nt < 2; nt++) {
            bB[0][nt] = smem_u32(sWhi + (col0 + nt*16 + nr)*LDA + nc);
            bB[1][nt] = smem_u32(sWlo + (col0 + nt*16 + nr)*LDA + nc);
        }
    }

    float acc[2][4][4];
    #pragma unroll
    for (int mi = 0; mi < 2; mi++)
        #pragma unroll
        for (int ni = 0; ni < 4; ni++)
            { acc[mi][ni][0]=0.f; acc[mi][ni][1]=0.f; acc[mi][ni][2]=0.f; acc[mi][ni][3]=0.f; }

    #pragma unroll 2
    for (int ks = 0; ks < K/16; ks++) {
        uint32_t koff = (uint32_t)ks * 32u;
        uint32_t ah[2][4], al[2][4], bh[2][4], bl[2][4];
        #pragma unroll
        for (int mi = 0; mi < 2; mi++) { ldm_x4(ah[mi], aB[0][mi] + koff); ldm_x4(al[mi], aB[1][mi] + koff); }
        #pragma unroll
        for (int nt = 0; nt < 2; nt++) { ldm_x4(bh[nt], bB[0][nt] + koff); ldm_x4(bl[nt], bB[1][nt] + koff); }
        #pragma unroll
        for (int mi = 0; mi < 2; mi++)
            #pragma unroll
            for (int nt = 0; nt < 2; nt++) {
                mma_bf16(acc[mi][nt*2],   ah[mi], &bh[nt][0]);
                mma_bf16(acc[mi][nt*2+1], ah[mi], &bh[nt][2]);
                mma_bf16(acc[mi][nt*2],   ah[mi], &bl[nt][0]);
                mma_bf16(acc[mi][nt*2+1], ah[mi], &bl[nt][2]);
                mma_bf16(acc[mi][nt*2],   al[mi], &bh[nt][0]);
                mma_bf16(acc[mi][nt*2+1], al[mi], &bh[nt][2]);
            }
    }

    const int g = lane >> 2, t = lane & 3;
    #pragma unroll
    for (int mi = 0; mi < 2; mi++) {
        #pragma unroll
        for (int ni = 0; ni < 4; ni++) {
            int cc = col0 + ni*8 + t*2;
            float bx = 0.f, by = 0.f;
            if (BIAS) { bx = bias[cc]; by = bias[cc+1]; }
            int r1 = bm + row0 + mi*16 + g;
            float2 v0 = make_float2(acc[mi][ni][0] + bx, acc[mi][ni][1] + by);
            float2 v1 = make_float2(acc[mi][ni][2] + bx, acc[mi][ni][3] + by);
            if (RELU) {
                v0.x = fmaxf(v0.x, 0.f); v0.y = fmaxf(v0.y, 0.f);
                v1.x = fmaxf(v1.x, 0.f); v1.y = fmaxf(v1.y, 0.f);
            }
            if (r1 < M)     *reinterpret_cast<float2*>(C + (size_t)r1*128 + cc)     = v0;
            if (r1 + 8 < M) *reinterpret_cast<float2*>(C + (size_t)(r1+8)*128 + cc) = v1;
        }
    }
}

// -------- TRIPLE: ht = relu(x_t@W0 + b0) (K=64) -> [resident] -> hs, hd + all logits --------
// Also writes ht to gmem (GAT skip path) and fused a_dct = ht . wv^T (cross-warp reduce).
__global__ void __launch_bounds__(256, 2) tc_gemm_triple(
    const float* __restrict__ xt,
    const __nv_bfloat16* __restrict__ W0hi, const __nv_bfloat16* __restrict__ W0lo,
    const float* __restrict__ b0, const float* __restrict__ wv,
    float* __restrict__ htO, float* __restrict__ adct,
    const __nv_bfloat16* __restrict__ Whi0, const __nv_bfloat16* __restrict__ Wlo0,
    const __nv_bfloat16* __restrict__ Whi1, const __nv_bfloat16* __restrict__ Wlo1,
    __half* __restrict__ C0, __half* __restrict__ C1, int M,
    const float* __restrict__ attS0, const float* __restrict__ attD0,
    const float* __restrict__ attS1, const float* __restrict__ attD1,
    float* __restrict__ outS0, float* __restrict__ outD0,
    float* __restrict__ outS1, float* __restrict__ outD1)
{
    constexpr int LDA = 136;
    extern __shared__ __nv_bfloat16 smb[];
    __nv_bfloat16* sAhi = smb;
    __nv_bfloat16* sAlo = sAhi + 64*LDA;
    __nv_bfloat16* sWhi = sAlo + 64*LDA;
    __nv_bfloat16* sWlo = sWhi + 128*LDA;
    float* sRed = reinterpret_cast<float*>(smb + (size_t)(2*64 + 2*128)*LDA);  // [64][16]

    const int tid  = threadIdx.x;
    const int lane = tid & 31;
    const int wid  = tid >> 5;
    const int bm   = blockIdx.x * 64;

    // ---- phase 1 loads: x_t tile [64,64] split; W0 (K=64) [128,64] ----
    for (int idx = tid; idx < 64*16; idx += 256) {
        int r  = idx >> 4;
        int k0 = (idx & 15) * 4;
        int row = bm + r;
        float4 v = make_float4(0.f, 0.f, 0.f, 0.f);
        if (row < M) v = *reinterpret_cast<const float4*>(xt + (size_t)row*64 + k0);
        __nv_bfloat16 h0 = __float2bfloat16(v.x), h1 = __float2bfloat16(v.y);
        __nv_bfloat16 h2 = __float2bfloat16(v.z), h3 = __float2bfloat16(v.w);
        __nv_bfloat16 l0 = __float2bfloat16(v.x - __bfloat162float(h0));
        __nv_bfloat16 l1 = __float2bfloat16(v.y - __bfloat162float(h1));
        __nv_bfloat16 l2 = __float2bfloat16(v.z - __bfloat162float(h2));
        __nv_bfloat16 l3 = __float2bfloat16(v.w - __bfloat162float(h3));
        __nv_bfloat16* pH = sAhi + r*LDA + k0;
        __nv_bfloat16* pL = sAlo + r*LDA + k0;
        *reinterpret_cast<__nv_bfloat162*>(pH)     = __halves2bfloat162(h0, h1);
        *reinterpret_cast<__nv_bfloat162*>(pH + 2) = __halves2bfloat162(h2, h3);
        *reinterpret_cast<__nv_bfloat162*>(pL)     = __halves2bfloat162(l0, l1);
        *reinterpret_cast<__nv_bfloat162*>(pL + 2) = __halves2bfloat162(l2, l3);
    }
    for (int idx = tid; idx < 128*8; idx += 256) {
        int n  = idx >> 3;
        int k0 = (idx & 7) * 8;
        *reinterpret_cast<uint4*>(sWhi + n*LDA + k0) = *reinterpret_cast<const uint4*>(W0hi + (size_t)n*64 + k0);
        *reinterpret_cast<uint4*>(sWlo + n*LDA + k0) = *reinterpret_cast<const uint4*>(W0lo + (size_t)n*64 + k0);
    }
    __syncthreads();

    const int row0 = (wid & 1) * 32;
    const int col0 = (wid >> 1) * 32;
    uint32_t aB[2][2], bB[2][2];
    {
        int ar = (lane & 15), ac = (lane >> 4) * 8;
        #pragma unroll
        for (int mi = 0; mi < 2; mi++) {
            aB[0][mi] = smem_u32(sAhi + (row0 + mi*16 + ar)*LDA + ac);
            aB[1][mi] = smem_u32(sAlo + (row0 + mi*16 + ar)*LDA + ac);
        }
        int q  = lane >> 3;
        int nr = (q >> 1)*8 + (lane & 7);
        int nc = (q & 1)*8;
        #pragma unroll
        for (int nt = 0; nt < 2; nt++) {
            bB[0][nt] = smem_u32(sWhi + (col0 + nt*16 + nr)*LDA + nc);
            bB[1][nt] = smem_u32(sWlo + (col0 + nt*16 + nr)*LDA + nc);
        }
    }
    const int g = lane >> 2, t = lane & 3;

    float acc[2][4][4];
    #pragma unroll
    for (int mi = 0; mi < 2; mi++)
        #pragma unroll
        for (int ni = 0; ni < 4; ni++)
            { acc[mi][ni][0]=0.f; acc[mi][ni][1]=0.f; acc[mi][ni][2]=0.f; acc[mi][ni][3]=0.f; }

    #pragma unroll
    for (int ks = 0; ks < 4; ks++) {     // K=64
        uint32_t koff = (uint32_t)ks * 32u;
        uint32_t ah[2][4], al[2][4], bh[2][4], bl[2][4];
        #pragma unroll
        for (int mi = 0; mi < 2; mi++) { ldm_x4(ah[mi], aB[0][mi] + koff); ldm_x4(al[mi], aB[1][mi] + koff); }
        #pragma unroll
        for (int nt = 0; nt < 2; nt++) { ldm_x4(bh[nt], bB[0][nt] + koff); ldm_x4(bl[nt], bB[1][nt] + koff); }
        #pragma unroll
        for (int mi = 0; mi < 2; mi++)
            #pragma unroll
            for (int nt = 0; nt < 2; nt++) {
                mma_bf16(acc[mi][nt*2],   ah[mi], &bh[nt][0]);
                mma_bf16(acc[mi][nt*2+1], ah[mi], &bh[nt][2]);
                mma_bf16(acc[mi][nt*2],   ah[mi], &bl[nt][0]);
                mma_bf16(acc[mi][nt*2+1], ah[mi], &bl[nt][2]);
                mma_bf16(acc[mi][nt*2],   al[mi], &bh[nt][0]);
                mma_bf16(acc[mi][nt*2+1], al[mi], &bh[nt][2]);
            }
    }

    // ---- epilogue 1: ht = relu(acc + b0); write gmem; lsA dots; split into A tiles ----
    float lsA[2][2][4];
    #pragma unroll
    for (int a = 0; a < 2; a++)
        #pragma unroll
        for (int b = 0; b < 2; b++)
            #pragma unroll
            for (int h = 0; h < 4; h++) lsA[a][b][h] = 0.f;

    #pragma unroll
    for (int mi = 0; mi < 2; mi++) {
        #pragma unroll
        for (int ni = 0; ni < 4; ni++) {
            int cc = col0 + ni*8 + t*2;
            float bx = b0[cc], by = b0[cc+1];
            float2 v0 = make_float2(fmaxf(acc[mi][ni][0] + bx, 0.f), fmaxf(acc[mi][ni][1] + by, 0.f));
            float2 v1 = make_float2(fmaxf(acc[mi][ni][2] + bx, 0.f), fmaxf(acc[mi][ni][3] + by, 0.f));
            acc[mi][ni][0] = v0.x; acc[mi][ni][1] = v0.y;
            acc[mi][ni][2] = v1.x; acc[mi][ni][3] = v1.y;
            int r1 = bm + row0 + mi*16 + g;
            if (r1 < M)     *reinterpret_cast<float2*>(htO + (size_t)r1*128 + cc)     = v0;
            if (r1 + 8 < M) *reinterpret_cast<float2*>(htO + (size_t)(r1+8)*128 + cc) = v1;
            #pragma unroll
            for (int h = 0; h < 4; h++) {
                float w0 = __ldg(wv + h*128 + cc), w1 = __ldg(wv + h*128 + cc + 1);
                lsA[mi][0][h] += v0.x*w0 + v0.y*w1;
                lsA[mi][1][h] += v1.x*w0 + v1.y*w1;
            }
        }
    }
    #pragma unroll
    for (int mi = 0; mi < 2; mi++)
        #pragma unroll
        for (int rr = 0; rr < 2; rr++)
            #pragma unroll
            for (int h = 0; h < 4; h++) {
                float v = lsA[mi][rr][h];
                v += __shfl_xor_sync(0xffffffffu, v, 1);
                v += __shfl_xor_sync(0xffffffffu, v, 2);
                lsA[mi][rr][h] = v;
            }

    __syncthreads();   // phase-1 ldmatrix complete; safe to overwrite A/W tiles

    // split ht tile into A operands
    #pragma unroll
    for (int mi = 0; mi < 2; mi++) {
        #pragma unroll
        for (int ni = 0; ni < 4; ni++) {
            int cc = col0 + ni*8 + t*2;
            int rl0 = row0 + mi*16 + g;
            float2 v0 = make_float2(acc[mi][ni][0], acc[mi][ni][1]);
            float2 v1 = make_float2(acc[mi][ni][2], acc[mi][ni][3]);
            __nv_bfloat16 a0 = __float2bfloat16(v0.x), a1 = __float2bfloat16(v0.y);
            __nv_bfloat16 c0 = __float2bfloat16(v1.x), c1 = __float2bfloat16(v1.y);
            *reinterpret_cast<__nv_bfloat162*>(sAhi + rl0*LDA + cc)     = __halves2bfloat162(a0, a1);
            *reinterpret_cast<__nv_bfloat162*>(sAlo + rl0*LDA + cc)     =
                __halves2bfloat162(__float2bfloat16(v0.x - __bfloat162float(a0)),
                                   __float2bfloat16(v0.y - __bfloat162float(a1)));
            *reinterpret_cast<__nv_bfloat162*>(sAhi + (rl0+8)*LDA + cc) = __halves2bfloat162(c0, c1);
            *reinterpret_cast<__nv_bfloat162*>(sAlo + (rl0+8)*LDA + cc) =
                __halves2bfloat162(__float2bfloat16(v1.x - __bfloat162float(c0)),
                                   __float2bfloat16(v1.y - __bfloat162float(c1)));
        }
    }
    {
        int cg = wid >> 1;
        if (t == 0) {
            #pragma unroll
            for (int mi = 0; mi < 2; mi++)
                #pragma unroll
                for (int rr = 0; rr < 2; rr++) {
                    int lr = row0 + mi*16 + g + rr*8;
                    #pragma unroll
                    for (int h = 0; h < 4; h++)
                        sRed[lr*16 + cg*4 + h] = lsA[mi][rr][h];
                }
        }
    }
    __syncthreads();
    {
        int lr = tid >> 2, h = tid & 3;
        float s = sRed[lr*16 + h] + sRed[lr*16 + 4 + h]
                + sRed[lr*16 + 8 + h] + sRed[lr*16 + 12 + h];
        int r = bm + lr;
        if (r < M) adct[(size_t)r*4 + h] = s;
    }

    // ---- slot loop: sd / ds (A resident) ----
    #pragma unroll
    for (int slot = 0; slot < 2; slot++) {
        const __nv_bfloat16* Whi = slot ? Whi1 : Whi0;
        const __nv_bfloat16* Wlo = slot ? Wlo1 : Wlo0;
        __half* C = slot ? C1 : C0;
        const float* attS = slot ? attS1 : attS0;
        const float* attD = slot ? attD1 : attD0;
        float* outS = slot ? outS1 : outS0;
        float* outD = slot ? outD1 : outD0;

        for (int idx = tid; idx < 128*16; idx += 256) {
            int n  = idx >> 4;
            int k0 = (idx & 15) * 8;
            *reinterpret_cast<uint4*>(sWhi + n*LDA + k0) = *reinterpret_cast<const uint4*>(Whi + (size_t)n*128 + k0);
            *reinterpret_cast<uint4*>(sWlo + n*LDA + k0) = *reinterpret_cast<const uint4*>(Wlo + (size_t)n*128 + k0);
        }
        __syncthreads();

        #pragma unroll
        for (int mi = 0; mi < 2; mi++)
            #pragma unroll
            for (int ni = 0; ni < 4; ni++)
                { acc[mi][ni][0]=0.f; acc[mi][ni][1]=0.f; acc[mi][ni][2]=0.f; acc[mi][ni][3]=0.f; }

        #pragma unroll 2
        for (int ks = 0; ks < 8; ks++) {
            uint32_t koff = (uint32_t)ks * 32u;
            uint32_t ah[2][4], al[2][4], bh[2][4], bl[2][4];
            #pragma unroll
            for (int mi = 0; mi < 2; mi++) { ldm_x4(ah[mi], aB[0][mi] + koff); ldm_x4(al[mi], aB[1][mi] + koff); }
            #pragma unroll
            for (int nt = 0; nt < 2; nt++) { ldm_x4(bh[nt], bB[0][nt] + koff); ldm_x4(bl[nt], bB[1][nt] + koff); }
            #pragma unroll
            for (int mi = 0; mi < 2; mi++)
                #pragma unroll
                for (int nt = 0; nt < 2; nt++) {
                    mma_bf16(acc[mi][nt*2],   ah[mi], &bh[nt][0]);
                    mma_bf16(acc[mi][nt*2+1], ah[mi], &bh[nt][2]);
                    mma_bf16(acc[mi][nt*2],   ah[mi], &bl[nt][0]);
                    mma_bf16(acc[mi][nt*2+1], ah[mi], &bl[nt][2]);
                    mma_bf16(acc[mi][nt*2],   al[mi], &bh[nt][0]);
                    mma_bf16(acc[mi][nt*2+1], al[mi], &bh[nt][2]);
                }
        }

        float lsS[2][2], lsD[2][2];
        lsS[0][0]=0.f; lsS[0][1]=0.f; lsS[1][0]=0.f; lsS[1][1]=0.f;
        lsD[0][0]=0.f; lsD[0][1]=0.f; lsD[1][0]=0.f; lsD[1][1]=0.f;

        #pragma unroll
        for (int mi = 0; mi < 2; mi++) {
            #pragma unroll
            for (int ni = 0; ni < 4; ni++) {
                int cc = col0 + ni*8 + t*2;
                int r1 = bm + row0 + mi*16 + g;
                float2 v0 = make_float2(acc[mi][ni][0], acc[mi][ni][1]);
                float2 v1 = make_float2(acc[mi][ni][2], acc[mi][ni][3]);
                float a0 = __ldg(attS + cc), a1 = __ldg(attS + cc + 1);
                float d0 = __ldg(attD + cc), d1 = __ldg(attD + cc + 1);
                lsS[mi][0] += v0.x*a0 + v0.y*a1;
                lsS[mi][1] += v1.x*a0 + v1.y*a1;
                lsD[mi][0] += v0.x*d0 + v0.y*d1;
                lsD[mi][1] += v1.x*d0 + v1.y*d1;
                if (r1 < M)     *reinterpret_cast<__half2*>(C + (size_t)r1*128 + cc)     = __floats2half2_rn(v0.x, v0.y);
                if (r1 + 8 < M) *reinterpret_cast<__half2*>(C + (size_t)(r1+8)*128 + cc) = __floats2half2_rn(v1.x, v1.y);
            }
        }
        #pragma unroll
        for (int mi = 0; mi < 2; mi++)
            #pragma unroll
            for (int rr = 0; rr < 2; rr++) {
                float v = lsS[mi][rr];
                v += __shfl_xor_sync(0xffffffffu, v, 1);
                v += __shfl_xor_sync(0xffffffffu, v, 2);
                lsS[mi][rr] = v;
                float w = lsD[mi][rr];
                w += __shfl_xor_sync(0xffffffffu, w, 1);
                w += __shfl_xor_sync(0xffffffffu, w, 2);
                lsD[mi][rr] = w;
            }
        if (t == 0) {
            int head = col0 >> 5;
            #pragma unroll
            for (int mi = 0; mi < 2; mi++)
                #pragma unroll
                for (int rr = 0; rr < 2; rr++) {
                    int r = bm + row0 + mi*16 + g + rr*8;
                    if (r < M) {
                        outS[(size_t)r*4 + head] = lsS[mi][rr];
                        outD[(size_t)r*4 + head] = lsD[mi][rr];
                    }
                }
        }
        __syncthreads();   // all warps done with W smem before next slot reload
    }
}

// ----- chained GEMM: hc = relu(x_c@W_pre_c + b) (K=32, smem-resident) -> hcs = hc@W_ct_s ----
__global__ void __launch_bounds__(256, 2) tc_gemm_chain(
    const float* __restrict__ xc,
    const __nv_bfloat16* __restrict__ W1hi, const __nv_bfloat16* __restrict__ W1lo,
    const float* __restrict__ b1,
    const __nv_bfloat16* __restrict__ W2hi, const __nv_bfloat16* __restrict__ W2lo,
    __half* __restrict__ C, int M,
    const float* __restrict__ attS, float* __restrict__ outS)
{
    constexpr int LDA = 136;
    extern __shared__ __nv_bfloat16 smb[];
    __nv_bfloat16* sAhi = smb;
    __nv_bfloat16* sAlo = sAhi + 64*LDA;
    __nv_bfloat16* sWhi = sAlo + 64*LDA;
    __nv_bfloat16* sWlo = sWhi + 128*LDA;

    const int tid  = threadIdx.x;
    const int lane = tid & 31;
    const int wid  = tid >> 5;
    const int bm   = blockIdx.x * 64;

    for (int idx = tid; idx < 64*8; idx += 256) {
        int r  = idx >> 3;
        int k0 = (idx & 7) * 4;
        int row = bm + r;
        float4 v = make_float4(0.f, 0.f, 0.f, 0.f);
        if (row < M) v = *reinterpret_cast<const float4*>(xc + (size_t)row*32 + k0);
        __nv_bfloat16 h0 = __float2bfloat16(v.x), h1 = __float2bfloat16(v.y);
        __nv_bfloat16 h2 = __float2bfloat16(v.z), h3 = __float2bfloat16(v.w);
        __nv_bfloat16 l0 = __float2bfloat16(v.x - __bfloat162float(h0));
        __nv_bfloat16 l1 = __float2bfloat16(v.y - __bfloat162float(h1));
        __nv_bfloat16 l2 = __float2bfloat16(v.z - __bfloat162float(h2));
        __nv_bfloat16 l3 = __float2bfloat16(v.w - __bfloat162float(h3));
        __nv_bfloat16* pH = sAhi + r*LDA + k0;
        __nv_bfloat16* pL = sAlo + r*LDA + k0;
        *reinterpret_cast<__nv_bfloat162*>(pH)     = __halves2bfloat162(h0, h1);
        *reinterpret_cast<__nv_bfloat162*>(pH + 2) = __halves2bfloat162(h2, h3);
        *reinterpret_cast<__nv_bfloat162*>(pL)     = __halves2bfloat162(l0, l1);
        *reinterpret_cast<__nv_bfloat162*>(pL + 2) = __halves2bfloat162(l2, l3);
    }
    for (int idx = tid; idx < 128*4; idx += 256) {
        int n  = idx >> 2;
        int k0 = (idx & 3) * 8;
        *reinterpret_cast<uint4*>(sWhi + n*LDA + k0) = *reinterpret_cast<const uint4*>(W1hi + (size_t)n*32 + k0);
        *reinterpret_cast<uint4*>(sWlo + n*LDA + k0) = *reinterpret_cast<const uint4*>(W1lo + (size_t)n*32 + k0);
    }
    __syncthreads();

    const int row0 = (wid & 1) * 32;
    const int col0 = (wid >> 1) * 32;
    uint32_t aB[2][2], bB[2][2];
    {
        int ar = (lane & 15), ac = (lane >> 4) * 8;
        #pragma unroll
        for (int mi = 0; mi < 2; mi++) {
            aB[0][mi] = smem_u32(sAhi + (row0 + mi*16 + ar)*LDA + ac);
            aB[1][mi] = smem_u32(sAlo + (row0 + mi*16 + ar)*LDA + ac);
        }
        int q  = lane >> 3;
        int nr = (q >> 1)*8 + (lane & 7);
        int nc = (q & 1)*8;
        #pragma unroll
        for (int nt = 0; nt < 2; nt++) {
            bB[0][nt] = smem_u32(sWhi + (col0 + nt*16 + nr)*LDA + nc);
            bB[1][nt] = smem_u32(sWlo + (col0 + nt*16 + nr)*LDA + nc);
        }
    }
    const int g = lane >> 2, t = lane & 3;

    float acc[2][4][4];
    #pragma unroll
    for (int mi = 0; mi < 2; mi++)
        #pragma unroll
        for (int ni = 0; ni < 4; ni++)
            { acc[mi][ni][0]=0.f; acc[mi][ni][1]=0.f; acc[mi][ni][2]=0.f; acc[mi][ni][3]=0.f; }

    #pragma unroll
    for (int ks = 0; ks < 2; ks++) {     // K=32
        uint32_t koff = (uint32_t)ks * 32u;
        uint32_t ah[2][4], al[2][4], bh[2][4], bl[2][4];
        #pragma unroll
        for (int mi = 0; mi < 2; mi++) { ldm_x4(ah[mi], aB[0][mi] + koff); ldm_x4(al[mi], aB[1][mi] + koff); }
        #pragma unroll
        for (int nt = 0; nt < 2; nt++) { ldm_x4(bh[nt], bB[0][nt] + koff); ldm_x4(bl[nt], bB[1][nt] + koff); }
        #pragma unroll
        for (int mi = 0; mi < 2; mi++)
            #pragma unroll
            for (int nt = 0; nt < 2; nt++) {
                mma_bf16(acc[mi][nt*2],   ah[mi], &bh[nt][0]);
                mma_bf16(acc[mi][nt*2+1], ah[mi], &bh[nt][2]);
                mma_bf16(acc[mi][nt*2],   ah[mi], &bl[nt][0]);
                mma_bf16(acc[mi][nt*2+1], ah[mi], &bl[nt][2]);
                mma_bf16(acc[mi][nt*2],   al[mi], &bh[nt][0]);
                mma_bf16(acc[mi][nt*2+1], al[mi], &bh[nt][2]);
            }
    }
    __syncthreads();

    // ---- epilogue 1: hc = relu(acc + b1) -> split directly into smem A tiles ----
    #pragma unroll
    for (int mi = 0; mi < 2; mi++) {
        #pragma unroll
        for (int ni = 0; ni < 4; ni++) {
            int cc = col0 + ni*8 + t*2;
            float bx = b1[cc], by = b1[cc+1];
            float2 v0 = make_float2(fmaxf(acc[mi][ni][0] + bx, 0.f), fmaxf(acc[mi][ni][1] + by, 0.f));
            float2 v1 = make_float2(fmaxf(acc[mi][ni][2] + bx, 0.f), fmaxf(acc[mi][ni][3] + by, 0.f));
            int rl0 = row0 + mi*16 + g;
            __nv_bfloat16 a0 = __float2bfloat16(v0.x), a1 = __float2bfloat16(v0.y);
            __nv_bfloat16 c0 = __float2bfloat16(v1.x), c1 = __float2bfloat16(v1.y);
            *reinterpret_cast<__nv_bfloat162*>(sAhi + rl0*LDA + cc)     = __halves2bfloat162(a0, a1);
            *reinterpret_cast<__nv_bfloat162*>(sAlo + rl0*LDA + cc)     =
                __halves2bfloat162(__float2bfloat16(v0.x - __bfloat162float(a0)),
                                   __float2bfloat16(v0.y - __bfloat162float(a1)));
            *reinterpret_cast<__nv_bfloat162*>(sAhi + (rl0+8)*LDA + cc) = __halves2bfloat162(c0, c1);
            *reinterpret_cast<__nv_bfloat162*>(sAlo + (rl0+8)*LDA + cc) =
                __halves2bfloat162(__float2bfloat16(v1.x - __bfloat162float(c0)),
                                   __float2bfloat16(v1.y - __bfloat162float(c1)));
        }
    }
    for (int idx = tid; idx < 128*16; idx += 256) {
        int n  = idx >> 4;
        int k0 = (idx & 15) * 8;
        *reinterpret_cast<uint4*>(sWhi + n*LDA + k0) = *reinterpret_cast<const uint4*>(W2hi + (size_t)n*128 + k0);
        *reinterpret_cast<uint4*>(sWlo + n*LDA + k0) = *reinterpret_cast<const uint4*>(W2lo + (size_t)n*128 + k0);
    }
    __syncthreads();

    #pragma unroll
    for (int mi = 0; mi < 2; mi++)
        #pragma unroll
        for (int ni = 0; ni < 4; ni++)
            { acc[mi][ni][0]=0.f; acc[mi][ni][1]=0.f; acc[mi][ni][2]=0.f; acc[mi][ni][3]=0.f; }

    #pragma unroll 2
    for (int ks = 0; ks < 8; ks++) {
        uint32_t koff = (uint32_t)ks * 32u;
        uint32_t ah[2][4], al[2][4], bh[2][4], bl[2][4];
        #pragma unroll
        for (int mi = 0; mi < 2; mi++) { ldm_x4(ah[mi], aB[0][mi] + koff); ldm_x4(al[mi], aB[1][mi] + koff); }
        #pragma unroll
        for (int nt = 0; nt < 2; nt++) { ldm_x4(bh[nt], bB[0][nt] + koff); ldm_x4(bl[nt], bB[1][nt] + koff); }
        #pragma unroll
        for (int mi = 0; mi < 2; mi++)
            #pragma unroll
            for (int nt = 0; nt < 2; nt++) {
                mma_bf16(acc[mi][nt*2],   ah[mi], &bh[nt][0]);
                mma_bf16(acc[mi][nt*2+1], ah[mi], &bh[nt][2]);
                mma_bf16(acc[mi][nt*2],   ah[mi], &bl[nt][0]);
                mma_bf16(acc[mi][nt*2+1], ah[mi], &bl[nt][2]);
                mma_bf16(acc[mi][nt*2],   al[mi], &bh[nt][0]);
                mma_bf16(acc[mi][nt*2+1], al[mi], &bh[nt][2]);
            }
    }

    // ---- epilogue 2: hcs (fp16) to gmem + fused logits (att_s_ct) ----
    float lsS[2][2];
    lsS[0][0]=0.f; lsS[0][1]=0.f; lsS[1][0]=0.f; lsS[1][1]=0.f;
    #pragma unroll
    for (int mi = 0; mi < 2; mi++) {
        #pragma unroll
        for (int ni = 0; ni < 4; ni++) {
            int cc = col0 + ni*8 + t*2;
            int r1 = bm + row0 + mi*16 + g;
            float2 v0 = make_float2(acc[mi][ni][0], acc[mi][ni][1]);
            float2 v1 = make_float2(acc[mi][ni][2], acc[mi][ni][3]);
            float a0 = __ldg(attS + cc), a1 = __ldg(attS + cc + 1);
            lsS[mi][0] += v0.x*a0 + v0.y*a1;
            lsS[mi][1] += v1.x*a0 + v1.y*a1;
            if (r1 < M)     *reinterpret_cast<__half2*>(C + (size_t)r1*128 + cc)     = __floats2half2_rn(v0.x, v0.y);
            if (r1 + 8 < M) *reinterpret_cast<__half2*>(C + (size_t)(r1+8)*128 + cc) = __floats2half2_rn(v1.x, v1.y);
        }
    }
    #pragma unroll
    for (int mi = 0; mi < 2; mi++)
        #pragma unroll
        for (int rr = 0; rr < 2; rr++) {
            float v = lsS[mi][rr];
            v += __shfl_xor_sync(0xffffffffu, v, 1);
            v += __shfl_xor_sync(0xffffffffu, v, 2);
            lsS[mi][rr] = v;
        }
    if (t == 0) {
        int head = col0 >> 5;
        #pragma unroll
        for (int mi = 0; mi < 2; mi++)
            #pragma unroll
            for (int rr = 0; rr < 2; rr++) {
                int r = bm + row0 + mi*16 + g + rr*8;
                if (r < M) outS[(size_t)r*4 + head] = lsS[mi][rr];
            }
    }
}

// --------------------------------- CSR build ------------------------------------------------
__global__ void hist_all_kernel(const int* __restrict__ e0, const int* __restrict__ e1,
                                const int* __restrict__ ed)
{
    const int total = ETTg + ECTg;
    for (int i = blockIdx.x*blockDim.x + threadIdx.x; i < total; i += gridDim.x*blockDim.x) {
        if (i < ETTg) {
            atomicAdd(&g_deg[0*NTg + e1[i]], 1);
            atomicAdd(&g_deg[1*NTg + e0[i]], 1);
        } else {
            atomicAdd(&g_deg[2*NTg + ed[i - ETTg]], 1);
        }
    }
}

__global__ void scan1_kernel()
{
    int arr  = blockIdx.y;
    int base = blockIdx.x * 1024 + threadIdx.x;
    int lane = threadIdx.x & 31, wid = threadIdx.x >> 5;
    int v = (base < NTg) ? g_deg[arr*NTg + base] : 0;
    int x = v;
    #pragma unroll
    for (int o = 1; o < 32; o <<= 1) { int y = __shfl_up_sync(0xffffffffu, x, o); if (lane >= o) x += y; }
    __shared__ int ws[32];
    if (lane == 31) ws[wid] = x;
    __syncthreads();
    if (wid == 0) {
        int wv = ws[lane]; int wx = wv;
        #pragma unroll
        for (int o = 1; o < 32; o <<= 1) { int y = __shfl_up_sync(0xffffffffu, wx, o); if (lane >= o) wx += y; }
        if (lane == 31) g_aux[arr*128 + blockIdx.x] = wx;
        ws[lane] = wx - wv;
    }
    __syncthreads();
    int excl = x - v + ws[wid];
    if (base < NTg) g_cur[arr*NTg + base] = excl;
}

__global__ void scan2_kernel()
{
    int arr  = threadIdx.x >> 5;
    int lane = threadIdx.x & 31;
    if (arr >= 3) return;
    const int NB = (NTg + 1023) / 1024;
    int carry = 0;
    for (int c = 0; c*32 < NB; c++) {
        int idx = c*32 + lane;
        int v = (idx < NB) ? g_aux[arr*128 + idx] : 0;
        int x = v;
        #pragma unroll
        for (int o = 1; o < 32; o <<= 1) { int y = __shfl_up_sync(0xffffffffu, x, o); if (lane >= o) x += y; }
        if (idx < NB) g_aux[arr*128 + idx] = x - v + carry;
        carry += __shfl_sync(0xffffffffu, x, 31);
    }
}

__global__ void scan3_kernel()
{
    for (int i = blockIdx.x*blockDim.x + threadIdx.x; i < 3*NTg; i += gridDim.x*blockDim.x) {
        int arr = i / NTg; int idx = i - arr*NTg;
        g_cur[i] += g_aux[arr*128 + (idx >> 10)];
    }
}

__global__ void fill_all_kernel(const int* __restrict__ e0, const int* __restrict__ e1,
                                const int* __restrict__ es, const int* __restrict__ ed)
{
    const int total = ETTg + ECTg;
    for (int i = blockIdx.x*blockDim.x + threadIdx.x; i < total; i += gridDim.x*blockDim.x) {
        if (i < ETTg) {
            int s = e0[i], d = e1[i];
            int p = atomicAdd(&g_cur[0*NTg + d], 1); g_csrf[p] = s;
            int q = atomicAdd(&g_cur[1*NTg + s], 1); g_csrr[q] = d;
        } else {
            int j = i - ETTg;
            int p = atomicAdd(&g_cur[2*NTg + ed[j]], 1); g_csrct[p] = es[j];
        }
    }
}

// ----- per-relation GAT, half2 layout: lane owns cols {2l,2l+1} (head l>=16) and {64+2l,..} --
template<bool SELF>
__device__ __forceinline__ void gat_rel(
    const __half* __restrict__ hsrc, const float* __restrict__ a_s,
    const int* __restrict__ csr, int start, int cnt, int d, int lane,
    float4 ad, float wgt, float r[4])
{
    if (!SELF && cnt == 0) { r[0]=0.f; r[1]=0.f; r[2]=0.f; r[3]=0.f; return; }

    const bool hi16 = (lane >= 16);
    const float adA = hi16 ? ad.y : ad.x;
    const float adB = hi16 ? ad.w : ad.z;

    float denA = 0.f, denB = 0.f;
    float2 acA = make_float2(0.f, 0.f), acB = make_float2(0.f, 0.f);

    if (SELF) {
        float4 as = *reinterpret_cast<const float4*>(a_s + (size_t)d*4);
        float pa = __expf(lrelu02((hi16 ? as.y : as.x) + adA));
        float pb = __expf(lrelu02((hi16 ? as.w : as.z) + adB));
        denA = pa; denB = pb;
        const __half2* row2 = reinterpret_cast<const __half2*>(hsrc + (size_t)d*128);
        float2 fa = __half22float2(row2[lane]);
        float2 fb = __half22float2(row2[32 + lane]);
        acA.x = pa * fa.x; acA.y = pa * fa.y;
        acB.x = pb * fb.x; acB.y = pb * fb.y;
    }
    #pragma unroll 2
    for (int i = 0; i < cnt; i++) {
        int s = csr[start + i];
        float4 as = *reinterpret_cast<const float4*>(a_s + (size_t)s*4);
        float pa = __expf(lrelu02((hi16 ? as.y : as.x) + adA));
        float pb = __expf(lrelu02((hi16 ? as.w : as.z) + adB));
        denA += pa; denB += pb;
        const __half2* row2 = reinterpret_cast<const __half2*>(hsrc + (size_t)s*128);
        float2 fa = __half22float2(row2[lane]);
        float2 fb = __half22float2(row2[32 + lane]);
        acA.x = fmaf(pa, fa.x, acA.x); acA.y = fmaf(pa, fa.y, acA.y);
        acB.x = fmaf(pb, fb.x, acB.x); acB.y = fmaf(pb, fb.y, acB.y);
    }

    float ia = wgt / denA, ib = wgt / denB;
    r[0] = acA.x * ia; r[1] = acA.y * ia;
    r[2] = acB.x * ib; r[3] = acB.y * ib;
}

// --- merged GAT over all 3 relations; writes z = relu(acc + cbias + ht) (half2 lane map) ----
__global__ void gat_all_kernel(
    const __half* __restrict__ hs, const __half* __restrict__ hd, const __half* __restrict__ hcs,
    const float* __restrict__ ht,
    const float* __restrict__ asf, const float* __restrict__ adf,
    const float* __restrict__ asr, const float* __restrict__ adr,
    const float* __restrict__ asct, const float* __restrict__ adct,
    const int* __restrict__ cur, const int* __restrict__ deg,
    const int* __restrict__ csrf, const int* __restrict__ csrr, const int* __restrict__ csrct,
    const float* __restrict__ bsd, const float* __restrict__ bds, const float* __restrict__ bct,
    float* __restrict__ z)
{
    int d    = (blockIdx.x * blockDim.x + threadIdx.x) >> 5;
    int lane = threadIdx.x & 31;
    if (d >= NTg) return;

    float rf[4], rr_[4], rc[4];
    {
        int c = deg[0*NTg + d];
        gat_rel<true >(hs, asf, csrf, cur[0*NTg + d] - c, c, d, lane,
                       *reinterpret_cast<const float4*>(adf + (size_t)d*4), 0.25f, rf);
    }
    {
        int c = deg[1*NTg + d];
        gat_rel<true >(hd, asr, csrr, cur[1*NTg + d] - c, c, d, lane,
                       *reinterpret_cast<const float4*>(adr + (size_t)d*4), 0.25f, rr_);
    }
    {
        int c = deg[2*NTg + d];
        gat_rel<false>(hcs, asct, csrct, cur[2*NTg + d] - c, c, d, lane,
                       *reinterpret_cast<const float4*>(adct + (size_t)d*4), 0.5f, rc);
    }

    int cA = 2*lane, cB = 64 + 2*lane;
    const float2* hrow2 = reinterpret_cast<const float2*>(ht + (size_t)d*128);
    float2 ha = hrow2[lane], hb = hrow2[32 + lane];
    float cbA0 = 0.25f*bsd[cA]   + 0.25f*bds[cA]   + 0.5f*bct[cA];
    float cbA1 = 0.25f*bsd[cA+1] + 0.25f*bds[cA+1] + 0.5f*bct[cA+1];
    float cbB0 = 0.25f*bsd[cB]   + 0.25f*bds[cB]   + 0.5f*bct[cB];
    float cbB1 = 0.25f*bsd[cB+1] + 0.25f*bds[cB+1] + 0.5f*bct[cB+1];

    float2* zrow2 = reinterpret_cast<float2*>(z + (size_t)d*128);
    float2 za, zb;
    za.x = fmaxf(rf[0] + rr_[0] + rc[0] + ha.x + cbA0, 0.f);
    za.y = fmaxf(rf[1] + rr_[1] + rc[1] + ha.y + cbA1, 0.f);
    zb.x = fmaxf(rf[2] + rr_[2] + rc[2] + hb.x + cbB0, 0.f);
    zb.y = fmaxf(rf[3] + rr_[3] + rc[3] + hb.y + cbB1, 0.f);
    zrow2[lane]      = za;
    zrow2[32 + lane] = zb;
}

// ----------------------------------- launch -------------------------------------------------
extern "C" void kernel_launch(void* const* d_in, const int* in_sizes, int n_in,
                              void* d_out, int out_size)
{
    const float* x_t     = (const float*)d_in[0];
    const float* x_c     = (const float*)d_in[1];
    const int*   ett     = (const int*)d_in[2];
    const int*   e0      = ett;
    const int*   e1      = ett + ETTg;
    const int*   ect_s   = (const int*)d_in[3];
    const int*   ect_d   = (const int*)d_in[4];
    const float* W_pre_t = (const float*)d_in[5];
    const float* b_pre_t = (const float*)d_in[6];
    const float* W_pre_c = (const float*)d_in[7];
    const float* b_pre_c = (const float*)d_in[8];
    const float* W_sd    = (const float*)d_in[9];
    const float* att_s_sd= (const float*)d_in[10];
    const float* att_d_sd= (const float*)d_in[11];
    const float* b_sd    = (const float*)d_in[12];
    const float* W_ds    = (const float*)d_in[13];
    const float* att_s_ds= (const float*)d_in[14];
    const float* att_d_ds= (const float*)d_in[15];
    const float* b_ds    = (const float*)d_in[16];
    const float* W_ct_s  = (const float*)d_in[17];
    const float* W_ct_d  = (const float*)d_in[18];
    const float* att_s_ct= (const float*)d_in[19];
    const float* att_d_ct= (const float*)d_in[20];
    const float* b_ct    = (const float*)d_in[21];
    const float* W_out   = (const float*)d_in[22];
    const float* b_out   = (const float*)d_in[23];
    float* out = (float*)d_out;

    float *p_ht, *p_z, *p_wv;
    __half *p_hs, *p_hd, *p_hcs;
    float *p_asf, *p_adf, *p_asr, *p_adr, *p_adct, *p_asct;
    int *p_deg, *p_cur, *p_csrf, *p_csrr, *p_csrct;
    __nv_bfloat16 *p_whi, *p_wlo;
    cudaGetSymbolAddress((void**)&p_ht,  g_ht);
    cudaGetSymbolAddress((void**)&p_hs,  g_hs);
    cudaGetSymbolAddress((void**)&p_hd,  g_hd);
    cudaGetSymbolAddress((void**)&p_hcs, g_hcs);
    cudaGetSymbolAddress((void**)&p_z,   g_z);
    cudaGetSymbolAddress((void**)&p_wv,  g_wv);
    cudaGetSymbolAddress((void**)&p_asf, g_asf);
    cudaGetSymbolAddress((void**)&p_adf, g_adf);
    cudaGetSymbolAddress((void**)&p_asr, g_asr);
    cudaGetSymbolAddress((void**)&p_adr, g_adr);
    cudaGetSymbolAddress((void**)&p_adct,g_adct);
    cudaGetSymbolAddress((void**)&p_asct,g_asct);
    cudaGetSymbolAddress((void**)&p_deg, g_deg);
    cudaGetSymbolAddress((void**)&p_cur, g_cur);
    cudaGetSymbolAddress((void**)&p_csrf, g_csrf);
    cudaGetSymbolAddress((void**)&p_csrr, g_csrr);
    cudaGetSymbolAddress((void**)&p_csrct,g_csrct);
    cudaGetSymbolAddress((void**)&p_whi, g_whi);
    cudaGetSymbolAddress((void**)&p_wlo, g_wlo);

    const int SM128 = (2*64 + 2*128) * (128 + 8) * 2;   // 104448
    cudaFuncSetAttribute(tc_gemm_triple,          cudaFuncAttributeMaxDynamicSharedMemorySize, SM128 + 4096);
    cudaFuncSetAttribute(tc_gemm_chain,           cudaFuncAttributeMaxDynamicSharedMemorySize, SM128);
    cudaFuncSetAttribute(tc_gemm<128,false,true>, cudaFuncAttributeMaxDynamicSharedMemorySize, SM128);

    const int GT = (NTg + 63) / 64;   // 1563
    const int GC = (NCg + 63) / 64;   // 391

    // slots: 0 pre_t K=64, 1 pre_c K=32, 2 sd, 3 ds, 4 ct_s, 5 out  (W_ct_d folded into wv)
    WJobs jobs;
    jobs.W[0] = W_pre_t; jobs.K[0] = 64;
    jobs.W[1] = W_pre_c; jobs.K[1] = 32;
    jobs.W[2] = W_sd;    jobs.K[2] = 128;
    jobs.W[3] = W_ds;    jobs.K[3] = 128;
    jobs.W[4] = W_ct_s;  jobs.K[4] = 128;
    jobs.W[5] = W_out;   jobs.K[5] = 128;

    wv_kernel<<<1, 512>>>(W_ct_d, att_d_ct, p_wv);                                  // k1
    wsplit_all<<<dim3(64, 6), 256>>>(jobs, p_whi, p_wlo);                           // k2
    // TRIPLE: ht = relu(x_t@W0+b0); a_dct; hs = ht@W_sd; hd = ht@W_ds (+4 logit sets)
    tc_gemm_triple<<<GT, 256, SM128 + 4096>>>(x_t,
        p_whi + 0*16384, p_wlo + 0*16384, b_pre_t, p_wv, p_ht, p_adct,
        p_whi + 2*16384, p_wlo + 2*16384, p_whi + 3*16384, p_wlo + 3*16384,
        p_hs, p_hd, NTg,
        att_s_sd, att_d_sd, att_s_ds, att_d_ds,
        p_asf, p_adf, p_asr, p_adr);                                                // k3
    // chained: hc (K=32, smem-resident) -> hcs = hc @ W_ct_s, fused asct logits
    tc_gemm_chain<<<GC, 256, SM128>>>(x_c,
        p_whi + 1*16384, p_wlo + 1*16384, b_pre_c,
        p_whi + 4*16384, p_wlo + 4*16384,
        p_hcs, NCg, att_s_ct, p_asct);                                              // k4

    // CSR build
    cudaMemsetAsync(p_deg, 0, 3*NTg*sizeof(int));
    hist_all_kernel<<<768, 256>>>(e0, e1, ect_d);
    dim3 g1((NTg + 1023) / 1024, 3);
    scan1_kernel<<<g1, 1024>>>();
    scan2_kernel<<<1, 96>>>();
    scan3_kernel<<<256, 256>>>();
    fill_all_kernel<<<768, 256>>>(e0, e1, ect_s, ect_d);

    // merged GAT (half2 layout)
    gat_all_kernel<<<(NTg + 7) / 8, 256>>>(
        p_hs, p_hd, p_hcs, p_ht,
        p_asf, p_adf, p_asr, p_adr, p_asct, p_adct,
        p_cur, p_deg, p_csrf, p_csrr, p_csrct,
        b_sd, b_ds, b_ct, p_z);

    // final: out = z @ W_out + b_out
    tc_gemm<128,false,true><<<GT, 256, SM128>>>(p_z, p_whi + 5*16384, p_wlo + 5*16384,
        b_out, out, NTg);
}

// round 14
// speedup vs baseline: 1.5224x; 1.0146x over previous
#include <cuda_runtime.h>
#include <cuda_bf16.h>
#include <cuda_fp16.h>
#include <cstdint>

#define NTg  100000
#define NCg  25000
#define ETTg 800000
#define ECTg 400000
#define HIDg 128

// ------------------------- scratch (device globals; allocation-free) -------------------------
__device__ float  g_ht [NTg*HIDg];
__device__ __half g_hs [NTg*HIDg];
__device__ __half g_hd [NTg*HIDg];
__device__ __half g_hcs[NCg*HIDg];
__device__ float  g_z  [NTg*HIDg];
__device__ float g_asf[NTg*4];
__device__ float g_adf[NTg*4];
__device__ float g_asr[NTg*4];
__device__ float g_adr[NTg*4];
__device__ float g_adct[NTg*4];
__device__ float g_asct[NCg*4];
__device__ float g_wv [4*128];
__device__ int   g_deg[3*NTg];
__device__ int   g_cur[3*NTg];
__device__ int   g_aux[3*128];
__device__ int   g_csrf[ETTg];
__device__ int   g_csrr[ETTg];
__device__ int   g_csrct[ECTg];
// split weights: 6 slots of up to 128x128 bf16 ([N,K] layout, i.e., W^T)
__device__ __nv_bfloat16 g_whi[6*128*128];
__device__ __nv_bfloat16 g_wlo[6*128*128];

__device__ __forceinline__ float lrelu02(float x) { return x > 0.f ? x : 0.2f * x; }

__device__ __forceinline__ uint32_t smem_u32(const void* p) {
    uint32_t a;
    asm("{ .reg .u64 t; cvta.to.shared.u64 t, %1; cvt.u32.u64 %0, t; }" : "=r"(a) : "l"(p));
    return a;
}

__device__ __forceinline__ void ldm_x4(uint32_t* r, uint32_t addr) {
    asm volatile("ldmatrix.sync.aligned.m8n8.x4.shared.b16 {%0,%1,%2,%3}, [%4];"
                 : "=r"(r[0]), "=r"(r[1]), "=r"(r[2]), "=r"(r[3]) : "r"(addr));
}
__device__ __forceinline__ void mma_bf16(float* c, const uint32_t* a, const uint32_t* b) {
    asm volatile("mma.sync.aligned.m16n8k16.row.col.f32.bf16.bf16.f32 "
                 "{%0,%1,%2,%3}, {%4,%5,%6,%7}, {%8,%9}, {%0,%1,%2,%3};"
                 : "+f"(c[0]), "+f"(c[1]), "+f"(c[2]), "+f"(c[3])
                 : "r"(a[0]), "r"(a[1]), "r"(a[2]), "r"(a[3]), "r"(b[0]), "r"(b[1]));
}

// ------------------- batched W split/transpose: hi/lo[n*K+k] = split(W[k*128+n]) ------------
struct WJobs { const float* W[6]; int K[6]; };

__global__ void wsplit_all(WJobs jobs, __nv_bfloat16* __restrict__ hiB,
                           __nv_bfloat16* __restrict__ loB)
{
    int slot = blockIdx.y;
    const float* W = jobs.W[slot];
    int K = jobs.K[slot];
    __nv_bfloat16* hi = hiB + slot*16384;
    __nv_bfloat16* lo = loB + slot*16384;
    int tot = 128 * K;
    for (int i = blockIdx.x*blockDim.x + threadIdx.x; i < tot; i += gridDim.x*blockDim.x) {
        int n = i / K, k = i - n*K;
        float v = W[k*128 + n];
        __nv_bfloat16 h = __float2bfloat16(v);
        hi[i] = h;
        lo[i] = __float2bfloat16(v - __bfloat162float(h));
    }
}

// ----------------- wv[h*128+k] = sum_c W_ct_dst[k*128 + h*32 + c] * att[h*32+c] -------------
__global__ void wv_kernel(const float* __restrict__ W, const float* __restrict__ att,
                          float* __restrict__ wv)
{
    int i = threadIdx.x;           // 512 threads: k = i>>2, h = i&3
    int k = i >> 2, h = i & 3;
    float s = 0.f;
    #pragma unroll 8
    for (int c = 0; c < 32; c++) s += W[k*128 + h*32 + c] * att[h*32 + c];
    wv[h*128 + k] = s;
}

// ---------------- HMMA GEMM: C[M,128] = A[M,K] @ W[K,128]  (3-split bf16) -------------------
template<int K, bool RELU, bool BIAS>
__global__ void __launch_bounds__(256, 2) tc_gemm(
    const float* __restrict__ A, const __nv_bfloat16* __restrict__ Whi,
    const __nv_bfloat16* __restrict__ Wlo, const float* __restrict__ bias,
    float* __restrict__ C, int M)
{
    constexpr int LDA = K + 8;
    extern __shared__ __nv_bfloat16 smb[];
    __nv_bfloat16* sAhi = smb;
    __nv_bfloat16* sAlo = sAhi + 64*LDA;
    __nv_bfloat16* sWhi = sAlo + 64*LDA;
    __nv_bfloat16* sWlo = sWhi + 128*LDA;

    const int tid  = threadIdx.x;
    const int lane = tid & 31;
    const int wid  = tid >> 5;
    const int bm   = blockIdx.x * 64;

    for (int idx = tid; idx < 64*(K/4); idx += 256) {
        int r  = idx / (K/4);
        int k0 = (idx % (K/4)) * 4;
        int row = bm + r;
        float4 v = make_float4(0.f, 0.f, 0.f, 0.f);
        if (row < M) v = *reinterpret_cast<const float4*>(A + (size_t)row*K + k0);
        __nv_bfloat16 h0 = __float2bfloat16(v.x), h1 = __float2bfloat16(v.y);
        __nv_bfloat16 h2 = __float2bfloat16(v.z), h3 = __float2bfloat16(v.w);
        __nv_bfloat16 l0 = __float2bfloat16(v.x - __bfloat162float(h0));
        __nv_bfloat16 l1 = __float2bfloat16(v.y - __bfloat162float(h1));
        __nv_bfloat16 l2 = __float2bfloat16(v.z - __bfloat162float(h2));
        __nv_bfloat16 l3 = __float2bfloat16(v.w - __bfloat162float(h3));
        __nv_bfloat16* pH = sAhi + r*LDA + k0;
        __nv_bfloat16* pL = sAlo + r*LDA + k0;
        *reinterpret_cast<__nv_bfloat162*>(pH)     = __halves2bfloat162(h0, h1);
        *reinterpret_cast<__nv_bfloat162*>(pH + 2) = __halves2bfloat162(h2, h3);
        *reinterpret_cast<__nv_bfloat162*>(pL)     = __halves2bfloat162(l0, l1);
        *reinterpret_cast<__nv_bfloat162*>(pL + 2) = __halves2bfloat162(l2, l3);
    }
    for (int idx = tid; idx < 128*(K/8); idx += 256) {
        int n  = idx / (K/8);
        int k0 = (idx % (K/8)) * 8;
        *reinterpret_cast<uint4*>(sWhi + n*LDA + k0) = *reinterpret_cast<const uint4*>(Whi + (size_t)n*K + k0);
        *reinterpret_cast<uint4*>(sWlo + n*LDA + k0) = *reinterpret_cast<const uint4*>(Wlo + (size_t)n*K + k0);
    }
    __syncthreads();

    const int row0 = (wid & 1) * 32;
    const int col0 = (wid >> 1) * 32;

    uint32_t aB[2][2], bB[2][2];
    {
        int ar = (lane & 15), ac = (lane >> 4) * 8;
        #pragma unroll
        for (int mi = 0; mi < 2; mi++) {
            aB[0][mi] = smem_u32(sAhi + (row0 + mi*16 + ar)*LDA + ac);
            aB[1][mi] = smem_u32(sAlo + (row0 + mi*16 + ar)*LDA + ac);
        }
        int q  = lane >> 3;
        int nr = (q >> 1)*8 + (lane & 7);
        int nc = (q & 1)*8;
        #pragma unroll
        for (int nt = 0; nt < 2; nt++) {
            bB[0][nt] = smem_u32(sWhi + (col0 + nt*16 + nr)*LDA + nc);
            bB[1][nt] = smem_u32(sWlo + (col0 + nt*16 + nr)*LDA + nc);
        }
    }

    float acc[2][4][4];
    #pragma unroll
    for (int mi = 0; mi < 2; mi++)
        #pragma unroll
        for (int ni = 0; ni < 4; ni++)
            { acc[mi][ni][0]=0.f; acc[mi][ni][1]=0.f; acc[mi][ni][2]=0.f; acc[mi][ni][3]=0.f; }

    #pragma unroll 2
    for (int ks = 0; ks < K/16; ks++) {
        uint32_t koff = (uint32_t)ks * 32u;
        uint32_t ah[2][4], al[2][4], bh[2][4], bl[2][4];
        #pragma unroll
        for (int mi = 0; mi < 2; mi++) { ldm_x4(ah[mi], aB[0][mi] + koff); ldm_x4(al[mi], aB[1][mi] + koff); }
        #pragma unroll
        for (int nt = 0; nt < 2; nt++) { ldm_x4(bh[nt], bB[0][nt] + koff); ldm_x4(bl[nt], bB[1][nt] + koff); }
        #pragma unroll
        for (int mi = 0; mi < 2; mi++)
            #pragma unroll
            for (int nt = 0; nt < 2; nt++) {
                mma_bf16(acc[mi][nt*2],   ah[mi], &bh[nt][0]);
                mma_bf16(acc[mi][nt*2+1], ah[mi], &bh[nt][2]);
                mma_bf16(acc[mi][nt*2],   ah[mi], &bl[nt][0]);
                mma_bf16(acc[mi][nt*2+1], ah[mi], &bl[nt][2]);
                mma_bf16(acc[mi][nt*2],   al[mi], &bh[nt][0]);
                mma_bf16(acc[mi][nt*2+1], al[mi], &bh[nt][2]);
            }
    }

    const int g = lane >> 2, t = lane & 3;
    #pragma unroll
    for (int mi = 0; mi < 2; mi++) {
        #pragma unroll
        for (int ni = 0; ni < 4; ni++) {
            int cc = col0 + ni*8 + t*2;
            float bx = 0.f, by = 0.f;
            if (BIAS) { bx = bias[cc]; by = bias[cc+1]; }
            int r1 = bm + row0 + mi*16 + g;
            float2 v0 = make_float2(acc[mi][ni][0] + bx, acc[mi][ni][1] + by);
            float2 v1 = make_float2(acc[mi][ni][2] + bx, acc[mi][ni][3] + by);
            if (RELU) {
                v0.x = fmaxf(v0.x, 0.f); v0.y = fmaxf(v0.y, 0.f);
                v1.x = fmaxf(v1.x, 0.f); v1.y = fmaxf(v1.y, 0.f);
            }
            if (r1 < M)     *reinterpret_cast<float2*>(C + (size_t)r1*128 + cc)     = v0;
            if (r1 + 8 < M) *reinterpret_cast<float2*>(C + (size_t)(r1+8)*128 + cc) = v1;
        }
    }
}

// -------- TRIPLE: ht = relu(x_t@W0 + b0) (K=64) -> [resident] -> hs, hd + all logits --------
__global__ void __launch_bounds__(256, 2) tc_gemm_triple(
    const float* __restrict__ xt,
    const __nv_bfloat16* __restrict__ W0hi, const __nv_bfloat16* __restrict__ W0lo,
    const float* __restrict__ b0, const float* __restrict__ wv,
    float* __restrict__ htO, float* __restrict__ adct,
    const __nv_bfloat16* __restrict__ Whi0, const __nv_bfloat16* __restrict__ Wlo0,
    const __nv_bfloat16* __restrict__ Whi1, const __nv_bfloat16* __restrict__ Wlo1,
    __half* __restrict__ C0, __half* __restrict__ C1, int M,
    const float* __restrict__ attS0, const float* __restrict__ attD0,
    const float* __restrict__ attS1, const float* __restrict__ attD1,
    float* __restrict__ outS0, float* __restrict__ outD0,
    float* __restrict__ outS1, float* __restrict__ outD1)
{
    constexpr int LDA = 136;
    extern __shared__ __nv_bfloat16 smb[];
    __nv_bfloat16* sAhi = smb;
    __nv_bfloat16* sAlo = sAhi + 64*LDA;
    __nv_bfloat16* sWhi = sAlo + 64*LDA;
    __nv_bfloat16* sWlo = sWhi + 128*LDA;
    float* sRed = reinterpret_cast<float*>(smb + (size_t)(2*64 + 2*128)*LDA);  // [64][16]

    const int tid  = threadIdx.x;
    const int lane = tid & 31;
    const int wid  = tid >> 5;
    const int bm   = blockIdx.x * 64;

    for (int idx = tid; idx < 64*16; idx += 256) {
        int r  = idx >> 4;
        int k0 = (idx & 15) * 4;
        int row = bm + r;
        float4 v = make_float4(0.f, 0.f, 0.f, 0.f);
        if (row < M) v = *reinterpret_cast<const float4*>(xt + (size_t)row*64 + k0);
        __nv_bfloat16 h0 = __float2bfloat16(v.x), h1 = __float2bfloat16(v.y);
        __nv_bfloat16 h2 = __float2bfloat16(v.z), h3 = __float2bfloat16(v.w);
        __nv_bfloat16 l0 = __float2bfloat16(v.x - __bfloat162float(h0));
        __nv_bfloat16 l1 = __float2bfloat16(v.y - __bfloat162float(h1));
        __nv_bfloat16 l2 = __float2bfloat16(v.z - __bfloat162float(h2));
        __nv_bfloat16 l3 = __float2bfloat16(v.w - __bfloat162float(h3));
        __nv_bfloat16* pH = sAhi + r*LDA + k0;
        __nv_bfloat16* pL = sAlo + r*LDA + k0;
        *reinterpret_cast<__nv_bfloat162*>(pH)     = __halves2bfloat162(h0, h1);
        *reinterpret_cast<__nv_bfloat162*>(pH + 2) = __halves2bfloat162(h2, h3);
        *reinterpret_cast<__nv_bfloat162*>(pL)     = __halves2bfloat162(l0, l1);
        *reinterpret_cast<__nv_bfloat162*>(pL + 2) = __halves2bfloat162(l2, l3);
    }
    for (int idx = tid; idx < 128*8; idx += 256) {
        int n  = idx >> 3;
        int k0 = (idx & 7) * 8;
        *reinterpret_cast<uint4*>(sWhi + n*LDA + k0) = *reinterpret_cast<const uint4*>(W0hi + (size_t)n*64 + k0);
        *reinterpret_cast<uint4*>(sWlo + n*LDA + k0) = *reinterpret_cast<const uint4*>(W0lo + (size_t)n*64 + k0);
    }
    __syncthreads();

    const int row0 = (wid & 1) * 32;
    const int col0 = (wid >> 1) * 32;
    uint32_t aB[2][2], bB[2][2];
    {
        int ar = (lane & 15), ac = (lane >> 4) * 8;
        #pragma unroll
        for (int mi = 0; mi < 2; mi++) {
            aB[0][mi] = smem_u32(sAhi + (row0 + mi*16 + ar)*LDA + ac);
            aB[1][mi] = smem_u32(sAlo + (row0 + mi*16 + ar)*LDA + ac);
        }
        int q  = lane >> 3;
        int nr = (q >> 1)*8 + (lane & 7);
        int nc = (q & 1)*8;
        #pragma unroll
        for (int nt = 0; nt < 2; nt++) {
            bB[0][nt] = smem_u32(sWhi + (col0 + nt*16 + nr)*LDA + nc);
            bB[1][nt] = smem_u32(sWlo + (col0 + nt*16 + nr)*LDA + nc);
        }
    }
    const int g = lane >> 2, t = lane & 3;

    float acc[2][4][4];
    #pragma unroll
    for (int mi = 0; mi < 2; mi++)
        #pragma unroll
        for (int ni = 0; ni < 4; ni++)
            { acc[mi][ni][0]=0.f; acc[mi][ni][1]=0.f; acc[mi][ni][2]=0.f; acc[mi][ni][3]=0.f; }

    #pragma unroll
    for (int ks = 0; ks < 4; ks++) {     // K=64
        uint32_t koff = (uint32_t)ks * 32u;
        uint32_t ah[2][4], al[2][4], bh[2][4], bl[2][4];
        #pragma unroll
        for (int mi = 0; mi < 2; mi++) { ldm_x4(ah[mi], aB[0][mi] + koff); ldm_x4(al[mi], aB[1][mi] + koff); }
        #pragma unroll
        for (int nt = 0; nt < 2; nt++) { ldm_x4(bh[nt], bB[0][nt] + koff); ldm_x4(bl[nt], bB[1][nt] + koff); }
        #pragma unroll
        for (int mi = 0; mi < 2; mi++)
            #pragma unroll
            for (int nt = 0; nt < 2; nt++) {
                mma_bf16(acc[mi][nt*2],   ah[mi], &bh[nt][0]);
                mma_bf16(acc[mi][nt*2+1], ah[mi], &bh[nt][2]);
                mma_bf16(acc[mi][nt*2],   ah[mi], &bl[nt][0]);
                mma_bf16(acc[mi][nt*2+1], ah[mi], &bl[nt][2]);
                mma_bf16(acc[mi][nt*2],   al[mi], &bh[nt][0]);
                mma_bf16(acc[mi][nt*2+1], al[mi], &bh[nt][2]);
            }
    }

    float lsA[2][2][4];
    #pragma unroll
    for (int a = 0; a < 2; a++)
        #pragma unroll
        for (int b = 0; b < 2; b++)
            #pragma unroll
            for (int h = 0; h < 4; h++) lsA[a][b][h] = 0.f;

    #pragma unroll
    for (int mi = 0; mi < 2; mi++) {
        #pragma unroll
        for (int ni = 0; ni < 4; ni++) {
            int cc = col0 + ni*8 + t*2;
            float bx = b0[cc], by = b0[cc+1];
            float2 v0 = make_float2(fmaxf(acc[mi][ni][0] + bx, 0.f), fmaxf(acc[mi][ni][1] + by, 0.f));
            float2 v1 = make_float2(fmaxf(acc[mi][ni][2] + bx, 0.f), fmaxf(acc[mi][ni][3] + by, 0.f));
            acc[mi][ni][0] = v0.x; acc[mi][ni][1] = v0.y;
            acc[mi][ni][2] = v1.x; acc[mi][ni][3] = v1.y;
            int r1 = bm + row0 + mi*16 + g;
            if (r1 < M)     *reinterpret_cast<float2*>(htO + (size_t)r1*128 + cc)     = v0;
            if (r1 + 8 < M) *reinterpret_cast<float2*>(htO + (size_t)(r1+8)*128 + cc) = v1;
            #pragma unroll
            for (int h = 0; h < 4; h++) {
                float w0 = __ldg(wv + h*128 + cc), w1 = __ldg(wv + h*128 + cc + 1);
                lsA[mi][0][h] += v0.x*w0 + v0.y*w1;
                lsA[mi][1][h] += v1.x*w0 + v1.y*w1;
            }
        }
    }
    #pragma unroll
    for (int mi = 0; mi < 2; mi++)
        #pragma unroll
        for (int rr = 0; rr < 2; rr++)
            #pragma unroll
            for (int h = 0; h < 4; h++) {
                float v = lsA[mi][rr][h];
                v += __shfl_xor_sync(0xffffffffu, v, 1);
                v += __shfl_xor_sync(0xffffffffu, v, 2);
                lsA[mi][rr][h] = v;
            }

    __syncthreads();

    #pragma unroll
    for (int mi = 0; mi < 2; mi++) {
        #pragma unroll
        for (int ni = 0; ni < 4; ni++) {
            int cc = col0 + ni*8 + t*2;
            int rl0 = row0 + mi*16 + g;
            float2 v0 = make_float2(acc[mi][ni][0], acc[mi][ni][1]);
            float2 v1 = make_float2(acc[mi][ni][2], acc[mi][ni][3]);
            __nv_bfloat16 a0 = __float2bfloat16(v0.x), a1 = __float2bfloat16(v0.y);
            __nv_bfloat16 c0 = __float2bfloat16(v1.x), c1 = __float2bfloat16(v1.y);
            *reinterpret_cast<__nv_bfloat162*>(sAhi + rl0*LDA + cc)     = __halves2bfloat162(a0, a1);
            *reinterpret_cast<__nv_bfloat162*>(sAlo + rl0*LDA + cc)     =
                __halves2bfloat162(__float2bfloat16(v0.x - __bfloat162float(a0)),
                                   __float2bfloat16(v0.y - __bfloat162float(a1)));
            *reinterpret_cast<__nv_bfloat162*>(sAhi + (rl0+8)*LDA + cc) = __halves2bfloat162(c0, c1);
            *reinterpret_cast<__nv_bfloat162*>(sAlo + (rl0+8)*LDA + cc) =
                __halves2bfloat162(__float2bfloat16(v1.x - __bfloat162float(c0)),
                                   __float2bfloat16(v1.y - __bfloat162float(c1)));
        }
    }
    {
        int cg = wid >> 1;
        if (t == 0) {
            #pragma unroll
            for (int mi = 0; mi < 2; mi++)
                #pragma unroll
                for (int rr = 0; rr < 2; rr++) {
                    int lr = row0 + mi*16 + g + rr*8;
                    #pragma unroll
                    for (int h = 0; h < 4; h++)
                        sRed[lr*16 + cg*4 + h] = lsA[mi][rr][h];
                }
        }
    }
    __syncthreads();
    {
        int lr = tid >> 2, h = tid & 3;
        float s = sRed[lr*16 + h] + sRed[lr*16 + 4 + h]
                + sRed[lr*16 + 8 + h] + sRed[lr*16 + 12 + h];
        int r = bm + lr;
        if (r < M) adct[(size_t)r*4 + h] = s;
    }

    #pragma unroll
    for (int slot = 0; slot < 2; slot++) {
        const __nv_bfloat16* Whi = slot ? Whi1 : Whi0;
        const __nv_bfloat16* Wlo = slot ? Wlo1 : Wlo0;
        __half* C = slot ? C1 : C0;
        const float* attS = slot ? attS1 : attS0;
        const float* attD = slot ? attD1 : attD0;
        float* outS = slot ? outS1 : outS0;
        float* outD = slot ? outD1 : outD0;

        for (int idx = tid; idx < 128*16; idx += 256) {
            int n  = idx >> 4;
            int k0 = (idx & 15) * 8;
            *reinterpret_cast<uint4*>(sWhi + n*LDA + k0) = *reinterpret_cast<const uint4*>(Whi + (size_t)n*128 + k0);
            *reinterpret_cast<uint4*>(sWlo + n*LDA + k0) = *reinterpret_cast<const uint4*>(Wlo + (size_t)n*128 + k0);
        }
        __syncthreads();

        #pragma unroll
        for (int mi = 0; mi < 2; mi++)
            #pragma unroll
            for (int ni = 0; ni < 4; ni++)
                { acc[mi][ni][0]=0.f; acc[mi][ni][1]=0.f; acc[mi][ni][2]=0.f; acc[mi][ni][3]=0.f; }

        #pragma unroll 2
        for (int ks = 0; ks < 8; ks++) {
            uint32_t koff = (uint32_t)ks * 32u;
            uint32_t ah[2][4], al[2][4], bh[2][4], bl[2][4];
            #pragma unroll
            for (int mi = 0; mi < 2; mi++) { ldm_x4(ah[mi], aB[0][mi] + koff); ldm_x4(al[mi], aB[1][mi] + koff); }
            #pragma unroll
            for (int nt = 0; nt < 2; nt++) { ldm_x4(bh[nt], bB[0][nt] + koff); ldm_x4(bl[nt], bB[1][nt] + koff); }
            #pragma unroll
            for (int mi = 0; mi < 2; mi++)
                #pragma unroll
                for (int nt = 0; nt < 2; nt++) {
                    mma_bf16(acc[mi][nt*2],   ah[mi], &bh[nt][0]);
                    mma_bf16(acc[mi][nt*2+1], ah[mi], &bh[nt][2]);
                    mma_bf16(acc[mi][nt*2],   ah[mi], &bl[nt][0]);
                    mma_bf16(acc[mi][nt*2+1], ah[mi], &bl[nt][2]);
                    mma_bf16(acc[mi][nt*2],   al[mi], &bh[nt][0]);
                    mma_bf16(acc[mi][nt*2+1], al[mi], &bh[nt][2]);
                }
        }

        float lsS[2][2], lsD[2][2];
        lsS[0][0]=0.f; lsS[0][1]=0.f; lsS[1][0]=0.f; lsS[1][1]=0.f;
        lsD[0][0]=0.f; lsD[0][1]=0.f; lsD[1][0]=0.f; lsD[1][1]=0.f;

        #pragma unroll
        for (int mi = 0; mi < 2; mi++) {
            #pragma unroll
            for (int ni = 0; ni < 4; ni++) {
                int cc = col0 + ni*8 + t*2;
                int r1 = bm + row0 + mi*16 + g;
                float2 v0 = make_float2(acc[mi][ni][0], acc[mi][ni][1]);
                float2 v1 = make_float2(acc[mi][ni][2], acc[mi][ni][3]);
                float a0 = __ldg(attS + cc), a1 = __ldg(attS + cc + 1);
                float d0 = __ldg(attD + cc), d1 = __ldg(attD + cc + 1);
                lsS[mi][0] += v0.x*a0 + v0.y*a1;
                lsS[mi][1] += v1.x*a0 + v1.y*a1;
                lsD[mi][0] += v0.x*d0 + v0.y*d1;
                lsD[mi][1] += v1.x*d0 + v1.y*d1;
                if (r1 < M)     *reinterpret_cast<__half2*>(C + (size_t)r1*128 + cc)     = __floats2half2_rn(v0.x, v0.y);
                if (r1 + 8 < M) *reinterpret_cast<__half2*>(C + (size_t)(r1+8)*128 + cc) = __floats2half2_rn(v1.x, v1.y);
            }
        }
        #pragma unroll
        for (int mi = 0; mi < 2; mi++)
            #pragma unroll
            for (int rr = 0; rr < 2; rr++) {
                float v = lsS[mi][rr];
                v += __shfl_xor_sync(0xffffffffu, v, 1);
                v += __shfl_xor_sync(0xffffffffu, v, 2);
                lsS[mi][rr] = v;
                float w = lsD[mi][rr];
                w += __shfl_xor_sync(0xffffffffu, w, 1);
                w += __shfl_xor_sync(0xffffffffu, w, 2);
                lsD[mi][rr] = w;
            }
        if (t == 0) {
            int head = col0 >> 5;
            #pragma unroll
            for (int mi = 0; mi < 2; mi++)
                #pragma unroll
                for (int rr = 0; rr < 2; rr++) {
                    int r = bm + row0 + mi*16 + g + rr*8;
                    if (r < M) {
                        outS[(size_t)r*4 + head] = lsS[mi][rr];
                        outD[(size_t)r*4 + head] = lsD[mi][rr];
                    }
                }
        }
        __syncthreads();
    }
}

// ----- chained GEMM: hc = relu(x_c@W_pre_c + b) (K=32, smem-resident) -> hcs = hc@W_ct_s ----
__global__ void __launch_bounds__(256, 2) tc_gemm_chain(
    const float* __restrict__ xc,
    const __nv_bfloat16* __restrict__ W1hi, const __nv_bfloat16* __restrict__ W1lo,
    const float* __restrict__ b1,
    const __nv_bfloat16* __restrict__ W2hi, const __nv_bfloat16* __restrict__ W2lo,
    __half* __restrict__ C, int M,
    const float* __restrict__ attS, float* __restrict__ outS)
{
    constexpr int LDA = 136;
    extern __shared__ __nv_bfloat16 smb[];
    __nv_bfloat16* sAhi = smb;
    __nv_bfloat16* sAlo = sAhi + 64*LDA;
    __nv_bfloat16* sWhi = sAlo + 64*LDA;
    __nv_bfloat16* sWlo = sWhi + 128*LDA;

    const int tid  = threadIdx.x;
    const int lane = tid & 31;
    const int wid  = tid >> 5;
    const int bm   = blockIdx.x * 64;

    for (int idx = tid; idx < 64*8; idx += 256) {
        int r  = idx >> 3;
        int k0 = (idx & 7) * 4;
        int row = bm + r;
        float4 v = make_float4(0.f, 0.f, 0.f, 0.f);
        if (row < M) v = *reinterpret_cast<const float4*>(xc + (size_t)row*32 + k0);
        __nv_bfloat16 h0 = __float2bfloat16(v.x), h1 = __float2bfloat16(v.y);
        __nv_bfloat16 h2 = __float2bfloat16(v.z), h3 = __float2bfloat16(v.w);
        __nv_bfloat16 l0 = __float2bfloat16(v.x - __bfloat162float(h0));
        __nv_bfloat16 l1 = __float2bfloat16(v.y - __bfloat162float(h1));
        __nv_bfloat16 l2 = __float2bfloat16(v.z - __bfloat162float(h2));
        __nv_bfloat16 l3 = __float2bfloat16(v.w - __bfloat162float(h3));
        __nv_bfloat16* pH = sAhi + r*LDA + k0;
        __nv_bfloat16* pL = sAlo + r*LDA + k0;
        *reinterpret_cast<__nv_bfloat162*>(pH)     = __halves2bfloat162(h0, h1);
        *reinterpret_cast<__nv_bfloat162*>(pH + 2) = __halves2bfloat162(h2, h3);
        *reinterpret_cast<__nv_bfloat162*>(pL)     = __halves2bfloat162(l0, l1);
        *reinterpret_cast<__nv_bfloat162*>(pL + 2) = __halves2bfloat162(l2, l3);
    }
    for (int idx = tid; idx < 128*4; idx += 256) {
        int n  = idx >> 2;
        int k0 = (idx & 3) * 8;
        *reinterpret_cast<uint4*>(sWhi + n*LDA + k0) = *reinterpret_cast<const uint4*>(W1hi + (size_t)n*32 + k0);
        *reinterpret_cast<uint4*>(sWlo + n*LDA + k0) = *reinterpret_cast<const uint4*>(W1lo + (size_t)n*32 + k0);
    }
    __syncthreads();

    const int row0 = (wid & 1) * 32;
    const int col0 = (wid >> 1) * 32;
    uint32_t aB[2][2], bB[2][2];
    {
        int ar = (lane & 15), ac = (lane >> 4) * 8;
        #pragma unroll
        for (int mi = 0; mi < 2; mi++) {
            aB[0][mi] = smem_u32(sAhi + (row0 + mi*16 + ar)*LDA + ac);
            aB[1][mi] = smem_u32(sAlo + (row0 + mi*16 + ar)*LDA + ac);
        }
        int q  = lane >> 3;
        int nr = (q >> 1)*8 + (lane & 7);
        int nc = (q & 1)*8;
        #pragma unroll
        for (int nt = 0; nt < 2; nt++) {
            bB[0][nt] = smem_u32(sWhi + (col0 + nt*16 + nr)*LDA + nc);
            bB[1][nt] = smem_u32(sWlo + (col0 + nt*16 + nr)*LDA + nc);
        }
    }
    const int g = lane >> 2, t = lane & 3;

    float acc[2][4][4];
    #pragma unroll
    for (int mi = 0; mi < 2; mi++)
        #pragma unroll
        for (int ni = 0; ni < 4; ni++)
            { acc[mi][ni][0]=0.f; acc[mi][ni][1]=0.f; acc[mi][ni][2]=0.f; acc[mi][ni][3]=0.f; }

    #pragma unroll
    for (int ks = 0; ks < 2; ks++) {     // K=32
        uint32_t koff = (uint32_t)ks * 32u;
        uint32_t ah[2][4], al[2][4], bh[2][4], bl[2][4];
        #pragma unroll
        for (int mi = 0; mi < 2; mi++) { ldm_x4(ah[mi], aB[0][mi] + koff); ldm_x4(al[mi], aB[1][mi] + koff); }
        #pragma unroll
        for (int nt = 0; nt < 2; nt++) { ldm_x4(bh[nt], bB[0][nt] + koff); ldm_x4(bl[nt], bB[1][nt] + koff); }
        #pragma unroll
        for (int mi = 0; mi < 2; mi++)
            #pragma unroll
            for (int nt = 0; nt < 2; nt++) {
                mma_bf16(acc[mi][nt*2],   ah[mi], &bh[nt][0]);
                mma_bf16(acc[mi][nt*2+1], ah[mi], &bh[nt][2]);
                mma_bf16(acc[mi][nt*2],   ah[mi], &bl[nt][0]);
                mma_bf16(acc[mi][nt*2+1], ah[mi], &bl[nt][2]);
                mma_bf16(acc[mi][nt*2],   al[mi], &bh[nt][0]);
                mma_bf16(acc[mi][nt*2+1], al[mi], &bh[nt][2]);
            }
    }
    __syncthreads();

    #pragma unroll
    for (int mi = 0; mi < 2; mi++) {
        #pragma unroll
        for (int ni = 0; ni < 4; ni++) {
            int cc = col0 + ni*8 + t*2;
            float bx = b1[cc], by = b1[cc+1];
            float2 v0 = make_float2(fmaxf(acc[mi][ni][0] + bx, 0.f), fmaxf(acc[mi][ni][1] + by, 0.f));
            float2 v1 = make_float2(fmaxf(acc[mi][ni][2] + bx, 0.f), fmaxf(acc[mi][ni][3] + by, 0.f));
            int rl0 = row0 + mi*16 + g;
            __nv_bfloat16 a0 = __float2bfloat16(v0.x), a1 = __float2bfloat16(v0.y);
            __nv_bfloat16 c0 = __float2bfloat16(v1.x), c1 = __float2bfloat16(v1.y);
            *reinterpret_cast<__nv_bfloat162*>(sAhi + rl0*LDA + cc)     = __halves2bfloat162(a0, a1);
            *reinterpret_cast<__nv_bfloat162*>(sAlo + rl0*LDA + cc)     =
                __halves2bfloat162(__float2bfloat16(v0.x - __bfloat162float(a0)),
                                   __float2bfloat16(v0.y - __bfloat162float(a1)));
            *reinterpret_cast<__nv_bfloat162*>(sAhi + (rl0+8)*LDA + cc) = __halves2bfloat162(c0, c1);
            *reinterpret_cast<__nv_bfloat162*>(sAlo + (rl0+8)*LDA + cc) =
                __halves2bfloat162(__float2bfloat16(v1.x - __bfloat162float(c0)),
                                   __float2bfloat16(v1.y - __bfloat162float(c1)));
        }
    }
    for (int idx = tid; idx < 128*16; idx += 256) {
        int n  = idx >> 4;
        int k0 = (idx & 15) * 8;
        *reinterpret_cast<uint4*>(sWhi + n*LDA + k0) = *reinterpret_cast<const uint4*>(W2hi + (size_t)n*128 + k0);
        *reinterpret_cast<uint4*>(sWlo + n*LDA + k0) = *reinterpret_cast<const uint4*>(W2lo + (size_t)n*128 + k0);
    }
    __syncthreads();

    #pragma unroll
    for (int mi = 0; mi < 2; mi++)
        #pragma unroll
        for (int ni = 0; ni < 4; ni++)
            { acc[mi][ni][0]=0.f; acc[mi][ni][1]=0.f; acc[mi][ni][2]=0.f; acc[mi][ni][3]=0.f; }

    #pragma unroll 2
    for (int ks = 0; ks < 8; ks++) {
        uint32_t koff = (uint32_t)ks * 32u;
        uint32_t ah[2][4], al[2][4], bh[2][4], bl[2][4];
        #pragma unroll
        for (int mi = 0; mi < 2; mi++) { ldm_x4(ah[mi], aB[0][mi] + koff); ldm_x4(al[mi], aB[1][mi] + koff); }
        #pragma unroll
        for (int nt = 0; nt < 2; nt++) { ldm_x4(bh[nt], bB[0][nt] + koff); ldm_x4(bl[nt], bB[1][nt] + koff); }
        #pragma unroll
        for (int mi = 0; mi < 2; mi++)
            #pragma unroll
            for (int nt = 0; nt < 2; nt++) {
                mma_bf16(acc[mi][nt*2],   ah[mi], &bh[nt][0]);
                mma_bf16(acc[mi][nt*2+1], ah[mi], &bh[nt][2]);
                mma_bf16(acc[mi][nt*2],   ah[mi], &bl[nt][0]);
                mma_bf16(acc[mi][nt*2+1], ah[mi], &bl[nt][2]);
                mma_bf16(acc[mi][nt*2],   al[mi], &bh[nt][0]);
                mma_bf16(acc[mi][nt*2+1], al[mi], &bh[nt][2]);
            }
    }

    float lsS[2][2];
    lsS[0][0]=0.f; lsS[0][1]=0.f; lsS[1][0]=0.f; lsS[1][1]=0.f;
    #pragma unroll
    for (int mi = 0; mi < 2; mi++) {
        #pragma unroll
        for (int ni = 0; ni < 4; ni++) {
            int cc = col0 + ni*8 + t*2;
            int r1 = bm + row0 + mi*16 + g;
            float2 v0 = make_float2(acc[mi][ni][0], acc[mi][ni][1]);
            float2 v1 = make_float2(acc[mi][ni][2], acc[mi][ni][3]);
            float a0 = __ldg(attS + cc), a1 = __ldg(attS + cc + 1);
            lsS[mi][0] += v0.x*a0 + v0.y*a1;
            lsS[mi][1] += v1.x*a0 + v1.y*a1;
            if (r1 < M)     *reinterpret_cast<__half2*>(C + (size_t)r1*128 + cc)     = __floats2half2_rn(v0.x, v0.y);
            if (r1 + 8 < M) *reinterpret_cast<__half2*>(C + (size_t)(r1+8)*128 + cc) = __floats2half2_rn(v1.x, v1.y);
        }
    }
    #pragma unroll
    for (int mi = 0; mi < 2; mi++)
        #pragma unroll
        for (int rr = 0; rr < 2; rr++) {
            float v = lsS[mi][rr];
            v += __shfl_xor_sync(0xffffffffu, v, 1);
            v += __shfl_xor_sync(0xffffffffu, v, 2);
            lsS[mi][rr] = v;
        }
    if (t == 0) {
        int head = col0 >> 5;
        #pragma unroll
        for (int mi = 0; mi < 2; mi++)
            #pragma unroll
            for (int rr = 0; rr < 2; rr++) {
                int r = bm + row0 + mi*16 + g + rr*8;
                if (r < M) outS[(size_t)r*4 + head] = lsS[mi][rr];
            }
    }
}

// --------------------------------- CSR build ------------------------------------------------
__global__ void hist_all_kernel(const int* __restrict__ e0, const int* __restrict__ e1,
                                const int* __restrict__ ed)
{
    const int total = ETTg + ECTg;
    for (int i = blockIdx.x*blockDim.x + threadIdx.x; i < total; i += gridDim.x*blockDim.x) {
        if (i < ETTg) {
            atomicAdd(&g_deg[0*NTg + e1[i]], 1);
            atomicAdd(&g_deg[1*NTg + e0[i]], 1);
        } else {
            atomicAdd(&g_deg[2*NTg + ed[i - ETTg]], 1);
        }
    }
}

__global__ void scan1_kernel()
{
    int arr  = blockIdx.y;
    int base = blockIdx.x * 1024 + threadIdx.x;
    int lane = threadIdx.x & 31, wid = threadIdx.x >> 5;
    int v = (base < NTg) ? g_deg[arr*NTg + base] : 0;
    int x = v;
    #pragma unroll
    for (int o = 1; o < 32; o <<= 1) { int y = __shfl_up_sync(0xffffffffu, x, o); if (lane >= o) x += y; }
    __shared__ int ws[32];
    if (lane == 31) ws[wid] = x;
    __syncthreads();
    if (wid == 0) {
        int wv = ws[lane]; int wx = wv;
        #pragma unroll
        for (int o = 1; o < 32; o <<= 1) { int y = __shfl_up_sync(0xffffffffu, wx, o); if (lane >= o) wx += y; }
        if (lane == 31) g_aux[arr*128 + blockIdx.x] = wx;
        ws[lane] = wx - wv;
    }
    __syncthreads();
    int excl = x - v + ws[wid];
    if (base < NTg) g_cur[arr*NTg + base] = excl;
}

__global__ void scan2_kernel()
{
    int arr  = threadIdx.x >> 5;
    int lane = threadIdx.x & 31;
    if (arr >= 3) return;
    const int NB = (NTg + 1023) / 1024;
    int carry = 0;
    for (int c = 0; c*32 < NB; c++) {
        int idx = c*32 + lane;
        int v = (idx < NB) ? g_aux[arr*128 + idx] : 0;
        int x = v;
        #pragma unroll
        for (int o = 1; o < 32; o <<= 1) { int y = __shfl_up_sync(0xffffffffu, x, o); if (lane >= o) x += y; }
        if (idx < NB) g_aux[arr*128 + idx] = x - v + carry;
        carry += __shfl_sync(0xffffffffu, x, 31);
    }
}

__global__ void scan3_kernel()
{
    for (int i = blockIdx.x*blockDim.x + threadIdx.x; i < 3*NTg; i += gridDim.x*blockDim.x) {
        int arr = i / NTg; int idx = i - arr*NTg;
        g_cur[i] += g_aux[arr*128 + (idx >> 10)];
    }
}

__global__ void fill_all_kernel(const int* __restrict__ e0, const int* __restrict__ e1,
                                const int* __restrict__ es, const int* __restrict__ ed)
{
    const int total = ETTg + ECTg;
    for (int i = blockIdx.x*blockDim.x + threadIdx.x; i < total; i += gridDim.x*blockDim.x) {
        if (i < ETTg) {
            int s = e0[i], d = e1[i];
            int p = atomicAdd(&g_cur[0*NTg + d], 1); g_csrf[p] = s;
            int q = atomicAdd(&g_cur[1*NTg + s], 1); g_csrr[q] = d;
        } else {
            int j = i - ETTg;
            int p = atomicAdd(&g_cur[2*NTg + ed[j]], 1); g_csrct[p] = es[j];
        }
    }
}

// ----- per-relation GAT, half2 layout: lane owns cols {2l,2l+1} (head l>=16) and {64+2l,..} --
template<bool SELF>
__device__ __forceinline__ void gat_rel(
    const __half* __restrict__ hsrc, const float* __restrict__ a_s,
    const int* __restrict__ csr, int start, int cnt, int d, int lane,
    float4 ad, float wgt, float r[4])
{
    if (!SELF && cnt == 0) { r[0]=0.f; r[1]=0.f; r[2]=0.f; r[3]=0.f; return; }

    const bool hi16 = (lane >= 16);
    const float adA = hi16 ? ad.y : ad.x;
    const float adB = hi16 ? ad.w : ad.z;

    float denA = 0.f, denB = 0.f;
    float2 acA = make_float2(0.f, 0.f), acB = make_float2(0.f, 0.f);

    if (SELF) {
        float4 as = *reinterpret_cast<const float4*>(a_s + (size_t)d*4);
        float pa = __expf(lrelu02((hi16 ? as.y : as.x) + adA));
        float pb = __expf(lrelu02((hi16 ? as.w : as.z) + adB));
        denA = pa; denB = pb;
        const __half2* row2 = reinterpret_cast<const __half2*>(hsrc + (size_t)d*128);
        float2 fa = __half22float2(row2[lane]);
        float2 fb = __half22float2(row2[32 + lane]);
        acA.x = pa * fa.x; acA.y = pa * fa.y;
        acB.x = pb * fb.x; acB.y = pb * fb.y;
    }
    #pragma unroll 2
    for (int i = 0; i < cnt; i++) {
        int s = csr[start + i];
        float4 as = *reinterpret_cast<const float4*>(a_s + (size_t)s*4);
        float pa = __expf(lrelu02((hi16 ? as.y : as.x) + adA));
        float pb = __expf(lrelu02((hi16 ? as.w : as.z) + adB));
        denA += pa; denB += pb;
        const __half2* row2 = reinterpret_cast<const __half2*>(hsrc + (size_t)s*128);
        float2 fa = __half22float2(row2[lane]);
        float2 fb = __half22float2(row2[32 + lane]);
        acA.x = fmaf(pa, fa.x, acA.x); acA.y = fmaf(pa, fa.y, acA.y);
        acB.x = fmaf(pb, fb.x, acB.x); acB.y = fmaf(pb, fb.y, acB.y);
    }

    float ia = wgt / denA, ib = wgt / denB;
    r[0] = acA.x * ia; r[1] = acA.y * ia;
    r[2] = acB.x * ib; r[3] = acB.y * ib;
}

// --- merged GAT over all 3 relations; writes z = relu(acc + cbias + ht) (half2 lane map) ----
__global__ void gat_all_kernel(
    const __half* __restrict__ hs, const __half* __restrict__ hd, const __half* __restrict__ hcs,
    const float* __restrict__ ht,
    const float* __restrict__ asf, const float* __restrict__ adf,
    const float* __restrict__ asr, const float* __restrict__ adr,
    const float* __restrict__ asct, const float* __restrict__ adct,
    const int* __restrict__ cur, const int* __restrict__ deg,
    const int* __restrict__ csrf, const int* __restrict__ csrr, const int* __restrict__ csrct,
    const float* __restrict__ bsd, const float* __restrict__ bds, const float* __restrict__ bct,
    float* __restrict__ z)
{
    int d    = (blockIdx.x * blockDim.x + threadIdx.x) >> 5;
    int lane = threadIdx.x & 31;
    if (d >= NTg) return;

    float rf[4], rr_[4], rc[4];
    {
        int c = deg[0*NTg + d];
        gat_rel<true >(hs, asf, csrf, cur[0*NTg + d] - c, c, d, lane,
                       *reinterpret_cast<const float4*>(adf + (size_t)d*4), 0.25f, rf);
    }
    {
        int c = deg[1*NTg + d];
        gat_rel<true >(hd, asr, csrr, cur[1*NTg + d] - c, c, d, lane,
                       *reinterpret_cast<const float4*>(adr + (size_t)d*4), 0.25f, rr_);
    }
    {
        int c = deg[2*NTg + d];
        gat_rel<false>(hcs, asct, csrct, cur[2*NTg + d] - c, c, d, lane,
                       *reinterpret_cast<const float4*>(adct + (size_t)d*4), 0.5f, rc);
    }

    int cA = 2*lane, cB = 64 + 2*lane;
    const float2* hrow2 = reinterpret_cast<const float2*>(ht + (size_t)d*128);
    float2 ha = hrow2[lane], hb = hrow2[32 + lane];
    float cbA0 = 0.25f*bsd[cA]   + 0.25f*bds[cA]   + 0.5f*bct[cA];
    float cbA1 = 0.25f*bsd[cA+1] + 0.25f*bds[cA+1] + 0.5f*bct[cA+1];
    float cbB0 = 0.25f*bsd[cB]   + 0.25f*bds[cB]   + 0.5f*bct[cB];
    float cbB1 = 0.25f*bsd[cB+1] + 0.25f*bds[cB+1] + 0.5f*bct[cB+1];

    float2* zrow2 = reinterpret_cast<float2*>(z + (size_t)d*128);
    float2 za, zb;
    za.x = fmaxf(rf[0] + rr_[0] + rc[0] + ha.x + cbA0, 0.f);
    za.y = fmaxf(rf[1] + rr_[1] + rc[1] + ha.y + cbA1, 0.f);
    zb.x = fmaxf(rf[2] + rr_[2] + rc[2] + hb.x + cbB0, 0.f);
    zb.y = fmaxf(rf[3] + rr_[3] + rc[3] + hb.y + cbB1, 0.f);
    zrow2[lane]      = za;
    zrow2[32 + lane] = zb;
}

// ----------------------------------- launch -------------------------------------------------
extern "C" void kernel_launch(void* const* d_in, const int* in_sizes, int n_in,
                              void* d_out, int out_size)
{
    const float* x_t     = (const float*)d_in[0];
    const float* x_c     = (const float*)d_in[1];
    const int*   ett     = (const int*)d_in[2];
    const int*   e0      = ett;
    const int*   e1      = ett + ETTg;
    const int*   ect_s   = (const int*)d_in[3];
    const int*   ect_d   = (const int*)d_in[4];
    const float* W_pre_t = (const float*)d_in[5];
    const float* b_pre_t = (const float*)d_in[6];
    const float* W_pre_c = (const float*)d_in[7];
    const float* b_pre_c = (const float*)d_in[8];
    const float* W_sd    = (const float*)d_in[9];
    const float* att_s_sd= (const float*)d_in[10];
    const float* att_d_sd= (const float*)d_in[11];
    const float* b_sd    = (const float*)d_in[12];
    const float* W_ds    = (const float*)d_in[13];
    const float* att_s_ds= (const float*)d_in[14];
    const float* att_d_ds= (const float*)d_in[15];
    const float* b_ds    = (const float*)d_in[16];
    const float* W_ct_s  = (const float*)d_in[17];
    const float* W_ct_d  = (const float*)d_in[18];
    const float* att_s_ct= (const float*)d_in[19];
    const float* att_d_ct= (const float*)d_in[20];
    const float* b_ct    = (const float*)d_in[21];
    const float* W_out   = (const float*)d_in[22];
    const float* b_out   = (const float*)d_in[23];
    float* out = (float*)d_out;

    float *p_ht, *p_z, *p_wv;
    __half *p_hs, *p_hd, *p_hcs;
    float *p_asf, *p_adf, *p_asr, *p_adr, *p_adct, *p_asct;
    int *p_deg, *p_cur, *p_csrf, *p_csrr, *p_csrct;
    __nv_bfloat16 *p_whi, *p_wlo;
    cudaGetSymbolAddress((void**)&p_ht,  g_ht);
    cudaGetSymbolAddress((void**)&p_hs,  g_hs);
    cudaGetSymbolAddress((void**)&p_hd,  g_hd);
    cudaGetSymbolAddress((void**)&p_hcs, g_hcs);
    cudaGetSymbolAddress((void**)&p_z,   g_z);
    cudaGetSymbolAddress((void**)&p_wv,  g_wv);
    cudaGetSymbolAddress((void**)&p_asf, g_asf);
    cudaGetSymbolAddress((void**)&p_adf, g_adf);
    cudaGetSymbolAddress((void**)&p_asr, g_asr);
    cudaGetSymbolAddress((void**)&p_adr, g_adr);
    cudaGetSymbolAddress((void**)&p_adct,g_adct);
    cudaGetSymbolAddress((void**)&p_asct,g_asct);
    cudaGetSymbolAddress((void**)&p_deg, g_deg);
    cudaGetSymbolAddress((void**)&p_cur, g_cur);
    cudaGetSymbolAddress((void**)&p_csrf, g_csrf);
    cudaGetSymbolAddress((void**)&p_csrr, g_csrr);
    cudaGetSymbolAddress((void**)&p_csrct,g_csrct);
    cudaGetSymbolAddress((void**)&p_whi, g_whi);
    cudaGetSymbolAddress((void**)&p_wlo, g_wlo);

    const int SM128 = (2*64 + 2*128) * (128 + 8) * 2;   // 104448
    cudaFuncSetAttribute(tc_gemm_triple,          cudaFuncAttributeMaxDynamicSharedMemorySize, SM128 + 4096);
    cudaFuncSetAttribute(tc_gemm_chain,           cudaFuncAttributeMaxDynamicSharedMemorySize, SM128);
    cudaFuncSetAttribute(tc_gemm<128,false,true>, cudaFuncAttributeMaxDynamicSharedMemorySize, SM128);

    const int GT = (NTg + 63) / 64;   // 1563
    const int GC = (NCg + 63) / 64;   // 391

    WJobs jobs;
    jobs.W[0] = W_pre_t; jobs.K[0] = 64;
    jobs.W[1] = W_pre_c; jobs.K[1] = 32;
    jobs.W[2] = W_sd;    jobs.K[2] = 128;
    jobs.W[3] = W_ds;    jobs.K[3] = 128;
    jobs.W[4] = W_ct_s;  jobs.K[4] = 128;
    jobs.W[5] = W_out;   jobs.K[5] = 128;

    // Second stream for the CSR branch (created once; host-side objects only).
    static cudaStream_t s2 = nullptr;
    static cudaEvent_t evFork = nullptr, evJoin = nullptr;
    if (!s2) {
        cudaStreamCreateWithFlags(&s2, cudaStreamNonBlocking);
        cudaEventCreateWithFlags(&evFork, cudaEventDisableTiming);
        cudaEventCreateWithFlags(&evJoin, cudaEventDisableTiming);
    }

    // ---- fork: CSR branch on s2 (independent of all GEMM work) ----
    cudaEventRecord(evFork, 0);
    cudaStreamWaitEvent(s2, evFork, 0);
    cudaMemsetAsync(p_deg, 0, 3*NTg*sizeof(int), s2);
    hist_all_kernel<<<768, 256, 0, s2>>>(e0, e1, ect_d);
    {
        dim3 g1((NTg + 1023) / 1024, 3);
        scan1_kernel<<<g1, 1024, 0, s2>>>();
    }
    scan2_kernel<<<1, 96, 0, s2>>>();
    scan3_kernel<<<256, 256, 0, s2>>>();
    fill_all_kernel<<<768, 256, 0, s2>>>(e0, e1, ect_s, ect_d);
    cudaEventRecord(evJoin, s2);

    // ---- main branch: GEMM phase ----
    wv_kernel<<<1, 512>>>(W_ct_d, att_d_ct, p_wv);
    wsplit_all<<<dim3(64, 6), 256>>>(jobs, p_whi, p_wlo);
    tc_gemm_triple<<<GT, 256, SM128 + 4096>>>(x_t,
        p_whi + 0*16384, p_wlo + 0*16384, b_pre_t, p_wv, p_ht, p_adct,
        p_whi + 2*16384, p_wlo + 2*16384, p_whi + 3*16384, p_wlo + 3*16384,
        p_hs, p_hd, NTg,
        att_s_sd, att_d_sd, att_s_ds, att_d_ds,
        p_asf, p_adf, p_asr, p_adr);
    tc_gemm_chain<<<GC, 256, SM128>>>(x_c,
        p_whi + 1*16384, p_wlo + 1*16384, b_pre_c,
        p_whi + 4*16384, p_wlo + 4*16384,
        p_hcs, NCg, att_s_ct, p_asct);

    // ---- join: GAT needs both branches ----
    cudaStreamWaitEvent(0, evJoin, 0);

    gat_all_kernel<<<(NTg + 7) / 8, 256>>>(
        p_hs, p_hd, p_hcs, p_ht,
        p_asf, p_adf, p_asr, p_adr, p_asct, p_adct,
        p_cur, p_deg, p_csrf, p_csrr, p_csrct,
        b_sd, b_ds, b_ct, p_z);

    tc_gemm<128,false,true><<<GT, 256, SM128>>>(p_z, p_whi + 5*16384, p_wlo + 5*16384,
        b_out, out, NTg);
}

// round 15
// speedup vs baseline: 1.6090x; 1.0569x over previous
#include <cuda_runtime.h>
#include <cuda_bf16.h>
#include <cuda_fp16.h>
#include <cstdint>

#define NTg  100000
#define NCg  25000
#define ETTg 800000
#define ECTg 400000
#define HIDg 128

// ------------------------- scratch (device globals; allocation-free) -------------------------
__device__ float  g_ht [NTg*HIDg];
__device__ __half g_hs [NTg*HIDg];
__device__ __half g_hd [NTg*HIDg];
__device__ __half g_hcs[NCg*HIDg];
__device__ __half g_z  [NTg*HIDg];
__device__ float g_asf[NTg*4];
__device__ float g_adf[NTg*4];
__device__ float g_asr[NTg*4];
__device__ float g_adr[NTg*4];
__device__ float g_adct[NTg*4];
__device__ float g_asct[NCg*4];
__device__ float g_wv [4*128];
__device__ int   g_deg[3*NTg];
__device__ int   g_cur[3*NTg];
__device__ int   g_aux[3*128];
__device__ int   g_csrf[ETTg];
__device__ int   g_csrr[ETTg];
__device__ int   g_csrct[ECTg];
// split weights: 6 slots of up to 128x128 bf16 ([N,K] layout, i.e., W^T)
__device__ __nv_bfloat16 g_whi[6*128*128];
__device__ __nv_bfloat16 g_wlo[6*128*128];

__device__ __forceinline__ float lrelu02(float x) { return x > 0.f ? x : 0.2f * x; }

__device__ __forceinline__ uint32_t smem_u32(const void* p) {
    uint32_t a;
    asm("{ .reg .u64 t; cvta.to.shared.u64 t, %1; cvt.u32.u64 %0, t; }" : "=r"(a) : "l"(p));
    return a;
}

__device__ __forceinline__ void ldm_x4(uint32_t* r, uint32_t addr) {
    asm volatile("ldmatrix.sync.aligned.m8n8.x4.shared.b16 {%0,%1,%2,%3}, [%4];"
                 : "=r"(r[0]), "=r"(r[1]), "=r"(r[2]), "=r"(r[3]) : "r"(addr));
}
__device__ __forceinline__ void mma_bf16(float* c, const uint32_t* a, const uint32_t* b) {
    asm volatile("mma.sync.aligned.m16n8k16.row.col.f32.bf16.bf16.f32 "
                 "{%0,%1,%2,%3}, {%4,%5,%6,%7}, {%8,%9}, {%0,%1,%2,%3};"
                 : "+f"(c[0]), "+f"(c[1]), "+f"(c[2]), "+f"(c[3])
                 : "r"(a[0]), "r"(a[1]), "r"(a[2]), "r"(a[3]), "r"(b[0]), "r"(b[1]));
}

// ------------------- batched W split/transpose: hi/lo[n*K+k] = split(W[k*128+n]) ------------
struct WJobs { const float* W[6]; int K[6]; };

__global__ void wsplit_all(WJobs jobs, __nv_bfloat16* __restrict__ hiB,
                           __nv_bfloat16* __restrict__ loB)
{
    int slot = blockIdx.y;
    const float* W = jobs.W[slot];
    int K = jobs.K[slot];
    __nv_bfloat16* hi = hiB + slot*16384;
    __nv_bfloat16* lo = loB + slot*16384;
    int tot = 128 * K;
    for (int i = blockIdx.x*blockDim.x + threadIdx.x; i < tot; i += gridDim.x*blockDim.x) {
        int n = i / K, k = i - n*K;
        float v = W[k*128 + n];
        __nv_bfloat16 h = __float2bfloat16(v);
        hi[i] = h;
        lo[i] = __float2bfloat16(v - __bfloat162float(h));
    }
}

// ----------------- wv[h*128+k] = sum_c W_ct_dst[k*128 + h*32 + c] * att[h*32+c] -------------
__global__ void wv_kernel(const float* __restrict__ W, const float* __restrict__ att,
                          float* __restrict__ wv)
{
    int i = threadIdx.x;           // 512 threads: k = i>>2, h = i&3
    int k = i >> 2, h = i & 3;
    float s = 0.f;
    #pragma unroll 8
    for (int c = 0; c < 32; c++) s += W[k*128 + h*32 + c] * att[h*32 + c];
    wv[h*128 + k] = s;
}

// -------- final HMMA GEMM (fp16 A): out = z @ W_out + b  (exact fp16->bf16 hi/lo split) ------
__global__ void __launch_bounds__(256, 2) tc_gemm_h(
    const __half* __restrict__ A, const __nv_bfloat16* __restrict__ Whi,
    const __nv_bfloat16* __restrict__ Wlo, const float* __restrict__ bias,
    float* __restrict__ C, int M)
{
    constexpr int K = 128, LDA = K + 8;
    extern __shared__ __nv_bfloat16 smb[];
    __nv_bfloat16* sAhi = smb;
    __nv_bfloat16* sAlo = sAhi + 64*LDA;
    __nv_bfloat16* sWhi = sAlo + 64*LDA;
    __nv_bfloat16* sWlo = sWhi + 128*LDA;

    const int tid  = threadIdx.x;
    const int lane = tid & 31;
    const int wid  = tid >> 5;
    const int bm   = blockIdx.x * 64;

    for (int idx = tid; idx < 64*(K/8); idx += 256) {
        int r  = idx / (K/8);
        int k0 = (idx % (K/8)) * 8;
        int row = bm + r;
        uint4 raw = make_uint4(0u, 0u, 0u, 0u);
        if (row < M) raw = *reinterpret_cast<const uint4*>(A + (size_t)row*K + k0);
        const __half* hsrc = reinterpret_cast<const __half*>(&raw);
        __nv_bfloat16 hiv[8], lov[8];
        #pragma unroll
        for (int j = 0; j < 8; j++) {
            float v = __half2float(hsrc[j]);
            __nv_bfloat16 h = __float2bfloat16(v);
            hiv[j] = h;
            lov[j] = __float2bfloat16(v - __bfloat162float(h));
        }
        __nv_bfloat16* pH = sAhi + r*LDA + k0;
        __nv_bfloat16* pL = sAlo + r*LDA + k0;
        #pragma unroll
        for (int j = 0; j < 4; j++) {
            *reinterpret_cast<__nv_bfloat162*>(pH + 2*j) = __halves2bfloat162(hiv[2*j], hiv[2*j+1]);
            *reinterpret_cast<__nv_bfloat162*>(pL + 2*j) = __halves2bfloat162(lov[2*j], lov[2*j+1]);
        }
    }
    for (int idx = tid; idx < 128*(K/8); idx += 256) {
        int n  = idx / (K/8);
        int k0 = (idx % (K/8)) * 8;
        *reinterpret_cast<uint4*>(sWhi + n*LDA + k0) = *reinterpret_cast<const uint4*>(Whi + (size_t)n*K + k0);
        *reinterpret_cast<uint4*>(sWlo + n*LDA + k0) = *reinterpret_cast<const uint4*>(Wlo + (size_t)n*K + k0);
    }
    __syncthreads();

    const int row0 = (wid & 1) * 32;
    const int col0 = (wid >> 1) * 32;

    uint32_t aB[2][2], bB[2][2];
    {
        int ar = (lane & 15), ac = (lane >> 4) * 8;
        #pragma unroll
        for (int mi = 0; mi < 2; mi++) {
            aB[0][mi] = smem_u32(sAhi + (row0 + mi*16 + ar)*LDA + ac);
            aB[1][mi] = smem_u32(sAlo + (row0 + mi*16 + ar)*LDA + ac);
        }
        int q  = lane >> 3;
        int nr = (q >> 1)*8 + (lane & 7);
        int nc = (q & 1)*8;
        #pragma unroll
        for (int nt = 0; nt < 2; nt++) {
            bB[0][nt] = smem_u32(sWhi + (col0 + nt*16 + nr)*LDA + nc);
            bB[1][nt] = smem_u32(sWlo + (col0 + nt*16 + nr)*LDA + nc);
        }
    }

    float acc[2][4][4];
    #pragma unroll
    for (int mi = 0; mi < 2; mi++)
        #pragma unroll
        for (int ni = 0; ni < 4; ni++)
            { acc[mi][ni][0]=0.f; acc[mi][ni][1]=0.f; acc[mi][ni][2]=0.f; acc[mi][ni][3]=0.f; }

    #pragma unroll 2
    for (int ks = 0; ks < K/16; ks++) {
        uint32_t koff = (uint32_t)ks * 32u;
        uint32_t ah[2][4], al[2][4], bh[2][4], bl[2][4];
        #pragma unroll
        for (int mi = 0; mi < 2; mi++) { ldm_x4(ah[mi], aB[0][mi] + koff); ldm_x4(al[mi], aB[1][mi] + koff); }
        #pragma unroll
        for (int nt = 0; nt < 2; nt++) { ldm_x4(bh[nt], bB[0][nt] + koff); ldm_x4(bl[nt], bB[1][nt] + koff); }
        #pragma unroll
        for (int mi = 0; mi < 2; mi++)
            #pragma unroll
            for (int nt = 0; nt < 2; nt++) {
                mma_bf16(acc[mi][nt*2],   ah[mi], &bh[nt][0]);
                mma_bf16(acc[mi][nt*2+1], ah[mi], &bh[nt][2]);
                mma_bf16(acc[mi][nt*2],   ah[mi], &bl[nt][0]);
                mma_bf16(acc[mi][nt*2+1], ah[mi], &bl[nt][2]);
                mma_bf16(acc[mi][nt*2],   al[mi], &bh[nt][0]);
                mma_bf16(acc[mi][nt*2+1], al[mi], &bh[nt][2]);
            }
    }

    const int g = lane >> 2, t = lane & 3;
    #pragma unroll
    for (int mi = 0; mi < 2; mi++) {
        #pragma unroll
        for (int ni = 0; ni < 4; ni++) {
            int cc = col0 + ni*8 + t*2;
            float bx = bias[cc], by = bias[cc+1];
            int r1 = bm + row0 + mi*16 + g;
            float2 v0 = make_float2(acc[mi][ni][0] + bx, acc[mi][ni][1] + by);
            float2 v1 = make_float2(acc[mi][ni][2] + bx, acc[mi][ni][3] + by);
            if (r1 < M)     *reinterpret_cast<float2*>(C + (size_t)r1*128 + cc)     = v0;
            if (r1 + 8 < M) *reinterpret_cast<float2*>(C + (size_t)(r1+8)*128 + cc) = v1;
        }
    }
}

// -------- TRIPLE: ht = relu(x_t@W0 + b0) (K=64) -> [resident] -> hs, hd + all logits --------
__global__ void __launch_bounds__(256, 2) tc_gemm_triple(
    const float* __restrict__ xt,
    const __nv_bfloat16* __restrict__ W0hi, const __nv_bfloat16* __restrict__ W0lo,
    const float* __restrict__ b0, const float* __restrict__ wv,
    float* __restrict__ htO, float* __restrict__ adct,
    const __nv_bfloat16* __restrict__ Whi0, const __nv_bfloat16* __restrict__ Wlo0,
    const __nv_bfloat16* __restrict__ Whi1, const __nv_bfloat16* __restrict__ Wlo1,
    __half* __restrict__ C0, __half* __restrict__ C1, int M,
    const float* __restrict__ attS0, const float* __restrict__ attD0,
    const float* __restrict__ attS1, const float* __restrict__ attD1,
    float* __restrict__ outS0, float* __restrict__ outD0,
    float* __restrict__ outS1, float* __restrict__ outD1)
{
    constexpr int LDA = 136;
    extern __shared__ __nv_bfloat16 smb[];
    __nv_bfloat16* sAhi = smb;
    __nv_bfloat16* sAlo = sAhi + 64*LDA;
    __nv_bfloat16* sWhi = sAlo + 64*LDA;
    __nv_bfloat16* sWlo = sWhi + 128*LDA;
    float* sRed = reinterpret_cast<float*>(smb + (size_t)(2*64 + 2*128)*LDA);  // [64][16]

    const int tid  = threadIdx.x;
    const int lane = tid & 31;
    const int wid  = tid >> 5;
    const int bm   = blockIdx.x * 64;

    for (int idx = tid; idx < 64*16; idx += 256) {
        int r  = idx >> 4;
        int k0 = (idx & 15) * 4;
        int row = bm + r;
        float4 v = make_float4(0.f, 0.f, 0.f, 0.f);
        if (row < M) v = *reinterpret_cast<const float4*>(xt + (size_t)row*64 + k0);
        __nv_bfloat16 h0 = __float2bfloat16(v.x), h1 = __float2bfloat16(v.y);
        __nv_bfloat16 h2 = __float2bfloat16(v.z), h3 = __float2bfloat16(v.w);
        __nv_bfloat16 l0 = __float2bfloat16(v.x - __bfloat162float(h0));
        __nv_bfloat16 l1 = __float2bfloat16(v.y - __bfloat162float(h1));
        __nv_bfloat16 l2 = __float2bfloat16(v.z - __bfloat162float(h2));
        __nv_bfloat16 l3 = __float2bfloat16(v.w - __bfloat162float(h3));
        __nv_bfloat16* pH = sAhi + r*LDA + k0;
        __nv_bfloat16* pL = sAlo + r*LDA + k0;
        *reinterpret_cast<__nv_bfloat162*>(pH)     = __halves2bfloat162(h0, h1);
        *reinterpret_cast<__nv_bfloat162*>(pH + 2) = __halves2bfloat162(h2, h3);
        *reinterpret_cast<__nv_bfloat162*>(pL)     = __halves2bfloat162(l0, l1);
        *reinterpret_cast<__nv_bfloat162*>(pL + 2) = __halves2bfloat162(l2, l3);
    }
    for (int idx = tid; idx < 128*8; idx += 256) {
        int n  = idx >> 3;
        int k0 = (idx & 7) * 8;
        *reinterpret_cast<uint4*>(sWhi + n*LDA + k0) = *reinterpret_cast<const uint4*>(W0hi + (size_t)n*64 + k0);
        *reinterpret_cast<uint4*>(sWlo + n*LDA + k0) = *reinterpret_cast<const uint4*>(W0lo + (size_t)n*64 + k0);
    }
    __syncthreads();

    const int row0 = (wid & 1) * 32;
    const int col0 = (wid >> 1) * 32;
    uint32_t aB[2][2], bB[2][2];
    {
        int ar = (lane & 15), ac = (lane >> 4) * 8;
        #pragma unroll
        for (int mi = 0; mi < 2; mi++) {
            aB[0][mi] = smem_u32(sAhi + (row0 + mi*16 + ar)*LDA + ac);
            aB[1][mi] = smem_u32(sAlo + (row0 + mi*16 + ar)*LDA + ac);
        }
        int q  = lane >> 3;
        int nr = (q >> 1)*8 + (lane & 7);
        int nc = (q & 1)*8;
        #pragma unroll
        for (int nt = 0; nt < 2; nt++) {
            bB[0][nt] = smem_u32(sWhi + (col0 + nt*16 + nr)*LDA + nc);
            bB[1][nt] = smem_u32(sWlo + (col0 + nt*16 + nr)*LDA + nc);
        }
    }
    const int g = lane >> 2, t = lane & 3;

    float acc[2][4][4];
    #pragma unroll
    for (int mi = 0; mi < 2; mi++)
        #pragma unroll
        for (int ni = 0; ni < 4; ni++)
            { acc[mi][ni][0]=0.f; acc[mi][ni][1]=0.f; acc[mi][ni][2]=0.f; acc[mi][ni][3]=0.f; }

    #pragma unroll
    for (int ks = 0; ks < 4; ks++) {     // K=64
        uint32_t koff = (uint32_t)ks * 32u;
        uint32_t ah[2][4], al[2][4], bh[2][4], bl[2][4];
        #pragma unroll
        for (int mi = 0; mi < 2; mi++) { ldm_x4(ah[mi], aB[0][mi] + koff); ldm_x4(al[mi], aB[1][mi] + koff); }
        #pragma unroll
        for (int nt = 0; nt < 2; nt++) { ldm_x4(bh[nt], bB[0][nt] + koff); ldm_x4(bl[nt], bB[1][nt] + koff); }
        #pragma unroll
        for (int mi = 0; mi < 2; mi++)
            #pragma unroll
            for (int nt = 0; nt < 2; nt++) {
                mma_bf16(acc[mi][nt*2],   ah[mi], &bh[nt][0]);
                mma_bf16(acc[mi][nt*2+1], ah[mi], &bh[nt][2]);
                mma_bf16(acc[mi][nt*2],   ah[mi], &bl[nt][0]);
                mma_bf16(acc[mi][nt*2+1], ah[mi], &bl[nt][2]);
                mma_bf16(acc[mi][nt*2],   al[mi], &bh[nt][0]);
                mma_bf16(acc[mi][nt*2+1], al[mi], &bh[nt][2]);
            }
    }

    float lsA[2][2][4];
    #pragma unroll
    for (int a = 0; a < 2; a++)
        #pragma unroll
        for (int b = 0; b < 2; b++)
            #pragma unroll
            for (int h = 0; h < 4; h++) lsA[a][b][h] = 0.f;

    #pragma unroll
    for (int mi = 0; mi < 2; mi++) {
        #pragma unroll
        for (int ni = 0; ni < 4; ni++) {
            int cc = col0 + ni*8 + t*2;
            float bx = b0[cc], by = b0[cc+1];
            float2 v0 = make_float2(fmaxf(acc[mi][ni][0] + bx, 0.f), fmaxf(acc[mi][ni][1] + by, 0.f));
            float2 v1 = make_float2(fmaxf(acc[mi][ni][2] + bx, 0.f), fmaxf(acc[mi][ni][3] + by, 0.f));
            acc[mi][ni][0] = v0.x; acc[mi][ni][1] = v0.y;
            acc[mi][ni][2] = v1.x; acc[mi][ni][3] = v1.y;
            int r1 = bm + row0 + mi*16 + g;
            if (r1 < M)     *reinterpret_cast<float2*>(htO + (size_t)r1*128 + cc)     = v0;
            if (r1 + 8 < M) *reinterpret_cast<float2*>(htO + (size_t)(r1+8)*128 + cc) = v1;
            #pragma unroll
            for (int h = 0; h < 4; h++) {
                float w0 = __ldg(wv + h*128 + cc), w1 = __ldg(wv + h*128 + cc + 1);
                lsA[mi][0][h] += v0.x*w0 + v0.y*w1;
                lsA[mi][1][h] += v1.x*w0 + v1.y*w1;
            }
        }
    }
    #pragma unroll
    for (int mi = 0; mi < 2; mi++)
        #pragma unroll
        for (int rr = 0; rr < 2; rr++)
            #pragma unroll
            for (int h = 0; h < 4; h++) {
                float v = lsA[mi][rr][h];
                v += __shfl_xor_sync(0xffffffffu, v, 1);
                v += __shfl_xor_sync(0xffffffffu, v, 2);
                lsA[mi][rr][h] = v;
            }

    __syncthreads();

    #pragma unroll
    for (int mi = 0; mi < 2; mi++) {
        #pragma unroll
        for (int ni = 0; ni < 4; ni++) {
            int cc = col0 + ni*8 + t*2;
            int rl0 = row0 + mi*16 + g;
            float2 v0 = make_float2(acc[mi][ni][0], acc[mi][ni][1]);
            float2 v1 = make_float2(acc[mi][ni][2], acc[mi][ni][3]);
            __nv_bfloat16 a0 = __float2bfloat16(v0.x), a1 = __float2bfloat16(v0.y);
            __nv_bfloat16 c0 = __float2bfloat16(v1.x), c1 = __float2bfloat16(v1.y);
            *reinterpret_cast<__nv_bfloat162*>(sAhi + rl0*LDA + cc)     = __halves2bfloat162(a0, a1);
            *reinterpret_cast<__nv_bfloat162*>(sAlo + rl0*LDA + cc)     =
                __halves2bfloat162(__float2bfloat16(v0.x - __bfloat162float(a0)),
                                   __float2bfloat16(v0.y - __bfloat162float(a1)));
            *reinterpret_cast<__nv_bfloat162*>(sAhi + (rl0+8)*LDA + cc) = __halves2bfloat162(c0, c1);
            *reinterpret_cast<__nv_bfloat162*>(sAlo + (rl0+8)*LDA + cc) =
                __halves2bfloat162(__float2bfloat16(v1.x - __bfloat162float(c0)),
                                   __float2bfloat16(v1.y - __bfloat162float(c1)));
        }
    }
    {
        int cg = wid >> 1;
        if (t == 0) {
            #pragma unroll
            for (int mi = 0; mi < 2; mi++)
                #pragma unroll
                for (int rr = 0; rr < 2; rr++) {
                    int lr = row0 + mi*16 + g + rr*8;
                    #pragma unroll
                    for (int h = 0; h < 4; h++)
                        sRed[lr*16 + cg*4 + h] = lsA[mi][rr][h];
                }
        }
    }
    __syncthreads();
    {
        int lr = tid >> 2, h = tid & 3;
        float s = sRed[lr*16 + h] + sRed[lr*16 + 4 + h]
                + sRed[lr*16 + 8 + h] + sRed[lr*16 + 12 + h];
        int r = bm + lr;
        if (r < M) adct[(size_t)r*4 + h] = s;
    }

    #pragma unroll
    for (int slot = 0; slot < 2; slot++) {
        const __nv_bfloat16* Whi = slot ? Whi1 : Whi0;
        const __nv_bfloat16* Wlo = slot ? Wlo1 : Wlo0;
        __half* C = slot ? C1 : C0;
        const float* attS = slot ? attS1 : attS0;
        const float* attD = slot ? attD1 : attD0;
        float* outS = slot ? outS1 : outS0;
        float* outD = slot ? outD1 : outD0;

        for (int idx = tid; idx < 128*16; idx += 256) {
            int n  = idx >> 4;
            int k0 = (idx & 15) * 8;
            *reinterpret_cast<uint4*>(sWhi + n*LDA + k0) = *reinterpret_cast<const uint4*>(Whi + (size_t)n*128 + k0);
            *reinterpret_cast<uint4*>(sWlo + n*LDA + k0) = *reinterpret_cast<const uint4*>(Wlo + (size_t)n*128 + k0);
        }
        __syncthreads();

        #pragma unroll
        for (int mi = 0; mi < 2; mi++)
            #pragma unroll
            for (int ni = 0; ni < 4; ni++)
                { acc[mi][ni][0]=0.f; acc[mi][ni][1]=0.f; acc[mi][ni][2]=0.f; acc[mi][ni][3]=0.f; }

        #pragma unroll 2
        for (int ks = 0; ks < 8; ks++) {
            uint32_t koff = (uint32_t)ks * 32u;
            uint32_t ah[2][4], al[2][4], bh[2][4], bl[2][4];
            #pragma unroll
            for (int mi = 0; mi < 2; mi++) { ldm_x4(ah[mi], aB[0][mi] + koff); ldm_x4(al[mi], aB[1][mi] + koff); }
            #pragma unroll
            for (int nt = 0; nt < 2; nt++) { ldm_x4(bh[nt], bB[0][nt] + koff); ldm_x4(bl[nt], bB[1][nt] + koff); }
            #pragma unroll
            for (int mi = 0; mi < 2; mi++)
                #pragma unroll
                for (int nt = 0; nt < 2; nt++) {
                    mma_bf16(acc[mi][nt*2],   ah[mi], &bh[nt][0]);
                    mma_bf16(acc[mi][nt*2+1], ah[mi], &bh[nt][2]);
                    mma_bf16(acc[mi][nt*2],   ah[mi], &bl[nt][0]);
                    mma_bf16(acc[mi][nt*2+1], ah[mi], &bl[nt][2]);
                    mma_bf16(acc[mi][nt*2],   al[mi], &bh[nt][0]);
                    mma_bf16(acc[mi][nt*2+1], al[mi], &bh[nt][2]);
                }
        }

        float lsS[2][2], lsD[2][2];
        lsS[0][0]=0.f; lsS[0][1]=0.f; lsS[1][0]=0.f; lsS[1][1]=0.f;
        lsD[0][0]=0.f; lsD[0][1]=0.f; lsD[1][0]=0.f; lsD[1][1]=0.f;

        #pragma unroll
        for (int mi = 0; mi < 2; mi++) {
            #pragma unroll
            for (int ni = 0; ni < 4; ni++) {
                int cc = col0 + ni*8 + t*2;
                int r1 = bm + row0 + mi*16 + g;
                float2 v0 = make_float2(acc[mi][ni][0], acc[mi][ni][1]);
                float2 v1 = make_float2(acc[mi][ni][2], acc[mi][ni][3]);
                float a0 = __ldg(attS + cc), a1 = __ldg(attS + cc + 1);
                float d0 = __ldg(attD + cc), d1 = __ldg(attD + cc + 1);
                lsS[mi][0] += v0.x*a0 + v0.y*a1;
                lsS[mi][1] += v1.x*a0 + v1.y*a1;
                lsD[mi][0] += v0.x*d0 + v0.y*d1;
                lsD[mi][1] += v1.x*d0 + v1.y*d1;
                if (r1 < M)     *reinterpret_cast<__half2*>(C + (size_t)r1*128 + cc)     = __floats2half2_rn(v0.x, v0.y);
                if (r1 + 8 < M) *reinterpret_cast<__half2*>(C + (size_t)(r1+8)*128 + cc) = __floats2half2_rn(v1.x, v1.y);
            }
        }
        #pragma unroll
        for (int mi = 0; mi < 2; mi++)
            #pragma unroll
            for (int rr = 0; rr < 2; rr++) {
                float v = lsS[mi][rr];
                v += __shfl_xor_sync(0xffffffffu, v, 1);
                v += __shfl_xor_sync(0xffffffffu, v, 2);
                lsS[mi][rr] = v;
                float w = lsD[mi][rr];
                w += __shfl_xor_sync(0xffffffffu, w, 1);
                w += __shfl_xor_sync(0xffffffffu, w, 2);
                lsD[mi][rr] = w;
            }
        if (t == 0) {
            int head = col0 >> 5;
            #pragma unroll
            for (int mi = 0; mi < 2; mi++)
                #pragma unroll
                for (int rr = 0; rr < 2; rr++) {
                    int r = bm + row0 + mi*16 + g + rr*8;
                    if (r < M) {
                        outS[(size_t)r*4 + head] = lsS[mi][rr];
                        outD[(size_t)r*4 + head] = lsD[mi][rr];
                    }
                }
        }
        __syncthreads();
    }
}

// ----- chained GEMM: hc = relu(x_c@W_pre_c + b) (K=32, smem-resident) -> hcs = hc@W_ct_s ----
__global__ void __launch_bounds__(256, 2) tc_gemm_chain(
    const float* __restrict__ xc,
    const __nv_bfloat16* __restrict__ W1hi, const __nv_bfloat16* __restrict__ W1lo,
    const float* __restrict__ b1,
    const __nv_bfloat16* __restrict__ W2hi, const __nv_bfloat16* __restrict__ W2lo,
    __half* __restrict__ C, int M,
    const float* __restrict__ attS, float* __restrict__ outS)
{
    constexpr int LDA = 136;
    extern __shared__ __nv_bfloat16 smb[];
    __nv_bfloat16* sAhi = smb;
    __nv_bfloat16* sAlo = sAhi + 64*LDA;
    __nv_bfloat16* sWhi = sAlo + 64*LDA;
    __nv_bfloat16* sWlo = sWhi + 128*LDA;

    const int tid  = threadIdx.x;
    const int lane = tid & 31;
    const int wid  = tid >> 5;
    const int bm   = blockIdx.x * 64;

    for (int idx = tid; idx < 64*8; idx += 256) {
        int r  = idx >> 3;
        int k0 = (idx & 7) * 4;
        int row = bm + r;
        float4 v = make_float4(0.f, 0.f, 0.f, 0.f);
        if (row < M) v = *reinterpret_cast<const float4*>(xc + (size_t)row*32 + k0);
        __nv_bfloat16 h0 = __float2bfloat16(v.x), h1 = __float2bfloat16(v.y);
        __nv_bfloat16 h2 = __float2bfloat16(v.z), h3 = __float2bfloat16(v.w);
        __nv_bfloat16 l0 = __float2bfloat16(v.x - __bfloat162float(h0));
        __nv_bfloat16 l1 = __float2bfloat16(v.y - __bfloat162float(h1));
        __nv_bfloat16 l2 = __float2bfloat16(v.z - __bfloat162float(h2));
        __nv_bfloat16 l3 = __float2bfloat16(v.w - __bfloat162float(h3));
        __nv_bfloat16* pH = sAhi + r*LDA + k0;
        __nv_bfloat16* pL = sAlo + r*LDA + k0;
        *reinterpret_cast<__nv_bfloat162*>(pH)     = __halves2bfloat162(h0, h1);
        *reinterpret_cast<__nv_bfloat162*>(pH + 2) = __halves2bfloat162(h2, h3);
        *reinterpret_cast<__nv_bfloat162*>(pL)     = __halves2bfloat162(l0, l1);
        *reinterpret_cast<__nv_bfloat162*>(pL + 2) = __halves2bfloat162(l2, l3);
    }
    for (int idx = tid; idx < 128*4; idx += 256) {
        int n  = idx >> 2;
        int k0 = (idx & 3) * 8;
        *reinterpret_cast<uint4*>(sWhi + n*LDA + k0) = *reinterpret_cast<const uint4*>(W1hi + (size_t)n*32 + k0);
        *reinterpret_cast<uint4*>(sWlo + n*LDA + k0) = *reinterpret_cast<const uint4*>(W1lo + (size_t)n*32 + k0);
    }
    __syncthreads();

    const int row0 = (wid & 1) * 32;
    const int col0 = (wid >> 1) * 32;
    uint32_t aB[2][2], bB[2][2];
    {
        int ar = (lane & 15), ac = (lane >> 4) * 8;
        #pragma unroll
        for (int mi = 0; mi < 2; mi++) {
            aB[0][mi] = smem_u32(sAhi + (row0 + mi*16 + ar)*LDA + ac);
            aB[1][mi] = smem_u32(sAlo + (row0 + mi*16 + ar)*LDA + ac);
        }
        int q  = lane >> 3;
        int nr = (q >> 1)*8 + (lane & 7);
        int nc = (q & 1)*8;
        #pragma unroll
        for (int nt = 0; nt < 2; nt++) {
            bB[0][nt] = smem_u32(sWhi + (col0 + nt*16 + nr)*LDA + nc);
            bB[1][nt] = smem_u32(sWlo + (col0 + nt*16 + nr)*LDA + nc);
        }
    }
    const int g = lane >> 2, t = lane & 3;

    float acc[2][4][4];
    #pragma unroll
    for (int mi = 0; mi < 2; mi++)
        #pragma unroll
        for (int ni = 0; ni < 4; ni++)
            { acc[mi][ni][0]=0.f; acc[mi][ni][1]=0.f; acc[mi][ni][2]=0.f; acc[mi][ni][3]=0.f; }

    #pragma unroll
    for (int ks = 0; ks < 2; ks++) {     // K=32
        uint32_t koff = (uint32_t)ks * 32u;
        uint32_t ah[2][4], al[2][4], bh[2][4], bl[2][4];
        #pragma unroll
        for (int mi = 0; mi < 2; mi++) { ldm_x4(ah[mi], aB[0][mi] + koff); ldm_x4(al[mi], aB[1][mi] + koff); }
        #pragma unroll
        for (int nt = 0; nt < 2; nt++) { ldm_x4(bh[nt], bB[0][nt] + koff); ldm_x4(bl[nt], bB[1][nt] + koff); }
        #pragma unroll
        for (int mi = 0; mi < 2; mi++)
            #pragma unroll
            for (int nt = 0; nt < 2; nt++) {
                mma_bf16(acc[mi][nt*2],   ah[mi], &bh[nt][0]);
                mma_bf16(acc[mi][nt*2+1], ah[mi], &bh[nt][2]);
                mma_bf16(acc[mi][nt*2],   ah[mi], &bl[nt][0]);
                mma_bf16(acc[mi][nt*2+1], ah[mi], &bl[nt][2]);
                mma_bf16(acc[mi][nt*2],   al[mi], &bh[nt][0]);
                mma_bf16(acc[mi][nt*2+1], al[mi], &bh[nt][2]);
            }
    }
    __syncthreads();

    #pragma unroll
    for (int mi = 0; mi < 2; mi++) {
        #pragma unroll
        for (int ni = 0; ni < 4; ni++) {
            int cc = col0 + ni*8 + t*2;
            float bx = b1[cc], by = b1[cc+1];
            float2 v0 = make_float2(fmaxf(acc[mi][ni][0] + bx, 0.f), fmaxf(acc[mi][ni][1] + by, 0.f));
            float2 v1 = make_float2(fmaxf(acc[mi][ni][2] + bx, 0.f), fmaxf(acc[mi][ni][3] + by, 0.f));
            int rl0 = row0 + mi*16 + g;
            __nv_bfloat16 a0 = __float2bfloat16(v0.x), a1 = __float2bfloat16(v0.y);
            __nv_bfloat16 c0 = __float2bfloat16(v1.x), c1 = __float2bfloat16(v1.y);
            *reinterpret_cast<__nv_bfloat162*>(sAhi + rl0*LDA + cc)     = __halves2bfloat162(a0, a1);
            *reinterpret_cast<__nv_bfloat162*>(sAlo + rl0*LDA + cc)     =
                __halves2bfloat162(__float2bfloat16(v0.x - __bfloat162float(a0)),
                                   __float2bfloat16(v0.y - __bfloat162float(a1)));
            *reinterpret_cast<__nv_bfloat162*>(sAhi + (rl0+8)*LDA + cc) = __halves2bfloat162(c0, c1);
            *reinterpret_cast<__nv_bfloat162*>(sAlo + (rl0+8)*LDA + cc) =
                __halves2bfloat162(__float2bfloat16(v1.x - __bfloat162float(c0)),
                                   __float2bfloat16(v1.y - __bfloat162float(c1)));
        }
    }
    for (int idx = tid; idx < 128*16; idx += 256) {
        int n  = idx >> 4;
        int k0 = (idx & 15) * 8;
        *reinterpret_cast<uint4*>(sWhi + n*LDA + k0) = *reinterpret_cast<const uint4*>(W2hi + (size_t)n*128 + k0);
        *reinterpret_cast<uint4*>(sWlo + n*LDA + k0) = *reinterpret_cast<const uint4*>(W2lo + (size_t)n*128 + k0);
    }
    __syncthreads();

    #pragma unroll
    for (int mi = 0; mi < 2; mi++)
        #pragma unroll
        for (int ni = 0; ni < 4; ni++)
            { acc[mi][ni][0]=0.f; acc[mi][ni][1]=0.f; acc[mi][ni][2]=0.f; acc[mi][ni][3]=0.f; }

    #pragma unroll 2
    for (int ks = 0; ks < 8; ks++) {
        uint32_t koff = (uint32_t)ks * 32u;
        uint32_t ah[2][4], al[2][4], bh[2][4], bl[2][4];
        #pragma unroll
        for (int mi = 0; mi < 2; mi++) { ldm_x4(ah[mi], aB[0][mi] + koff); ldm_x4(al[mi], aB[1][mi] + koff); }
        #pragma unroll
        for (int nt = 0; nt < 2; nt++) { ldm_x4(bh[nt], bB[0][nt] + koff); ldm_x4(bl[nt], bB[1][nt] + koff); }
        #pragma unroll
        for (int mi = 0; mi < 2; mi++)
            #pragma unroll
            for (int nt = 0; nt < 2; nt++) {
                mma_bf16(acc[mi][nt*2],   ah[mi], &bh[nt][0]);
                mma_bf16(acc[mi][nt*2+1], ah[mi], &bh[nt][2]);
                mma_bf16(acc[mi][nt*2],   ah[mi], &bl[nt][0]);
                mma_bf16(acc[mi][nt*2+1], ah[mi], &bl[nt][2]);
                mma_bf16(acc[mi][nt*2],   al[mi], &bh[nt][0]);
                mma_bf16(acc[mi][nt*2+1], al[mi], &bh[nt][2]);
            }
    }

    float lsS[2][2];
    lsS[0][0]=0.f; lsS[0][1]=0.f; lsS[1][0]=0.f; lsS[1][1]=0.f;
    #pragma unroll
    for (int mi = 0; mi < 2; mi++) {
        #pragma unroll
        for (int ni = 0; ni < 4; ni++) {
            int cc = col0 + ni*8 + t*2;
            int r1 = bm + row0 + mi*16 + g;
            float2 v0 = make_float2(acc[mi][ni][0], acc[mi][ni][1]);
            float2 v1 = make_float2(acc[mi][ni][2], acc[mi][ni][3]);
            float a0 = __ldg(attS + cc), a1 = __ldg(attS + cc + 1);
            lsS[mi][0] += v0.x*a0 + v0.y*a1;
            lsS[mi][1] += v1.x*a0 + v1.y*a1;
            if (r1 < M)     *reinterpret_cast<__half2*>(C + (size_t)r1*128 + cc)     = __floats2half2_rn(v0.x, v0.y);
            if (r1 + 8 < M) *reinterpret_cast<__half2*>(C + (size_t)(r1+8)*128 + cc) = __floats2half2_rn(v1.x, v1.y);
        }
    }
    #pragma unroll
    for (int mi = 0; mi < 2; mi++)
        #pragma unroll
        for (int rr = 0; rr < 2; rr++) {
            float v = lsS[mi][rr];
            v += __shfl_xor_sync(0xffffffffu, v, 1);
            v += __shfl_xor_sync(0xffffffffu, v, 2);
            lsS[mi][rr] = v;
        }
    if (t == 0) {
        int head = col0 >> 5;
        #pragma unroll
        for (int mi = 0; mi < 2; mi++)
            #pragma unroll
            for (int rr = 0; rr < 2; rr++) {
                int r = bm + row0 + mi*16 + g + rr*8;
                if (r < M) outS[(size_t)r*4 + head] = lsS[mi][rr];
            }
    }
}

// --------------------------------- CSR build ------------------------------------------------
__global__ void hist_all_kernel(const int* __restrict__ e0, const int* __restrict__ e1,
                                const int* __restrict__ ed)
{
    const int total = ETTg + ECTg;
    for (int i = blockIdx.x*blockDim.x + threadIdx.x; i < total; i += gridDim.x*blockDim.x) {
        if (i < ETTg) {
            atomicAdd(&g_deg[0*NTg + e1[i]], 1);
            atomicAdd(&g_deg[1*NTg + e0[i]], 1);
        } else {
            atomicAdd(&g_deg[2*NTg + ed[i - ETTg]], 1);
        }
    }
}

__global__ void scan1_kernel()
{
    int arr  = blockIdx.y;
    int base = blockIdx.x * 1024 + threadIdx.x;
    int lane = threadIdx.x & 31, wid = threadIdx.x >> 5;
    int v = (base < NTg) ? g_deg[arr*NTg + base] : 0;
    int x = v;
    #pragma unroll
    for (int o = 1; o < 32; o <<= 1) { int y = __shfl_up_sync(0xffffffffu, x, o); if (lane >= o) x += y; }
    __shared__ int ws[32];
    if (lane == 31) ws[wid] = x;
    __syncthreads();
    if (wid == 0) {
        int wv = ws[lane]; int wx = wv;
        #pragma unroll
        for (int o = 1; o < 32; o <<= 1) { int y = __shfl_up_sync(0xffffffffu, wx, o); if (lane >= o) wx += y; }
        if (lane == 31) g_aux[arr*128 + blockIdx.x] = wx;
        ws[lane] = wx - wv;
    }
    __syncthreads();
    int excl = x - v + ws[wid];
    if (base < NTg) g_cur[arr*NTg + base] = excl;
}

__global__ void scan2_kernel()
{
    int arr  = threadIdx.x >> 5;
    int lane = threadIdx.x & 31;
    if (arr >= 3) return;
    const int NB = (NTg + 1023) / 1024;
    int carry = 0;
    for (int c = 0; c*32 < NB; c++) {
        int idx = c*32 + lane;
        int v = (idx < NB) ? g_aux[arr*128 + idx] : 0;
        int x = v;
        #pragma unroll
        for (int o = 1; o < 32; o <<= 1) { int y = __shfl_up_sync(0xffffffffu, x, o); if (lane >= o) x += y; }
        if (idx < NB) g_aux[arr*128 + idx] = x - v + carry;
        carry += __shfl_sync(0xffffffffu, x, 31);
    }
}

__global__ void scan3_kernel()
{
    for (int i = blockIdx.x*blockDim.x + threadIdx.x; i < 3*NTg; i += gridDim.x*blockDim.x) {
        int arr = i / NTg; int idx = i - arr*NTg;
        g_cur[i] += g_aux[arr*128 + (idx >> 10)];
    }
}

__global__ void fill_all_kernel(const int* __restrict__ e0, const int* __restrict__ e1,
                                const int* __restrict__ es, const int* __restrict__ ed)
{
    const int total = ETTg + ECTg;
    for (int i = blockIdx.x*blockDim.x + threadIdx.x; i < total; i += gridDim.x*blockDim.x) {
        if (i < ETTg) {
            int s = e0[i], d = e1[i];
            int p = atomicAdd(&g_cur[0*NTg + d], 1); g_csrf[p] = s;
            int q = atomicAdd(&g_cur[1*NTg + s], 1); g_csrr[q] = d;
        } else {
            int j = i - ETTg;
            int p = atomicAdd(&g_cur[2*NTg + ed[j]], 1); g_csrct[p] = es[j];
        }
    }
}

// ----- per-relation GAT, half2 layout: lane owns cols {2l,2l+1} (head l>=16) and {64+2l,..} --
template<bool SELF>
__device__ __forceinline__ void gat_rel(
    const __half* __restrict__ hsrc, const float* __restrict__ a_s,
    const int* __restrict__ csr, int start, int cnt, int d, int lane,
    float4 ad, float wgt, float r[4])
{
    if (!SELF && cnt == 0) { r[0]=0.f; r[1]=0.f; r[2]=0.f; r[3]=0.f; return; }

    const bool hi16 = (lane >= 16);
    const float adA = hi16 ? ad.y : ad.x;
    const float adB = hi16 ? ad.w : ad.z;

    float denA = 0.f, denB = 0.f;
    float2 acA = make_float2(0.f, 0.f), acB = make_float2(0.f, 0.f);

    if (SELF) {
        float4 as = *reinterpret_cast<const float4*>(a_s + (size_t)d*4);
        float pa = __expf(lrelu02((hi16 ? as.y : as.x) + adA));
        float pb = __expf(lrelu02((hi16 ? as.w : as.z) + adB));
        denA = pa; denB = pb;
        const __half2* row2 = reinterpret_cast<const __half2*>(hsrc + (size_t)d*128);
        float2 fa = __half22float2(row2[lane]);
        float2 fb = __half22float2(row2[32 + lane]);
        acA.x = pa * fa.x; acA.y = pa * fa.y;
        acB.x = pb * fb.x; acB.y = pb * fb.y;
    }
    #pragma unroll 2
    for (int i = 0; i < cnt; i++) {
        int s = csr[start + i];
        float4 as = *reinterpret_cast<const float4*>(a_s + (size_t)s*4);
        float pa = __expf(lrelu02((hi16 ? as.y : as.x) + adA));
        float pb = __expf(lrelu02((hi16 ? as.w : as.z) + adB));
        denA += pa; denB += pb;
        const __half2* row2 = reinterpret_cast<const __half2*>(hsrc + (size_t)s*128);
        float2 fa = __half22float2(row2[lane]);
        float2 fb = __half22float2(row2[32 + lane]);
        acA.x = fmaf(pa, fa.x, acA.x); acA.y = fmaf(pa, fa.y, acA.y);
        acB.x = fmaf(pb, fb.x, acB.x); acB.y = fmaf(pb, fb.y, acB.y);
    }

    float ia = wgt / denA, ib = wgt / denB;
    r[0] = acA.x * ia; r[1] = acA.y * ia;
    r[2] = acB.x * ib; r[3] = acB.y * ib;
}

// --- merged GAT over all 3 relations; writes z = relu(acc + cbias + ht) as fp16 -------------
__global__ void gat_all_kernel(
    const __half* __restrict__ hs, const __half* __restrict__ hd, const __half* __restrict__ hcs,
    const float* __restrict__ ht,
    const float* __restrict__ asf, const float* __restrict__ adf,
    const float* __restrict__ asr, const float* __restrict__ adr,
    const float* __restrict__ asct, const float* __restrict__ adct,
    const int* __restrict__ cur, const int* __restrict__ deg,
    const int* __restrict__ csrf, const int* __restrict__ csrr, const int* __restrict__ csrct,
    const float* __restrict__ bsd, const float* __restrict__ bds, const float* __restrict__ bct,
    __half* __restrict__ z)
{
    int d    = (blockIdx.x * blockDim.x + threadIdx.x) >> 5;
    int lane = threadIdx.x & 31;
    if (d >= NTg) return;

    float rf[4], rr_[4], rc[4];
    {
        int c = deg[0*NTg + d];
        gat_rel<true >(hs, asf, csrf, cur[0*NTg + d] - c, c, d, lane,
                       *reinterpret_cast<const float4*>(adf + (size_t)d*4), 0.25f, rf);
    }
    {
        int c = deg[1*NTg + d];
        gat_rel<true >(hd, asr, csrr, cur[1*NTg + d] - c, c, d, lane,
                       *reinterpret_cast<const float4*>(adr + (size_t)d*4), 0.25f, rr_);
    }
    {
        int c = deg[2*NTg + d];
        gat_rel<false>(hcs, asct, csrct, cur[2*NTg + d] - c, c, d, lane,
                       *reinterpret_cast<const float4*>(adct + (size_t)d*4), 0.5f, rc);
    }

    int cA = 2*lane, cB = 64 + 2*lane;
    const float2* hrow2 = reinterpret_cast<const float2*>(ht + (size_t)d*128);
    float2 ha = hrow2[lane], hb = hrow2[32 + lane];
    float cbA0 = 0.25f*bsd[cA]   + 0.25f*bds[cA]   + 0.5f*bct[cA];
    float cbA1 = 0.25f*bsd[cA+1] + 0.25f*bds[cA+1] + 0.5f*bct[cA+1];
    float cbB0 = 0.25f*bsd[cB]   + 0.25f*bds[cB]   + 0.5f*bct[cB];
    float cbB1 = 0.25f*bsd[cB+1] + 0.25f*bds[cB+1] + 0.5f*bct[cB+1];

    __half2* zrow2 = reinterpret_cast<__half2*>(z + (size_t)d*128);
    float zA0 = fmaxf(rf[0] + rr_[0] + rc[0] + ha.x + cbA0, 0.f);
    float zA1 = fmaxf(rf[1] + rr_[1] + rc[1] + ha.y + cbA1, 0.f);
    float zB0 = fmaxf(rf[2] + rr_[2] + rc[2] + hb.x + cbB0, 0.f);
    float zB1 = fmaxf(rf[3] + rr_[3] + rc[3] + hb.y + cbB1, 0.f);
    zrow2[lane]      = __floats2half2_rn(zA0, zA1);
    zrow2[32 + lane] = __floats2half2_rn(zB0, zB1);
}

// ----------------------------------- launch -------------------------------------------------
extern "C" void kernel_launch(void* const* d_in, const int* in_sizes, int n_in,
                              void* d_out, int out_size)
{
    const float* x_t     = (const float*)d_in[0];
    const float* x_c     = (const float*)d_in[1];
    const int*   ett     = (const int*)d_in[2];
    const int*   e0      = ett;
    const int*   e1      = ett + ETTg;
    const int*   ect_s   = (const int*)d_in[3];
    const int*   ect_d   = (const int*)d_in[4];
    const float* W_pre_t = (const float*)d_in[5];
    const float* b_pre_t = (const float*)d_in[6];
    const float* W_pre_c = (const float*)d_in[7];
    const float* b_pre_c = (const float*)d_in[8];
    const float* W_sd    = (const float*)d_in[9];
    const float* att_s_sd= (const float*)d_in[10];
    const float* att_d_sd= (const float*)d_in[11];
    const float* b_sd    = (const float*)d_in[12];
    const float* W_ds    = (const float*)d_in[13];
    const float* att_s_ds= (const float*)d_in[14];
    const float* att_d_ds= (const float*)d_in[15];
    const float* b_ds    = (const float*)d_in[16];
    const float* W_ct_s  = (const float*)d_in[17];
    const float* W_ct_d  = (const float*)d_in[18];
    const float* att_s_ct= (const float*)d_in[19];
    const float* att_d_ct= (const float*)d_in[20];
    const float* b_ct    = (const float*)d_in[21];
    const float* W_out   = (const float*)d_in[22];
    const float* b_out   = (const float*)d_in[23];
    float* out = (float*)d_out;

    float *p_ht, *p_wv;
    __half *p_hs, *p_hd, *p_hcs, *p_z;
    float *p_asf, *p_adf, *p_asr, *p_adr, *p_adct, *p_asct;
    int *p_deg, *p_cur, *p_csrf, *p_csrr, *p_csrct;
    __nv_bfloat16 *p_whi, *p_wlo;
    cudaGetSymbolAddress((void**)&p_ht,  g_ht);
    cudaGetSymbolAddress((void**)&p_hs,  g_hs);
    cudaGetSymbolAddress((void**)&p_hd,  g_hd);
    cudaGetSymbolAddress((void**)&p_hcs, g_hcs);
    cudaGetSymbolAddress((void**)&p_z,   g_z);
    cudaGetSymbolAddress((void**)&p_wv,  g_wv);
    cudaGetSymbolAddress((void**)&p_asf, g_asf);
    cudaGetSymbolAddress((void**)&p_adf, g_adf);
    cudaGetSymbolAddress((void**)&p_asr, g_asr);
    cudaGetSymbolAddress((void**)&p_adr, g_adr);
    cudaGetSymbolAddress((void**)&p_adct,g_adct);
    cudaGetSymbolAddress((void**)&p_asct,g_asct);
    cudaGetSymbolAddress((void**)&p_deg, g_deg);
    cudaGetSymbolAddress((void**)&p_cur, g_cur);
    cudaGetSymbolAddress((void**)&p_csrf, g_csrf);
    cudaGetSymbolAddress((void**)&p_csrr, g_csrr);
    cudaGetSymbolAddress((void**)&p_csrct,g_csrct);
    cudaGetSymbolAddress((void**)&p_whi, g_whi);
    cudaGetSymbolAddress((void**)&p_wlo, g_wlo);

    const int SM128 = (2*64 + 2*128) * (128 + 8) * 2;   // 104448
    cudaFuncSetAttribute(tc_gemm_triple, cudaFuncAttributeMaxDynamicSharedMemorySize, SM128 + 4096);
    cudaFuncSetAttribute(tc_gemm_chain,  cudaFuncAttributeMaxDynamicSharedMemorySize, SM128);
    cudaFuncSetAttribute(tc_gemm_h,      cudaFuncAttributeMaxDynamicSharedMemorySize, SM128);

    const int GT = (NTg + 63) / 64;   // 1563
    const int GC = (NCg + 63) / 64;   // 391

    WJobs jobs;
    jobs.W[0] = W_pre_t; jobs.K[0] = 64;
    jobs.W[1] = W_pre_c; jobs.K[1] = 32;
    jobs.W[2] = W_sd;    jobs.K[2] = 128;
    jobs.W[3] = W_ds;    jobs.K[3] = 128;
    jobs.W[4] = W_ct_s;  jobs.K[4] = 128;
    jobs.W[5] = W_out;   jobs.K[5] = 128;

    // Second stream for the CSR branch (created once; host-side objects only).
    static cudaStream_t s2 = nullptr;
    static cudaEvent_t evFork = nullptr, evJoin = nullptr;
    if (!s2) {
        cudaStreamCreateWithFlags(&s2, cudaStreamNonBlocking);
        cudaEventCreateWithFlags(&evFork, cudaEventDisableTiming);
        cudaEventCreateWithFlags(&evJoin, cudaEventDisableTiming);
    }

    // ---- fork: CSR branch on s2 (independent of all GEMM work) ----
    cudaEventRecord(evFork, 0);
    cudaStreamWaitEvent(s2, evFork, 0);
    cudaMemsetAsync(p_deg, 0, 3*NTg*sizeof(int), s2);
    hist_all_kernel<<<768, 256, 0, s2>>>(e0, e1, ect_d);
    {
        dim3 g1((NTg + 1023) / 1024, 3);
        scan1_kernel<<<g1, 1024, 0, s2>>>();
    }
    scan2_kernel<<<1, 96, 0, s2>>>();
    scan3_kernel<<<256, 256, 0, s2>>>();
    fill_all_kernel<<<768, 256, 0, s2>>>(e0, e1, ect_s, ect_d);
    cudaEventRecord(evJoin, s2);

    // ---- main branch: GEMM phase ----
    wv_kernel<<<1, 512>>>(W_ct_d, att_d_ct, p_wv);
    wsplit_all<<<dim3(64, 6), 256>>>(jobs, p_whi, p_wlo);
    tc_gemm_triple<<<GT, 256, SM128 + 4096>>>(x_t,
        p_whi + 0*16384, p_wlo + 0*16384, b_pre_t, p_wv, p_ht, p_adct,
        p_whi + 2*16384, p_wlo + 2*16384, p_whi + 3*16384, p_wlo + 3*16384,
        p_hs, p_hd, NTg,
        att_s_sd, att_d_sd, att_s_ds, att_d_ds,
        p_asf, p_adf, p_asr, p_adr);
    tc_gemm_chain<<<GC, 256, SM128>>>(x_c,
        p_whi + 1*16384, p_wlo + 1*16384, b_pre_c,
        p_whi + 4*16384, p_wlo + 4*16384,
        p_hcs, NCg, att_s_ct, p_asct);

    // ---- join: GAT needs both branches ----
    cudaStreamWaitEvent(0, evJoin, 0);

    gat_all_kernel<<<(NTg + 7) / 8, 256>>>(
        p_hs, p_hd, p_hcs, p_ht,
        p_asf, p_adf, p_asr, p_adr, p_asct, p_adct,
        p_cur, p_deg, p_csrf, p_csrr, p_csrct,
        b_sd, b_ds, b_ct, p_z);

    tc_gemm_h<<<GT, 256, SM128>>>(p_z, p_whi + 5*16384, p_wlo + 5*16384,
        b_out, out, NTg);
}